// round 7
// baseline (speedup 1.0000x reference)
#include <cuda_runtime.h>
#include <math.h>
#include <float.h>

// ---------------------------------------------------------------------------
// Problem constants
// ---------------------------------------------------------------------------
constexpr int cB   = 16;
constexpr int cN   = 2048;
constexpr int cG   = 128;
constexpr int cM   = 32;
constexpr int cDM  = 384;
constexpr int cNL  = 12;
constexpr int cDI  = 768;
constexpr int cDS  = 16;
constexpr int cDTR = 24;
constexpr int cTOK = cB * cG;        // 2048 tokens
constexpr int cPTS = cTOK * cM;      // 65536 points

// ---------------------------------------------------------------------------
// Scratch (device globals; no dynamic allocation allowed)
// ---------------------------------------------------------------------------
__device__ __align__(16) float g_center[cTOK * 3];
__device__ __align__(16) float g_nb[cPTS * 3];
__device__ __align__(16) float g_f2[(size_t)cPTS * 256];
__device__ __align__(16) float g_fg[cTOK * 256];
__device__ __align__(16) float g_f3[(size_t)cPTS * 512];
__device__ __align__(16) float g_pos1[cTOK * 128];
__device__ __align__(16) float g_h[cTOK * cDM];
__device__ __align__(16) float g_res[cTOK * cDM];
__device__ __align__(16) float g_xln[cTOK * cDM];
__device__ __align__(16) float g_xz[(size_t)cTOK * 2 * cDI];
__device__ __align__(16) float g_dbl64[cTOK * 64];
__device__ __align__(16) float g_dt[(size_t)cTOK * cDI];
__device__ __align__(16) float g_u[(size_t)cTOK * cDI];
__device__ __align__(16) float g_xpw[cNL * 64 * cDI];
__device__ __align__(16) float g_dtw[cNL * cDI * 32];

using u32 = unsigned int;

__device__ __forceinline__ u32 cvt_tf32(float x) {
    u32 r;
    asm("cvt.rna.tf32.f32 %0, %1;" : "=r"(r) : "f"(x));
    return r;
}

__device__ __forceinline__ void mma_tf32(float* c, u32 a0, u32 a1, u32 a2, u32 a3,
                                         u32 b0, u32 b1) {
    asm volatile(
        "mma.sync.aligned.m16n8k8.row.col.f32.tf32.tf32.f32 "
        "{%0,%1,%2,%3}, {%4,%5,%6,%7}, {%8,%9}, {%0,%1,%2,%3};"
        : "+f"(c[0]), "+f"(c[1]), "+f"(c[2]), "+f"(c[3])
        : "r"(a0), "r"(a1), "r"(a2), "r"(a3), "r"(b0), "r"(b1));
}

// ---------------------------------------------------------------------------
// Generic tf32 tensor-core GEMM: C = epi(A' @ W^T) where A' depends on MODEA.
//   CTA tile BM x BN, warp grid WGM x WGN. BK=16, double-buffered smem.
//   EPI 0: +bias(opt). 1: relu(bn(.+bias)). 2: softplus(.+bias). 3: C += .+bias
//   MODEA 0: A' = A (row-major, lda)
//   MODEA 1: A' cols [0,256) from aux1[row>>5][k] (group feat), rest from A
//   MODEA 2: A' = relu(bn1(nb @ w1^T + b1)): A=nb, aux1=w1, aux2=b1,
//            p1=bn gamma, p2=bn beta  (K=128)
//   MODEA 3: A' = silu(causalconv4(A)): A=xz (lda=1536), aux1=cw, aux2=cb;
//            BM must equal 128 (batch-aligned tiles)
//   EMAX  0: normal epilogue.
//   EMAX  1: EPI must be 0 w/ bias; write C AND 32-row group max to fgout.
//   EMAX  2: write ONLY 32-row group max (C unused). Requires WTM==64.
// ---------------------------------------------------------------------------
template<int BM, int BN, int WGM, int WGN, int EPI, int MODEA, int EMAX>
__global__ void __launch_bounds__(WGM * WGN * 32)
tc2(const float* __restrict__ A, const float* __restrict__ W,
    const float* __restrict__ bias, const float* __restrict__ p1,
    const float* __restrict__ p2, float* __restrict__ C,
    int K, int lda, int ldw, int ldc,
    const float* __restrict__ aux1, const float* __restrict__ aux2,
    float* __restrict__ fgout, int ldfg)
{
    constexpr int THREADS = WGM * WGN * 32;
    constexpr int WTM = BM / WGM, WTN = BN / WGN;
    constexpr int MT = WTM / 16, NT = WTN / 8;
    constexpr int LA = BM + 8, LB = BN + 8;
    constexpr int A4 = (BM * 16) / (THREADS * 4);
    constexpr int W4 = (BN * 16) / (THREADS * 4);
    static_assert(EMAX == 0 || WTM == 64, "EMAX needs WTM==64");

    __shared__ float As[2][16][LA];
    __shared__ float Ws[2][16][LB];

    const int tid = threadIdx.x;
    const int wid = tid >> 5, lane = tid & 31;
    const int grp = lane >> 2, tig = lane & 3;
    const int wm = wid % WGM, wn = wid / WGM;
    const int m0 = blockIdx.x * BM, n0 = blockIdx.y * BN;
    const float bnscale = rsqrtf(1.0f + 1e-5f);

    float acc[MT][NT][4];
#pragma unroll
    for (int mt = 0; mt < MT; mt++)
#pragma unroll
        for (int nt = 0; nt < NT; nt++)
#pragma unroll
            for (int r = 0; r < 4; r++) acc[mt][nt][r] = 0.f;

    // MODEA==2: hoist per-row point coords (rows fixed per thread across chunks)
    float nbr[MODEA == 2 ? A4 : 1][3];
    if (MODEA == 2) {
#pragma unroll
        for (int v = 0; v < A4; v++) {
            int row = (tid + v * THREADS) >> 2;
            nbr[v][0] = A[(size_t)(m0 + row) * 3 + 0];
            nbr[v][1] = A[(size_t)(m0 + row) * 3 + 1];
            nbr[v][2] = A[(size_t)(m0 + row) * 3 + 2];
        }
    }

    float4 ra[A4], rw[W4];

    auto loadG = [&](int kc) {
#pragma unroll
        for (int v = 0; v < A4; v++) {
            int s = tid + v * THREADS;
            int row = s >> 2;
            int k = kc + (s & 3) * 4;
            if (MODEA == 0) {
                ra[v] = *(const float4*)(A + (size_t)(m0 + row) * lda + k);
            } else if (MODEA == 1) {
                int r = m0 + row;
                const float* src = (k < 256)
                    ? (aux1 + ((size_t)(r >> 5)) * 256 + k)
                    : (A + (size_t)r * lda + (k - 256));
                ra[v] = *(const float4*)src;
            } else if (MODEA == 2) {
                float out[4];
#pragma unroll
                for (int e = 0; e < 4; e++) {
                    int kk = k + e;
                    float val = nbr[v][0] * aux1[kk * 3 + 0]
                              + nbr[v][1] * aux1[kk * 3 + 1]
                              + nbr[v][2] * aux1[kk * 3 + 2] + aux2[kk];
                    val = val * (p1[kk] * bnscale) + p2[kk];
                    out[e] = fmaxf(val, 0.f);
                }
                ra[v] = make_float4(out[0], out[1], out[2], out[3]);
            } else { // MODEA == 3: causal 4-tap conv + silu over A=xz
                int t = m0 + row;
                int l = t & 127;
                float4 cbv = *(const float4*)(aux2 + k);
                float accv[4] = {cbv.x, cbv.y, cbv.z, cbv.w};
                float4 cwv[4];
#pragma unroll
                for (int e = 0; e < 4; e++)
                    cwv[e] = *(const float4*)(aux1 + (size_t)(k + e) * 4);
#pragma unroll
                for (int j = 0; j < 4; j++) {
                    if (l - 3 + j >= 0) {
                        float4 xv = *(const float4*)(A + (size_t)(t - 3 + j) * lda + k);
                        accv[0] += xv.x * ((const float*)&cwv[0])[j];
                        accv[1] += xv.y * ((const float*)&cwv[1])[j];
                        accv[2] += xv.z * ((const float*)&cwv[2])[j];
                        accv[3] += xv.w * ((const float*)&cwv[3])[j];
                    }
                }
                float out[4];
#pragma unroll
                for (int e = 0; e < 4; e++)
                    out[e] = accv[e] / (1.0f + expf(-accv[e]));
                ra[v] = make_float4(out[0], out[1], out[2], out[3]);
            }
        }
#pragma unroll
        for (int v = 0; v < W4; v++) {
            int s = tid + v * THREADS;
            int row = s >> 2, k4 = s & 3;
            rw[v] = *(const float4*)(W + (size_t)(n0 + row) * ldw + kc + k4 * 4);
        }
    };
    auto stsG = [&](int buf) {
#pragma unroll
        for (int v = 0; v < A4; v++) {
            int s = tid + v * THREADS;
            int row = s >> 2, kq = (s & 3) << 2;
            As[buf][kq + 0][row] = __uint_as_float(cvt_tf32(ra[v].x));
            As[buf][kq + 1][row] = __uint_as_float(cvt_tf32(ra[v].y));
            As[buf][kq + 2][row] = __uint_as_float(cvt_tf32(ra[v].z));
            As[buf][kq + 3][row] = __uint_as_float(cvt_tf32(ra[v].w));
        }
#pragma unroll
        for (int v = 0; v < W4; v++) {
            int s = tid + v * THREADS;
            int row = s >> 2, kq = (s & 3) << 2;
            Ws[buf][kq + 0][row] = __uint_as_float(cvt_tf32(rw[v].x));
            Ws[buf][kq + 1][row] = __uint_as_float(cvt_tf32(rw[v].y));
            Ws[buf][kq + 2][row] = __uint_as_float(cvt_tf32(rw[v].z));
            Ws[buf][kq + 3][row] = __uint_as_float(cvt_tf32(rw[v].w));
        }
    };

    const int nIter = K >> 4;
    loadG(0);
    stsG(0);
    __syncthreads();
    int buf = 0;

    for (int it = 0; it < nIter; it++) {
        bool more = (it + 1 < nIter);
        if (more) loadG((it + 1) << 4);
#pragma unroll
        for (int ks = 0; ks < 2; ks++) {
            const int k0 = ks * 8;
            u32 af[MT][4];
#pragma unroll
            for (int mt = 0; mt < MT; mt++) {
                int m = wm * WTM + mt * 16 + grp;
                af[mt][0] = __float_as_uint(As[buf][k0 + tig][m]);
                af[mt][1] = __float_as_uint(As[buf][k0 + tig][m + 8]);
                af[mt][2] = __float_as_uint(As[buf][k0 + tig + 4][m]);
                af[mt][3] = __float_as_uint(As[buf][k0 + tig + 4][m + 8]);
            }
            u32 bf[NT][2];
#pragma unroll
            for (int nt = 0; nt < NT; nt++) {
                int n = wn * WTN + nt * 8 + grp;
                bf[nt][0] = __float_as_uint(Ws[buf][k0 + tig][n]);
                bf[nt][1] = __float_as_uint(Ws[buf][k0 + tig + 4][n]);
            }
#pragma unroll
            for (int mt = 0; mt < MT; mt++)
#pragma unroll
                for (int nt = 0; nt < NT; nt++)
                    mma_tf32(acc[mt][nt], af[mt][0], af[mt][1], af[mt][2], af[mt][3],
                             bf[nt][0], bf[nt][1]);
        }
        if (more) {
            stsG(buf ^ 1);
            __syncthreads();
            buf ^= 1;
        }
    }

    if constexpr (EMAX == 0) {
        auto emit = [&](int mrow, int n, float v0, float v1) {
            if (EPI == 3) {
                C[(size_t)mrow * ldc + n]     += v0 + bias[n];
                C[(size_t)mrow * ldc + n + 1] += v1 + bias[n + 1];
                return;
            }
            if (EPI == 0) {
                if (bias) { v0 += bias[n]; v1 += bias[n + 1]; }
            } else if (EPI == 1) {
                v0 = fmaxf((v0 + bias[n]) * (p1[n] * bnscale) + p2[n], 0.f);
                v1 = fmaxf((v1 + bias[n + 1]) * (p1[n + 1] * bnscale) + p2[n + 1], 0.f);
            } else if (EPI == 2) {
                v0 += bias[n]; v1 += bias[n + 1];
                v0 = fmaxf(v0, 0.f) + log1pf(expf(-fabsf(v0)));
                v1 = fmaxf(v1, 0.f) + log1pf(expf(-fabsf(v1)));
            }
            float2 o; o.x = v0; o.y = v1;
            *(float2*)&C[(size_t)mrow * ldc + n] = o;
        };
#pragma unroll
        for (int mt = 0; mt < MT; mt++) {
            int mrow = m0 + wm * WTM + mt * 16 + grp;
#pragma unroll
            for (int nt = 0; nt < NT; nt++) {
                int n = n0 + wn * WTN + nt * 8 + tig * 2;
                emit(mrow,     n, acc[mt][nt][0], acc[mt][nt][1]);
                emit(mrow + 8, n, acc[mt][nt][2], acc[mt][nt][3]);
            }
        }
    } else {
        // 32-row group max epilogue (warp covers rows wm*64..+63 = 2 groups)
        float mx[2][NT][2];
#pragma unroll
        for (int g = 0; g < 2; g++)
#pragma unroll
            for (int nt = 0; nt < NT; nt++) {
                mx[g][nt][0] = -FLT_MAX; mx[g][nt][1] = -FLT_MAX;
            }
#pragma unroll
        for (int mt = 0; mt < MT; mt++) {
            int gsel = (mt >= MT / 2) ? 1 : 0;
            int mrow = m0 + wm * WTM + mt * 16 + grp;
#pragma unroll
            for (int nt = 0; nt < NT; nt++) {
                int n = n0 + wn * WTN + nt * 8 + tig * 2;
                float v0 = acc[mt][nt][0] + bias[n];
                float v1 = acc[mt][nt][1] + bias[n + 1];
                float v2 = acc[mt][nt][2] + bias[n];
                float v3 = acc[mt][nt][3] + bias[n + 1];
                if (EMAX == 1) {
                    float2 o0; o0.x = v0; o0.y = v1;
                    float2 o1; o1.x = v2; o1.y = v3;
                    *(float2*)&C[(size_t)mrow * ldc + n] = o0;
                    *(float2*)&C[(size_t)(mrow + 8) * ldc + n] = o1;
                }
                mx[gsel][nt][0] = fmaxf(mx[gsel][nt][0], fmaxf(v0, v2));
                mx[gsel][nt][1] = fmaxf(mx[gsel][nt][1], fmaxf(v1, v3));
            }
        }
#pragma unroll
        for (int g = 0; g < 2; g++) {
#pragma unroll
            for (int nt = 0; nt < NT; nt++)
#pragma unroll
                for (int c = 0; c < 2; c++) {
                    float v = mx[g][nt][c];
                    v = fmaxf(v, __shfl_xor_sync(0xffffffffu, v, 4));
                    v = fmaxf(v, __shfl_xor_sync(0xffffffffu, v, 8));
                    v = fmaxf(v, __shfl_xor_sync(0xffffffffu, v, 16));
                    mx[g][nt][c] = v;
                }
            if (lane < 4) {
                int grow = (m0 >> 5) + wm * 2 + g;
#pragma unroll
                for (int nt = 0; nt < NT; nt++) {
                    int n = n0 + wn * WTN + nt * 8 + tig * 2;
                    fgout[(size_t)grow * ldfg + n]     = mx[g][nt][0];
                    fgout[(size_t)grow * ldfg + n + 1] = mx[g][nt][1];
                }
            }
        }
    }
}

// ---------------------------------------------------------------------------
// Pad xp_w (56x768 -> 64x768, zero rows) and dt_w (768x24 -> 768x32, zero cols)
// ---------------------------------------------------------------------------
__global__ void pad_weights(const float* __restrict__ xp_w,
                            const float* __restrict__ dt_w) {
    int idx = blockIdx.x * 256 + threadIdx.x;
    constexpr int NXP = cNL * 64 * cDI;
    constexpr int NDT = cNL * cDI * 32;
    if (idx < NXP) {
        int l = idx / (64 * cDI);
        int r = (idx / cDI) % 64;
        int k = idx % cDI;
        g_xpw[idx] = (r < 56) ? xp_w[((size_t)l * 56 + r) * cDI + k] : 0.f;
    } else if (idx < NXP + NDT) {
        int j = idx - NXP;
        int l = j / (cDI * 32);
        int d = (j / 32) % cDI;
        int k = j % 32;
        g_dtw[j] = (k < 24) ? dt_w[((size_t)l * cDI + d) * cDTR + k] : 0.f;
    }
}

// ---------------------------------------------------------------------------
// FPS: per batch, exact replication of reference scan (incl. tie-breaking)
// ---------------------------------------------------------------------------
__global__ void fps_kernel(const float* __restrict__ xyz) {
    int b = blockIdx.x;
    __shared__ float px[cN], py[cN], pz[cN], dmin[cN];
    __shared__ float wv[8];
    __shared__ int   wi[8];
    __shared__ int   s_cur;
    int tid = threadIdx.x;
    int wid = tid >> 5, lane = tid & 31;
    for (int i = tid; i < cN; i += 256) {
        px[i] = xyz[(b * cN + i) * 3 + 0];
        py[i] = xyz[(b * cN + i) * 3 + 1];
        pz[i] = xyz[(b * cN + i) * 3 + 2];
        dmin[i] = 1e10f;
    }
    __syncthreads();
    int cur = 0;
    for (int g = 0; g < cG; g++) {
        float cx = px[cur], cy = py[cur], cz = pz[cur];
        if (tid == 0) {
            g_center[(b * cG + g) * 3 + 0] = cx;
            g_center[(b * cG + g) * 3 + 1] = cy;
            g_center[(b * cG + g) * 3 + 2] = cz;
        }
        float bv = -1.f; int bi = 0x7fffffff;
        for (int i = tid; i < cN; i += 256) {
            float dx = __fsub_rn(px[i], cx);
            float dy = __fsub_rn(py[i], cy);
            float dz = __fsub_rn(pz[i], cz);
            float dd = __fadd_rn(__fadd_rn(__fmul_rn(dx, dx), __fmul_rn(dy, dy)),
                                 __fmul_rn(dz, dz));
            float dm = fminf(dmin[i], dd);
            dmin[i] = dm;
            if (dm > bv) { bv = dm; bi = i; }
        }
#pragma unroll
        for (int off = 16; off > 0; off >>= 1) {
            float ov = __shfl_xor_sync(0xffffffffu, bv, off);
            int oi = __shfl_xor_sync(0xffffffffu, bi, off);
            if (ov > bv || (ov == bv && oi < bi)) { bv = ov; bi = oi; }
        }
        if (lane == 0) { wv[wid] = bv; wi[wid] = bi; }
        __syncthreads();
        if (tid < 8) {
            bv = wv[tid]; bi = wi[tid];
#pragma unroll
            for (int off = 4; off > 0; off >>= 1) {
                float ov = __shfl_xor_sync(0xffu, bv, off);
                int oi = __shfl_xor_sync(0xffu, bi, off);
                if (ov > bv || (ov == bv && oi < bi)) { bv = ov; bi = oi; }
            }
            if (tid == 0) s_cur = bi;
        }
        __syncthreads();
        cur = s_cur;
    }
}

// ---------------------------------------------------------------------------
// KNN: 32 smallest d2, ties -> lowest index; writes nb
// ---------------------------------------------------------------------------
__global__ void knn_kernel(const float* __restrict__ xyz) {
    int bg = blockIdx.x;
    int b = bg >> 7;
    __shared__ float d2s[cN];
    __shared__ float wv[8];
    __shared__ int   wi[8];
    __shared__ int   s_idx;
    int tid = threadIdx.x;
    int wid = tid >> 5, lane = tid & 31;
    float cx = g_center[bg * 3 + 0], cy = g_center[bg * 3 + 1], cz = g_center[bg * 3 + 2];
    const float* P = xyz + (size_t)b * cN * 3;
    for (int i = tid; i < cN; i += 256) {
        float dx = __fsub_rn(cx, P[i * 3 + 0]);
        float dy = __fsub_rn(cy, P[i * 3 + 1]);
        float dz = __fsub_rn(cz, P[i * 3 + 2]);
        d2s[i] = __fadd_rn(__fadd_rn(__fmul_rn(dx, dx), __fmul_rn(dy, dy)),
                           __fmul_rn(dz, dz));
    }
    __syncthreads();
    for (int m = 0; m < cM; m++) {
        float bv = FLT_MAX; int bi = 0x7fffffff;
        for (int i = tid; i < cN; i += 256) {
            float v = d2s[i];
            if (v < bv) { bv = v; bi = i; }
        }
#pragma unroll
        for (int off = 16; off > 0; off >>= 1) {
            float ov = __shfl_xor_sync(0xffffffffu, bv, off);
            int oi = __shfl_xor_sync(0xffffffffu, bi, off);
            if (ov < bv || (ov == bv && oi < bi)) { bv = ov; bi = oi; }
        }
        if (lane == 0) { wv[wid] = bv; wi[wid] = bi; }
        __syncthreads();
        if (tid < 8) {
            bv = wv[tid]; bi = wi[tid];
#pragma unroll
            for (int off = 4; off > 0; off >>= 1) {
                float ov = __shfl_xor_sync(0xffu, bv, off);
                int oi = __shfl_xor_sync(0xffu, bi, off);
                if (ov < bv || (ov == bv && oi < bi)) { bv = ov; bi = oi; }
            }
            if (tid == 0) s_idx = bi;
        }
        __syncthreads();
        int idx = s_idx;
        if (tid < 3) {
            float c = (tid == 0) ? cx : ((tid == 1) ? cy : cz);
            g_nb[((size_t)bg * cM + m) * 3 + tid] = __fsub_rn(P[idx * 3 + tid], c);
        }
        if (tid == 0) d2s[idx] = FLT_MAX;
        __syncthreads();
    }
}

// ---------------------------------------------------------------------------
// Positional MLP stage 1 (gelu)
// ---------------------------------------------------------------------------
__global__ void pos1_kernel(const float* __restrict__ pw1, const float* __restrict__ pb1) {
    int idx = blockIdx.x * blockDim.x + threadIdx.x;
    if (idx >= cTOK * 128) return;
    int t = idx >> 7, j = idx & 127;
    float x0 = g_center[t * 3 + 0], x1 = g_center[t * 3 + 1], x2 = g_center[t * 3 + 2];
    float v = x0 * pw1[j * 3 + 0] + x1 * pw1[j * 3 + 1] + x2 * pw1[j * 3 + 2] + pb1[j];
    float v3 = v * v * v;
    float g = 0.5f * v * (1.0f + tanhf(0.7978845608028654f * (v + 0.044715f * v3)));
    g_pos1[idx] = g;
}

// ---------------------------------------------------------------------------
// Residual accumulate + LayerNorm
// ---------------------------------------------------------------------------
__device__ __forceinline__ float block_sum_128(float v, float* sm) {
    int tid = threadIdx.x;
    sm[tid] = v; __syncthreads();
    for (int s = 64; s > 0; s >>= 1) {
        if (tid < s) sm[tid] += sm[tid + s];
        __syncthreads();
    }
    float r = sm[0]; __syncthreads();
    return r;
}

__global__ void resln_kernel(const float* __restrict__ w, const float* __restrict__ b,
                             int first) {
    __shared__ float sm[128];
    int t = blockIdx.x;
    float v[3];
#pragma unroll
    for (int j = 0; j < 3; j++) {
        int c = threadIdx.x + j * 128;
        float r = g_h[t * 384 + c];
        if (!first) r += g_res[t * 384 + c];
        g_res[t * 384 + c] = r;
        v[j] = r;
    }
    float mean = block_sum_128(v[0] + v[1] + v[2], sm) * (1.0f / 384.0f);
    float sq = 0.f;
#pragma unroll
    for (int j = 0; j < 3; j++) { float d = v[j] - mean; sq += d * d; }
    float var = block_sum_128(sq, sm) * (1.0f / 384.0f);
    float inv = rsqrtf(var + 1e-5f);
#pragma unroll
    for (int j = 0; j < 3; j++) {
        int c = threadIdx.x + j * 128;
        g_xln[t * 384 + c] = (v[j] - mean) * inv * w[c] + b[c];
    }
}

__global__ void final_kernel(const float* __restrict__ w, const float* __restrict__ b,
                             float* __restrict__ out) {
    __shared__ float sm[128];
    int t = blockIdx.x;
    float v[3];
#pragma unroll
    for (int j = 0; j < 3; j++) {
        int c = threadIdx.x + j * 128;
        v[j] = g_h[t * 384 + c] + g_res[t * 384 + c];
    }
    float mean = block_sum_128(v[0] + v[1] + v[2], sm) * (1.0f / 384.0f);
    float sq = 0.f;
#pragma unroll
    for (int j = 0; j < 3; j++) { float d = v[j] - mean; sq += d * d; }
    float var = block_sum_128(sq, sm) * (1.0f / 384.0f);
    float inv = rsqrtf(var + 1e-5f);
#pragma unroll
    for (int j = 0; j < 3; j++) {
        int c = threadIdx.x + j * 128;
        out[t * 384 + c] = (v[j] - mean) * inv * w[c] + b[c];
    }
}

// ---------------------------------------------------------------------------
// Selective scan + D skip + silu(z) gate; conv+silu of xin computed via a
// 4-register sliding window on g_xz (identical fp32 math to the old conv).
// ---------------------------------------------------------------------------
__global__ void scan_kernel(const float* __restrict__ Alog, const float* __restrict__ Dp,
                            const float* __restrict__ cw, const float* __restrict__ cb) {
    int b = blockIdx.y;
    int lane16 = threadIdx.x & 15;
    int dl = threadIdx.x >> 4;
    int d = blockIdx.x * 16 + dl;
    float A = -expf(Alog[d * 16 + lane16]);
    float Dpd = Dp[d];
    float cw0 = cw[d * 4 + 0], cw1 = cw[d * 4 + 1];
    float cw2 = cw[d * 4 + 2], cw3 = cw[d * 4 + 3];
    float cbd = cb[d];
    float xm3 = 0.f, xm2 = 0.f, xm1 = 0.f;
    float h = 0.f;
    for (int l = 0; l < 128; l++) {
        int t = b * 128 + l;
        float xl = g_xz[(size_t)t * 1536 + d];
        float pre = cbd + xm3 * cw0 + xm2 * cw1 + xm1 * cw2 + xl * cw3;
        float xin = pre * (1.0f / (1.0f + expf(-pre)));
        xm3 = xm2; xm2 = xm1; xm1 = xl;
        float dt = g_dt[(size_t)t * cDI + d];
        float Bm = g_dbl64[t * 64 + 24 + lane16];
        float Cc = g_dbl64[t * 64 + 40 + lane16];
        h = expf(dt * A) * h + dt * xin * Bm;
        float y = h * Cc;
#pragma unroll
        for (int off = 8; off > 0; off >>= 1)
            y += __shfl_xor_sync(0xffffffffu, y, off, 16);
        if (lane16 == 0) {
            y += Dpd * xin;
            float z = g_xz[(size_t)t * 1536 + 768 + d];
            float sz = z / (1.0f + expf(-z));
            g_u[(size_t)t * cDI + d] = y * sz;
        }
    }
}

// ---------------------------------------------------------------------------
// Host-side launch sequence
// ---------------------------------------------------------------------------
extern "C" void kernel_launch(void* const* d_in, const int* in_sizes, int n_in,
                              void* d_out, int out_size) {
    const float* xyz   = (const float*)d_in[0];
    const float* e1w1  = (const float*)d_in[1];
    const float* e1b1  = (const float*)d_in[2];
    const float* bn1g  = (const float*)d_in[3];
    const float* bn1b  = (const float*)d_in[4];
    const float* e1w2  = (const float*)d_in[5];
    const float* e1b2  = (const float*)d_in[6];
    const float* e2w1  = (const float*)d_in[7];
    const float* e2b1  = (const float*)d_in[8];
    const float* bn2g  = (const float*)d_in[9];
    const float* bn2b  = (const float*)d_in[10];
    const float* e2w2  = (const float*)d_in[11];
    const float* e2b2  = (const float*)d_in[12];
    const float* pw1   = (const float*)d_in[13];
    const float* pb1   = (const float*)d_in[14];
    const float* pw2   = (const float*)d_in[15];
    const float* pb2   = (const float*)d_in[16];
    const float* in_w  = (const float*)d_in[17];
    const float* convw = (const float*)d_in[18];
    const float* convb = (const float*)d_in[19];
    const float* xp_w  = (const float*)d_in[20];
    const float* dt_w  = (const float*)d_in[21];
    const float* dt_b  = (const float*)d_in[22];
    const float* A_log = (const float*)d_in[23];
    const float* Dp    = (const float*)d_in[24];
    const float* out_w = (const float*)d_in[25];
    const float* lnw   = (const float*)d_in[26];
    const float* lnb   = (const float*)d_in[27];
    const float* fnw   = (const float*)d_in[28];
    const float* fnb   = (const float*)d_in[29];
    float* out = (float*)d_out;

    float *pnb, *pf2, *pfg, *pf3, *pxln, *pxz, *pu, *ph, *ppos1,
          *pdbl, *pdt, *pxpw, *pdtw;
    cudaGetSymbolAddress((void**)&pnb,  g_nb);
    cudaGetSymbolAddress((void**)&pf2,  g_f2);
    cudaGetSymbolAddress((void**)&pfg,  g_fg);
    cudaGetSymbolAddress((void**)&pf3,  g_f3);
    cudaGetSymbolAddress((void**)&pxln, g_xln);
    cudaGetSymbolAddress((void**)&pxz,  g_xz);
    cudaGetSymbolAddress((void**)&pu,   g_u);
    cudaGetSymbolAddress((void**)&ph,   g_h);
    cudaGetSymbolAddress((void**)&ppos1, g_pos1);
    cudaGetSymbolAddress((void**)&pdbl, g_dbl64);
    cudaGetSymbolAddress((void**)&pdt,  g_dt);
    cudaGetSymbolAddress((void**)&pxpw, g_xpw);
    cudaGetSymbolAddress((void**)&pdtw, g_dtw);

    // ---- weight prep ----
    constexpr int NPAD = cNL * 64 * cDI + cNL * cDI * 32;
    pad_weights<<<(NPAD + 255) / 256, 256>>>(xp_w, dt_w);

    // ---- grouping ----
    fps_kernel<<<cB, 256>>>(xyz);
    knn_kernel<<<cTOK, 256>>>(xyz);

    // ---- encoder ----
    // f2 = (f1 computed on the fly) @ e1w2^T + bias; epilogue also emits g_fg
    tc2<128, 128, 2, 2, 0, 2, 1><<<dim3(cPTS / 128, 2), 128>>>(
        pnb, e1w2, e1b2, bn1g, bn1b, pf2, 128, 3, 128, 256,
        e1w1, e1b1, pfg, 256);
    // f3: concat(fg, f2) @ e2w1^T -> bn+relu
    tc2<128, 128, 2, 2, 1, 1, 0><<<dim3(cPTS / 128, 4), 128>>>(
        pf2, e2w1, e2b1, bn2g, bn2b, pf3, 512, 256, 512, 512,
        pfg, nullptr, nullptr, 0);
    // f4: epilogue emits ONLY token max -> g_h (no f4 materialization)
    tc2<128, 128, 2, 2, 0, 0, 2><<<dim3(cPTS / 128, 3), 128>>>(
        pf3, e2w2, e2b2, nullptr, nullptr, nullptr, 512, 512, 512, 384,
        nullptr, nullptr, ph, 384);

    // ---- positional MLP ----
    pos1_kernel<<<(cTOK * 128 + 255) / 256, 256>>>(pw1, pb1);
    tc2<128, 128, 2, 2, 3, 0, 0><<<dim3(cTOK / 128, 3), 128>>>(
        ppos1, pw2, pb2, nullptr, nullptr, ph, 128, 128, 128, 384,
        nullptr, nullptr, nullptr, 0);

    // ---- mamba layers ----
    for (int i = 0; i < cNL; i++) {
        const float* in_w_i  = in_w  + (size_t)i * 2 * cDI * cDM;
        const float* cw_i    = convw + (size_t)i * cDI * 4;
        const float* cb_i    = convb + (size_t)i * cDI;
        const float* dtb_i   = dt_b  + (size_t)i * cDI;
        const float* Al_i    = A_log + (size_t)i * cDI * cDS;
        const float* Dp_i    = Dp    + (size_t)i * cDI;
        const float* ow_i    = out_w + (size_t)i * cDM * cDI;
        const float* lnw_i   = lnw   + (size_t)i * cDM;
        const float* lnb_i   = lnb   + (size_t)i * cDM;
        const float* xpw_i   = pxpw  + (size_t)i * 64 * cDI;
        const float* dtw_i   = pdtw  + (size_t)i * cDI * 32;

        resln_kernel<<<cTOK, 128>>>(lnw_i, lnb_i, i == 0 ? 1 : 0);
        // in-proj: (2048,384)@(1536,384)^T
        tc2<128, 128, 2, 2, 0, 0, 0><<<dim3(cTOK / 128, 12), 128>>>(
            pxln, in_w_i, nullptr, nullptr, nullptr, pxz, 384, 384, 384, 1536,
            nullptr, nullptr, nullptr, 0);
        // xp: A = silu(conv4(xz)) computed on the fly; -> g_dbl64
        tc2<128, 64, 4, 1, 0, 3, 0><<<dim3(cTOK / 128, 1), 128>>>(
            pxz, xpw_i, nullptr, nullptr, nullptr, pdbl, 768, 1536, 768, 64,
            cw_i, cb_i, nullptr, 0);
        // dt: (2048,32pad)@(768,32)^T + bias -> softplus
        tc2<128, 128, 2, 2, 2, 0, 0><<<dim3(cTOK / 128, 6), 128>>>(
            pdbl, dtw_i, dtb_i, nullptr, nullptr, pdt, 32, 64, 32, 768,
            nullptr, nullptr, nullptr, 0);
        scan_kernel<<<dim3(cDI / 16, cB), 256>>>(Al_i, Dp_i, cw_i, cb_i);
        // out-proj: (2048,768)@(384,768)^T
        tc2<64, 128, 1, 2, 0, 0, 0><<<dim3(cTOK / 64, 3), 64>>>(
            pu, ow_i, nullptr, nullptr, nullptr, ph, 768, 768, 768, 384,
            nullptr, nullptr, nullptr, 0);
    }

    // ---- final LN ----
    final_kernel<<<cTOK, 128>>>(fnw, fnb, out);
}

// round 8
// speedup vs baseline: 1.4185x; 1.4185x over previous
#include <cuda_runtime.h>
#include <math.h>
#include <float.h>

// ---------------------------------------------------------------------------
// Problem constants
// ---------------------------------------------------------------------------
constexpr int cB   = 16;
constexpr int cN   = 2048;
constexpr int cG   = 128;
constexpr int cM   = 32;
constexpr int cDM  = 384;
constexpr int cNL  = 12;
constexpr int cDI  = 768;
constexpr int cDS  = 16;
constexpr int cDTR = 24;
constexpr int cTOK = cB * cG;        // 2048 tokens
constexpr int cPTS = cTOK * cM;      // 65536 points

// ---------------------------------------------------------------------------
// Scratch (device globals; no dynamic allocation allowed)
// ---------------------------------------------------------------------------
__device__ __align__(16) float g_center[cTOK * 3];
__device__ __align__(16) float g_nb[cPTS * 3];
__device__ __align__(16) float g_f2[(size_t)cPTS * 256];
__device__ __align__(16) float g_fg[cTOK * 256];
__device__ __align__(16) float g_f3[(size_t)cPTS * 512];
__device__ __align__(16) float g_pos1[cTOK * 128];
__device__ __align__(16) float g_h[cTOK * cDM];
__device__ __align__(16) float g_res[cTOK * cDM];
__device__ __align__(16) float g_xln[cTOK * cDM];
__device__ __align__(16) float g_xz[(size_t)cTOK * 2 * cDI];
__device__ __align__(16) float g_xc[(size_t)cTOK * cDI];
__device__ __align__(16) float g_dbl64[cTOK * 64];
__device__ __align__(16) float g_dt[(size_t)cTOK * cDI];
__device__ __align__(16) float g_u[(size_t)cTOK * cDI];
__device__ __align__(16) float g_xpw[cNL * 64 * cDI];
__device__ __align__(16) float g_dtw[cNL * cDI * 32];

using u32 = unsigned int;

__device__ __forceinline__ u32 cvt_tf32(float x) {
    u32 r;
    asm("cvt.rna.tf32.f32 %0, %1;" : "=r"(r) : "f"(x));
    return r;
}

__device__ __forceinline__ void mma_tf32(float* c, u32 a0, u32 a1, u32 a2, u32 a3,
                                         u32 b0, u32 b1) {
    asm volatile(
        "mma.sync.aligned.m16n8k8.row.col.f32.tf32.tf32.f32 "
        "{%0,%1,%2,%3}, {%4,%5,%6,%7}, {%8,%9}, {%0,%1,%2,%3};"
        : "+f"(c[0]), "+f"(c[1]), "+f"(c[2]), "+f"(c[3])
        : "r"(a0), "r"(a1), "r"(a2), "r"(a3), "r"(b0), "r"(b1));
}

// ---------------------------------------------------------------------------
// Generic tf32 tensor-core GEMM: C = epi(A' @ W^T) where A' depends on MODEA.
//   CTA tile BM x BN, warp grid WGM x WGN. BK=16, double-buffered smem.
//   EPI 0: +bias(opt). 1: relu(bn(.+bias)). 2: softplus(.+bias). 3: C += .+bias
//   MODEA 0: A' = A (row-major, lda)
//   MODEA 1: A' cols [0,256) from aux1[row>>5][k] (group feat), rest from A
//   MODEA 2: A' = relu(bn1(nb @ w1^T + b1)): A=nb, aux1=w1, aux2=b1,
//            p1=bn gamma, p2=bn beta  (K=128)
//   EMAX  0: normal epilogue.
//   EMAX  1: EPI must be 0 w/ bias; write C AND 32-row group max to fgout.
//   EMAX  2: write ONLY 32-row group max (C unused). Requires WTM==64.
// ---------------------------------------------------------------------------
template<int BM, int BN, int WGM, int WGN, int EPI, int MODEA, int EMAX>
__global__ void __launch_bounds__(WGM * WGN * 32)
tc2(const float* __restrict__ A, const float* __restrict__ W,
    const float* __restrict__ bias, const float* __restrict__ p1,
    const float* __restrict__ p2, float* __restrict__ C,
    int K, int lda, int ldw, int ldc,
    const float* __restrict__ aux1, const float* __restrict__ aux2,
    float* __restrict__ fgout, int ldfg)
{
    constexpr int THREADS = WGM * WGN * 32;
    constexpr int WTM = BM / WGM, WTN = BN / WGN;
    constexpr int MT = WTM / 16, NT = WTN / 8;
    constexpr int LA = BM + 8, LB = BN + 8;
    constexpr int A4 = (BM * 16) / (THREADS * 4);
    constexpr int W4 = (BN * 16) / (THREADS * 4);
    static_assert(EMAX == 0 || WTM == 64, "EMAX needs WTM==64");

    __shared__ float As[2][16][LA];
    __shared__ float Ws[2][16][LB];

    const int tid = threadIdx.x;
    const int wid = tid >> 5, lane = tid & 31;
    const int grp = lane >> 2, tig = lane & 3;
    const int wm = wid % WGM, wn = wid / WGM;
    const int m0 = blockIdx.x * BM, n0 = blockIdx.y * BN;
    const float bnscale = rsqrtf(1.0f + 1e-5f);

    float acc[MT][NT][4];
#pragma unroll
    for (int mt = 0; mt < MT; mt++)
#pragma unroll
        for (int nt = 0; nt < NT; nt++)
#pragma unroll
            for (int r = 0; r < 4; r++) acc[mt][nt][r] = 0.f;

    // MODEA==2: hoist per-row point coords (rows fixed per thread across chunks)
    float nbr[MODEA == 2 ? A4 : 1][3];
    if (MODEA == 2) {
#pragma unroll
        for (int v = 0; v < A4; v++) {
            int row = (tid + v * THREADS) >> 2;
            nbr[v][0] = A[(size_t)(m0 + row) * 3 + 0];
            nbr[v][1] = A[(size_t)(m0 + row) * 3 + 1];
            nbr[v][2] = A[(size_t)(m0 + row) * 3 + 2];
        }
    }

    float4 ra[A4], rw[W4];

    auto loadG = [&](int kc) {
#pragma unroll
        for (int v = 0; v < A4; v++) {
            int s = tid + v * THREADS;
            int row = s >> 2;
            int k = kc + (s & 3) * 4;
            if (MODEA == 0) {
                ra[v] = *(const float4*)(A + (size_t)(m0 + row) * lda + k);
            } else if (MODEA == 1) {
                int r = m0 + row;
                const float* src = (k < 256)
                    ? (aux1 + ((size_t)(r >> 5)) * 256 + k)
                    : (A + (size_t)r * lda + (k - 256));
                ra[v] = *(const float4*)src;
            } else { // MODEA == 2
                float out[4];
#pragma unroll
                for (int e = 0; e < 4; e++) {
                    int kk = k + e;
                    float val = nbr[v][0] * aux1[kk * 3 + 0]
                              + nbr[v][1] * aux1[kk * 3 + 1]
                              + nbr[v][2] * aux1[kk * 3 + 2] + aux2[kk];
                    val = val * (p1[kk] * bnscale) + p2[kk];
                    out[e] = fmaxf(val, 0.f);
                }
                ra[v] = make_float4(out[0], out[1], out[2], out[3]);
            }
        }
#pragma unroll
        for (int v = 0; v < W4; v++) {
            int s = tid + v * THREADS;
            int row = s >> 2, k4 = s & 3;
            rw[v] = *(const float4*)(W + (size_t)(n0 + row) * ldw + kc + k4 * 4);
        }
    };
    auto stsG = [&](int buf) {
#pragma unroll
        for (int v = 0; v < A4; v++) {
            int s = tid + v * THREADS;
            int row = s >> 2, kq = (s & 3) << 2;
            As[buf][kq + 0][row] = __uint_as_float(cvt_tf32(ra[v].x));
            As[buf][kq + 1][row] = __uint_as_float(cvt_tf32(ra[v].y));
            As[buf][kq + 2][row] = __uint_as_float(cvt_tf32(ra[v].z));
            As[buf][kq + 3][row] = __uint_as_float(cvt_tf32(ra[v].w));
        }
#pragma unroll
        for (int v = 0; v < W4; v++) {
            int s = tid + v * THREADS;
            int row = s >> 2, kq = (s & 3) << 2;
            Ws[buf][kq + 0][row] = __uint_as_float(cvt_tf32(rw[v].x));
            Ws[buf][kq + 1][row] = __uint_as_float(cvt_tf32(rw[v].y));
            Ws[buf][kq + 2][row] = __uint_as_float(cvt_tf32(rw[v].z));
            Ws[buf][kq + 3][row] = __uint_as_float(cvt_tf32(rw[v].w));
        }
    };

    const int nIter = K >> 4;
    loadG(0);
    stsG(0);
    __syncthreads();
    int buf = 0;

    for (int it = 0; it < nIter; it++) {
        bool more = (it + 1 < nIter);
        if (more) loadG((it + 1) << 4);
#pragma unroll
        for (int ks = 0; ks < 2; ks++) {
            const int k0 = ks * 8;
            u32 af[MT][4];
#pragma unroll
            for (int mt = 0; mt < MT; mt++) {
                int m = wm * WTM + mt * 16 + grp;
                af[mt][0] = __float_as_uint(As[buf][k0 + tig][m]);
                af[mt][1] = __float_as_uint(As[buf][k0 + tig][m + 8]);
                af[mt][2] = __float_as_uint(As[buf][k0 + tig + 4][m]);
                af[mt][3] = __float_as_uint(As[buf][k0 + tig + 4][m + 8]);
            }
            u32 bf[NT][2];
#pragma unroll
            for (int nt = 0; nt < NT; nt++) {
                int n = wn * WTN + nt * 8 + grp;
                bf[nt][0] = __float_as_uint(Ws[buf][k0 + tig][n]);
                bf[nt][1] = __float_as_uint(Ws[buf][k0 + tig + 4][n]);
            }
#pragma unroll
            for (int mt = 0; mt < MT; mt++)
#pragma unroll
                for (int nt = 0; nt < NT; nt++)
                    mma_tf32(acc[mt][nt], af[mt][0], af[mt][1], af[mt][2], af[mt][3],
                             bf[nt][0], bf[nt][1]);
        }
        if (more) {
            stsG(buf ^ 1);
            __syncthreads();
            buf ^= 1;
        }
    }

    if constexpr (EMAX == 0) {
        auto emit = [&](int mrow, int n, float v0, float v1) {
            if (EPI == 3) {
                C[(size_t)mrow * ldc + n]     += v0 + bias[n];
                C[(size_t)mrow * ldc + n + 1] += v1 + bias[n + 1];
                return;
            }
            if (EPI == 0) {
                if (bias) { v0 += bias[n]; v1 += bias[n + 1]; }
            } else if (EPI == 1) {
                v0 = fmaxf((v0 + bias[n]) * (p1[n] * bnscale) + p2[n], 0.f);
                v1 = fmaxf((v1 + bias[n + 1]) * (p1[n + 1] * bnscale) + p2[n + 1], 0.f);
            } else if (EPI == 2) {
                v0 += bias[n]; v1 += bias[n + 1];
                v0 = fmaxf(v0, 0.f) + log1pf(expf(-fabsf(v0)));
                v1 = fmaxf(v1, 0.f) + log1pf(expf(-fabsf(v1)));
            }
            float2 o; o.x = v0; o.y = v1;
            *(float2*)&C[(size_t)mrow * ldc + n] = o;
        };
#pragma unroll
        for (int mt = 0; mt < MT; mt++) {
            int mrow = m0 + wm * WTM + mt * 16 + grp;
#pragma unroll
            for (int nt = 0; nt < NT; nt++) {
                int n = n0 + wn * WTN + nt * 8 + tig * 2;
                emit(mrow,     n, acc[mt][nt][0], acc[mt][nt][1]);
                emit(mrow + 8, n, acc[mt][nt][2], acc[mt][nt][3]);
            }
        }
    } else {
        // 32-row group max epilogue (warp covers rows wm*64..+63 = 2 groups)
        float mx[2][NT][2];
#pragma unroll
        for (int g = 0; g < 2; g++)
#pragma unroll
            for (int nt = 0; nt < NT; nt++) {
                mx[g][nt][0] = -FLT_MAX; mx[g][nt][1] = -FLT_MAX;
            }
#pragma unroll
        for (int mt = 0; mt < MT; mt++) {
            int gsel = (mt >= MT / 2) ? 1 : 0;
            int mrow = m0 + wm * WTM + mt * 16 + grp;
#pragma unroll
            for (int nt = 0; nt < NT; nt++) {
                int n = n0 + wn * WTN + nt * 8 + tig * 2;
                float v0 = acc[mt][nt][0] + bias[n];
                float v1 = acc[mt][nt][1] + bias[n + 1];
                float v2 = acc[mt][nt][2] + bias[n];
                float v3 = acc[mt][nt][3] + bias[n + 1];
                if (EMAX == 1) {
                    float2 o0; o0.x = v0; o0.y = v1;
                    float2 o1; o1.x = v2; o1.y = v3;
                    *(float2*)&C[(size_t)mrow * ldc + n] = o0;
                    *(float2*)&C[(size_t)(mrow + 8) * ldc + n] = o1;
                }
                mx[gsel][nt][0] = fmaxf(mx[gsel][nt][0], fmaxf(v0, v2));
                mx[gsel][nt][1] = fmaxf(mx[gsel][nt][1], fmaxf(v1, v3));
            }
        }
#pragma unroll
        for (int g = 0; g < 2; g++) {
#pragma unroll
            for (int nt = 0; nt < NT; nt++)
#pragma unroll
                for (int c = 0; c < 2; c++) {
                    float v = mx[g][nt][c];
                    v = fmaxf(v, __shfl_xor_sync(0xffffffffu, v, 4));
                    v = fmaxf(v, __shfl_xor_sync(0xffffffffu, v, 8));
                    v = fmaxf(v, __shfl_xor_sync(0xffffffffu, v, 16));
                    mx[g][nt][c] = v;
                }
            if (lane < 4) {
                int grow = (m0 >> 5) + wm * 2 + g;
#pragma unroll
                for (int nt = 0; nt < NT; nt++) {
                    int n = n0 + wn * WTN + nt * 8 + tig * 2;
                    fgout[(size_t)grow * ldfg + n]     = mx[g][nt][0];
                    fgout[(size_t)grow * ldfg + n + 1] = mx[g][nt][1];
                }
            }
        }
    }
}

// ---------------------------------------------------------------------------
// Pad xp_w (56x768 -> 64x768, zero rows) and dt_w (768x24 -> 768x32, zero cols)
// ---------------------------------------------------------------------------
__global__ void pad_weights(const float* __restrict__ xp_w,
                            const float* __restrict__ dt_w) {
    int idx = blockIdx.x * 256 + threadIdx.x;
    constexpr int NXP = cNL * 64 * cDI;
    constexpr int NDT = cNL * cDI * 32;
    if (idx < NXP) {
        int l = idx / (64 * cDI);
        int r = (idx / cDI) % 64;
        int k = idx % cDI;
        g_xpw[idx] = (r < 56) ? xp_w[((size_t)l * 56 + r) * cDI + k] : 0.f;
    } else if (idx < NXP + NDT) {
        int j = idx - NXP;
        int l = j / (cDI * 32);
        int d = (j / 32) % cDI;
        int k = j % 32;
        g_dtw[j] = (k < 24) ? dt_w[((size_t)l * cDI + d) * cDTR + k] : 0.f;
    }
}

// ---------------------------------------------------------------------------
// FPS: per batch, exact replication of reference scan (incl. tie-breaking)
// ---------------------------------------------------------------------------
__global__ void fps_kernel(const float* __restrict__ xyz) {
    int b = blockIdx.x;
    __shared__ float px[cN], py[cN], pz[cN], dmin[cN];
    __shared__ float wv[8];
    __shared__ int   wi[8];
    __shared__ int   s_cur;
    int tid = threadIdx.x;
    int wid = tid >> 5, lane = tid & 31;
    for (int i = tid; i < cN; i += 256) {
        px[i] = xyz[(b * cN + i) * 3 + 0];
        py[i] = xyz[(b * cN + i) * 3 + 1];
        pz[i] = xyz[(b * cN + i) * 3 + 2];
        dmin[i] = 1e10f;
    }
    __syncthreads();
    int cur = 0;
    for (int g = 0; g < cG; g++) {
        float cx = px[cur], cy = py[cur], cz = pz[cur];
        if (tid == 0) {
            g_center[(b * cG + g) * 3 + 0] = cx;
            g_center[(b * cG + g) * 3 + 1] = cy;
            g_center[(b * cG + g) * 3 + 2] = cz;
        }
        float bv = -1.f; int bi = 0x7fffffff;
        for (int i = tid; i < cN; i += 256) {
            float dx = __fsub_rn(px[i], cx);
            float dy = __fsub_rn(py[i], cy);
            float dz = __fsub_rn(pz[i], cz);
            float dd = __fadd_rn(__fadd_rn(__fmul_rn(dx, dx), __fmul_rn(dy, dy)),
                                 __fmul_rn(dz, dz));
            float dm = fminf(dmin[i], dd);
            dmin[i] = dm;
            if (dm > bv) { bv = dm; bi = i; }
        }
#pragma unroll
        for (int off = 16; off > 0; off >>= 1) {
            float ov = __shfl_xor_sync(0xffffffffu, bv, off);
            int oi = __shfl_xor_sync(0xffffffffu, bi, off);
            if (ov > bv || (ov == bv && oi < bi)) { bv = ov; bi = oi; }
        }
        if (lane == 0) { wv[wid] = bv; wi[wid] = bi; }
        __syncthreads();
        if (tid < 8) {
            bv = wv[tid]; bi = wi[tid];
#pragma unroll
            for (int off = 4; off > 0; off >>= 1) {
                float ov = __shfl_xor_sync(0xffu, bv, off);
                int oi = __shfl_xor_sync(0xffu, bi, off);
                if (ov > bv || (ov == bv && oi < bi)) { bv = ov; bi = oi; }
            }
            if (tid == 0) s_cur = bi;
        }
        __syncthreads();
        cur = s_cur;
    }
}

// ---------------------------------------------------------------------------
// KNN: 32 smallest d2, ties -> lowest index; writes nb
// ---------------------------------------------------------------------------
__global__ void knn_kernel(const float* __restrict__ xyz) {
    int bg = blockIdx.x;
    int b = bg >> 7;
    __shared__ float d2s[cN];
    __shared__ float wv[8];
    __shared__ int   wi[8];
    __shared__ int   s_idx;
    int tid = threadIdx.x;
    int wid = tid >> 5, lane = tid & 31;
    float cx = g_center[bg * 3 + 0], cy = g_center[bg * 3 + 1], cz = g_center[bg * 3 + 2];
    const float* P = xyz + (size_t)b * cN * 3;
    for (int i = tid; i < cN; i += 256) {
        float dx = __fsub_rn(cx, P[i * 3 + 0]);
        float dy = __fsub_rn(cy, P[i * 3 + 1]);
        float dz = __fsub_rn(cz, P[i * 3 + 2]);
        d2s[i] = __fadd_rn(__fadd_rn(__fmul_rn(dx, dx), __fmul_rn(dy, dy)),
                           __fmul_rn(dz, dz));
    }
    __syncthreads();
    for (int m = 0; m < cM; m++) {
        float bv = FLT_MAX; int bi = 0x7fffffff;
        for (int i = tid; i < cN; i += 256) {
            float v = d2s[i];
            if (v < bv) { bv = v; bi = i; }
        }
#pragma unroll
        for (int off = 16; off > 0; off >>= 1) {
            float ov = __shfl_xor_sync(0xffffffffu, bv, off);
            int oi = __shfl_xor_sync(0xffffffffu, bi, off);
            if (ov < bv || (ov == bv && oi < bi)) { bv = ov; bi = oi; }
        }
        if (lane == 0) { wv[wid] = bv; wi[wid] = bi; }
        __syncthreads();
        if (tid < 8) {
            bv = wv[tid]; bi = wi[tid];
#pragma unroll
            for (int off = 4; off > 0; off >>= 1) {
                float ov = __shfl_xor_sync(0xffu, bv, off);
                int oi = __shfl_xor_sync(0xffu, bi, off);
                if (ov < bv || (ov == bv && oi < bi)) { bv = ov; bi = oi; }
            }
            if (tid == 0) s_idx = bi;
        }
        __syncthreads();
        int idx = s_idx;
        if (tid < 3) {
            float c = (tid == 0) ? cx : ((tid == 1) ? cy : cz);
            g_nb[((size_t)bg * cM + m) * 3 + tid] = __fsub_rn(P[idx * 3 + tid], c);
        }
        if (tid == 0) d2s[idx] = FLT_MAX;
        __syncthreads();
    }
}

// ---------------------------------------------------------------------------
// Positional MLP stage 1 (gelu)
// ---------------------------------------------------------------------------
__global__ void pos1_kernel(const float* __restrict__ pw1, const float* __restrict__ pb1) {
    int idx = blockIdx.x * blockDim.x + threadIdx.x;
    if (idx >= cTOK * 128) return;
    int t = idx >> 7, j = idx & 127;
    float x0 = g_center[t * 3 + 0], x1 = g_center[t * 3 + 1], x2 = g_center[t * 3 + 2];
    float v = x0 * pw1[j * 3 + 0] + x1 * pw1[j * 3 + 1] + x2 * pw1[j * 3 + 2] + pb1[j];
    float v3 = v * v * v;
    float g = 0.5f * v * (1.0f + tanhf(0.7978845608028654f * (v + 0.044715f * v3)));
    g_pos1[idx] = g;
}

// ---------------------------------------------------------------------------
// Residual accumulate + LayerNorm
// ---------------------------------------------------------------------------
__device__ __forceinline__ float block_sum_128(float v, float* sm) {
    int tid = threadIdx.x;
    sm[tid] = v; __syncthreads();
    for (int s = 64; s > 0; s >>= 1) {
        if (tid < s) sm[tid] += sm[tid + s];
        __syncthreads();
    }
    float r = sm[0]; __syncthreads();
    return r;
}

__global__ void resln_kernel(const float* __restrict__ w, const float* __restrict__ b,
                             int first) {
    __shared__ float sm[128];
    int t = blockIdx.x;
    float v[3];
#pragma unroll
    for (int j = 0; j < 3; j++) {
        int c = threadIdx.x + j * 128;
        float r = g_h[t * 384 + c];
        if (!first) r += g_res[t * 384 + c];
        g_res[t * 384 + c] = r;
        v[j] = r;
    }
    float mean = block_sum_128(v[0] + v[1] + v[2], sm) * (1.0f / 384.0f);
    float sq = 0.f;
#pragma unroll
    for (int j = 0; j < 3; j++) { float d = v[j] - mean; sq += d * d; }
    float var = block_sum_128(sq, sm) * (1.0f / 384.0f);
    float inv = rsqrtf(var + 1e-5f);
#pragma unroll
    for (int j = 0; j < 3; j++) {
        int c = threadIdx.x + j * 128;
        g_xln[t * 384 + c] = (v[j] - mean) * inv * w[c] + b[c];
    }
}

__global__ void final_kernel(const float* __restrict__ w, const float* __restrict__ b,
                             float* __restrict__ out) {
    __shared__ float sm[128];
    int t = blockIdx.x;
    float v[3];
#pragma unroll
    for (int j = 0; j < 3; j++) {
        int c = threadIdx.x + j * 128;
        v[j] = g_h[t * 384 + c] + g_res[t * 384 + c];
    }
    float mean = block_sum_128(v[0] + v[1] + v[2], sm) * (1.0f / 384.0f);
    float sq = 0.f;
#pragma unroll
    for (int j = 0; j < 3; j++) { float d = v[j] - mean; sq += d * d; }
    float var = block_sum_128(sq, sm) * (1.0f / 384.0f);
    float inv = rsqrtf(var + 1e-5f);
#pragma unroll
    for (int j = 0; j < 3; j++) {
        int c = threadIdx.x + j * 128;
        out[t * 384 + c] = (v[j] - mean) * inv * w[c] + b[c];
    }
}

// ---------------------------------------------------------------------------
// Depthwise causal conv (DC=4) + bias + silu
// ---------------------------------------------------------------------------
__global__ void conv_kernel(const float* __restrict__ cw, const float* __restrict__ cb) {
    int idx = blockIdx.x * blockDim.x + threadIdx.x;
    if (idx >= cTOK * cDI) return;
    int t = idx / cDI, d = idx % cDI;
    int l = t & 127;
    int tbase = t - l;
    float acc = cb[d];
#pragma unroll
    for (int k = 0; k < 4; k++) {
        int lk = l - 3 + k;
        if (lk >= 0)
            acc += g_xz[(size_t)(tbase + lk) * 1536 + d] * cw[d * 4 + k];
    }
    float sig = 1.0f / (1.0f + expf(-acc));
    g_xc[idx] = acc * sig;
}

// ---------------------------------------------------------------------------
// Selective scan + D skip + silu(z) gate
// ---------------------------------------------------------------------------
__global__ void scan_kernel(const float* __restrict__ Alog, const float* __restrict__ Dp) {
    int b = blockIdx.y;
    int lane16 = threadIdx.x & 15;
    int dl = threadIdx.x >> 4;
    int d = blockIdx.x * 16 + dl;
    float A = -expf(Alog[d * 16 + lane16]);
    float Dpd = Dp[d];
    float h = 0.f;
    for (int l = 0; l < 128; l++) {
        int t = b * 128 + l;
        float dt = g_dt[(size_t)t * cDI + d];
        float xin = g_xc[(size_t)t * cDI + d];
        float Bm = g_dbl64[t * 64 + 24 + lane16];
        float Cc = g_dbl64[t * 64 + 40 + lane16];
        h = expf(dt * A) * h + dt * xin * Bm;
        float y = h * Cc;
#pragma unroll
        for (int off = 8; off > 0; off >>= 1)
            y += __shfl_xor_sync(0xffffffffu, y, off, 16);
        if (lane16 == 0) {
            y += Dpd * xin;
            float z = g_xz[(size_t)t * 1536 + 768 + d];
            float sz = z / (1.0f + expf(-z));
            g_u[(size_t)t * cDI + d] = y * sz;
        }
    }
}

// ---------------------------------------------------------------------------
// Host-side launch sequence
// ---------------------------------------------------------------------------
extern "C" void kernel_launch(void* const* d_in, const int* in_sizes, int n_in,
                              void* d_out, int out_size) {
    const float* xyz   = (const float*)d_in[0];
    const float* e1w1  = (const float*)d_in[1];
    const float* e1b1  = (const float*)d_in[2];
    const float* bn1g  = (const float*)d_in[3];
    const float* bn1b  = (const float*)d_in[4];
    const float* e1w2  = (const float*)d_in[5];
    const float* e1b2  = (const float*)d_in[6];
    const float* e2w1  = (const float*)d_in[7];
    const float* e2b1  = (const float*)d_in[8];
    const float* bn2g  = (const float*)d_in[9];
    const float* bn2b  = (const float*)d_in[10];
    const float* e2w2  = (const float*)d_in[11];
    const float* e2b2  = (const float*)d_in[12];
    const float* pw1   = (const float*)d_in[13];
    const float* pb1   = (const float*)d_in[14];
    const float* pw2   = (const float*)d_in[15];
    const float* pb2   = (const float*)d_in[16];
    const float* in_w  = (const float*)d_in[17];
    const float* convw = (const float*)d_in[18];
    const float* convb = (const float*)d_in[19];
    const float* xp_w  = (const float*)d_in[20];
    const float* dt_w  = (const float*)d_in[21];
    const float* dt_b  = (const float*)d_in[22];
    const float* A_log = (const float*)d_in[23];
    const float* Dp    = (const float*)d_in[24];
    const float* out_w = (const float*)d_in[25];
    const float* lnw   = (const float*)d_in[26];
    const float* lnb   = (const float*)d_in[27];
    const float* fnw   = (const float*)d_in[28];
    const float* fnb   = (const float*)d_in[29];
    float* out = (float*)d_out;

    float *pnb, *pf2, *pfg, *pf3, *pxln, *pxz, *pxc, *pu, *ph, *ppos1,
          *pdbl, *pdt, *pxpw, *pdtw;
    cudaGetSymbolAddress((void**)&pnb,  g_nb);
    cudaGetSymbolAddress((void**)&pf2,  g_f2);
    cudaGetSymbolAddress((void**)&pfg,  g_fg);
    cudaGetSymbolAddress((void**)&pf3,  g_f3);
    cudaGetSymbolAddress((void**)&pxln, g_xln);
    cudaGetSymbolAddress((void**)&pxz,  g_xz);
    cudaGetSymbolAddress((void**)&pxc,  g_xc);
    cudaGetSymbolAddress((void**)&pu,   g_u);
    cudaGetSymbolAddress((void**)&ph,   g_h);
    cudaGetSymbolAddress((void**)&ppos1, g_pos1);
    cudaGetSymbolAddress((void**)&pdbl, g_dbl64);
    cudaGetSymbolAddress((void**)&pdt,  g_dt);
    cudaGetSymbolAddress((void**)&pxpw, g_xpw);
    cudaGetSymbolAddress((void**)&pdtw, g_dtw);

    // ---- weight prep ----
    constexpr int NPAD = cNL * 64 * cDI + cNL * cDI * 32;
    pad_weights<<<(NPAD + 255) / 256, 256>>>(xp_w, dt_w);

    // ---- grouping ----
    fps_kernel<<<cB, 256>>>(xyz);
    knn_kernel<<<cTOK, 256>>>(xyz);

    // ---- encoder ----
    // f2 = (f1 computed on the fly) @ e1w2^T + bias; epilogue also emits g_fg
    tc2<128, 128, 2, 2, 0, 2, 1><<<dim3(cPTS / 128, 2), 128>>>(
        pnb, e1w2, e1b2, bn1g, bn1b, pf2, 128, 3, 128, 256,
        e1w1, e1b1, pfg, 256);
    // f3: concat(fg, f2) @ e2w1^T -> bn+relu
    tc2<128, 128, 2, 2, 1, 1, 0><<<dim3(cPTS / 128, 4), 128>>>(
        pf2, e2w1, e2b1, bn2g, bn2b, pf3, 512, 256, 512, 512,
        pfg, nullptr, nullptr, 0);
    // f4: epilogue emits ONLY token max -> g_h (no f4 materialization)
    tc2<128, 128, 2, 2, 0, 0, 2><<<dim3(cPTS / 128, 3), 128>>>(
        pf3, e2w2, e2b2, nullptr, nullptr, nullptr, 512, 512, 512, 384,
        nullptr, nullptr, ph, 384);

    // ---- positional MLP ----
    pos1_kernel<<<(cTOK * 128 + 255) / 256, 256>>>(pw1, pb1);
    tc2<128, 128, 2, 2, 3, 0, 0><<<dim3(cTOK / 128, 3), 128>>>(
        ppos1, pw2, pb2, nullptr, nullptr, ph, 128, 128, 128, 384,
        nullptr, nullptr, nullptr, 0);

    // ---- mamba layers ----
    for (int i = 0; i < cNL; i++) {
        const float* in_w_i  = in_w  + (size_t)i * 2 * cDI * cDM;
        const float* cw_i    = convw + (size_t)i * cDI * 4;
        const float* cb_i    = convb + (size_t)i * cDI;
        const float* dtb_i   = dt_b  + (size_t)i * cDI;
        const float* Al_i    = A_log + (size_t)i * cDI * cDS;
        const float* Dp_i    = Dp    + (size_t)i * cDI;
        const float* ow_i    = out_w + (size_t)i * cDM * cDI;
        const float* lnw_i   = lnw   + (size_t)i * cDM;
        const float* lnb_i   = lnb   + (size_t)i * cDM;
        const float* xpw_i   = pxpw  + (size_t)i * 64 * cDI;
        const float* dtw_i   = pdtw  + (size_t)i * cDI * 32;

        resln_kernel<<<cTOK, 128>>>(lnw_i, lnb_i, i == 0 ? 1 : 0);
        // in-proj: (2048,384)@(1536,384)^T
        tc2<128, 128, 2, 2, 0, 0, 0><<<dim3(cTOK / 128, 12), 128>>>(
            pxln, in_w_i, nullptr, nullptr, nullptr, pxz, 384, 384, 384, 1536,
            nullptr, nullptr, nullptr, 0);
        conv_kernel<<<(cTOK * cDI + 255) / 256, 256>>>(cw_i, cb_i);
        // xp: (2048,768)@(64,768)^T -> g_dbl64
        tc2<128, 64, 4, 1, 0, 0, 0><<<dim3(cTOK / 128, 1), 128>>>(
            pxc, xpw_i, nullptr, nullptr, nullptr, pdbl, 768, 768, 768, 64,
            nullptr, nullptr, nullptr, 0);
        // dt: (2048,32pad)@(768,32)^T + bias -> softplus
        tc2<128, 128, 2, 2, 2, 0, 0><<<dim3(cTOK / 128, 6), 128>>>(
            pdbl, dtw_i, dtb_i, nullptr, nullptr, pdt, 32, 64, 32, 768,
            nullptr, nullptr, nullptr, 0);
        scan_kernel<<<dim3(cDI / 16, cB), 256>>>(Al_i, Dp_i);
        // out-proj: (2048,768)@(384,768)^T
        tc2<64, 128, 1, 2, 0, 0, 0><<<dim3(cTOK / 64, 3), 64>>>(
            pu, ow_i, nullptr, nullptr, nullptr, ph, 768, 768, 768, 384,
            nullptr, nullptr, nullptr, 0);
    }

    // ---- final LN ----
    final_kernel<<<cTOK, 128>>>(fnw, fnb, out);
}

// round 9
// speedup vs baseline: 1.6086x; 1.1339x over previous
#include <cuda_runtime.h>
#include <math.h>
#include <float.h>

// ---------------------------------------------------------------------------
// Problem constants
// ---------------------------------------------------------------------------
constexpr int cB   = 16;
constexpr int cN   = 2048;
constexpr int cG   = 128;
constexpr int cM   = 32;
constexpr int cDM  = 384;
constexpr int cNL  = 12;
constexpr int cDI  = 768;
constexpr int cDS  = 16;
constexpr int cDTR = 24;
constexpr int cTOK = cB * cG;        // 2048 tokens
constexpr int cPTS = cTOK * cM;      // 65536 points

// ---------------------------------------------------------------------------
// Scratch (device globals; no dynamic allocation allowed)
// ---------------------------------------------------------------------------
__device__ __align__(16) float g_center[cTOK * 3];
__device__ __align__(16) float g_nb[cPTS * 3];
__device__ __align__(16) float g_f2[(size_t)cPTS * 256];
__device__ __align__(16) float g_fg[cTOK * 256];
__device__ __align__(16) float g_f3[(size_t)cPTS * 512];
__device__ __align__(16) float g_pos1[cTOK * 128];
__device__ __align__(16) float g_h[cTOK * cDM];
__device__ __align__(16) float g_res[cTOK * cDM];
__device__ __align__(16) float g_xln[cTOK * cDM];
__device__ __align__(16) float g_xz[(size_t)cTOK * 2 * cDI];
__device__ __align__(16) float g_xc[(size_t)cTOK * cDI];
__device__ __align__(16) float g_dbl64[cTOK * 64];
__device__ __align__(16) float g_dt[(size_t)cTOK * cDI];
__device__ __align__(16) float g_u[(size_t)cTOK * cDI];
__device__ __align__(16) float g_xpw[cNL * 64 * cDI];
__device__ __align__(16) float g_dtw[cNL * cDI * 32];

using u32 = unsigned int;

__device__ __forceinline__ u32 cvt_tf32(float x) {
    u32 r;
    asm("cvt.rna.tf32.f32 %0, %1;" : "=r"(r) : "f"(x));
    return r;
}

__device__ __forceinline__ void mma_tf32(float* c, u32 a0, u32 a1, u32 a2, u32 a3,
                                         u32 b0, u32 b1) {
    asm volatile(
        "mma.sync.aligned.m16n8k8.row.col.f32.tf32.tf32.f32 "
        "{%0,%1,%2,%3}, {%4,%5,%6,%7}, {%8,%9}, {%0,%1,%2,%3};"
        : "+f"(c[0]), "+f"(c[1]), "+f"(c[2]), "+f"(c[3])
        : "r"(a0), "r"(a1), "r"(a2), "r"(a3), "r"(b0), "r"(b1));
}

// ---------------------------------------------------------------------------
// Generic tf32 tensor-core GEMM: C = epi(A' @ W^T) where A' depends on MODEA.
//   CTA tile BM x BN, warp grid WGM x WGN. BK=16, double-buffered smem.
//   EPI 0: +bias(opt). 1: relu(bn(.+bias)). 2: softplus(.+bias). 3: C += .+bias
//   MODEA 0: A' = A (row-major, lda)
//   MODEA 1: A' cols [0,256) from aux1[row>>5][k] (group feat), rest from A
//   MODEA 2: A' = relu(bn1(nb @ w1^T + b1)): A=nb, aux1=w1, aux2=b1,
//            p1=bn gamma, p2=bn beta  (K=128)
//   EMAX  0: normal epilogue.
//   EMAX  1: EPI must be 0 w/ bias; write C AND 32-row group max to fgout.
//   EMAX  2: write ONLY 32-row group max (C unused). Requires WTM==64.
// ---------------------------------------------------------------------------
template<int BM, int BN, int WGM, int WGN, int EPI, int MODEA, int EMAX>
__global__ void __launch_bounds__(WGM * WGN * 32)
tc2(const float* __restrict__ A, const float* __restrict__ W,
    const float* __restrict__ bias, const float* __restrict__ p1,
    const float* __restrict__ p2, float* __restrict__ C,
    int K, int lda, int ldw, int ldc,
    const float* __restrict__ aux1, const float* __restrict__ aux2,
    float* __restrict__ fgout, int ldfg)
{
    constexpr int THREADS = WGM * WGN * 32;
    constexpr int WTM = BM / WGM, WTN = BN / WGN;
    constexpr int MT = WTM / 16, NT = WTN / 8;
    constexpr int LA = BM + 8, LB = BN + 8;
    constexpr int A4 = (BM * 16) / (THREADS * 4);
    constexpr int W4 = (BN * 16) / (THREADS * 4);
    static_assert(EMAX == 0 || WTM == 64, "EMAX needs WTM==64");

    __shared__ float As[2][16][LA];
    __shared__ float Ws[2][16][LB];

    const int tid = threadIdx.x;
    const int wid = tid >> 5, lane = tid & 31;
    const int grp = lane >> 2, tig = lane & 3;
    const int wm = wid % WGM, wn = wid / WGM;
    const int m0 = blockIdx.x * BM, n0 = blockIdx.y * BN;
    const float bnscale = rsqrtf(1.0f + 1e-5f);

    float acc[MT][NT][4];
#pragma unroll
    for (int mt = 0; mt < MT; mt++)
#pragma unroll
        for (int nt = 0; nt < NT; nt++)
#pragma unroll
            for (int r = 0; r < 4; r++) acc[mt][nt][r] = 0.f;

    // MODEA==2: hoist per-row point coords (rows fixed per thread across chunks)
    float nbr[MODEA == 2 ? A4 : 1][3];
    if (MODEA == 2) {
#pragma unroll
        for (int v = 0; v < A4; v++) {
            int row = (tid + v * THREADS) >> 2;
            nbr[v][0] = A[(size_t)(m0 + row) * 3 + 0];
            nbr[v][1] = A[(size_t)(m0 + row) * 3 + 1];
            nbr[v][2] = A[(size_t)(m0 + row) * 3 + 2];
        }
    }

    float4 ra[A4], rw[W4];

    auto loadG = [&](int kc) {
#pragma unroll
        for (int v = 0; v < A4; v++) {
            int s = tid + v * THREADS;
            int row = s >> 2;
            int k = kc + (s & 3) * 4;
            if (MODEA == 0) {
                ra[v] = *(const float4*)(A + (size_t)(m0 + row) * lda + k);
            } else if (MODEA == 1) {
                int r = m0 + row;
                const float* src = (k < 256)
                    ? (aux1 + ((size_t)(r >> 5)) * 256 + k)
                    : (A + (size_t)r * lda + (k - 256));
                ra[v] = *(const float4*)src;
            } else { // MODEA == 2
                float out[4];
#pragma unroll
                for (int e = 0; e < 4; e++) {
                    int kk = k + e;
                    float val = nbr[v][0] * aux1[kk * 3 + 0]
                              + nbr[v][1] * aux1[kk * 3 + 1]
                              + nbr[v][2] * aux1[kk * 3 + 2] + aux2[kk];
                    val = val * (p1[kk] * bnscale) + p2[kk];
                    out[e] = fmaxf(val, 0.f);
                }
                ra[v] = make_float4(out[0], out[1], out[2], out[3]);
            }
        }
#pragma unroll
        for (int v = 0; v < W4; v++) {
            int s = tid + v * THREADS;
            int row = s >> 2, k4 = s & 3;
            rw[v] = *(const float4*)(W + (size_t)(n0 + row) * ldw + kc + k4 * 4);
        }
    };
    auto stsG = [&](int buf) {
#pragma unroll
        for (int v = 0; v < A4; v++) {
            int s = tid + v * THREADS;
            int row = s >> 2, kq = (s & 3) << 2;
            As[buf][kq + 0][row] = __uint_as_float(cvt_tf32(ra[v].x));
            As[buf][kq + 1][row] = __uint_as_float(cvt_tf32(ra[v].y));
            As[buf][kq + 2][row] = __uint_as_float(cvt_tf32(ra[v].z));
            As[buf][kq + 3][row] = __uint_as_float(cvt_tf32(ra[v].w));
        }
#pragma unroll
        for (int v = 0; v < W4; v++) {
            int s = tid + v * THREADS;
            int row = s >> 2, kq = (s & 3) << 2;
            Ws[buf][kq + 0][row] = __uint_as_float(cvt_tf32(rw[v].x));
            Ws[buf][kq + 1][row] = __uint_as_float(cvt_tf32(rw[v].y));
            Ws[buf][kq + 2][row] = __uint_as_float(cvt_tf32(rw[v].z));
            Ws[buf][kq + 3][row] = __uint_as_float(cvt_tf32(rw[v].w));
        }
    };

    const int nIter = K >> 4;
    loadG(0);
    stsG(0);
    __syncthreads();
    int buf = 0;

    for (int it = 0; it < nIter; it++) {
        bool more = (it + 1 < nIter);
        if (more) loadG((it + 1) << 4);
#pragma unroll
        for (int ks = 0; ks < 2; ks++) {
            const int k0 = ks * 8;
            u32 af[MT][4];
#pragma unroll
            for (int mt = 0; mt < MT; mt++) {
                int m = wm * WTM + mt * 16 + grp;
                af[mt][0] = __float_as_uint(As[buf][k0 + tig][m]);
                af[mt][1] = __float_as_uint(As[buf][k0 + tig][m + 8]);
                af[mt][2] = __float_as_uint(As[buf][k0 + tig + 4][m]);
                af[mt][3] = __float_as_uint(As[buf][k0 + tig + 4][m + 8]);
            }
            u32 bf[NT][2];
#pragma unroll
            for (int nt = 0; nt < NT; nt++) {
                int n = wn * WTN + nt * 8 + grp;
                bf[nt][0] = __float_as_uint(Ws[buf][k0 + tig][n]);
                bf[nt][1] = __float_as_uint(Ws[buf][k0 + tig + 4][n]);
            }
#pragma unroll
            for (int mt = 0; mt < MT; mt++)
#pragma unroll
                for (int nt = 0; nt < NT; nt++)
                    mma_tf32(acc[mt][nt], af[mt][0], af[mt][1], af[mt][2], af[mt][3],
                             bf[nt][0], bf[nt][1]);
        }
        if (more) {
            stsG(buf ^ 1);
            __syncthreads();
            buf ^= 1;
        }
    }

    if constexpr (EMAX == 0) {
        auto emit = [&](int mrow, int n, float v0, float v1) {
            if (EPI == 3) {
                C[(size_t)mrow * ldc + n]     += v0 + bias[n];
                C[(size_t)mrow * ldc + n + 1] += v1 + bias[n + 1];
                return;
            }
            if (EPI == 0) {
                if (bias) { v0 += bias[n]; v1 += bias[n + 1]; }
            } else if (EPI == 1) {
                v0 = fmaxf((v0 + bias[n]) * (p1[n] * bnscale) + p2[n], 0.f);
                v1 = fmaxf((v1 + bias[n + 1]) * (p1[n + 1] * bnscale) + p2[n + 1], 0.f);
            } else if (EPI == 2) {
                v0 += bias[n]; v1 += bias[n + 1];
                v0 = fmaxf(v0, 0.f) + log1pf(__expf(-fabsf(v0)));
                v1 = fmaxf(v1, 0.f) + log1pf(__expf(-fabsf(v1)));
            }
            float2 o; o.x = v0; o.y = v1;
            *(float2*)&C[(size_t)mrow * ldc + n] = o;
        };
#pragma unroll
        for (int mt = 0; mt < MT; mt++) {
            int mrow = m0 + wm * WTM + mt * 16 + grp;
#pragma unroll
            for (int nt = 0; nt < NT; nt++) {
                int n = n0 + wn * WTN + nt * 8 + tig * 2;
                emit(mrow,     n, acc[mt][nt][0], acc[mt][nt][1]);
                emit(mrow + 8, n, acc[mt][nt][2], acc[mt][nt][3]);
            }
        }
    } else {
        // 32-row group max epilogue (warp covers rows wm*64..+63 = 2 groups)
        float mx[2][NT][2];
#pragma unroll
        for (int g = 0; g < 2; g++)
#pragma unroll
            for (int nt = 0; nt < NT; nt++) {
                mx[g][nt][0] = -FLT_MAX; mx[g][nt][1] = -FLT_MAX;
            }
#pragma unroll
        for (int mt = 0; mt < MT; mt++) {
            int gsel = (mt >= MT / 2) ? 1 : 0;
            int mrow = m0 + wm * WTM + mt * 16 + grp;
#pragma unroll
            for (int nt = 0; nt < NT; nt++) {
                int n = n0 + wn * WTN + nt * 8 + tig * 2;
                float v0 = acc[mt][nt][0] + bias[n];
                float v1 = acc[mt][nt][1] + bias[n + 1];
                float v2 = acc[mt][nt][2] + bias[n];
                float v3 = acc[mt][nt][3] + bias[n + 1];
                if (EMAX == 1) {
                    float2 o0; o0.x = v0; o0.y = v1;
                    float2 o1; o1.x = v2; o1.y = v3;
                    *(float2*)&C[(size_t)mrow * ldc + n] = o0;
                    *(float2*)&C[(size_t)(mrow + 8) * ldc + n] = o1;
                }
                mx[gsel][nt][0] = fmaxf(mx[gsel][nt][0], fmaxf(v0, v2));
                mx[gsel][nt][1] = fmaxf(mx[gsel][nt][1], fmaxf(v1, v3));
            }
        }
#pragma unroll
        for (int g = 0; g < 2; g++) {
#pragma unroll
            for (int nt = 0; nt < NT; nt++)
#pragma unroll
                for (int c = 0; c < 2; c++) {
                    float v = mx[g][nt][c];
                    v = fmaxf(v, __shfl_xor_sync(0xffffffffu, v, 4));
                    v = fmaxf(v, __shfl_xor_sync(0xffffffffu, v, 8));
                    v = fmaxf(v, __shfl_xor_sync(0xffffffffu, v, 16));
                    mx[g][nt][c] = v;
                }
            if (lane < 4) {
                int grow = (m0 >> 5) + wm * 2 + g;
#pragma unroll
                for (int nt = 0; nt < NT; nt++) {
                    int n = n0 + wn * WTN + nt * 8 + tig * 2;
                    fgout[(size_t)grow * ldfg + n]     = mx[g][nt][0];
                    fgout[(size_t)grow * ldfg + n + 1] = mx[g][nt][1];
                }
            }
        }
    }
}

// ---------------------------------------------------------------------------
// Pad xp_w (56x768 -> 64x768, zero rows) and dt_w (768x24 -> 768x32, zero cols)
// ---------------------------------------------------------------------------
__global__ void pad_weights(const float* __restrict__ xp_w,
                            const float* __restrict__ dt_w) {
    int idx = blockIdx.x * 256 + threadIdx.x;
    constexpr int NXP = cNL * 64 * cDI;
    constexpr int NDT = cNL * cDI * 32;
    if (idx < NXP) {
        int l = idx / (64 * cDI);
        int r = (idx / cDI) % 64;
        int k = idx % cDI;
        g_xpw[idx] = (r < 56) ? xp_w[((size_t)l * 56 + r) * cDI + k] : 0.f;
    } else if (idx < NXP + NDT) {
        int j = idx - NXP;
        int l = j / (cDI * 32);
        int d = (j / 32) % cDI;
        int k = j % 32;
        g_dtw[j] = (k < 24) ? dt_w[((size_t)l * cDI + d) * cDTR + k] : 0.f;
    }
}

// ---------------------------------------------------------------------------
// FPS: per batch, exact replication of reference scan (incl. tie-breaking)
// ---------------------------------------------------------------------------
__global__ void fps_kernel(const float* __restrict__ xyz) {
    int b = blockIdx.x;
    __shared__ float px[cN], py[cN], pz[cN], dmin[cN];
    __shared__ float wv[8];
    __shared__ int   wi[8];
    __shared__ int   s_cur;
    int tid = threadIdx.x;
    int wid = tid >> 5, lane = tid & 31;
    for (int i = tid; i < cN; i += 256) {
        px[i] = xyz[(b * cN + i) * 3 + 0];
        py[i] = xyz[(b * cN + i) * 3 + 1];
        pz[i] = xyz[(b * cN + i) * 3 + 2];
        dmin[i] = 1e10f;
    }
    __syncthreads();
    int cur = 0;
    for (int g = 0; g < cG; g++) {
        float cx = px[cur], cy = py[cur], cz = pz[cur];
        if (tid == 0) {
            g_center[(b * cG + g) * 3 + 0] = cx;
            g_center[(b * cG + g) * 3 + 1] = cy;
            g_center[(b * cG + g) * 3 + 2] = cz;
        }
        float bv = -1.f; int bi = 0x7fffffff;
        for (int i = tid; i < cN; i += 256) {
            float dx = __fsub_rn(px[i], cx);
            float dy = __fsub_rn(py[i], cy);
            float dz = __fsub_rn(pz[i], cz);
            float dd = __fadd_rn(__fadd_rn(__fmul_rn(dx, dx), __fmul_rn(dy, dy)),
                                 __fmul_rn(dz, dz));
            float dm = fminf(dmin[i], dd);
            dmin[i] = dm;
            if (dm > bv) { bv = dm; bi = i; }
        }
#pragma unroll
        for (int off = 16; off > 0; off >>= 1) {
            float ov = __shfl_xor_sync(0xffffffffu, bv, off);
            int oi = __shfl_xor_sync(0xffffffffu, bi, off);
            if (ov > bv || (ov == bv && oi < bi)) { bv = ov; bi = oi; }
        }
        if (lane == 0) { wv[wid] = bv; wi[wid] = bi; }
        __syncthreads();
        if (tid < 8) {
            bv = wv[tid]; bi = wi[tid];
#pragma unroll
            for (int off = 4; off > 0; off >>= 1) {
                float ov = __shfl_xor_sync(0xffu, bv, off);
                int oi = __shfl_xor_sync(0xffu, bi, off);
                if (ov > bv || (ov == bv && oi < bi)) { bv = ov; bi = oi; }
            }
            if (tid == 0) s_cur = bi;
        }
        __syncthreads();
        cur = s_cur;
    }
}

// ---------------------------------------------------------------------------
// KNN: 32 smallest d2, ties -> lowest index; writes nb
// ---------------------------------------------------------------------------
__global__ void knn_kernel(const float* __restrict__ xyz) {
    int bg = blockIdx.x;
    int b = bg >> 7;
    __shared__ float d2s[cN];
    __shared__ float wv[8];
    __shared__ int   wi[8];
    __shared__ int   s_idx;
    int tid = threadIdx.x;
    int wid = tid >> 5, lane = tid & 31;
    float cx = g_center[bg * 3 + 0], cy = g_center[bg * 3 + 1], cz = g_center[bg * 3 + 2];
    const float* P = xyz + (size_t)b * cN * 3;
    for (int i = tid; i < cN; i += 256) {
        float dx = __fsub_rn(cx, P[i * 3 + 0]);
        float dy = __fsub_rn(cy, P[i * 3 + 1]);
        float dz = __fsub_rn(cz, P[i * 3 + 2]);
        d2s[i] = __fadd_rn(__fadd_rn(__fmul_rn(dx, dx), __fmul_rn(dy, dy)),
                           __fmul_rn(dz, dz));
    }
    __syncthreads();
    for (int m = 0; m < cM; m++) {
        float bv = FLT_MAX; int bi = 0x7fffffff;
        for (int i = tid; i < cN; i += 256) {
            float v = d2s[i];
            if (v < bv) { bv = v; bi = i; }
        }
#pragma unroll
        for (int off = 16; off > 0; off >>= 1) {
            float ov = __shfl_xor_sync(0xffffffffu, bv, off);
            int oi = __shfl_xor_sync(0xffffffffu, bi, off);
            if (ov < bv || (ov == bv && oi < bi)) { bv = ov; bi = oi; }
        }
        if (lane == 0) { wv[wid] = bv; wi[wid] = bi; }
        __syncthreads();
        if (tid < 8) {
            bv = wv[tid]; bi = wi[tid];
#pragma unroll
            for (int off = 4; off > 0; off >>= 1) {
                float ov = __shfl_xor_sync(0xffu, bv, off);
                int oi = __shfl_xor_sync(0xffu, bi, off);
                if (ov < bv || (ov == bv && oi < bi)) { bv = ov; bi = oi; }
            }
            if (tid == 0) s_idx = bi;
        }
        __syncthreads();
        int idx = s_idx;
        if (tid < 3) {
            float c = (tid == 0) ? cx : ((tid == 1) ? cy : cz);
            g_nb[((size_t)bg * cM + m) * 3 + tid] = __fsub_rn(P[idx * 3 + tid], c);
        }
        if (tid == 0) d2s[idx] = FLT_MAX;
        __syncthreads();
    }
}

// ---------------------------------------------------------------------------
// Positional MLP stage 1 (gelu)
// ---------------------------------------------------------------------------
__global__ void pos1_kernel(const float* __restrict__ pw1, const float* __restrict__ pb1) {
    int idx = blockIdx.x * blockDim.x + threadIdx.x;
    if (idx >= cTOK * 128) return;
    int t = idx >> 7, j = idx & 127;
    float x0 = g_center[t * 3 + 0], x1 = g_center[t * 3 + 1], x2 = g_center[t * 3 + 2];
    float v = x0 * pw1[j * 3 + 0] + x1 * pw1[j * 3 + 1] + x2 * pw1[j * 3 + 2] + pb1[j];
    float v3 = v * v * v;
    float g = 0.5f * v * (1.0f + tanhf(0.7978845608028654f * (v + 0.044715f * v3)));
    g_pos1[idx] = g;
}

// ---------------------------------------------------------------------------
// Residual accumulate + LayerNorm
// ---------------------------------------------------------------------------
__device__ __forceinline__ float block_sum_128(float v, float* sm) {
    int tid = threadIdx.x;
    sm[tid] = v; __syncthreads();
    for (int s = 64; s > 0; s >>= 1) {
        if (tid < s) sm[tid] += sm[tid + s];
        __syncthreads();
    }
    float r = sm[0]; __syncthreads();
    return r;
}

__global__ void resln_kernel(const float* __restrict__ w, const float* __restrict__ b,
                             int first) {
    __shared__ float sm[128];
    int t = blockIdx.x;
    float v[3];
#pragma unroll
    for (int j = 0; j < 3; j++) {
        int c = threadIdx.x + j * 128;
        float r = g_h[t * 384 + c];
        if (!first) r += g_res[t * 384 + c];
        g_res[t * 384 + c] = r;
        v[j] = r;
    }
    float mean = block_sum_128(v[0] + v[1] + v[2], sm) * (1.0f / 384.0f);
    float sq = 0.f;
#pragma unroll
    for (int j = 0; j < 3; j++) { float d = v[j] - mean; sq += d * d; }
    float var = block_sum_128(sq, sm) * (1.0f / 384.0f);
    float inv = rsqrtf(var + 1e-5f);
#pragma unroll
    for (int j = 0; j < 3; j++) {
        int c = threadIdx.x + j * 128;
        g_xln[t * 384 + c] = (v[j] - mean) * inv * w[c] + b[c];
    }
}

__global__ void final_kernel(const float* __restrict__ w, const float* __restrict__ b,
                             float* __restrict__ out) {
    __shared__ float sm[128];
    int t = blockIdx.x;
    float v[3];
#pragma unroll
    for (int j = 0; j < 3; j++) {
        int c = threadIdx.x + j * 128;
        v[j] = g_h[t * 384 + c] + g_res[t * 384 + c];
    }
    float mean = block_sum_128(v[0] + v[1] + v[2], sm) * (1.0f / 384.0f);
    float sq = 0.f;
#pragma unroll
    for (int j = 0; j < 3; j++) { float d = v[j] - mean; sq += d * d; }
    float var = block_sum_128(sq, sm) * (1.0f / 384.0f);
    float inv = rsqrtf(var + 1e-5f);
#pragma unroll
    for (int j = 0; j < 3; j++) {
        int c = threadIdx.x + j * 128;
        out[t * 384 + c] = (v[j] - mean) * inv * w[c] + b[c];
    }
}

// ---------------------------------------------------------------------------
// Depthwise causal conv (DC=4) + bias + silu
// ---------------------------------------------------------------------------
__global__ void conv_kernel(const float* __restrict__ cw, const float* __restrict__ cb) {
    int idx = blockIdx.x * blockDim.x + threadIdx.x;
    if (idx >= cTOK * cDI) return;
    int t = idx / cDI, d = idx % cDI;
    int l = t & 127;
    int tbase = t - l;
    float acc = cb[d];
#pragma unroll
    for (int k = 0; k < 4; k++) {
        int lk = l - 3 + k;
        if (lk >= 0)
            acc += g_xz[(size_t)(tbase + lk) * 1536 + d] * cw[d * 4 + k];
    }
    float sig = 1.0f / (1.0f + __expf(-acc));
    g_xc[idx] = acc * sig;
}

// ---------------------------------------------------------------------------
// Selective scan v3: one thread per (b, d); all 16 states in registers.
// B/C for the whole 128-step sequence staged into smem once.
// Fast path: if A[d][s] == (s+1)*A[d][0] (checked at runtime), dA_s = q^(s+1)
// with q = __expf(dt*A0) -> 1 MUFU per (t,d) instead of 16.
// ---------------------------------------------------------------------------
template<bool FAST>
__device__ __forceinline__ void scan_body(
    int b, int d, float a0, const float* a, float Dpd) {
    extern __shared__ float4 sBC[];   // [128][8]: B quads 0..3, C quads 4..7
    float h[16];
#pragma unroll
    for (int s = 0; s < 16; s++) h[s] = 0.f;

    const float* pdt = g_dt + (size_t)b * 128 * cDI + d;
    const float* pxc = g_xc + (size_t)b * 128 * cDI + d;
    const float* pz  = g_xz + (size_t)b * 128 * 1536 + cDI + d;
    float* pu = g_u + (size_t)b * 128 * cDI + d;

    for (int t = 0; t < 128; t++) {
        float dt = pdt[(size_t)t * cDI];
        float xin = pxc[(size_t)t * cDI];
        float u = dt * xin;
        float p[16];
        if (FAST) {
            float q = __expf(dt * a0);
            float q2 = q * q, q4 = q2 * q2, q8 = q4 * q4;
            p[0] = q;        p[1] = q2;       p[2] = q2 * q;   p[3] = q4;
            p[4] = q4 * q;   p[5] = q4 * q2;  p[6] = p[5] * q; p[7] = q8;
            p[8] = q8 * q;   p[9] = q8 * q2;  p[10] = p[9] * q;
            p[11] = q8 * q4; p[12] = p[11] * q; p[13] = p[11] * q2;
            p[14] = p[13] * q; p[15] = q8 * q8;
        } else {
#pragma unroll
            for (int s = 0; s < 16; s++) p[s] = __expf(dt * a[s]);
        }
        float4 Bq[4], Cq[4];
#pragma unroll
        for (int j = 0; j < 4; j++) { Bq[j] = sBC[t * 8 + j]; Cq[j] = sBC[t * 8 + 4 + j]; }
        const float* Bv = (const float*)Bq;
        const float* Cv = (const float*)Cq;
        float y = 0.f;
#pragma unroll
        for (int s = 0; s < 16; s++) {
            h[s] = p[s] * h[s] + u * Bv[s];
            y += h[s] * Cv[s];
        }
        y += Dpd * xin;
        float z = pz[(size_t)t * 1536];
        float sz = z / (1.0f + __expf(-z));
        pu[(size_t)t * cDI] = y * sz;
    }
}

__global__ void __launch_bounds__(256)
scan_kernel(const float* __restrict__ Alog, const float* __restrict__ Dp) {
    extern __shared__ float4 sBC[];   // 128*8 float4 = 16KB
    int tid = threadIdx.x;
    int b = blockIdx.y;
    int d = blockIdx.x * 256 + tid;

    for (int i = tid; i < 128 * 8; i += 256) {
        int t = i >> 3, j = i & 7;
        sBC[i] = *(const float4*)(g_dbl64 + (size_t)(b * 128 + t) * 64 + 24 + j * 4);
    }
    __syncthreads();

    float a[16];
    bool fast = true;
#pragma unroll
    for (int s = 0; s < 16; s++) a[s] = -expf(Alog[d * 16 + s]);
    float a0 = a[0];
#pragma unroll
    for (int s = 1; s < 16; s++) {
        float ideal = (float)(s + 1) * a0;
        if (fabsf(a[s] - ideal) > 1e-4f * fabsf(ideal)) fast = false;
    }
    float Dpd = Dp[d];

    if (fast) scan_body<true>(b, d, a0, a, Dpd);
    else      scan_body<false>(b, d, a0, a, Dpd);
}

// ---------------------------------------------------------------------------
// Host-side launch sequence
// ---------------------------------------------------------------------------
extern "C" void kernel_launch(void* const* d_in, const int* in_sizes, int n_in,
                              void* d_out, int out_size) {
    const float* xyz   = (const float*)d_in[0];
    const float* e1w1  = (const float*)d_in[1];
    const float* e1b1  = (const float*)d_in[2];
    const float* bn1g  = (const float*)d_in[3];
    const float* bn1b  = (const float*)d_in[4];
    const float* e1w2  = (const float*)d_in[5];
    const float* e1b2  = (const float*)d_in[6];
    const float* e2w1  = (const float*)d_in[7];
    const float* e2b1  = (const float*)d_in[8];
    const float* bn2g  = (const float*)d_in[9];
    const float* bn2b  = (const float*)d_in[10];
    const float* e2w2  = (const float*)d_in[11];
    const float* e2b2  = (const float*)d_in[12];
    const float* pw1   = (const float*)d_in[13];
    const float* pb1   = (const float*)d_in[14];
    const float* pw2   = (const float*)d_in[15];
    const float* pb2   = (const float*)d_in[16];
    const float* in_w  = (const float*)d_in[17];
    const float* convw = (const float*)d_in[18];
    const float* convb = (const float*)d_in[19];
    const float* xp_w  = (const float*)d_in[20];
    const float* dt_w  = (const float*)d_in[21];
    const float* dt_b  = (const float*)d_in[22];
    const float* A_log = (const float*)d_in[23];
    const float* Dp    = (const float*)d_in[24];
    const float* out_w = (const float*)d_in[25];
    const float* lnw   = (const float*)d_in[26];
    const float* lnb   = (const float*)d_in[27];
    const float* fnw   = (const float*)d_in[28];
    const float* fnb   = (const float*)d_in[29];
    float* out = (float*)d_out;

    float *pnb, *pf2, *pfg, *pf3, *pxln, *pxz, *pxc, *pu, *ph, *ppos1,
          *pdbl, *pdt, *pxpw, *pdtw;
    cudaGetSymbolAddress((void**)&pnb,  g_nb);
    cudaGetSymbolAddress((void**)&pf2,  g_f2);
    cudaGetSymbolAddress((void**)&pfg,  g_fg);
    cudaGetSymbolAddress((void**)&pf3,  g_f3);
    cudaGetSymbolAddress((void**)&pxln, g_xln);
    cudaGetSymbolAddress((void**)&pxz,  g_xz);
    cudaGetSymbolAddress((void**)&pxc,  g_xc);
    cudaGetSymbolAddress((void**)&pu,   g_u);
    cudaGetSymbolAddress((void**)&ph,   g_h);
    cudaGetSymbolAddress((void**)&ppos1, g_pos1);
    cudaGetSymbolAddress((void**)&pdbl, g_dbl64);
    cudaGetSymbolAddress((void**)&pdt,  g_dt);
    cudaGetSymbolAddress((void**)&pxpw, g_xpw);
    cudaGetSymbolAddress((void**)&pdtw, g_dtw);

    // ---- weight prep ----
    constexpr int NPAD = cNL * 64 * cDI + cNL * cDI * 32;
    pad_weights<<<(NPAD + 255) / 256, 256>>>(xp_w, dt_w);

    // ---- grouping ----
    fps_kernel<<<cB, 256>>>(xyz);
    knn_kernel<<<cTOK, 256>>>(xyz);

    // ---- encoder ----
    // f2 = (f1 computed on the fly) @ e1w2^T + bias; epilogue also emits g_fg
    tc2<128, 128, 2, 2, 0, 2, 1><<<dim3(cPTS / 128, 2), 128>>>(
        pnb, e1w2, e1b2, bn1g, bn1b, pf2, 128, 3, 128, 256,
        e1w1, e1b1, pfg, 256);
    // f3: concat(fg, f2) @ e2w1^T -> bn+relu
    tc2<128, 128, 2, 2, 1, 1, 0><<<dim3(cPTS / 128, 4), 128>>>(
        pf2, e2w1, e2b1, bn2g, bn2b, pf3, 512, 256, 512, 512,
        pfg, nullptr, nullptr, 0);
    // f4: epilogue emits ONLY token max -> g_h (no f4 materialization)
    tc2<128, 128, 2, 2, 0, 0, 2><<<dim3(cPTS / 128, 3), 128>>>(
        pf3, e2w2, e2b2, nullptr, nullptr, nullptr, 512, 512, 512, 384,
        nullptr, nullptr, ph, 384);

    // ---- positional MLP ----
    pos1_kernel<<<(cTOK * 128 + 255) / 256, 256>>>(pw1, pb1);
    tc2<128, 128, 2, 2, 3, 0, 0><<<dim3(cTOK / 128, 3), 128>>>(
        ppos1, pw2, pb2, nullptr, nullptr, ph, 128, 128, 128, 384,
        nullptr, nullptr, nullptr, 0);

    // ---- mamba layers ----
    constexpr int SCAN_SMEM = 128 * 8 * sizeof(float4);   // 16KB
    for (int i = 0; i < cNL; i++) {
        const float* in_w_i  = in_w  + (size_t)i * 2 * cDI * cDM;
        const float* cw_i    = convw + (size_t)i * cDI * 4;
        const float* cb_i    = convb + (size_t)i * cDI;
        const float* dtb_i   = dt_b  + (size_t)i * cDI;
        const float* Al_i    = A_log + (size_t)i * cDI * cDS;
        const float* Dp_i    = Dp    + (size_t)i * cDI;
        const float* ow_i    = out_w + (size_t)i * cDM * cDI;
        const float* lnw_i   = lnw   + (size_t)i * cDM;
        const float* lnb_i   = lnb   + (size_t)i * cDM;
        const float* xpw_i   = pxpw  + (size_t)i * 64 * cDI;
        const float* dtw_i   = pdtw  + (size_t)i * cDI * 32;

        resln_kernel<<<cTOK, 128>>>(lnw_i, lnb_i, i == 0 ? 1 : 0);
        // in-proj: (2048,384)@(1536,384)^T
        tc2<128, 128, 2, 2, 0, 0, 0><<<dim3(cTOK / 128, 12), 128>>>(
            pxln, in_w_i, nullptr, nullptr, nullptr, pxz, 384, 384, 384, 1536,
            nullptr, nullptr, nullptr, 0);
        conv_kernel<<<(cTOK * cDI + 255) / 256, 256>>>(cw_i, cb_i);
        // xp: (2048,768)@(64,768)^T -> g_dbl64
        tc2<128, 64, 4, 1, 0, 0, 0><<<dim3(cTOK / 128, 1), 128>>>(
            pxc, xpw_i, nullptr, nullptr, nullptr, pdbl, 768, 768, 768, 64,
            nullptr, nullptr, nullptr, 0);
        // dt: (2048,32pad)@(768,32)^T + bias -> softplus
        tc2<128, 128, 2, 2, 2, 0, 0><<<dim3(cTOK / 128, 6), 128>>>(
            pdbl, dtw_i, dtb_i, nullptr, nullptr, pdt, 32, 64, 32, 768,
            nullptr, nullptr, nullptr, 0);
        scan_kernel<<<dim3(cDI / 256, cB), 256, SCAN_SMEM>>>(Al_i, Dp_i);
        // out-proj: (2048,768)@(384,768)^T
        tc2<64, 128, 1, 2, 0, 0, 0><<<dim3(cTOK / 64, 3), 64>>>(
            pu, ow_i, nullptr, nullptr, nullptr, ph, 768, 768, 768, 384,
            nullptr, nullptr, nullptr, 0);
    }

    // ---- final LN ----
    final_kernel<<<cTOK, 128>>>(fnw, fnb, out);
}

// round 10
// speedup vs baseline: 1.8078x; 1.1238x over previous
#include <cuda_runtime.h>
#include <math.h>
#include <float.h>

// ---------------------------------------------------------------------------
// Problem constants
// ---------------------------------------------------------------------------
constexpr int cB   = 16;
constexpr int cN   = 2048;
constexpr int cG   = 128;
constexpr int cM   = 32;
constexpr int cDM  = 384;
constexpr int cNL  = 12;
constexpr int cDI  = 768;
constexpr int cDS  = 16;
constexpr int cDTR = 24;
constexpr int cTOK = cB * cG;        // 2048 tokens
constexpr int cPTS = cTOK * cM;      // 65536 points

// ---------------------------------------------------------------------------
// Scratch (device globals; no dynamic allocation allowed)
// ---------------------------------------------------------------------------
__device__ __align__(16) float g_center[cTOK * 3];
__device__ __align__(16) float g_nb[cPTS * 3];
__device__ __align__(16) float g_f2[(size_t)cPTS * 256];
__device__ __align__(16) float g_fg[cTOK * 256];
__device__ __align__(16) float g_f3[(size_t)cPTS * 512];
__device__ __align__(16) float g_pos1[cTOK * 128];
__device__ __align__(16) float g_h[cTOK * cDM];
__device__ __align__(16) float g_res[cTOK * cDM];
__device__ __align__(16) float g_xln[cTOK * cDM];
__device__ __align__(16) float g_xz[(size_t)cTOK * 2 * cDI];
__device__ __align__(16) float g_xc[(size_t)cTOK * cDI];
__device__ __align__(16) float g_dbl64[cTOK * 64];
__device__ __align__(16) float g_dt[(size_t)cTOK * cDI];
__device__ __align__(16) float g_u[(size_t)cTOK * cDI];
__device__ __align__(16) float g_xpw[cNL * 64 * cDI];
__device__ __align__(16) float g_dtw[cNL * cDI * 32];

using u32 = unsigned int;

__device__ __forceinline__ u32 cvt_tf32(float x) {
    u32 r;
    asm("cvt.rna.tf32.f32 %0, %1;" : "=r"(r) : "f"(x));
    return r;
}

__device__ __forceinline__ u32 smem_u32(const void* p) {
    u32 a;
    asm("{ .reg .u64 t; cvta.to.shared.u64 t, %1; cvt.u32.u64 %0, t; }"
        : "=r"(a) : "l"(p));
    return a;
}

__device__ __forceinline__ void ldsm4(u32& r0, u32& r1, u32& r2, u32& r3, u32 addr) {
    asm volatile("ldmatrix.sync.aligned.m8n8.x4.shared.b16 {%0,%1,%2,%3}, [%4];"
                 : "=r"(r0), "=r"(r1), "=r"(r2), "=r"(r3) : "r"(addr));
}

__device__ __forceinline__ void mma_tf32(float* c, u32 a0, u32 a1, u32 a2, u32 a3,
                                         u32 b0, u32 b1) {
    asm volatile(
        "mma.sync.aligned.m16n8k8.row.col.f32.tf32.tf32.f32 "
        "{%0,%1,%2,%3}, {%4,%5,%6,%7}, {%8,%9}, {%0,%1,%2,%3};"
        : "+f"(c[0]), "+f"(c[1]), "+f"(c[2]), "+f"(c[3])
        : "r"(a0), "r"(a1), "r"(a2), "r"(a3), "r"(b0), "r"(b1));
}

// ---------------------------------------------------------------------------
// Generic tf32 tensor-core GEMM: C = epi(A' @ W^T).
//   Smem tiles stored row-major [row][k] (stride 20 floats, conflict-free for
//   ldmatrix), fragments loaded via ldmatrix.x4.b16 (tf32-as-2xb16 trick).
//   EPI 0: +bias(opt). 1: relu(bn(.+bias)). 2: softplus(.+bias). 3: C += .+bias
//   MODEA 0: A' = A. 1: A' cols [0,256) from aux1[row>>5][k]. 2: A' =
//            relu(bn1(nb@w1^T+b1)) computed on the fly.
//   EMAX 0: normal. 1: write C AND 32-row group max. 2: ONLY group max.
// ---------------------------------------------------------------------------
template<int BM, int BN, int WGM, int WGN, int EPI, int MODEA, int EMAX>
__global__ void __launch_bounds__(WGM * WGN * 32)
tc2(const float* __restrict__ A, const float* __restrict__ W,
    const float* __restrict__ bias, const float* __restrict__ p1,
    const float* __restrict__ p2, float* __restrict__ C,
    int K, int lda, int ldw, int ldc,
    const float* __restrict__ aux1, const float* __restrict__ aux2,
    float* __restrict__ fgout, int ldfg)
{
    constexpr int THREADS = WGM * WGN * 32;
    constexpr int WTM = BM / WGM, WTN = BN / WGN;
    constexpr int MT = WTM / 16, NT = WTN / 8;
    constexpr int NP = NT / 2;
    constexpr int KS = 20;                       // smem row stride (floats)
    constexpr int A4 = (BM * 16) / (THREADS * 4);
    constexpr int W4 = (BN * 16) / (THREADS * 4);
    static_assert(EMAX == 0 || WTM == 64, "EMAX needs WTM==64");
    static_assert(NT % 2 == 0, "NT must be even");

    __shared__ __align__(16) float As[2][BM][KS];
    __shared__ __align__(16) float Ws[2][BN][KS];

    const int tid = threadIdx.x;
    const int wid = tid >> 5, lane = tid & 31;
    const int grp = lane >> 2, tig = lane & 3;
    const int wm = wid % WGM, wn = wid / WGM;
    const int m0 = blockIdx.x * BM, n0 = blockIdx.y * BN;
    const float bnscale = rsqrtf(1.0f + 1e-5f);

    const u32 asBase = smem_u32(&As[0][0][0]);
    const u32 wsBase = smem_u32(&Ws[0][0][0]);
    constexpr u32 ABUF = BM * KS * 4;
    constexpr u32 WBUF = BN * KS * 4;

    // ldmatrix per-thread byte offsets (fixed across iterations)
    u32 aOff[MT], bOff[NP];
    {
        int l7 = lane & 7;
        int aRow = ((lane >> 3) & 1) * 8;
        int aCol = (lane >> 4) * 16;
#pragma unroll
        for (int mt = 0; mt < MT; mt++) {
            int row = wm * WTM + mt * 16 + aRow + l7;
            aOff[mt] = (u32)(row * KS * 4 + aCol);
        }
        int bRow = (lane >> 4) * 8;
        int bCol = ((lane >> 3) & 1) * 16;
#pragma unroll
        for (int p = 0; p < NP; p++) {
            int row = wn * WTN + p * 16 + bRow + l7;
            bOff[p] = (u32)(row * KS * 4 + bCol);
        }
    }

    float acc[MT][NT][4];
#pragma unroll
    for (int mt = 0; mt < MT; mt++)
#pragma unroll
        for (int nt = 0; nt < NT; nt++)
#pragma unroll
            for (int r = 0; r < 4; r++) acc[mt][nt][r] = 0.f;

    // MODEA==2: hoist per-row point coords
    float nbr[MODEA == 2 ? A4 : 1][3];
    if (MODEA == 2) {
#pragma unroll
        for (int v = 0; v < A4; v++) {
            int row = (tid + v * THREADS) >> 2;
            nbr[v][0] = A[(size_t)(m0 + row) * 3 + 0];
            nbr[v][1] = A[(size_t)(m0 + row) * 3 + 1];
            nbr[v][2] = A[(size_t)(m0 + row) * 3 + 2];
        }
    }

    float4 ra[A4], rw[W4];

    auto loadG = [&](int kc) {
#pragma unroll
        for (int v = 0; v < A4; v++) {
            int s = tid + v * THREADS;
            int row = s >> 2;
            int k = kc + (s & 3) * 4;
            if (MODEA == 0) {
                ra[v] = *(const float4*)(A + (size_t)(m0 + row) * lda + k);
            } else if (MODEA == 1) {
                int r = m0 + row;
                const float* src = (k < 256)
                    ? (aux1 + ((size_t)(r >> 5)) * 256 + k)
                    : (A + (size_t)r * lda + (k - 256));
                ra[v] = *(const float4*)src;
            } else {
                float out[4];
#pragma unroll
                for (int e = 0; e < 4; e++) {
                    int kk = k + e;
                    float val = nbr[v][0] * aux1[kk * 3 + 0]
                              + nbr[v][1] * aux1[kk * 3 + 1]
                              + nbr[v][2] * aux1[kk * 3 + 2] + aux2[kk];
                    val = val * (p1[kk] * bnscale) + p2[kk];
                    out[e] = fmaxf(val, 0.f);
                }
                ra[v] = make_float4(out[0], out[1], out[2], out[3]);
            }
        }
#pragma unroll
        for (int v = 0; v < W4; v++) {
            int s = tid + v * THREADS;
            int row = s >> 2, k4 = s & 3;
            rw[v] = *(const float4*)(W + (size_t)(n0 + row) * ldw + kc + k4 * 4);
        }
    };
    auto stsG = [&](int buf) {
#pragma unroll
        for (int v = 0; v < A4; v++) {
            int s = tid + v * THREADS;
            int row = s >> 2, kq = (s & 3) << 2;
            uint4 o;
            o.x = cvt_tf32(ra[v].x); o.y = cvt_tf32(ra[v].y);
            o.z = cvt_tf32(ra[v].z); o.w = cvt_tf32(ra[v].w);
            *reinterpret_cast<uint4*>(&As[buf][row][kq]) = o;
        }
#pragma unroll
        for (int v = 0; v < W4; v++) {
            int s = tid + v * THREADS;
            int row = s >> 2, kq = (s & 3) << 2;
            uint4 o;
            o.x = cvt_tf32(rw[v].x); o.y = cvt_tf32(rw[v].y);
            o.z = cvt_tf32(rw[v].z); o.w = cvt_tf32(rw[v].w);
            *reinterpret_cast<uint4*>(&Ws[buf][row][kq]) = o;
        }
    };

    const int nIter = K >> 4;
    loadG(0);
    stsG(0);
    __syncthreads();
    int buf = 0;

    for (int it = 0; it < nIter; it++) {
        bool more = (it + 1 < nIter);
        if (more) loadG((it + 1) << 4);
        const u32 aB = asBase + (u32)buf * ABUF;
        const u32 wB = wsBase + (u32)buf * WBUF;
#pragma unroll
        for (int ks = 0; ks < 2; ks++) {
            const u32 kb = (u32)(ks * 32);
            u32 af[MT][4];
#pragma unroll
            for (int mt = 0; mt < MT; mt++)
                ldsm4(af[mt][0], af[mt][1], af[mt][2], af[mt][3],
                      aB + aOff[mt] + kb);
            u32 bf[NT][2];
#pragma unroll
            for (int p = 0; p < NP; p++) {
                u32 r0, r1, r2, r3;
                ldsm4(r0, r1, r2, r3, wB + bOff[p] + kb);
                bf[2 * p][0] = r0;     bf[2 * p][1] = r1;
                bf[2 * p + 1][0] = r2; bf[2 * p + 1][1] = r3;
            }
#pragma unroll
            for (int mt = 0; mt < MT; mt++)
#pragma unroll
                for (int nt = 0; nt < NT; nt++)
                    mma_tf32(acc[mt][nt], af[mt][0], af[mt][1], af[mt][2], af[mt][3],
                             bf[nt][0], bf[nt][1]);
        }
        if (more) {
            stsG(buf ^ 1);
            __syncthreads();
            buf ^= 1;
        }
    }

    if constexpr (EMAX == 0) {
        auto emit = [&](int mrow, int n, float v0, float v1) {
            if (EPI == 3) {
                C[(size_t)mrow * ldc + n]     += v0 + bias[n];
                C[(size_t)mrow * ldc + n + 1] += v1 + bias[n + 1];
                return;
            }
            if (EPI == 0) {
                if (bias) { v0 += bias[n]; v1 += bias[n + 1]; }
            } else if (EPI == 1) {
                v0 = fmaxf((v0 + bias[n]) * (p1[n] * bnscale) + p2[n], 0.f);
                v1 = fmaxf((v1 + bias[n + 1]) * (p1[n + 1] * bnscale) + p2[n + 1], 0.f);
            } else if (EPI == 2) {
                v0 += bias[n]; v1 += bias[n + 1];
                v0 = fmaxf(v0, 0.f) + log1pf(__expf(-fabsf(v0)));
                v1 = fmaxf(v1, 0.f) + log1pf(__expf(-fabsf(v1)));
            }
            float2 o; o.x = v0; o.y = v1;
            *(float2*)&C[(size_t)mrow * ldc + n] = o;
        };
#pragma unroll
        for (int mt = 0; mt < MT; mt++) {
            int mrow = m0 + wm * WTM + mt * 16 + grp;
#pragma unroll
            for (int nt = 0; nt < NT; nt++) {
                int n = n0 + wn * WTN + nt * 8 + tig * 2;
                emit(mrow,     n, acc[mt][nt][0], acc[mt][nt][1]);
                emit(mrow + 8, n, acc[mt][nt][2], acc[mt][nt][3]);
            }
        }
    } else {
        float mx[2][NT][2];
#pragma unroll
        for (int g = 0; g < 2; g++)
#pragma unroll
            for (int nt = 0; nt < NT; nt++) {
                mx[g][nt][0] = -FLT_MAX; mx[g][nt][1] = -FLT_MAX;
            }
#pragma unroll
        for (int mt = 0; mt < MT; mt++) {
            int gsel = (mt >= MT / 2) ? 1 : 0;
            int mrow = m0 + wm * WTM + mt * 16 + grp;
#pragma unroll
            for (int nt = 0; nt < NT; nt++) {
                int n = n0 + wn * WTN + nt * 8 + tig * 2;
                float v0 = acc[mt][nt][0] + bias[n];
                float v1 = acc[mt][nt][1] + bias[n + 1];
                float v2 = acc[mt][nt][2] + bias[n];
                float v3 = acc[mt][nt][3] + bias[n + 1];
                if (EMAX == 1) {
                    float2 o0; o0.x = v0; o0.y = v1;
                    float2 o1; o1.x = v2; o1.y = v3;
                    *(float2*)&C[(size_t)mrow * ldc + n] = o0;
                    *(float2*)&C[(size_t)(mrow + 8) * ldc + n] = o1;
                }
                mx[gsel][nt][0] = fmaxf(mx[gsel][nt][0], fmaxf(v0, v2));
                mx[gsel][nt][1] = fmaxf(mx[gsel][nt][1], fmaxf(v1, v3));
            }
        }
#pragma unroll
        for (int g = 0; g < 2; g++) {
#pragma unroll
            for (int nt = 0; nt < NT; nt++)
#pragma unroll
                for (int c = 0; c < 2; c++) {
                    float v = mx[g][nt][c];
                    v = fmaxf(v, __shfl_xor_sync(0xffffffffu, v, 4));
                    v = fmaxf(v, __shfl_xor_sync(0xffffffffu, v, 8));
                    v = fmaxf(v, __shfl_xor_sync(0xffffffffu, v, 16));
                    mx[g][nt][c] = v;
                }
            if (lane < 4) {
                int grow = (m0 >> 5) + wm * 2 + g;
#pragma unroll
                for (int nt = 0; nt < NT; nt++) {
                    int n = n0 + wn * WTN + nt * 8 + tig * 2;
                    fgout[(size_t)grow * ldfg + n]     = mx[g][nt][0];
                    fgout[(size_t)grow * ldfg + n + 1] = mx[g][nt][1];
                }
            }
        }
    }
}

// ---------------------------------------------------------------------------
// Pad xp_w (56x768 -> 64x768) and dt_w (768x24 -> 768x32)
// ---------------------------------------------------------------------------
__global__ void pad_weights(const float* __restrict__ xp_w,
                            const float* __restrict__ dt_w) {
    int idx = blockIdx.x * 256 + threadIdx.x;
    constexpr int NXP = cNL * 64 * cDI;
    constexpr int NDT = cNL * cDI * 32;
    if (idx < NXP) {
        int l = idx / (64 * cDI);
        int r = (idx / cDI) % 64;
        int k = idx % cDI;
        g_xpw[idx] = (r < 56) ? xp_w[((size_t)l * 56 + r) * cDI + k] : 0.f;
    } else if (idx < NXP + NDT) {
        int j = idx - NXP;
        int l = j / (cDI * 32);
        int d = (j / 32) % cDI;
        int k = j % 32;
        g_dtw[j] = (k < 24) ? dt_w[((size_t)l * cDI + d) * cDTR + k] : 0.f;
    }
}

// ---------------------------------------------------------------------------
// FPS
// ---------------------------------------------------------------------------
__global__ void fps_kernel(const float* __restrict__ xyz) {
    int b = blockIdx.x;
    __shared__ float px[cN], py[cN], pz[cN], dmin[cN];
    __shared__ float wv[8];
    __shared__ int   wi[8];
    __shared__ int   s_cur;
    int tid = threadIdx.x;
    int wid = tid >> 5, lane = tid & 31;
    for (int i = tid; i < cN; i += 256) {
        px[i] = xyz[(b * cN + i) * 3 + 0];
        py[i] = xyz[(b * cN + i) * 3 + 1];
        pz[i] = xyz[(b * cN + i) * 3 + 2];
        dmin[i] = 1e10f;
    }
    __syncthreads();
    int cur = 0;
    for (int g = 0; g < cG; g++) {
        float cx = px[cur], cy = py[cur], cz = pz[cur];
        if (tid == 0) {
            g_center[(b * cG + g) * 3 + 0] = cx;
            g_center[(b * cG + g) * 3 + 1] = cy;
            g_center[(b * cG + g) * 3 + 2] = cz;
        }
        float bv = -1.f; int bi = 0x7fffffff;
        for (int i = tid; i < cN; i += 256) {
            float dx = __fsub_rn(px[i], cx);
            float dy = __fsub_rn(py[i], cy);
            float dz = __fsub_rn(pz[i], cz);
            float dd = __fadd_rn(__fadd_rn(__fmul_rn(dx, dx), __fmul_rn(dy, dy)),
                                 __fmul_rn(dz, dz));
            float dm = fminf(dmin[i], dd);
            dmin[i] = dm;
            if (dm > bv) { bv = dm; bi = i; }
        }
#pragma unroll
        for (int off = 16; off > 0; off >>= 1) {
            float ov = __shfl_xor_sync(0xffffffffu, bv, off);
            int oi = __shfl_xor_sync(0xffffffffu, bi, off);
            if (ov > bv || (ov == bv && oi < bi)) { bv = ov; bi = oi; }
        }
        if (lane == 0) { wv[wid] = bv; wi[wid] = bi; }
        __syncthreads();
        if (tid < 8) {
            bv = wv[tid]; bi = wi[tid];
#pragma unroll
            for (int off = 4; off > 0; off >>= 1) {
                float ov = __shfl_xor_sync(0xffu, bv, off);
                int oi = __shfl_xor_sync(0xffu, bi, off);
                if (ov > bv || (ov == bv && oi < bi)) { bv = ov; bi = oi; }
            }
            if (tid == 0) s_cur = bi;
        }
        __syncthreads();
        cur = s_cur;
    }
}

// ---------------------------------------------------------------------------
// KNN
// ---------------------------------------------------------------------------
__global__ void knn_kernel(const float* __restrict__ xyz) {
    int bg = blockIdx.x;
    int b = bg >> 7;
    __shared__ float d2s[cN];
    __shared__ float wv[8];
    __shared__ int   wi[8];
    __shared__ int   s_idx;
    int tid = threadIdx.x;
    int wid = tid >> 5, lane = tid & 31;
    float cx = g_center[bg * 3 + 0], cy = g_center[bg * 3 + 1], cz = g_center[bg * 3 + 2];
    const float* P = xyz + (size_t)b * cN * 3;
    for (int i = tid; i < cN; i += 256) {
        float dx = __fsub_rn(cx, P[i * 3 + 0]);
        float dy = __fsub_rn(cy, P[i * 3 + 1]);
        float dz = __fsub_rn(cz, P[i * 3 + 2]);
        d2s[i] = __fadd_rn(__fadd_rn(__fmul_rn(dx, dx), __fmul_rn(dy, dy)),
                           __fmul_rn(dz, dz));
    }
    __syncthreads();
    for (int m = 0; m < cM; m++) {
        float bv = FLT_MAX; int bi = 0x7fffffff;
        for (int i = tid; i < cN; i += 256) {
            float v = d2s[i];
            if (v < bv) { bv = v; bi = i; }
        }
#pragma unroll
        for (int off = 16; off > 0; off >>= 1) {
            float ov = __shfl_xor_sync(0xffffffffu, bv, off);
            int oi = __shfl_xor_sync(0xffffffffu, bi, off);
            if (ov < bv || (ov == bv && oi < bi)) { bv = ov; bi = oi; }
        }
        if (lane == 0) { wv[wid] = bv; wi[wid] = bi; }
        __syncthreads();
        if (tid < 8) {
            bv = wv[tid]; bi = wi[tid];
#pragma unroll
            for (int off = 4; off > 0; off >>= 1) {
                float ov = __shfl_xor_sync(0xffu, bv, off);
                int oi = __shfl_xor_sync(0xffu, bi, off);
                if (ov < bv || (ov == bv && oi < bi)) { bv = ov; bi = oi; }
            }
            if (tid == 0) s_idx = bi;
        }
        __syncthreads();
        int idx = s_idx;
        if (tid < 3) {
            float c = (tid == 0) ? cx : ((tid == 1) ? cy : cz);
            g_nb[((size_t)bg * cM + m) * 3 + tid] = __fsub_rn(P[idx * 3 + tid], c);
        }
        if (tid == 0) d2s[idx] = FLT_MAX;
        __syncthreads();
    }
}

// ---------------------------------------------------------------------------
// Positional MLP stage 1 (gelu)
// ---------------------------------------------------------------------------
__global__ void pos1_kernel(const float* __restrict__ pw1, const float* __restrict__ pb1) {
    int idx = blockIdx.x * blockDim.x + threadIdx.x;
    if (idx >= cTOK * 128) return;
    int t = idx >> 7, j = idx & 127;
    float x0 = g_center[t * 3 + 0], x1 = g_center[t * 3 + 1], x2 = g_center[t * 3 + 2];
    float v = x0 * pw1[j * 3 + 0] + x1 * pw1[j * 3 + 1] + x2 * pw1[j * 3 + 2] + pb1[j];
    float v3 = v * v * v;
    float g = 0.5f * v * (1.0f + tanhf(0.7978845608028654f * (v + 0.044715f * v3)));
    g_pos1[idx] = g;
}

// ---------------------------------------------------------------------------
// Residual accumulate + LayerNorm
// ---------------------------------------------------------------------------
__device__ __forceinline__ float block_sum_128(float v, float* sm) {
    int tid = threadIdx.x;
    sm[tid] = v; __syncthreads();
    for (int s = 64; s > 0; s >>= 1) {
        if (tid < s) sm[tid] += sm[tid + s];
        __syncthreads();
    }
    float r = sm[0]; __syncthreads();
    return r;
}

__global__ void resln_kernel(const float* __restrict__ w, const float* __restrict__ b,
                             int first) {
    __shared__ float sm[128];
    int t = blockIdx.x;
    float v[3];
#pragma unroll
    for (int j = 0; j < 3; j++) {
        int c = threadIdx.x + j * 128;
        float r = g_h[t * 384 + c];
        if (!first) r += g_res[t * 384 + c];
        g_res[t * 384 + c] = r;
        v[j] = r;
    }
    float mean = block_sum_128(v[0] + v[1] + v[2], sm) * (1.0f / 384.0f);
    float sq = 0.f;
#pragma unroll
    for (int j = 0; j < 3; j++) { float d = v[j] - mean; sq += d * d; }
    float var = block_sum_128(sq, sm) * (1.0f / 384.0f);
    float inv = rsqrtf(var + 1e-5f);
#pragma unroll
    for (int j = 0; j < 3; j++) {
        int c = threadIdx.x + j * 128;
        g_xln[t * 384 + c] = (v[j] - mean) * inv * w[c] + b[c];
    }
}

__global__ void final_kernel(const float* __restrict__ w, const float* __restrict__ b,
                             float* __restrict__ out) {
    __shared__ float sm[128];
    int t = blockIdx.x;
    float v[3];
#pragma unroll
    for (int j = 0; j < 3; j++) {
        int c = threadIdx.x + j * 128;
        v[j] = g_h[t * 384 + c] + g_res[t * 384 + c];
    }
    float mean = block_sum_128(v[0] + v[1] + v[2], sm) * (1.0f / 384.0f);
    float sq = 0.f;
#pragma unroll
    for (int j = 0; j < 3; j++) { float d = v[j] - mean; sq += d * d; }
    float var = block_sum_128(sq, sm) * (1.0f / 384.0f);
    float inv = rsqrtf(var + 1e-5f);
#pragma unroll
    for (int j = 0; j < 3; j++) {
        int c = threadIdx.x + j * 128;
        out[t * 384 + c] = (v[j] - mean) * inv * w[c] + b[c];
    }
}

// ---------------------------------------------------------------------------
// Depthwise causal conv (DC=4) + bias + silu
// ---------------------------------------------------------------------------
__global__ void conv_kernel(const float* __restrict__ cw, const float* __restrict__ cb) {
    int idx = blockIdx.x * blockDim.x + threadIdx.x;
    if (idx >= cTOK * cDI) return;
    int t = idx / cDI, d = idx % cDI;
    int l = t & 127;
    int tbase = t - l;
    float acc = cb[d];
#pragma unroll
    for (int k = 0; k < 4; k++) {
        int lk = l - 3 + k;
        if (lk >= 0)
            acc += g_xz[(size_t)(tbase + lk) * 1536 + d] * cw[d * 4 + k];
    }
    float sig = 1.0f / (1.0f + __expf(-acc));
    g_xc[idx] = acc * sig;
}

// ---------------------------------------------------------------------------
// Selective scan v3 (one thread per (b,d), 16 states in registers,
// q-power fast path when A_log rows are multiples)
// ---------------------------------------------------------------------------
template<bool FAST>
__device__ __forceinline__ void scan_body(
    int b, int d, float a0, const float* a, float Dpd) {
    extern __shared__ float4 sBC[];
    float h[16];
#pragma unroll
    for (int s = 0; s < 16; s++) h[s] = 0.f;

    const float* pdt = g_dt + (size_t)b * 128 * cDI + d;
    const float* pxc = g_xc + (size_t)b * 128 * cDI + d;
    const float* pz  = g_xz + (size_t)b * 128 * 1536 + cDI + d;
    float* pu = g_u + (size_t)b * 128 * cDI + d;

    for (int t = 0; t < 128; t++) {
        float dt = pdt[(size_t)t * cDI];
        float xin = pxc[(size_t)t * cDI];
        float u = dt * xin;
        float p[16];
        if (FAST) {
            float q = __expf(dt * a0);
            float q2 = q * q, q4 = q2 * q2, q8 = q4 * q4;
            p[0] = q;        p[1] = q2;       p[2] = q2 * q;   p[3] = q4;
            p[4] = q4 * q;   p[5] = q4 * q2;  p[6] = p[5] * q; p[7] = q8;
            p[8] = q8 * q;   p[9] = q8 * q2;  p[10] = p[9] * q;
            p[11] = q8 * q4; p[12] = p[11] * q; p[13] = p[11] * q2;
            p[14] = p[13] * q; p[15] = q8 * q8;
        } else {
#pragma unroll
            for (int s = 0; s < 16; s++) p[s] = __expf(dt * a[s]);
        }
        float4 Bq[4], Cq[4];
#pragma unroll
        for (int j = 0; j < 4; j++) { Bq[j] = sBC[t * 8 + j]; Cq[j] = sBC[t * 8 + 4 + j]; }
        const float* Bv = (const float*)Bq;
        const float* Cv = (const float*)Cq;
        float y = 0.f;
#pragma unroll
        for (int s = 0; s < 16; s++) {
            h[s] = p[s] * h[s] + u * Bv[s];
            y += h[s] * Cv[s];
        }
        y += Dpd * xin;
        float z = pz[(size_t)t * 1536];
        float sz = z / (1.0f + __expf(-z));
        pu[(size_t)t * cDI] = y * sz;
    }
}

__global__ void __launch_bounds__(256)
scan_kernel(const float* __restrict__ Alog, const float* __restrict__ Dp) {
    extern __shared__ float4 sBC[];
    int tid = threadIdx.x;
    int b = blockIdx.y;
    int d = blockIdx.x * 256 + tid;

    for (int i = tid; i < 128 * 8; i += 256) {
        int t = i >> 3, j = i & 7;
        sBC[i] = *(const float4*)(g_dbl64 + (size_t)(b * 128 + t) * 64 + 24 + j * 4);
    }
    __syncthreads();

    float a[16];
    bool fast = true;
#pragma unroll
    for (int s = 0; s < 16; s++) a[s] = -expf(Alog[d * 16 + s]);
    float a0 = a[0];
#pragma unroll
    for (int s = 1; s < 16; s++) {
        float ideal = (float)(s + 1) * a0;
        if (fabsf(a[s] - ideal) > 1e-4f * fabsf(ideal)) fast = false;
    }
    float Dpd = Dp[d];

    if (fast) scan_body<true>(b, d, a0, a, Dpd);
    else      scan_body<false>(b, d, a0, a, Dpd);
}

// ---------------------------------------------------------------------------
// Host-side launch sequence
// ---------------------------------------------------------------------------
extern "C" void kernel_launch(void* const* d_in, const int* in_sizes, int n_in,
                              void* d_out, int out_size) {
    const float* xyz   = (const float*)d_in[0];
    const float* e1w1  = (const float*)d_in[1];
    const float* e1b1  = (const float*)d_in[2];
    const float* bn1g  = (const float*)d_in[3];
    const float* bn1b  = (const float*)d_in[4];
    const float* e1w2  = (const float*)d_in[5];
    const float* e1b2  = (const float*)d_in[6];
    const float* e2w1  = (const float*)d_in[7];
    const float* e2b1  = (const float*)d_in[8];
    const float* bn2g  = (const float*)d_in[9];
    const float* bn2b  = (const float*)d_in[10];
    const float* e2w2  = (const float*)d_in[11];
    const float* e2b2  = (const float*)d_in[12];
    const float* pw1   = (const float*)d_in[13];
    const float* pb1   = (const float*)d_in[14];
    const float* pw2   = (const float*)d_in[15];
    const float* pb2   = (const float*)d_in[16];
    const float* in_w  = (const float*)d_in[17];
    const float* convw = (const float*)d_in[18];
    const float* convb = (const float*)d_in[19];
    const float* xp_w  = (const float*)d_in[20];
    const float* dt_w  = (const float*)d_in[21];
    const float* dt_b  = (const float*)d_in[22];
    const float* A_log = (const float*)d_in[23];
    const float* Dp    = (const float*)d_in[24];
    const float* out_w = (const float*)d_in[25];
    const float* lnw   = (const float*)d_in[26];
    const float* lnb   = (const float*)d_in[27];
    const float* fnw   = (const float*)d_in[28];
    const float* fnb   = (const float*)d_in[29];
    float* out = (float*)d_out;

    float *pnb, *pf2, *pfg, *pf3, *pxln, *pxz, *pxc, *pu, *ph, *ppos1,
          *pdbl, *pdt, *pxpw, *pdtw;
    cudaGetSymbolAddress((void**)&pnb,  g_nb);
    cudaGetSymbolAddress((void**)&pf2,  g_f2);
    cudaGetSymbolAddress((void**)&pfg,  g_fg);
    cudaGetSymbolAddress((void**)&pf3,  g_f3);
    cudaGetSymbolAddress((void**)&pxln, g_xln);
    cudaGetSymbolAddress((void**)&pxz,  g_xz);
    cudaGetSymbolAddress((void**)&pxc,  g_xc);
    cudaGetSymbolAddress((void**)&pu,   g_u);
    cudaGetSymbolAddress((void**)&ph,   g_h);
    cudaGetSymbolAddress((void**)&ppos1, g_pos1);
    cudaGetSymbolAddress((void**)&pdbl, g_dbl64);
    cudaGetSymbolAddress((void**)&pdt,  g_dt);
    cudaGetSymbolAddress((void**)&pxpw, g_xpw);
    cudaGetSymbolAddress((void**)&pdtw, g_dtw);

    // ---- weight prep ----
    constexpr int NPAD = cNL * 64 * cDI + cNL * cDI * 32;
    pad_weights<<<(NPAD + 255) / 256, 256>>>(xp_w, dt_w);

    // ---- grouping ----
    fps_kernel<<<cB, 256>>>(xyz);
    knn_kernel<<<cTOK, 256>>>(xyz);

    // ---- encoder ----
    tc2<128, 128, 2, 2, 0, 2, 1><<<dim3(cPTS / 128, 2), 128>>>(
        pnb, e1w2, e1b2, bn1g, bn1b, pf2, 128, 3, 128, 256,
        e1w1, e1b1, pfg, 256);
    tc2<128, 128, 2, 2, 1, 1, 0><<<dim3(cPTS / 128, 4), 128>>>(
        pf2, e2w1, e2b1, bn2g, bn2b, pf3, 512, 256, 512, 512,
        pfg, nullptr, nullptr, 0);
    tc2<128, 128, 2, 2, 0, 0, 2><<<dim3(cPTS / 128, 3), 128>>>(
        pf3, e2w2, e2b2, nullptr, nullptr, nullptr, 512, 512, 512, 384,
        nullptr, nullptr, ph, 384);

    // ---- positional MLP ----
    pos1_kernel<<<(cTOK * 128 + 255) / 256, 256>>>(pw1, pb1);
    tc2<128, 128, 2, 2, 3, 0, 0><<<dim3(cTOK / 128, 3), 128>>>(
        ppos1, pw2, pb2, nullptr, nullptr, ph, 128, 128, 128, 384,
        nullptr, nullptr, nullptr, 0);

    // ---- mamba layers ----
    constexpr int SCAN_SMEM = 128 * 8 * sizeof(float4);
    for (int i = 0; i < cNL; i++) {
        const float* in_w_i  = in_w  + (size_t)i * 2 * cDI * cDM;
        const float* cw_i    = convw + (size_t)i * cDI * 4;
        const float* cb_i    = convb + (size_t)i * cDI;
        const float* dtb_i   = dt_b  + (size_t)i * cDI;
        const float* Al_i    = A_log + (size_t)i * cDI * cDS;
        const float* Dp_i    = Dp    + (size_t)i * cDI;
        const float* ow_i    = out_w + (size_t)i * cDM * cDI;
        const float* lnw_i   = lnw   + (size_t)i * cDM;
        const float* lnb_i   = lnb   + (size_t)i * cDM;
        const float* xpw_i   = pxpw  + (size_t)i * 64 * cDI;
        const float* dtw_i   = pdtw  + (size_t)i * cDI * 32;

        resln_kernel<<<cTOK, 128>>>(lnw_i, lnb_i, i == 0 ? 1 : 0);
        tc2<128, 128, 2, 2, 0, 0, 0><<<dim3(cTOK / 128, 12), 128>>>(
            pxln, in_w_i, nullptr, nullptr, nullptr, pxz, 384, 384, 384, 1536,
            nullptr, nullptr, nullptr, 0);
        conv_kernel<<<(cTOK * cDI + 255) / 256, 256>>>(cw_i, cb_i);
        tc2<128, 64, 4, 1, 0, 0, 0><<<dim3(cTOK / 128, 1), 128>>>(
            pxc, xpw_i, nullptr, nullptr, nullptr, pdbl, 768, 768, 768, 64,
            nullptr, nullptr, nullptr, 0);
        tc2<128, 128, 2, 2, 2, 0, 0><<<dim3(cTOK / 128, 6), 128>>>(
            pdbl, dtw_i, dtb_i, nullptr, nullptr, pdt, 32, 64, 32, 768,
            nullptr, nullptr, nullptr, 0);
        scan_kernel<<<dim3(cDI / 256, cB), 256, SCAN_SMEM>>>(Al_i, Dp_i);
        tc2<64, 128, 1, 2, 0, 0, 0><<<dim3(cTOK / 64, 3), 64>>>(
            pu, ow_i, nullptr, nullptr, nullptr, ph, 768, 768, 768, 384,
            nullptr, nullptr, nullptr, 0);
    }

    // ---- final LN ----
    final_kernel<<<cTOK, 128>>>(fnw, fnb, out);
}

// round 11
// speedup vs baseline: 1.8402x; 1.0179x over previous
#include <cuda_runtime.h>
#include <math.h>
#include <float.h>

// ---------------------------------------------------------------------------
// Problem constants
// ---------------------------------------------------------------------------
constexpr int cB   = 16;
constexpr int cN   = 2048;
constexpr int cG   = 128;
constexpr int cM   = 32;
constexpr int cDM  = 384;
constexpr int cNL  = 12;
constexpr int cDI  = 768;
constexpr int cDS  = 16;
constexpr int cDTR = 24;
constexpr int cTOK = cB * cG;        // 2048 tokens
constexpr int cPTS = cTOK * cM;      // 65536 points

// ---------------------------------------------------------------------------
// Scratch (device globals; no dynamic allocation allowed)
// ---------------------------------------------------------------------------
__device__ __align__(16) float g_center[cTOK * 3];
__device__ __align__(16) float g_nb[cPTS * 3];
__device__ __align__(16) float g_f2[(size_t)cPTS * 256];
__device__ __align__(16) float g_fg[cTOK * 256];
__device__ __align__(16) float g_f3[(size_t)cPTS * 512];
__device__ __align__(16) float g_h[cTOK * cDM];
__device__ __align__(16) float g_res[cTOK * cDM];
__device__ __align__(16) float g_xln[cTOK * cDM];
__device__ __align__(16) float g_xz[(size_t)cTOK * 2 * cDI];
__device__ __align__(16) float g_xc[(size_t)cTOK * cDI];
__device__ __align__(16) float g_dbl64[cTOK * 64];
__device__ __align__(16) float g_dt[(size_t)cTOK * cDI];
__device__ __align__(16) float g_u[(size_t)cTOK * cDI];
__device__ __align__(16) float g_xpw[cNL * 64 * cDI];
__device__ __align__(16) float g_dtw[cNL * cDI * 32];

using u32 = unsigned int;

__device__ __forceinline__ u32 cvt_tf32(float x) {
    u32 r;
    asm("cvt.rna.tf32.f32 %0, %1;" : "=r"(r) : "f"(x));
    return r;
}

__device__ __forceinline__ u32 smem_u32(const void* p) {
    u32 a;
    asm("{ .reg .u64 t; cvta.to.shared.u64 t, %1; cvt.u32.u64 %0, t; }"
        : "=r"(a) : "l"(p));
    return a;
}

__device__ __forceinline__ void ldsm4(u32& r0, u32& r1, u32& r2, u32& r3, u32 addr) {
    asm volatile("ldmatrix.sync.aligned.m8n8.x4.shared.b16 {%0,%1,%2,%3}, [%4];"
                 : "=r"(r0), "=r"(r1), "=r"(r2), "=r"(r3) : "r"(addr));
}

__device__ __forceinline__ void mma_tf32(float* c, u32 a0, u32 a1, u32 a2, u32 a3,
                                         u32 b0, u32 b1) {
    asm volatile(
        "mma.sync.aligned.m16n8k8.row.col.f32.tf32.tf32.f32 "
        "{%0,%1,%2,%3}, {%4,%5,%6,%7}, {%8,%9}, {%0,%1,%2,%3};"
        : "+f"(c[0]), "+f"(c[1]), "+f"(c[2]), "+f"(c[3])
        : "r"(a0), "r"(a1), "r"(a2), "r"(a3), "r"(b0), "r"(b1));
}

// ---------------------------------------------------------------------------
// Generic tf32 tensor-core GEMM: C = epi(A' @ W^T).
//   Smem tiles row-major [row][k] (stride 20 floats, ldmatrix conflict-free),
//   fragments via ldmatrix.x4.b16 (tf32-as-2xb16 trick).
//   EPI 0: +bias(opt). 1: relu(bn(.+bias)). 2: softplus(.+bias). 3: C += .+bias
//   MODEA 0: A' = A. 1: A' cols [0,256) from aux1[row>>5][k].
//         2: A' = relu(bn1(nb@w1^T+b1)) on the fly (aux1=w1,aux2=b1,p1/p2=bn).
//         4: A' = gelu(center@pw1^T+pb1) on the fly (aux1=pw1, aux2=pb1).
//   EMAX 0: normal. 1: write C AND 32-row group max. 2: ONLY group max.
//        (EMAX needs WTM % 32 == 0.)
// ---------------------------------------------------------------------------
template<int BM, int BN, int WGM, int WGN, int EPI, int MODEA, int EMAX>
__global__ void __launch_bounds__(WGM * WGN * 32)
tc2(const float* __restrict__ A, const float* __restrict__ W,
    const float* __restrict__ bias, const float* __restrict__ p1,
    const float* __restrict__ p2, float* __restrict__ C,
    int K, int lda, int ldw, int ldc,
    const float* __restrict__ aux1, const float* __restrict__ aux2,
    float* __restrict__ fgout, int ldfg)
{
    constexpr int THREADS = WGM * WGN * 32;
    constexpr int WTM = BM / WGM, WTN = BN / WGN;
    constexpr int MT = WTM / 16, NT = WTN / 8;
    constexpr int NP = NT / 2;
    constexpr int KS = 20;                       // smem row stride (floats)
    constexpr int A4 = (BM * 16) / (THREADS * 4);
    constexpr int W4 = (BN * 16) / (THREADS * 4);
    static_assert(EMAX == 0 || (WTM % 32) == 0, "EMAX needs WTM%32==0");
    static_assert(NT % 2 == 0, "NT must be even");

    __shared__ __align__(16) float As[2][BM][KS];
    __shared__ __align__(16) float Ws[2][BN][KS];

    const int tid = threadIdx.x;
    const int wid = tid >> 5, lane = tid & 31;
    const int grp = lane >> 2, tig = lane & 3;
    const int wm = wid % WGM, wn = wid / WGM;
    const int m0 = blockIdx.x * BM, n0 = blockIdx.y * BN;
    const float bnscale = rsqrtf(1.0f + 1e-5f);

    const u32 asBase = smem_u32(&As[0][0][0]);
    const u32 wsBase = smem_u32(&Ws[0][0][0]);
    constexpr u32 ABUF = BM * KS * 4;
    constexpr u32 WBUF = BN * KS * 4;

    // ldmatrix per-thread byte offsets
    u32 aOff[MT], bOff[NP];
    {
        int l7 = lane & 7;
        int aRow = ((lane >> 3) & 1) * 8;
        int aCol = (lane >> 4) * 16;
#pragma unroll
        for (int mt = 0; mt < MT; mt++) {
            int row = wm * WTM + mt * 16 + aRow + l7;
            aOff[mt] = (u32)(row * KS * 4 + aCol);
        }
        int bRow = (lane >> 4) * 8;
        int bCol = ((lane >> 3) & 1) * 16;
#pragma unroll
        for (int p = 0; p < NP; p++) {
            int row = wn * WTN + p * 16 + bRow + l7;
            bOff[p] = (u32)(row * KS * 4 + bCol);
        }
    }

    float acc[MT][NT][4];
#pragma unroll
    for (int mt = 0; mt < MT; mt++)
#pragma unroll
        for (int nt = 0; nt < NT; nt++)
#pragma unroll
            for (int r = 0; r < 4; r++) acc[mt][nt][r] = 0.f;

    // MODEA 2/4: hoist per-row point coords
    float nbr[(MODEA >= 2) ? A4 : 1][3];
    if (MODEA >= 2) {
#pragma unroll
        for (int v = 0; v < A4; v++) {
            int row = (tid + v * THREADS) >> 2;
            nbr[v][0] = A[(size_t)(m0 + row) * 3 + 0];
            nbr[v][1] = A[(size_t)(m0 + row) * 3 + 1];
            nbr[v][2] = A[(size_t)(m0 + row) * 3 + 2];
        }
    }

    float4 ra[A4], rw[W4];

    auto loadG = [&](int kc) {
#pragma unroll
        for (int v = 0; v < A4; v++) {
            int s = tid + v * THREADS;
            int row = s >> 2;
            int k = kc + (s & 3) * 4;
            if (MODEA == 0) {
                ra[v] = *(const float4*)(A + (size_t)(m0 + row) * lda + k);
            } else if (MODEA == 1) {
                int r = m0 + row;
                const float* src = (k < 256)
                    ? (aux1 + ((size_t)(r >> 5)) * 256 + k)
                    : (A + (size_t)r * lda + (k - 256));
                ra[v] = *(const float4*)src;
            } else {
                float out[4];
#pragma unroll
                for (int e = 0; e < 4; e++) {
                    int kk = k + e;
                    float val = nbr[v][0] * aux1[kk * 3 + 0]
                              + nbr[v][1] * aux1[kk * 3 + 1]
                              + nbr[v][2] * aux1[kk * 3 + 2] + aux2[kk];
                    if (MODEA == 2) {
                        val = val * (p1[kk] * bnscale) + p2[kk];
                        out[e] = fmaxf(val, 0.f);
                    } else {  // MODEA == 4: gelu (tanh approx)
                        float v3 = val * val * val;
                        out[e] = 0.5f * val *
                            (1.0f + tanhf(0.7978845608028654f *
                                          (val + 0.044715f * v3)));
                    }
                }
                ra[v] = make_float4(out[0], out[1], out[2], out[3]);
            }
        }
#pragma unroll
        for (int v = 0; v < W4; v++) {
            int s = tid + v * THREADS;
            int row = s >> 2, k4 = s & 3;
            rw[v] = *(const float4*)(W + (size_t)(n0 + row) * ldw + kc + k4 * 4);
        }
    };
    auto stsG = [&](int buf) {
#pragma unroll
        for (int v = 0; v < A4; v++) {
            int s = tid + v * THREADS;
            int row = s >> 2, kq = (s & 3) << 2;
            uint4 o;
            o.x = cvt_tf32(ra[v].x); o.y = cvt_tf32(ra[v].y);
            o.z = cvt_tf32(ra[v].z); o.w = cvt_tf32(ra[v].w);
            *reinterpret_cast<uint4*>(&As[buf][row][kq]) = o;
        }
#pragma unroll
        for (int v = 0; v < W4; v++) {
            int s = tid + v * THREADS;
            int row = s >> 2, kq = (s & 3) << 2;
            uint4 o;
            o.x = cvt_tf32(rw[v].x); o.y = cvt_tf32(rw[v].y);
            o.z = cvt_tf32(rw[v].z); o.w = cvt_tf32(rw[v].w);
            *reinterpret_cast<uint4*>(&Ws[buf][row][kq]) = o;
        }
    };

    const int nIter = K >> 4;
    loadG(0);
    stsG(0);
    __syncthreads();
    int buf = 0;

    for (int it = 0; it < nIter; it++) {
        bool more = (it + 1 < nIter);
        if (more) loadG((it + 1) << 4);
        const u32 aB = asBase + (u32)buf * ABUF;
        const u32 wB = wsBase + (u32)buf * WBUF;
#pragma unroll
        for (int ks = 0; ks < 2; ks++) {
            const u32 kb = (u32)(ks * 32);
            u32 af[MT][4];
#pragma unroll
            for (int mt = 0; mt < MT; mt++)
                ldsm4(af[mt][0], af[mt][1], af[mt][2], af[mt][3],
                      aB + aOff[mt] + kb);
            u32 bf[NT][2];
#pragma unroll
            for (int p = 0; p < NP; p++) {
                u32 r0, r1, r2, r3;
                ldsm4(r0, r1, r2, r3, wB + bOff[p] + kb);
                bf[2 * p][0] = r0;     bf[2 * p][1] = r1;
                bf[2 * p + 1][0] = r2; bf[2 * p + 1][1] = r3;
            }
#pragma unroll
            for (int mt = 0; mt < MT; mt++)
#pragma unroll
                for (int nt = 0; nt < NT; nt++)
                    mma_tf32(acc[mt][nt], af[mt][0], af[mt][1], af[mt][2], af[mt][3],
                             bf[nt][0], bf[nt][1]);
        }
        if (more) {
            stsG(buf ^ 1);
            __syncthreads();
            buf ^= 1;
        }
    }

    if constexpr (EMAX == 0) {
        auto emit = [&](int mrow, int n, float v0, float v1) {
            if (EPI == 3) {
                C[(size_t)mrow * ldc + n]     += v0 + bias[n];
                C[(size_t)mrow * ldc + n + 1] += v1 + bias[n + 1];
                return;
            }
            if (EPI == 0) {
                if (bias) { v0 += bias[n]; v1 += bias[n + 1]; }
            } else if (EPI == 1) {
                v0 = fmaxf((v0 + bias[n]) * (p1[n] * bnscale) + p2[n], 0.f);
                v1 = fmaxf((v1 + bias[n + 1]) * (p1[n + 1] * bnscale) + p2[n + 1], 0.f);
            } else if (EPI == 2) {
                v0 += bias[n]; v1 += bias[n + 1];
                v0 = fmaxf(v0, 0.f) + log1pf(__expf(-fabsf(v0)));
                v1 = fmaxf(v1, 0.f) + log1pf(__expf(-fabsf(v1)));
            }
            float2 o; o.x = v0; o.y = v1;
            *(float2*)&C[(size_t)mrow * ldc + n] = o;
        };
#pragma unroll
        for (int mt = 0; mt < MT; mt++) {
            int mrow = m0 + wm * WTM + mt * 16 + grp;
#pragma unroll
            for (int nt = 0; nt < NT; nt++) {
                int n = n0 + wn * WTN + nt * 8 + tig * 2;
                emit(mrow,     n, acc[mt][nt][0], acc[mt][nt][1]);
                emit(mrow + 8, n, acc[mt][nt][2], acc[mt][nt][3]);
            }
        }
    } else {
        constexpr int GPW = WTM / 32;   // 32-row groups per warp
        float mx[GPW][NT][2];
#pragma unroll
        for (int g = 0; g < GPW; g++)
#pragma unroll
            for (int nt = 0; nt < NT; nt++) {
                mx[g][nt][0] = -FLT_MAX; mx[g][nt][1] = -FLT_MAX;
            }
#pragma unroll
        for (int mt = 0; mt < MT; mt++) {
            int gsel = mt / 2;    // 2 mt-tiles (32 rows) per group
            int mrow = m0 + wm * WTM + mt * 16 + grp;
#pragma unroll
            for (int nt = 0; nt < NT; nt++) {
                int n = n0 + wn * WTN + nt * 8 + tig * 2;
                float v0 = acc[mt][nt][0] + bias[n];
                float v1 = acc[mt][nt][1] + bias[n + 1];
                float v2 = acc[mt][nt][2] + bias[n];
                float v3 = acc[mt][nt][3] + bias[n + 1];
                if (EMAX == 1) {
                    float2 o0; o0.x = v0; o0.y = v1;
                    float2 o1; o1.x = v2; o1.y = v3;
                    *(float2*)&C[(size_t)mrow * ldc + n] = o0;
                    *(float2*)&C[(size_t)(mrow + 8) * ldc + n] = o1;
                }
                mx[gsel][nt][0] = fmaxf(mx[gsel][nt][0], fmaxf(v0, v2));
                mx[gsel][nt][1] = fmaxf(mx[gsel][nt][1], fmaxf(v1, v3));
            }
        }
#pragma unroll
        for (int g = 0; g < GPW; g++) {
#pragma unroll
            for (int nt = 0; nt < NT; nt++)
#pragma unroll
                for (int c = 0; c < 2; c++) {
                    float v = mx[g][nt][c];
                    v = fmaxf(v, __shfl_xor_sync(0xffffffffu, v, 4));
                    v = fmaxf(v, __shfl_xor_sync(0xffffffffu, v, 8));
                    v = fmaxf(v, __shfl_xor_sync(0xffffffffu, v, 16));
                    mx[g][nt][c] = v;
                }
            if (lane < 4) {
                int grow = (m0 >> 5) + wm * GPW + g;
#pragma unroll
                for (int nt = 0; nt < NT; nt++) {
                    int n = n0 + wn * WTN + nt * 8 + tig * 2;
                    fgout[(size_t)grow * ldfg + n]     = mx[g][nt][0];
                    fgout[(size_t)grow * ldfg + n + 1] = mx[g][nt][1];
                }
            }
        }
    }
}

// ---------------------------------------------------------------------------
// Pad xp_w (56x768 -> 64x768) and dt_w (768x24 -> 768x32)
// ---------------------------------------------------------------------------
__global__ void pad_weights(const float* __restrict__ xp_w,
                            const float* __restrict__ dt_w) {
    int idx = blockIdx.x * 256 + threadIdx.x;
    constexpr int NXP = cNL * 64 * cDI;
    constexpr int NDT = cNL * cDI * 32;
    if (idx < NXP) {
        int l = idx / (64 * cDI);
        int r = (idx / cDI) % 64;
        int k = idx % cDI;
        g_xpw[idx] = (r < 56) ? xp_w[((size_t)l * 56 + r) * cDI + k] : 0.f;
    } else if (idx < NXP + NDT) {
        int j = idx - NXP;
        int l = j / (cDI * 32);
        int d = (j / 32) % cDI;
        int k = j % 32;
        g_dtw[j] = (k < 24) ? dt_w[((size_t)l * cDI + d) * cDTR + k] : 0.f;
    }
}

// ---------------------------------------------------------------------------
// FPS
// ---------------------------------------------------------------------------
__global__ void fps_kernel(const float* __restrict__ xyz) {
    int b = blockIdx.x;
    __shared__ float px[cN], py[cN], pz[cN], dmin[cN];
    __shared__ float wv[8];
    __shared__ int   wi[8];
    __shared__ int   s_cur;
    int tid = threadIdx.x;
    int wid = tid >> 5, lane = tid & 31;
    for (int i = tid; i < cN; i += 256) {
        px[i] = xyz[(b * cN + i) * 3 + 0];
        py[i] = xyz[(b * cN + i) * 3 + 1];
        pz[i] = xyz[(b * cN + i) * 3 + 2];
        dmin[i] = 1e10f;
    }
    __syncthreads();
    int cur = 0;
    for (int g = 0; g < cG; g++) {
        float cx = px[cur], cy = py[cur], cz = pz[cur];
        if (tid == 0) {
            g_center[(b * cG + g) * 3 + 0] = cx;
            g_center[(b * cG + g) * 3 + 1] = cy;
            g_center[(b * cG + g) * 3 + 2] = cz;
        }
        float bv = -1.f; int bi = 0x7fffffff;
        for (int i = tid; i < cN; i += 256) {
            float dx = __fsub_rn(px[i], cx);
            float dy = __fsub_rn(py[i], cy);
            float dz = __fsub_rn(pz[i], cz);
            float dd = __fadd_rn(__fadd_rn(__fmul_rn(dx, dx), __fmul_rn(dy, dy)),
                                 __fmul_rn(dz, dz));
            float dm = fminf(dmin[i], dd);
            dmin[i] = dm;
            if (dm > bv) { bv = dm; bi = i; }
        }
#pragma unroll
        for (int off = 16; off > 0; off >>= 1) {
            float ov = __shfl_xor_sync(0xffffffffu, bv, off);
            int oi = __shfl_xor_sync(0xffffffffu, bi, off);
            if (ov > bv || (ov == bv && oi < bi)) { bv = ov; bi = oi; }
        }
        if (lane == 0) { wv[wid] = bv; wi[wid] = bi; }
        __syncthreads();
        if (tid < 8) {
            bv = wv[tid]; bi = wi[tid];
#pragma unroll
            for (int off = 4; off > 0; off >>= 1) {
                float ov = __shfl_xor_sync(0xffu, bv, off);
                int oi = __shfl_xor_sync(0xffu, bi, off);
                if (ov > bv || (ov == bv && oi < bi)) { bv = ov; bi = oi; }
            }
            if (tid == 0) s_cur = bi;
        }
        __syncthreads();
        cur = s_cur;
    }
}

// ---------------------------------------------------------------------------
// KNN
// ---------------------------------------------------------------------------
__global__ void knn_kernel(const float* __restrict__ xyz) {
    int bg = blockIdx.x;
    int b = bg >> 7;
    __shared__ float d2s[cN];
    __shared__ float wv[8];
    __shared__ int   wi[8];
    __shared__ int   s_idx;
    int tid = threadIdx.x;
    int wid = tid >> 5, lane = tid & 31;
    float cx = g_center[bg * 3 + 0], cy = g_center[bg * 3 + 1], cz = g_center[bg * 3 + 2];
    const float* P = xyz + (size_t)b * cN * 3;
    for (int i = tid; i < cN; i += 256) {
        float dx = __fsub_rn(cx, P[i * 3 + 0]);
        float dy = __fsub_rn(cy, P[i * 3 + 1]);
        float dz = __fsub_rn(cz, P[i * 3 + 2]);
        d2s[i] = __fadd_rn(__fadd_rn(__fmul_rn(dx, dx), __fmul_rn(dy, dy)),
                           __fmul_rn(dz, dz));
    }
    __syncthreads();
    for (int m = 0; m < cM; m++) {
        float bv = FLT_MAX; int bi = 0x7fffffff;
        for (int i = tid; i < cN; i += 256) {
            float v = d2s[i];
            if (v < bv) { bv = v; bi = i; }
        }
#pragma unroll
        for (int off = 16; off > 0; off >>= 1) {
            float ov = __shfl_xor_sync(0xffffffffu, bv, off);
            int oi = __shfl_xor_sync(0xffffffffu, bi, off);
            if (ov < bv || (ov == bv && oi < bi)) { bv = ov; bi = oi; }
        }
        if (lane == 0) { wv[wid] = bv; wi[wid] = bi; }
        __syncthreads();
        if (tid < 8) {
            bv = wv[tid]; bi = wi[tid];
#pragma unroll
            for (int off = 4; off > 0; off >>= 1) {
                float ov = __shfl_xor_sync(0xffu, bv, off);
                int oi = __shfl_xor_sync(0xffu, bi, off);
                if (ov < bv || (ov == bv && oi < bi)) { bv = ov; bi = oi; }
            }
            if (tid == 0) s_idx = bi;
        }
        __syncthreads();
        int idx = s_idx;
        if (tid < 3) {
            float c = (tid == 0) ? cx : ((tid == 1) ? cy : cz);
            g_nb[((size_t)bg * cM + m) * 3 + tid] = __fsub_rn(P[idx * 3 + tid], c);
        }
        if (tid == 0) d2s[idx] = FLT_MAX;
        __syncthreads();
    }
}

// ---------------------------------------------------------------------------
// Residual accumulate + LayerNorm
// ---------------------------------------------------------------------------
__device__ __forceinline__ float block_sum_128(float v, float* sm) {
    int tid = threadIdx.x;
    sm[tid] = v; __syncthreads();
    for (int s = 64; s > 0; s >>= 1) {
        if (tid < s) sm[tid] += sm[tid + s];
        __syncthreads();
    }
    float r = sm[0]; __syncthreads();
    return r;
}

__global__ void resln_kernel(const float* __restrict__ w, const float* __restrict__ b,
                             int first) {
    __shared__ float sm[128];
    int t = blockIdx.x;
    float v[3];
#pragma unroll
    for (int j = 0; j < 3; j++) {
        int c = threadIdx.x + j * 128;
        float r = g_h[t * 384 + c];
        if (!first) r += g_res[t * 384 + c];
        g_res[t * 384 + c] = r;
        v[j] = r;
    }
    float mean = block_sum_128(v[0] + v[1] + v[2], sm) * (1.0f / 384.0f);
    float sq = 0.f;
#pragma unroll
    for (int j = 0; j < 3; j++) { float d = v[j] - mean; sq += d * d; }
    float var = block_sum_128(sq, sm) * (1.0f / 384.0f);
    float inv = rsqrtf(var + 1e-5f);
#pragma unroll
    for (int j = 0; j < 3; j++) {
        int c = threadIdx.x + j * 128;
        g_xln[t * 384 + c] = (v[j] - mean) * inv * w[c] + b[c];
    }
}

__global__ void final_kernel(const float* __restrict__ w, const float* __restrict__ b,
                             float* __restrict__ out) {
    __shared__ float sm[128];
    int t = blockIdx.x;
    float v[3];
#pragma unroll
    for (int j = 0; j < 3; j++) {
        int c = threadIdx.x + j * 128;
        v[j] = g_h[t * 384 + c] + g_res[t * 384 + c];
    }
    float mean = block_sum_128(v[0] + v[1] + v[2], sm) * (1.0f / 384.0f);
    float sq = 0.f;
#pragma unroll
    for (int j = 0; j < 3; j++) { float d = v[j] - mean; sq += d * d; }
    float var = block_sum_128(sq, sm) * (1.0f / 384.0f);
    float inv = rsqrtf(var + 1e-5f);
#pragma unroll
    for (int j = 0; j < 3; j++) {
        int c = threadIdx.x + j * 128;
        out[t * 384 + c] = (v[j] - mean) * inv * w[c] + b[c];
    }
}

// ---------------------------------------------------------------------------
// Depthwise causal conv (DC=4) + bias + silu
// ---------------------------------------------------------------------------
__global__ void conv_kernel(const float* __restrict__ cw, const float* __restrict__ cb) {
    int idx = blockIdx.x * blockDim.x + threadIdx.x;
    if (idx >= cTOK * cDI) return;
    int t = idx / cDI, d = idx % cDI;
    int l = t & 127;
    int tbase = t - l;
    float acc = cb[d];
#pragma unroll
    for (int k = 0; k < 4; k++) {
        int lk = l - 3 + k;
        if (lk >= 0)
            acc += g_xz[(size_t)(tbase + lk) * 1536 + d] * cw[d * 4 + k];
    }
    float sig = 1.0f / (1.0f + __expf(-acc));
    g_xc[idx] = acc * sig;
}

// ---------------------------------------------------------------------------
// Selective scan v3 (one thread per (b,d), 16 states in registers,
// q-power fast path when A_log rows are multiples)
// ---------------------------------------------------------------------------
template<bool FAST>
__device__ __forceinline__ void scan_body(
    int b, int d, float a0, const float* a, float Dpd) {
    extern __shared__ float4 sBC[];
    float h[16];
#pragma unroll
    for (int s = 0; s < 16; s++) h[s] = 0.f;

    const float* pdt = g_dt + (size_t)b * 128 * cDI + d;
    const float* pxc = g_xc + (size_t)b * 128 * cDI + d;
    const float* pz  = g_xz + (size_t)b * 128 * 1536 + cDI + d;
    float* pu = g_u + (size_t)b * 128 * cDI + d;

    for (int t = 0; t < 128; t++) {
        float dt = pdt[(size_t)t * cDI];
        float xin = pxc[(size_t)t * cDI];
        float u = dt * xin;
        float p[16];
        if (FAST) {
            float q = __expf(dt * a0);
            float q2 = q * q, q4 = q2 * q2, q8 = q4 * q4;
            p[0] = q;        p[1] = q2;       p[2] = q2 * q;   p[3] = q4;
            p[4] = q4 * q;   p[5] = q4 * q2;  p[6] = p[5] * q; p[7] = q8;
            p[8] = q8 * q;   p[9] = q8 * q2;  p[10] = p[9] * q;
            p[11] = q8 * q4; p[12] = p[11] * q; p[13] = p[11] * q2;
            p[14] = p[13] * q; p[15] = q8 * q8;
        } else {
#pragma unroll
            for (int s = 0; s < 16; s++) p[s] = __expf(dt * a[s]);
        }
        float4 Bq[4], Cq[4];
#pragma unroll
        for (int j = 0; j < 4; j++) { Bq[j] = sBC[t * 8 + j]; Cq[j] = sBC[t * 8 + 4 + j]; }
        const float* Bv = (const float*)Bq;
        const float* Cv = (const float*)Cq;
        float y = 0.f;
#pragma unroll
        for (int s = 0; s < 16; s++) {
            h[s] = p[s] * h[s] + u * Bv[s];
            y += h[s] * Cv[s];
        }
        y += Dpd * xin;
        float z = pz[(size_t)t * 1536];
        float sz = z / (1.0f + __expf(-z));
        pu[(size_t)t * cDI] = y * sz;
    }
}

__global__ void __launch_bounds__(256)
scan_kernel(const float* __restrict__ Alog, const float* __restrict__ Dp) {
    extern __shared__ float4 sBC[];
    int tid = threadIdx.x;
    int b = blockIdx.y;
    int d = blockIdx.x * 256 + tid;

    for (int i = tid; i < 128 * 8; i += 256) {
        int t = i >> 3, j = i & 7;
        sBC[i] = *(const float4*)(g_dbl64 + (size_t)(b * 128 + t) * 64 + 24 + j * 4);
    }
    __syncthreads();

    float a[16];
    bool fast = true;
#pragma unroll
    for (int s = 0; s < 16; s++) a[s] = -expf(Alog[d * 16 + s]);
    float a0 = a[0];
#pragma unroll
    for (int s = 1; s < 16; s++) {
        float ideal = (float)(s + 1) * a0;
        if (fabsf(a[s] - ideal) > 1e-4f * fabsf(ideal)) fast = false;
    }
    float Dpd = Dp[d];

    if (fast) scan_body<true>(b, d, a0, a, Dpd);
    else      scan_body<false>(b, d, a0, a, Dpd);
}

// ---------------------------------------------------------------------------
// Host-side launch sequence
// ---------------------------------------------------------------------------
extern "C" void kernel_launch(void* const* d_in, const int* in_sizes, int n_in,
                              void* d_out, int out_size) {
    const float* xyz   = (const float*)d_in[0];
    const float* e1w1  = (const float*)d_in[1];
    const float* e1b1  = (const float*)d_in[2];
    const float* bn1g  = (const float*)d_in[3];
    const float* bn1b  = (const float*)d_in[4];
    const float* e1w2  = (const float*)d_in[5];
    const float* e1b2  = (const float*)d_in[6];
    const float* e2w1  = (const float*)d_in[7];
    const float* e2b1  = (const float*)d_in[8];
    const float* bn2g  = (const float*)d_in[9];
    const float* bn2b  = (const float*)d_in[10];
    const float* e2w2  = (const float*)d_in[11];
    const float* e2b2  = (const float*)d_in[12];
    const float* pw1   = (const float*)d_in[13];
    const float* pb1   = (const float*)d_in[14];
    const float* pw2   = (const float*)d_in[15];
    const float* pb2   = (const float*)d_in[16];
    const float* in_w  = (const float*)d_in[17];
    const float* convw = (const float*)d_in[18];
    const float* convb = (const float*)d_in[19];
    const float* xp_w  = (const float*)d_in[20];
    const float* dt_w  = (const float*)d_in[21];
    const float* dt_b  = (const float*)d_in[22];
    const float* A_log = (const float*)d_in[23];
    const float* Dp    = (const float*)d_in[24];
    const float* out_w = (const float*)d_in[25];
    const float* lnw   = (const float*)d_in[26];
    const float* lnb   = (const float*)d_in[27];
    const float* fnw   = (const float*)d_in[28];
    const float* fnb   = (const float*)d_in[29];
    float* out = (float*)d_out;

    float *pnb, *pf2, *pfg, *pf3, *pxln, *pxz, *pxc, *pu, *ph, *pcenter,
          *pdbl, *pdt, *pxpw, *pdtw;
    cudaGetSymbolAddress((void**)&pnb,  g_nb);
    cudaGetSymbolAddress((void**)&pf2,  g_f2);
    cudaGetSymbolAddress((void**)&pfg,  g_fg);
    cudaGetSymbolAddress((void**)&pf3,  g_f3);
    cudaGetSymbolAddress((void**)&pxln, g_xln);
    cudaGetSymbolAddress((void**)&pxz,  g_xz);
    cudaGetSymbolAddress((void**)&pxc,  g_xc);
    cudaGetSymbolAddress((void**)&pu,   g_u);
    cudaGetSymbolAddress((void**)&ph,   g_h);
    cudaGetSymbolAddress((void**)&pcenter, g_center);
    cudaGetSymbolAddress((void**)&pdbl, g_dbl64);
    cudaGetSymbolAddress((void**)&pdt,  g_dt);
    cudaGetSymbolAddress((void**)&pxpw, g_xpw);
    cudaGetSymbolAddress((void**)&pdtw, g_dtw);

    // ---- weight prep ----
    constexpr int NPAD = cNL * 64 * cDI + cNL * cDI * 32;
    pad_weights<<<(NPAD + 255) / 256, 256>>>(xp_w, dt_w);

    // ---- grouping ----
    fps_kernel<<<cB, 256>>>(xyz);
    knn_kernel<<<cTOK, 256>>>(xyz);

    // ---- encoder (64x128 tiles, 4 warps) ----
    tc2<64, 128, 2, 2, 0, 2, 1><<<dim3(cPTS / 64, 2), 128>>>(
        pnb, e1w2, e1b2, bn1g, bn1b, pf2, 128, 3, 128, 256,
        e1w1, e1b1, pfg, 256);
    tc2<64, 128, 2, 2, 1, 1, 0><<<dim3(cPTS / 64, 4), 128>>>(
        pf2, e2w1, e2b1, bn2g, bn2b, pf3, 512, 256, 512, 512,
        pfg, nullptr, nullptr, 0);
    tc2<64, 128, 2, 2, 0, 0, 2><<<dim3(cPTS / 64, 3), 128>>>(
        pf3, e2w2, e2b2, nullptr, nullptr, nullptr, 512, 512, 512, 384,
        nullptr, nullptr, ph, 384);

    // ---- positional MLP (pos1 fused into pos2 A-loader, MODEA=4) ----
    tc2<64, 128, 2, 2, 3, 4, 0><<<dim3(cTOK / 64, 3), 128>>>(
        pcenter, pw2, pb2, nullptr, nullptr, ph, 128, 3, 128, 384,
        pw1, pb1, nullptr, 0);

    // ---- mamba layers ----
    constexpr int SCAN_SMEM = 128 * 8 * sizeof(float4);
    for (int i = 0; i < cNL; i++) {
        const float* in_w_i  = in_w  + (size_t)i * 2 * cDI * cDM;
        const float* cw_i    = convw + (size_t)i * cDI * 4;
        const float* cb_i    = convb + (size_t)i * cDI;
        const float* dtb_i   = dt_b  + (size_t)i * cDI;
        const float* Al_i    = A_log + (size_t)i * cDI * cDS;
        const float* Dp_i    = Dp    + (size_t)i * cDI;
        const float* ow_i    = out_w + (size_t)i * cDM * cDI;
        const float* lnw_i   = lnw   + (size_t)i * cDM;
        const float* lnb_i   = lnb   + (size_t)i * cDM;
        const float* xpw_i   = pxpw  + (size_t)i * 64 * cDI;
        const float* dtw_i   = pdtw  + (size_t)i * cDI * 32;

        resln_kernel<<<cTOK, 128>>>(lnw_i, lnb_i, i == 0 ? 1 : 0);
        // in-proj: (2048,384)@(1536,384)^T
        tc2<64, 128, 2, 2, 0, 0, 0><<<dim3(cTOK / 64, 12), 128>>>(
            pxln, in_w_i, nullptr, nullptr, nullptr, pxz, 384, 384, 384, 1536,
            nullptr, nullptr, nullptr, 0);
        conv_kernel<<<(cTOK * cDI + 255) / 256, 256>>>(cw_i, cb_i);
        // xp: (2048,768)@(64,768)^T -> g_dbl64
        tc2<64, 64, 2, 1, 0, 0, 0><<<dim3(cTOK / 64, 1), 64>>>(
            pxc, xpw_i, nullptr, nullptr, nullptr, pdbl, 768, 768, 768, 64,
            nullptr, nullptr, nullptr, 0);
        // dt: (2048,32pad)@(768,32)^T + bias -> softplus
        tc2<64, 128, 2, 2, 2, 0, 0><<<dim3(cTOK / 64, 6), 128>>>(
            pdbl, dtw_i, dtb_i, nullptr, nullptr, pdt, 32, 64, 32, 768,
            nullptr, nullptr, nullptr, 0);
        scan_kernel<<<dim3(cDI / 256, cB), 256, SCAN_SMEM>>>(Al_i, Dp_i);
        // out-proj: (2048,768)@(384,768)^T
        tc2<64, 128, 2, 2, 0, 0, 0><<<dim3(cTOK / 64, 3), 128>>>(
            pu, ow_i, nullptr, nullptr, nullptr, ph, 768, 768, 768, 384,
            nullptr, nullptr, nullptr, 0);
    }

    // ---- final LN ----
    final_kernel<<<cTOK, 128>>>(fnw, fnb, out);
}

// round 12
// speedup vs baseline: 1.8819x; 1.0227x over previous
#include <cuda_runtime.h>
#include <math.h>
#include <float.h>

// ---------------------------------------------------------------------------
// Problem constants
// ---------------------------------------------------------------------------
constexpr int cB   = 16;
constexpr int cN   = 2048;
constexpr int cG   = 128;
constexpr int cM   = 32;
constexpr int cDM  = 384;
constexpr int cNL  = 12;
constexpr int cDI  = 768;
constexpr int cDS  = 16;
constexpr int cDTR = 24;
constexpr int cTOK = cB * cG;        // 2048 tokens
constexpr int cPTS = cTOK * cM;      // 65536 points

// ---------------------------------------------------------------------------
// Scratch (device globals; no dynamic allocation allowed)
// ---------------------------------------------------------------------------
__device__ __align__(16) float g_center[cTOK * 3];
__device__ __align__(16) float g_nb[cPTS * 3];
__device__ __align__(16) float g_f2[(size_t)cPTS * 256];
__device__ __align__(16) float g_fg[cTOK * 256];
__device__ __align__(16) float g_f3[(size_t)cPTS * 512];
__device__ __align__(16) float g_h[cTOK * cDM];
__device__ __align__(16) float g_res[cTOK * cDM];
__device__ __align__(16) float g_xln[cTOK * cDM];
__device__ __align__(16) float g_xz[(size_t)cTOK * 2 * cDI];
__device__ __align__(16) float g_xc[(size_t)cTOK * cDI];
__device__ __align__(16) float g_dbl64[cTOK * 64];
__device__ __align__(16) float g_dt[(size_t)cTOK * cDI];
__device__ __align__(16) float g_u[(size_t)cTOK * cDI];
// pre-rounded (tf32/RNA) weights
__device__ __align__(16) float g_xpw[cNL * 64 * cDI];
__device__ __align__(16) float g_dtw[cNL * cDI * 32];
__device__ __align__(16) float g_we1w2[256 * 128];
__device__ __align__(16) float g_we2w1[512 * 512];
__device__ __align__(16) float g_we2w2[384 * 512];
__device__ __align__(16) float g_wpw2[384 * 128];
__device__ __align__(16) float g_winw[(size_t)cNL * 1536 * 384];
__device__ __align__(16) float g_woutw[(size_t)cNL * 384 * 768];

using u32 = unsigned int;

__device__ __forceinline__ u32 cvt_tf32(float x) {
    u32 r;
    asm("cvt.rna.tf32.f32 %0, %1;" : "=r"(r) : "f"(x));
    return r;
}
__device__ __forceinline__ float rnd_tf32(float x) {
    return __uint_as_float(cvt_tf32(x));
}

__device__ __forceinline__ u32 smem_u32(const void* p) {
    u32 a;
    asm("{ .reg .u64 t; cvta.to.shared.u64 t, %1; cvt.u32.u64 %0, t; }"
        : "=r"(a) : "l"(p));
    return a;
}

__device__ __forceinline__ void ldsm4(u32& r0, u32& r1, u32& r2, u32& r3, u32 addr) {
    asm volatile("ldmatrix.sync.aligned.m8n8.x4.shared.b16 {%0,%1,%2,%3}, [%4];"
                 : "=r"(r0), "=r"(r1), "=r"(r2), "=r"(r3) : "r"(addr));
}

__device__ __forceinline__ void cpasync16(u32 dst, const void* src) {
    asm volatile("cp.async.cg.shared.global [%0], [%1], 16;"
                 :: "r"(dst), "l"(src) : "memory");
}
#define CP_COMMIT() asm volatile("cp.async.commit_group;" ::: "memory")
#define CP_WAIT0()  asm volatile("cp.async.wait_group 0;" ::: "memory")

__device__ __forceinline__ void mma_tf32(float* c, u32 a0, u32 a1, u32 a2, u32 a3,
                                         u32 b0, u32 b1) {
    asm volatile(
        "mma.sync.aligned.m16n8k8.row.col.f32.tf32.tf32.f32 "
        "{%0,%1,%2,%3}, {%4,%5,%6,%7}, {%8,%9}, {%0,%1,%2,%3};"
        : "+f"(c[0]), "+f"(c[1]), "+f"(c[2]), "+f"(c[3])
        : "r"(a0), "r"(a1), "r"(a2), "r"(a3), "r"(b0), "r"(b1));
}

// ---------------------------------------------------------------------------
// Generic tf32 tensor-core GEMM: C = epi(A' @ W^T).
//   Smem row-major [row][k] (stride 20 floats), ldmatrix.x4.b16 fragments,
//   cp.async gmem->smem for MODEA<=1 (A) and always for W. Inputs must be
//   pre-rounded to tf32 (RNA) by producers; HW truncation is then a no-op.
//   EPI 0:+bias(opt). 1: relu(bn(.+bias)). 2: softplus(.+bias). 3: C+=.+bias
//   MODEA 0: A'=A. 1: cols[0,256) from aux1[row>>5][k].
//         2: relu(bn1(nb@w1^T+b1)) on the fly. 4: gelu(center@pw1^T+pb1).
//   EMAX 0: normal. 1: write C AND 32-row group max. 2: ONLY group max.
//   ROUNDC 1: RNA-round outputs (consumer is a GEMM).
// ---------------------------------------------------------------------------
template<int BM, int BN, int WGM, int WGN, int EPI, int MODEA, int EMAX, int ROUNDC>
__global__ void __launch_bounds__(WGM * WGN * 32)
tc2(const float* __restrict__ A, const float* __restrict__ W,
    const float* __restrict__ bias, const float* __restrict__ p1,
    const float* __restrict__ p2, float* __restrict__ C,
    int K, int lda, int ldw, int ldc,
    const float* __restrict__ aux1, const float* __restrict__ aux2,
    float* __restrict__ fgout, int ldfg)
{
    constexpr int THREADS = WGM * WGN * 32;
    constexpr int WTM = BM / WGM, WTN = BN / WGN;
    constexpr int MT = WTM / 16, NT = WTN / 8;
    constexpr int NP = NT / 2;
    constexpr int KS = 20;
    constexpr int A4 = (BM * 16) / (THREADS * 4);
    constexpr int W4 = (BN * 16) / (THREADS * 4);
    static_assert(EMAX == 0 || (WTM % 32) == 0, "EMAX needs WTM%32==0");
    static_assert(NT % 2 == 0, "NT must be even");

    __shared__ __align__(16) float As[2][BM][KS];
    __shared__ __align__(16) float Ws[2][BN][KS];

    const int tid = threadIdx.x;
    const int wid = tid >> 5, lane = tid & 31;
    const int grp = lane >> 2, tig = lane & 3;
    const int wm = wid % WGM, wn = wid / WGM;
    const int m0 = blockIdx.x * BM, n0 = blockIdx.y * BN;
    const float bnscale = rsqrtf(1.0f + 1e-5f);

    const u32 asBase = smem_u32(&As[0][0][0]);
    const u32 wsBase = smem_u32(&Ws[0][0][0]);
    constexpr u32 ABUF = BM * KS * 4;
    constexpr u32 WBUF = BN * KS * 4;

    u32 aOff[MT], bOff[NP];
    {
        int l7 = lane & 7;
        int aRow = ((lane >> 3) & 1) * 8;
        int aCol = (lane >> 4) * 16;
#pragma unroll
        for (int mt = 0; mt < MT; mt++) {
            int row = wm * WTM + mt * 16 + aRow + l7;
            aOff[mt] = (u32)(row * KS * 4 + aCol);
        }
        int bRow = (lane >> 4) * 8;
        int bCol = ((lane >> 3) & 1) * 16;
#pragma unroll
        for (int p = 0; p < NP; p++) {
            int row = wn * WTN + p * 16 + bRow + l7;
            bOff[p] = (u32)(row * KS * 4 + bCol);
        }
    }

    float acc[MT][NT][4];
#pragma unroll
    for (int mt = 0; mt < MT; mt++)
#pragma unroll
        for (int nt = 0; nt < NT; nt++)
#pragma unroll
            for (int r = 0; r < 4; r++) acc[mt][nt][r] = 0.f;

    float nbr[(MODEA >= 2) ? A4 : 1][3];
    if (MODEA >= 2) {
#pragma unroll
        for (int v = 0; v < A4; v++) {
            int row = (tid + v * THREADS) >> 2;
            nbr[v][0] = A[(size_t)(m0 + row) * 3 + 0];
            nbr[v][1] = A[(size_t)(m0 + row) * 3 + 1];
            nbr[v][2] = A[(size_t)(m0 + row) * 3 + 2];
        }
    }

    float4 ra[(MODEA >= 2) ? A4 : 1];

    auto issueAW = [&](int kc, int bufSel) {
        const u32 aB = asBase + (u32)bufSel * ABUF;
        const u32 wB = wsBase + (u32)bufSel * WBUF;
        if (MODEA <= 1) {
#pragma unroll
            for (int v = 0; v < A4; v++) {
                int s = tid + v * THREADS;
                int row = s >> 2;
                int kq = (s & 3) * 4;
                int k = kc + kq;
                const float* src;
                if (MODEA == 0) {
                    src = A + (size_t)(m0 + row) * lda + k;
                } else {
                    int r = m0 + row;
                    src = (k < 256)
                        ? (aux1 + ((size_t)(r >> 5)) * 256 + k)
                        : (A + (size_t)r * lda + (k - 256));
                }
                cpasync16(aB + (u32)((row * KS + kq) * 4), src);
            }
        } else {
#pragma unroll
            for (int v = 0; v < A4; v++) {
                int s = tid + v * THREADS;
                int k = kc + (s & 3) * 4;
                float out[4];
#pragma unroll
                for (int e = 0; e < 4; e++) {
                    int kk = k + e;
                    float val = nbr[v][0] * aux1[kk * 3 + 0]
                              + nbr[v][1] * aux1[kk * 3 + 1]
                              + nbr[v][2] * aux1[kk * 3 + 2] + aux2[kk];
                    if (MODEA == 2) {
                        val = val * (p1[kk] * bnscale) + p2[kk];
                        out[e] = fmaxf(val, 0.f);
                    } else {  // gelu (tanh approx)
                        float v3 = val * val * val;
                        out[e] = 0.5f * val *
                            (1.0f + tanhf(0.7978845608028654f *
                                          (val + 0.044715f * v3)));
                    }
                }
                ra[v] = make_float4(out[0], out[1], out[2], out[3]);
            }
        }
#pragma unroll
        for (int v = 0; v < W4; v++) {
            int s = tid + v * THREADS;
            int row = s >> 2;
            int kq = (s & 3) * 4;
            cpasync16(wB + (u32)((row * KS + kq) * 4),
                      W + (size_t)(n0 + row) * ldw + kc + kq);
        }
        CP_COMMIT();
    };

    auto stsA = [&](int bufSel) {
        if (MODEA >= 2) {
#pragma unroll
            for (int v = 0; v < A4; v++) {
                int s = tid + v * THREADS;
                int row = s >> 2, kq = (s & 3) << 2;
                uint4 o;
                o.x = cvt_tf32(ra[v].x); o.y = cvt_tf32(ra[v].y);
                o.z = cvt_tf32(ra[v].z); o.w = cvt_tf32(ra[v].w);
                *reinterpret_cast<uint4*>(&As[bufSel][row][kq]) = o;
            }
        }
    };

    const int nIter = K >> 4;
    issueAW(0, 0);
    stsA(0);
    CP_WAIT0();
    __syncthreads();
    int buf = 0;

    for (int it = 0; it < nIter; it++) {
        bool more = (it + 1 < nIter);
        if (more) issueAW((it + 1) << 4, buf ^ 1);
        const u32 aB = asBase + (u32)buf * ABUF;
        const u32 wB = wsBase + (u32)buf * WBUF;
#pragma unroll
        for (int ks = 0; ks < 2; ks++) {
            const u32 kb = (u32)(ks * 32);
            u32 af[MT][4];
#pragma unroll
            for (int mt = 0; mt < MT; mt++)
                ldsm4(af[mt][0], af[mt][1], af[mt][2], af[mt][3],
                      aB + aOff[mt] + kb);
            u32 bf[NT][2];
#pragma unroll
            for (int p = 0; p < NP; p++) {
                u32 r0, r1, r2, r3;
                ldsm4(r0, r1, r2, r3, wB + bOff[p] + kb);
                bf[2 * p][0] = r0;     bf[2 * p][1] = r1;
                bf[2 * p + 1][0] = r2; bf[2 * p + 1][1] = r3;
            }
#pragma unroll
            for (int mt = 0; mt < MT; mt++)
#pragma unroll
                for (int nt = 0; nt < NT; nt++)
                    mma_tf32(acc[mt][nt], af[mt][0], af[mt][1], af[mt][2], af[mt][3],
                             bf[nt][0], bf[nt][1]);
        }
        if (more) {
            stsA(buf ^ 1);
            CP_WAIT0();
            __syncthreads();
            buf ^= 1;
        }
    }

    if constexpr (EMAX == 0) {
        auto emit = [&](int mrow, int n, float v0, float v1) {
            if (EPI == 3) {
                C[(size_t)mrow * ldc + n]     += v0 + bias[n];
                C[(size_t)mrow * ldc + n + 1] += v1 + bias[n + 1];
                return;
            }
            if (EPI == 0) {
                if (bias) { v0 += bias[n]; v1 += bias[n + 1]; }
            } else if (EPI == 1) {
                v0 = fmaxf((v0 + bias[n]) * (p1[n] * bnscale) + p2[n], 0.f);
                v1 = fmaxf((v1 + bias[n + 1]) * (p1[n + 1] * bnscale) + p2[n + 1], 0.f);
            } else if (EPI == 2) {
                v0 += bias[n]; v1 += bias[n + 1];
                v0 = fmaxf(v0, 0.f) + log1pf(__expf(-fabsf(v0)));
                v1 = fmaxf(v1, 0.f) + log1pf(__expf(-fabsf(v1)));
            }
            if (ROUNDC) { v0 = rnd_tf32(v0); v1 = rnd_tf32(v1); }
            float2 o; o.x = v0; o.y = v1;
            *(float2*)&C[(size_t)mrow * ldc + n] = o;
        };
#pragma unroll
        for (int mt = 0; mt < MT; mt++) {
            int mrow = m0 + wm * WTM + mt * 16 + grp;
#pragma unroll
            for (int nt = 0; nt < NT; nt++) {
                int n = n0 + wn * WTN + nt * 8 + tig * 2;
                emit(mrow,     n, acc[mt][nt][0], acc[mt][nt][1]);
                emit(mrow + 8, n, acc[mt][nt][2], acc[mt][nt][3]);
            }
        }
    } else {
        constexpr int GPW = WTM / 32;
        float mx[GPW][NT][2];
#pragma unroll
        for (int g = 0; g < GPW; g++)
#pragma unroll
            for (int nt = 0; nt < NT; nt++) {
                mx[g][nt][0] = -FLT_MAX; mx[g][nt][1] = -FLT_MAX;
            }
#pragma unroll
        for (int mt = 0; mt < MT; mt++) {
            int gsel = mt / 2;
            int mrow = m0 + wm * WTM + mt * 16 + grp;
#pragma unroll
            for (int nt = 0; nt < NT; nt++) {
                int n = n0 + wn * WTN + nt * 8 + tig * 2;
                float v0 = acc[mt][nt][0] + bias[n];
                float v1 = acc[mt][nt][1] + bias[n + 1];
                float v2 = acc[mt][nt][2] + bias[n];
                float v3 = acc[mt][nt][3] + bias[n + 1];
                if (ROUNDC) {
                    v0 = rnd_tf32(v0); v1 = rnd_tf32(v1);
                    v2 = rnd_tf32(v2); v3 = rnd_tf32(v3);
                }
                if (EMAX == 1) {
                    float2 o0; o0.x = v0; o0.y = v1;
                    float2 o1; o1.x = v2; o1.y = v3;
                    *(float2*)&C[(size_t)mrow * ldc + n] = o0;
                    *(float2*)&C[(size_t)(mrow + 8) * ldc + n] = o1;
                }
                mx[gsel][nt][0] = fmaxf(mx[gsel][nt][0], fmaxf(v0, v2));
                mx[gsel][nt][1] = fmaxf(mx[gsel][nt][1], fmaxf(v1, v3));
            }
        }
#pragma unroll
        for (int g = 0; g < GPW; g++) {
#pragma unroll
            for (int nt = 0; nt < NT; nt++)
#pragma unroll
                for (int c = 0; c < 2; c++) {
                    float v = mx[g][nt][c];
                    v = fmaxf(v, __shfl_xor_sync(0xffffffffu, v, 4));
                    v = fmaxf(v, __shfl_xor_sync(0xffffffffu, v, 8));
                    v = fmaxf(v, __shfl_xor_sync(0xffffffffu, v, 16));
                    mx[g][nt][c] = v;
                }
            if (lane < 4) {
                int grow = (m0 >> 5) + wm * GPW + g;
#pragma unroll
                for (int nt = 0; nt < NT; nt++) {
                    int n = n0 + wn * WTN + nt * 8 + tig * 2;
                    fgout[(size_t)grow * ldfg + n]     = mx[g][nt][0];
                    fgout[(size_t)grow * ldfg + n + 1] = mx[g][nt][1];
                }
            }
        }
    }
}

// ---------------------------------------------------------------------------
// Pre-round all GEMM weights to tf32 (RNA); pad xp_w/dt_w
// ---------------------------------------------------------------------------
constexpr int PW_N0 = 256 * 128;
constexpr int PW_N1 = 512 * 512;
constexpr int PW_N2 = 384 * 512;
constexpr int PW_N3 = 384 * 128;
constexpr int PW_N4 = cNL * 1536 * 384;
constexpr int PW_N5 = cNL * 384 * 768;
constexpr int PW_N6 = cNL * 64 * cDI;
constexpr int PW_N7 = cNL * cDI * 32;
constexpr int PW_O1 = PW_N0;
constexpr int PW_O2 = PW_O1 + PW_N1;
constexpr int PW_O3 = PW_O2 + PW_N2;
constexpr int PW_O4 = PW_O3 + PW_N3;
constexpr int PW_O5 = PW_O4 + PW_N4;
constexpr int PW_O6 = PW_O5 + PW_N5;
constexpr int PW_O7 = PW_O6 + PW_N6;
constexpr int PW_TOT = PW_O7 + PW_N7;

__global__ void prep_weights(const float* __restrict__ e1w2,
                             const float* __restrict__ e2w1,
                             const float* __restrict__ e2w2,
                             const float* __restrict__ pw2,
                             const float* __restrict__ in_w,
                             const float* __restrict__ out_w,
                             const float* __restrict__ xp_w,
                             const float* __restrict__ dt_w) {
    int idx = blockIdx.x * 256 + threadIdx.x;
    if (idx >= PW_TOT) return;
    float v; float* dst;
    if (idx < PW_O1)      { v = e1w2[idx];          dst = g_we1w2 + idx; }
    else if (idx < PW_O2) { v = e2w1[idx - PW_O1];  dst = g_we2w1 + (idx - PW_O1); }
    else if (idx < PW_O3) { v = e2w2[idx - PW_O2];  dst = g_we2w2 + (idx - PW_O2); }
    else if (idx < PW_O4) { v = pw2[idx - PW_O3];   dst = g_wpw2 + (idx - PW_O3); }
    else if (idx < PW_O5) { v = in_w[idx - PW_O4];  dst = g_winw + (idx - PW_O4); }
    else if (idx < PW_O6) { v = out_w[idx - PW_O5]; dst = g_woutw + (idx - PW_O5); }
    else if (idx < PW_O7) {
        int j = idx - PW_O6;
        int l = j / (64 * cDI);
        int r = (j / cDI) % 64;
        int k = j % cDI;
        v = (r < 56) ? xp_w[((size_t)l * 56 + r) * cDI + k] : 0.f;
        dst = g_xpw + j;
    } else {
        int j = idx - PW_O7;
        int l = j / (cDI * 32);
        int d = (j / 32) % cDI;
        int k = j % 32;
        v = (k < 24) ? dt_w[((size_t)l * cDI + d) * cDTR + k] : 0.f;
        dst = g_dtw + j;
    }
    *dst = __uint_as_float(cvt_tf32(v));
}

// ---------------------------------------------------------------------------
// FPS
// ---------------------------------------------------------------------------
__global__ void fps_kernel(const float* __restrict__ xyz) {
    int b = blockIdx.x;
    __shared__ float px[cN], py[cN], pz[cN], dmin[cN];
    __shared__ float wv[8];
    __shared__ int   wi[8];
    __shared__ int   s_cur;
    int tid = threadIdx.x;
    int wid = tid >> 5, lane = tid & 31;
    for (int i = tid; i < cN; i += 256) {
        px[i] = xyz[(b * cN + i) * 3 + 0];
        py[i] = xyz[(b * cN + i) * 3 + 1];
        pz[i] = xyz[(b * cN + i) * 3 + 2];
        dmin[i] = 1e10f;
    }
    __syncthreads();
    int cur = 0;
    for (int g = 0; g < cG; g++) {
        float cx = px[cur], cy = py[cur], cz = pz[cur];
        if (tid == 0) {
            g_center[(b * cG + g) * 3 + 0] = cx;
            g_center[(b * cG + g) * 3 + 1] = cy;
            g_center[(b * cG + g) * 3 + 2] = cz;
        }
        float bv = -1.f; int bi = 0x7fffffff;
        for (int i = tid; i < cN; i += 256) {
            float dx = __fsub_rn(px[i], cx);
            float dy = __fsub_rn(py[i], cy);
            float dz = __fsub_rn(pz[i], cz);
            float dd = __fadd_rn(__fadd_rn(__fmul_rn(dx, dx), __fmul_rn(dy, dy)),
                                 __fmul_rn(dz, dz));
            float dm = fminf(dmin[i], dd);
            dmin[i] = dm;
            if (dm > bv) { bv = dm; bi = i; }
        }
#pragma unroll
        for (int off = 16; off > 0; off >>= 1) {
            float ov = __shfl_xor_sync(0xffffffffu, bv, off);
            int oi = __shfl_xor_sync(0xffffffffu, bi, off);
            if (ov > bv || (ov == bv && oi < bi)) { bv = ov; bi = oi; }
        }
        if (lane == 0) { wv[wid] = bv; wi[wid] = bi; }
        __syncthreads();
        if (tid < 8) {
            bv = wv[tid]; bi = wi[tid];
#pragma unroll
            for (int off = 4; off > 0; off >>= 1) {
                float ov = __shfl_xor_sync(0xffu, bv, off);
                int oi = __shfl_xor_sync(0xffu, bi, off);
                if (ov > bv || (ov == bv && oi < bi)) { bv = ov; bi = oi; }
            }
            if (tid == 0) s_cur = bi;
        }
        __syncthreads();
        cur = s_cur;
    }
}

// ---------------------------------------------------------------------------
// KNN
// ---------------------------------------------------------------------------
__global__ void knn_kernel(const float* __restrict__ xyz) {
    int bg = blockIdx.x;
    int b = bg >> 7;
    __shared__ float d2s[cN];
    __shared__ float wv[8];
    __shared__ int   wi[8];
    __shared__ int   s_idx;
    int tid = threadIdx.x;
    int wid = tid >> 5, lane = tid & 31;
    float cx = g_center[bg * 3 + 0], cy = g_center[bg * 3 + 1], cz = g_center[bg * 3 + 2];
    const float* P = xyz + (size_t)b * cN * 3;
    for (int i = tid; i < cN; i += 256) {
        float dx = __fsub_rn(cx, P[i * 3 + 0]);
        float dy = __fsub_rn(cy, P[i * 3 + 1]);
        float dz = __fsub_rn(cz, P[i * 3 + 2]);
        d2s[i] = __fadd_rn(__fadd_rn(__fmul_rn(dx, dx), __fmul_rn(dy, dy)),
                           __fmul_rn(dz, dz));
    }
    __syncthreads();
    for (int m = 0; m < cM; m++) {
        float bv = FLT_MAX; int bi = 0x7fffffff;
        for (int i = tid; i < cN; i += 256) {
            float v = d2s[i];
            if (v < bv) { bv = v; bi = i; }
        }
#pragma unroll
        for (int off = 16; off > 0; off >>= 1) {
            float ov = __shfl_xor_sync(0xffffffffu, bv, off);
            int oi = __shfl_xor_sync(0xffffffffu, bi, off);
            if (ov < bv || (ov == bv && oi < bi)) { bv = ov; bi = oi; }
        }
        if (lane == 0) { wv[wid] = bv; wi[wid] = bi; }
        __syncthreads();
        if (tid < 8) {
            bv = wv[tid]; bi = wi[tid];
#pragma unroll
            for (int off = 4; off > 0; off >>= 1) {
                float ov = __shfl_xor_sync(0xffu, bv, off);
                int oi = __shfl_xor_sync(0xffu, bi, off);
                if (ov < bv || (ov == bv && oi < bi)) { bv = ov; bi = oi; }
            }
            if (tid == 0) s_idx = bi;
        }
        __syncthreads();
        int idx = s_idx;
        if (tid < 3) {
            float c = (tid == 0) ? cx : ((tid == 1) ? cy : cz);
            g_nb[((size_t)bg * cM + m) * 3 + tid] = __fsub_rn(P[idx * 3 + tid], c);
        }
        if (tid == 0) d2s[idx] = FLT_MAX;
        __syncthreads();
    }
}

// ---------------------------------------------------------------------------
// Residual accumulate + LayerNorm (xln rounded to tf32; res stays fp32)
// ---------------------------------------------------------------------------
__device__ __forceinline__ float block_sum_128(float v, float* sm) {
    int tid = threadIdx.x;
    sm[tid] = v; __syncthreads();
    for (int s = 64; s > 0; s >>= 1) {
        if (tid < s) sm[tid] += sm[tid + s];
        __syncthreads();
    }
    float r = sm[0]; __syncthreads();
    return r;
}

__global__ void resln_kernel(const float* __restrict__ w, const float* __restrict__ b,
                             int first) {
    __shared__ float sm[128];
    int t = blockIdx.x;
    float v[3];
#pragma unroll
    for (int j = 0; j < 3; j++) {
        int c = threadIdx.x + j * 128;
        float r = g_h[t * 384 + c];
        if (!first) r += g_res[t * 384 + c];
        g_res[t * 384 + c] = r;
        v[j] = r;
    }
    float mean = block_sum_128(v[0] + v[1] + v[2], sm) * (1.0f / 384.0f);
    float sq = 0.f;
#pragma unroll
    for (int j = 0; j < 3; j++) { float d = v[j] - mean; sq += d * d; }
    float var = block_sum_128(sq, sm) * (1.0f / 384.0f);
    float inv = rsqrtf(var + 1e-5f);
#pragma unroll
    for (int j = 0; j < 3; j++) {
        int c = threadIdx.x + j * 128;
        g_xln[t * 384 + c] = rnd_tf32((v[j] - mean) * inv * w[c] + b[c]);
    }
}

__global__ void final_kernel(const float* __restrict__ w, const float* __restrict__ b,
                             float* __restrict__ out) {
    __shared__ float sm[128];
    int t = blockIdx.x;
    float v[3];
#pragma unroll
    for (int j = 0; j < 3; j++) {
        int c = threadIdx.x + j * 128;
        v[j] = g_h[t * 384 + c] + g_res[t * 384 + c];
    }
    float mean = block_sum_128(v[0] + v[1] + v[2], sm) * (1.0f / 384.0f);
    float sq = 0.f;
#pragma unroll
    for (int j = 0; j < 3; j++) { float d = v[j] - mean; sq += d * d; }
    float var = block_sum_128(sq, sm) * (1.0f / 384.0f);
    float inv = rsqrtf(var + 1e-5f);
#pragma unroll
    for (int j = 0; j < 3; j++) {
        int c = threadIdx.x + j * 128;
        out[t * 384 + c] = (v[j] - mean) * inv * w[c] + b[c];
    }
}

// ---------------------------------------------------------------------------
// Depthwise causal conv (DC=4) + bias + silu (output rounded to tf32)
// ---------------------------------------------------------------------------
__global__ void conv_kernel(const float* __restrict__ cw, const float* __restrict__ cb) {
    int idx = blockIdx.x * blockDim.x + threadIdx.x;
    if (idx >= cTOK * cDI) return;
    int t = idx / cDI, d = idx % cDI;
    int l = t & 127;
    int tbase = t - l;
    float acc = cb[d];
#pragma unroll
    for (int k = 0; k < 4; k++) {
        int lk = l - 3 + k;
        if (lk >= 0)
            acc += g_xz[(size_t)(tbase + lk) * 1536 + d] * cw[d * 4 + k];
    }
    float sig = 1.0f / (1.0f + __expf(-acc));
    g_xc[idx] = rnd_tf32(acc * sig);
}

// ---------------------------------------------------------------------------
// Selective scan v3 (u output rounded to tf32)
// ---------------------------------------------------------------------------
template<bool FAST>
__device__ __forceinline__ void scan_body(
    int b, int d, float a0, const float* a, float Dpd) {
    extern __shared__ float4 sBC[];
    float h[16];
#pragma unroll
    for (int s = 0; s < 16; s++) h[s] = 0.f;

    const float* pdt = g_dt + (size_t)b * 128 * cDI + d;
    const float* pxc = g_xc + (size_t)b * 128 * cDI + d;
    const float* pz  = g_xz + (size_t)b * 128 * 1536 + cDI + d;
    float* pu = g_u + (size_t)b * 128 * cDI + d;

    for (int t = 0; t < 128; t++) {
        float dt = pdt[(size_t)t * cDI];
        float xin = pxc[(size_t)t * cDI];
        float u = dt * xin;
        float p[16];
        if (FAST) {
            float q = __expf(dt * a0);
            float q2 = q * q, q4 = q2 * q2, q8 = q4 * q4;
            p[0] = q;        p[1] = q2;       p[2] = q2 * q;   p[3] = q4;
            p[4] = q4 * q;   p[5] = q4 * q2;  p[6] = p[5] * q; p[7] = q8;
            p[8] = q8 * q;   p[9] = q8 * q2;  p[10] = p[9] * q;
            p[11] = q8 * q4; p[12] = p[11] * q; p[13] = p[11] * q2;
            p[14] = p[13] * q; p[15] = q8 * q8;
        } else {
#pragma unroll
            for (int s = 0; s < 16; s++) p[s] = __expf(dt * a[s]);
        }
        float4 Bq[4], Cq[4];
#pragma unroll
        for (int j = 0; j < 4; j++) { Bq[j] = sBC[t * 8 + j]; Cq[j] = sBC[t * 8 + 4 + j]; }
        const float* Bv = (const float*)Bq;
        const float* Cv = (const float*)Cq;
        float y = 0.f;
#pragma unroll
        for (int s = 0; s < 16; s++) {
            h[s] = p[s] * h[s] + u * Bv[s];
            y += h[s] * Cv[s];
        }
        y += Dpd * xin;
        float z = pz[(size_t)t * 1536];
        float sz = z / (1.0f + __expf(-z));
        pu[(size_t)t * cDI] = rnd_tf32(y * sz);
    }
}

__global__ void __launch_bounds__(256)
scan_kernel(const float* __restrict__ Alog, const float* __restrict__ Dp) {
    extern __shared__ float4 sBC[];
    int tid = threadIdx.x;
    int b = blockIdx.y;
    int d = blockIdx.x * 256 + tid;

    for (int i = tid; i < 128 * 8; i += 256) {
        int t = i >> 3, j = i & 7;
        sBC[i] = *(const float4*)(g_dbl64 + (size_t)(b * 128 + t) * 64 + 24 + j * 4);
    }
    __syncthreads();

    float a[16];
    bool fast = true;
#pragma unroll
    for (int s = 0; s < 16; s++) a[s] = -expf(Alog[d * 16 + s]);
    float a0 = a[0];
#pragma unroll
    for (int s = 1; s < 16; s++) {
        float ideal = (float)(s + 1) * a0;
        if (fabsf(a[s] - ideal) > 1e-4f * fabsf(ideal)) fast = false;
    }
    float Dpd = Dp[d];

    if (fast) scan_body<true>(b, d, a0, a, Dpd);
    else      scan_body<false>(b, d, a0, a, Dpd);
}

// ---------------------------------------------------------------------------
// Host-side launch sequence
// ---------------------------------------------------------------------------
extern "C" void kernel_launch(void* const* d_in, const int* in_sizes, int n_in,
                              void* d_out, int out_size) {
    const float* xyz   = (const float*)d_in[0];
    const float* e1w1  = (const float*)d_in[1];
    const float* e1b1  = (const float*)d_in[2];
    const float* bn1g  = (const float*)d_in[3];
    const float* bn1b  = (const float*)d_in[4];
    const float* e1w2  = (const float*)d_in[5];
    const float* e1b2  = (const float*)d_in[6];
    const float* e2w1  = (const float*)d_in[7];
    const float* e2b1  = (const float*)d_in[8];
    const float* bn2g  = (const float*)d_in[9];
    const float* bn2b  = (const float*)d_in[10];
    const float* e2w2  = (const float*)d_in[11];
    const float* e2b2  = (const float*)d_in[12];
    const float* pw1   = (const float*)d_in[13];
    const float* pb1   = (const float*)d_in[14];
    const float* pw2   = (const float*)d_in[15];
    const float* pb2   = (const float*)d_in[16];
    const float* in_w  = (const float*)d_in[17];
    const float* convw = (const float*)d_in[18];
    const float* convb = (const float*)d_in[19];
    const float* xp_w  = (const float*)d_in[20];
    const float* dt_w  = (const float*)d_in[21];
    const float* dt_b  = (const float*)d_in[22];
    const float* A_log = (const float*)d_in[23];
    const float* Dp    = (const float*)d_in[24];
    const float* out_w = (const float*)d_in[25];
    const float* lnw   = (const float*)d_in[26];
    const float* lnb   = (const float*)d_in[27];
    const float* fnw   = (const float*)d_in[28];
    const float* fnb   = (const float*)d_in[29];
    float* out = (float*)d_out;

    float *pnb, *pf2, *pfg, *pf3, *pxln, *pxz, *pxc, *pu, *ph, *pcenter,
          *pdbl, *pdt, *pxpw, *pdtw;
    float *pwe1w2, *pwe2w1, *pwe2w2, *pwpw2, *pwinw, *pwoutw;
    cudaGetSymbolAddress((void**)&pnb,  g_nb);
    cudaGetSymbolAddress((void**)&pf2,  g_f2);
    cudaGetSymbolAddress((void**)&pfg,  g_fg);
    cudaGetSymbolAddress((void**)&pf3,  g_f3);
    cudaGetSymbolAddress((void**)&pxln, g_xln);
    cudaGetSymbolAddress((void**)&pxz,  g_xz);
    cudaGetSymbolAddress((void**)&pxc,  g_xc);
    cudaGetSymbolAddress((void**)&pu,   g_u);
    cudaGetSymbolAddress((void**)&ph,   g_h);
    cudaGetSymbolAddress((void**)&pcenter, g_center);
    cudaGetSymbolAddress((void**)&pdbl, g_dbl64);
    cudaGetSymbolAddress((void**)&pdt,  g_dt);
    cudaGetSymbolAddress((void**)&pxpw, g_xpw);
    cudaGetSymbolAddress((void**)&pdtw, g_dtw);
    cudaGetSymbolAddress((void**)&pwe1w2, g_we1w2);
    cudaGetSymbolAddress((void**)&pwe2w1, g_we2w1);
    cudaGetSymbolAddress((void**)&pwe2w2, g_we2w2);
    cudaGetSymbolAddress((void**)&pwpw2,  g_wpw2);
    cudaGetSymbolAddress((void**)&pwinw,  g_winw);
    cudaGetSymbolAddress((void**)&pwoutw, g_woutw);

    // ---- weight prep (pre-round to tf32) ----
    prep_weights<<<(PW_TOT + 255) / 256, 256>>>(
        e1w2, e2w1, e2w2, pw2, in_w, out_w, xp_w, dt_w);

    // ---- grouping ----
    fps_kernel<<<cB, 256>>>(xyz);
    knn_kernel<<<cTOK, 256>>>(xyz);

    // ---- encoder ----
    tc2<64, 128, 2, 2, 0, 2, 1, 1><<<dim3(cPTS / 64, 2), 128>>>(
        pnb, pwe1w2, e1b2, bn1g, bn1b, pf2, 128, 3, 128, 256,
        e1w1, e1b1, pfg, 256);
    tc2<64, 128, 2, 2, 1, 1, 0, 1><<<dim3(cPTS / 64, 4), 128>>>(
        pf2, pwe2w1, e2b1, bn2g, bn2b, pf3, 512, 256, 512, 512,
        pfg, nullptr, nullptr, 0);
    tc2<64, 128, 2, 2, 0, 0, 2, 0><<<dim3(cPTS / 64, 3), 128>>>(
        pf3, pwe2w2, e2b2, nullptr, nullptr, nullptr, 512, 512, 512, 384,
        nullptr, nullptr, ph, 384);

    // ---- positional MLP (pos1 fused into pos2 A-loader) ----
    tc2<64, 128, 2, 2, 3, 4, 0, 0><<<dim3(cTOK / 64, 3), 128>>>(
        pcenter, pwpw2, pb2, nullptr, nullptr, ph, 128, 3, 128, 384,
        pw1, pb1, nullptr, 0);

    // ---- mamba layers ----
    constexpr int SCAN_SMEM = 128 * 8 * sizeof(float4);
    for (int i = 0; i < cNL; i++) {
        const float* in_w_i  = pwinw  + (size_t)i * 1536 * 384;
        const float* cw_i    = convw  + (size_t)i * cDI * 4;
        const float* cb_i    = convb  + (size_t)i * cDI;
        const float* dtb_i   = dt_b   + (size_t)i * cDI;
        const float* Al_i    = A_log  + (size_t)i * cDI * cDS;
        const float* Dp_i    = Dp     + (size_t)i * cDI;
        const float* ow_i    = pwoutw + (size_t)i * 384 * 768;
        const float* lnw_i   = lnw    + (size_t)i * cDM;
        const float* lnb_i   = lnb    + (size_t)i * cDM;
        const float* xpw_i   = pxpw   + (size_t)i * 64 * cDI;
        const float* dtw_i   = pdtw   + (size_t)i * cDI * 32;

        resln_kernel<<<cTOK, 128>>>(lnw_i, lnb_i, i == 0 ? 1 : 0);
        // in-proj: (2048,384)@(1536,384)^T
        tc2<64, 128, 2, 2, 0, 0, 0, 1><<<dim3(cTOK / 64, 12), 128>>>(
            pxln, in_w_i, nullptr, nullptr, nullptr, pxz, 384, 384, 384, 1536,
            nullptr, nullptr, nullptr, 0);
        conv_kernel<<<(cTOK * cDI + 255) / 256, 256>>>(cw_i, cb_i);
        // xp: (2048,768)@(64,768)^T -> g_dbl64
        tc2<64, 64, 2, 1, 0, 0, 0, 1><<<dim3(cTOK / 64, 1), 64>>>(
            pxc, xpw_i, nullptr, nullptr, nullptr, pdbl, 768, 768, 768, 64,
            nullptr, nullptr, nullptr, 0);
        // dt: (2048,32pad)@(768,32)^T + bias -> softplus
        tc2<64, 128, 2, 2, 2, 0, 0, 0><<<dim3(cTOK / 64, 6), 128>>>(
            pdbl, dtw_i, dtb_i, nullptr, nullptr, pdt, 32, 64, 32, 768,
            nullptr, nullptr, nullptr, 0);
        scan_kernel<<<dim3(cDI / 256, cB), 256, SCAN_SMEM>>>(Al_i, Dp_i);
        // out-proj: (2048,768)@(384,768)^T
        tc2<64, 128, 2, 2, 0, 0, 0, 0><<<dim3(cTOK / 64, 3), 128>>>(
            pu, ow_i, nullptr, nullptr, nullptr, ph, 768, 768, 768, 384,
            nullptr, nullptr, nullptr, 0);
    }

    // ---- final LN ----
    final_kernel<<<cTOK, 128>>>(fnw, fnb, out);
}

// round 13
// speedup vs baseline: 1.9198x; 1.0201x over previous
#include <cuda_runtime.h>
#include <math.h>
#include <float.h>

// ---------------------------------------------------------------------------
// Problem constants
// ---------------------------------------------------------------------------
constexpr int cB   = 16;
constexpr int cN   = 2048;
constexpr int cG   = 128;
constexpr int cM   = 32;
constexpr int cDM  = 384;
constexpr int cNL  = 12;
constexpr int cDI  = 768;
constexpr int cDS  = 16;
constexpr int cDTR = 24;
constexpr int cTOK = cB * cG;        // 2048 tokens
constexpr int cPTS = cTOK * cM;      // 65536 points

// ---------------------------------------------------------------------------
// Scratch (device globals; no dynamic allocation allowed)
// ---------------------------------------------------------------------------
__device__ __align__(16) float g_center[cTOK * 3];
__device__ __align__(16) float g_nb[cPTS * 3];
__device__ __align__(16) float g_f2[(size_t)cPTS * 256];
__device__ __align__(16) float g_fg[cTOK * 256];
__device__ __align__(16) float g_f3[(size_t)cPTS * 512];
__device__ __align__(16) float g_h[cTOK * cDM];
__device__ __align__(16) float g_res[cTOK * cDM];
__device__ __align__(16) float g_xln[cTOK * cDM];
__device__ __align__(16) float g_xz[(size_t)cTOK * 2 * cDI];
__device__ __align__(16) float g_xc[(size_t)cTOK * cDI];
__device__ __align__(16) float g_dbl64[cTOK * 64];
__device__ __align__(16) float g_u[(size_t)cTOK * cDI];
// pre-rounded (tf32/RNA) weights
__device__ __align__(16) float g_xpw[cNL * 64 * cDI];
__device__ __align__(16) float g_dtw[cNL * cDI * 32];
__device__ __align__(16) float g_we1w2[256 * 128];
__device__ __align__(16) float g_we2w1[512 * 512];
__device__ __align__(16) float g_we2w2[384 * 512];
__device__ __align__(16) float g_wpw2[384 * 128];
__device__ __align__(16) float g_winw[(size_t)cNL * 1536 * 384];
__device__ __align__(16) float g_woutw[(size_t)cNL * 384 * 768];

using u32 = unsigned int;

__device__ __forceinline__ u32 cvt_tf32(float x) {
    u32 r;
    asm("cvt.rna.tf32.f32 %0, %1;" : "=r"(r) : "f"(x));
    return r;
}
__device__ __forceinline__ float rnd_tf32(float x) {
    return __uint_as_float(cvt_tf32(x));
}

__device__ __forceinline__ u32 smem_u32(const void* p) {
    u32 a;
    asm("{ .reg .u64 t; cvta.to.shared.u64 t, %1; cvt.u32.u64 %0, t; }"
        : "=r"(a) : "l"(p));
    return a;
}

__device__ __forceinline__ void ldsm4(u32& r0, u32& r1, u32& r2, u32& r3, u32 addr) {
    asm volatile("ldmatrix.sync.aligned.m8n8.x4.shared.b16 {%0,%1,%2,%3}, [%4];"
                 : "=r"(r0), "=r"(r1), "=r"(r2), "=r"(r3) : "r"(addr));
}

__device__ __forceinline__ void cpasync16(u32 dst, const void* src) {
    asm volatile("cp.async.cg.shared.global [%0], [%1], 16;"
                 :: "r"(dst), "l"(src) : "memory");
}
#define CP_COMMIT() asm volatile("cp.async.commit_group;" ::: "memory")
#define CP_WAIT0()  asm volatile("cp.async.wait_group 0;" ::: "memory")

__device__ __forceinline__ void mma_tf32(float* c, u32 a0, u32 a1, u32 a2, u32 a3,
                                         u32 b0, u32 b1) {
    asm volatile(
        "mma.sync.aligned.m16n8k8.row.col.f32.tf32.tf32.f32 "
        "{%0,%1,%2,%3}, {%4,%5,%6,%7}, {%8,%9}, {%0,%1,%2,%3};"
        : "+f"(c[0]), "+f"(c[1]), "+f"(c[2]), "+f"(c[3])
        : "r"(a0), "r"(a1), "r"(a2), "r"(a3), "r"(b0), "r"(b1));
}

// ---------------------------------------------------------------------------
// Generic tf32 tensor-core GEMM: C = epi(A' @ W^T).
//   Smem row-major [row][k] (stride 20 floats), ldmatrix.x4.b16 fragments,
//   cp.async gmem->smem for MODEA<=1 (A) and always for W. Inputs must be
//   pre-rounded to tf32 (RNA) by producers; HW truncation is then a no-op.
//   EPI 0:+bias(opt). 1: relu(bn(.+bias)). 2: softplus(.+bias). 3: C+=.+bias
//   MODEA 0: A'=A. 1: cols[0,256) from aux1[row>>5][k].
//         2: relu(bn1(nb@w1^T+b1)) on the fly. 4: gelu(center@pw1^T+pb1).
//   EMAX 0: normal. 1: write C AND 32-row group max. 2: ONLY group max.
//   ROUNDC 1: RNA-round outputs (consumer is a GEMM).
// ---------------------------------------------------------------------------
template<int BM, int BN, int WGM, int WGN, int EPI, int MODEA, int EMAX, int ROUNDC>
__global__ void __launch_bounds__(WGM * WGN * 32)
tc2(const float* __restrict__ A, const float* __restrict__ W,
    const float* __restrict__ bias, const float* __restrict__ p1,
    const float* __restrict__ p2, float* __restrict__ C,
    int K, int lda, int ldw, int ldc,
    const float* __restrict__ aux1, const float* __restrict__ aux2,
    float* __restrict__ fgout, int ldfg)
{
    constexpr int THREADS = WGM * WGN * 32;
    constexpr int WTM = BM / WGM, WTN = BN / WGN;
    constexpr int MT = WTM / 16, NT = WTN / 8;
    constexpr int NP = NT / 2;
    constexpr int KS = 20;
    constexpr int A4 = (BM * 16) / (THREADS * 4);
    constexpr int W4 = (BN * 16) / (THREADS * 4);
    static_assert(EMAX == 0 || (WTM % 32) == 0, "EMAX needs WTM%32==0");
    static_assert(NT % 2 == 0, "NT must be even");

    __shared__ __align__(16) float As[2][BM][KS];
    __shared__ __align__(16) float Ws[2][BN][KS];

    const int tid = threadIdx.x;
    const int wid = tid >> 5, lane = tid & 31;
    const int grp = lane >> 2, tig = lane & 3;
    const int wm = wid % WGM, wn = wid / WGM;
    const int m0 = blockIdx.x * BM, n0 = blockIdx.y * BN;
    const float bnscale = rsqrtf(1.0f + 1e-5f);

    const u32 asBase = smem_u32(&As[0][0][0]);
    const u32 wsBase = smem_u32(&Ws[0][0][0]);
    constexpr u32 ABUF = BM * KS * 4;
    constexpr u32 WBUF = BN * KS * 4;

    u32 aOff[MT], bOff[NP];
    {
        int l7 = lane & 7;
        int aRow = ((lane >> 3) & 1) * 8;
        int aCol = (lane >> 4) * 16;
#pragma unroll
        for (int mt = 0; mt < MT; mt++) {
            int row = wm * WTM + mt * 16 + aRow + l7;
            aOff[mt] = (u32)(row * KS * 4 + aCol);
        }
        int bRow = (lane >> 4) * 8;
        int bCol = ((lane >> 3) & 1) * 16;
#pragma unroll
        for (int p = 0; p < NP; p++) {
            int row = wn * WTN + p * 16 + bRow + l7;
            bOff[p] = (u32)(row * KS * 4 + bCol);
        }
    }

    float acc[MT][NT][4];
#pragma unroll
    for (int mt = 0; mt < MT; mt++)
#pragma unroll
        for (int nt = 0; nt < NT; nt++)
#pragma unroll
            for (int r = 0; r < 4; r++) acc[mt][nt][r] = 0.f;

    float nbr[(MODEA >= 2) ? A4 : 1][3];
    if (MODEA >= 2) {
#pragma unroll
        for (int v = 0; v < A4; v++) {
            int row = (tid + v * THREADS) >> 2;
            nbr[v][0] = A[(size_t)(m0 + row) * 3 + 0];
            nbr[v][1] = A[(size_t)(m0 + row) * 3 + 1];
            nbr[v][2] = A[(size_t)(m0 + row) * 3 + 2];
        }
    }

    float4 ra[(MODEA >= 2) ? A4 : 1];

    auto issueAW = [&](int kc, int bufSel) {
        const u32 aB = asBase + (u32)bufSel * ABUF;
        const u32 wB = wsBase + (u32)bufSel * WBUF;
        if (MODEA <= 1) {
#pragma unroll
            for (int v = 0; v < A4; v++) {
                int s = tid + v * THREADS;
                int row = s >> 2;
                int kq = (s & 3) * 4;
                int k = kc + kq;
                const float* src;
                if (MODEA == 0) {
                    src = A + (size_t)(m0 + row) * lda + k;
                } else {
                    int r = m0 + row;
                    src = (k < 256)
                        ? (aux1 + ((size_t)(r >> 5)) * 256 + k)
                        : (A + (size_t)r * lda + (k - 256));
                }
                cpasync16(aB + (u32)((row * KS + kq) * 4), src);
            }
        } else {
#pragma unroll
            for (int v = 0; v < A4; v++) {
                int s = tid + v * THREADS;
                int k = kc + (s & 3) * 4;
                float out[4];
#pragma unroll
                for (int e = 0; e < 4; e++) {
                    int kk = k + e;
                    float val = nbr[v][0] * aux1[kk * 3 + 0]
                              + nbr[v][1] * aux1[kk * 3 + 1]
                              + nbr[v][2] * aux1[kk * 3 + 2] + aux2[kk];
                    if (MODEA == 2) {
                        val = val * (p1[kk] * bnscale) + p2[kk];
                        out[e] = fmaxf(val, 0.f);
                    } else {  // gelu (tanh approx)
                        float v3 = val * val * val;
                        out[e] = 0.5f * val *
                            (1.0f + tanhf(0.7978845608028654f *
                                          (val + 0.044715f * v3)));
                    }
                }
                ra[v] = make_float4(out[0], out[1], out[2], out[3]);
            }
        }
#pragma unroll
        for (int v = 0; v < W4; v++) {
            int s = tid + v * THREADS;
            int row = s >> 2;
            int kq = (s & 3) * 4;
            cpasync16(wB + (u32)((row * KS + kq) * 4),
                      W + (size_t)(n0 + row) * ldw + kc + kq);
        }
        CP_COMMIT();
    };

    auto stsA = [&](int bufSel) {
        if (MODEA >= 2) {
#pragma unroll
            for (int v = 0; v < A4; v++) {
                int s = tid + v * THREADS;
                int row = s >> 2, kq = (s & 3) << 2;
                uint4 o;
                o.x = cvt_tf32(ra[v].x); o.y = cvt_tf32(ra[v].y);
                o.z = cvt_tf32(ra[v].z); o.w = cvt_tf32(ra[v].w);
                *reinterpret_cast<uint4*>(&As[bufSel][row][kq]) = o;
            }
        }
    };

    const int nIter = K >> 4;
    issueAW(0, 0);
    stsA(0);
    CP_WAIT0();
    __syncthreads();
    int buf = 0;

    for (int it = 0; it < nIter; it++) {
        bool more = (it + 1 < nIter);
        if (more) issueAW((it + 1) << 4, buf ^ 1);
        const u32 aB = asBase + (u32)buf * ABUF;
        const u32 wB = wsBase + (u32)buf * WBUF;
#pragma unroll
        for (int ks = 0; ks < 2; ks++) {
            const u32 kb = (u32)(ks * 32);
            u32 af[MT][4];
#pragma unroll
            for (int mt = 0; mt < MT; mt++)
                ldsm4(af[mt][0], af[mt][1], af[mt][2], af[mt][3],
                      aB + aOff[mt] + kb);
            u32 bf[NT][2];
#pragma unroll
            for (int p = 0; p < NP; p++) {
                u32 r0, r1, r2, r3;
                ldsm4(r0, r1, r2, r3, wB + bOff[p] + kb);
                bf[2 * p][0] = r0;     bf[2 * p][1] = r1;
                bf[2 * p + 1][0] = r2; bf[2 * p + 1][1] = r3;
            }
#pragma unroll
            for (int mt = 0; mt < MT; mt++)
#pragma unroll
                for (int nt = 0; nt < NT; nt++)
                    mma_tf32(acc[mt][nt], af[mt][0], af[mt][1], af[mt][2], af[mt][3],
                             bf[nt][0], bf[nt][1]);
        }
        if (more) {
            stsA(buf ^ 1);
            CP_WAIT0();
            __syncthreads();
            buf ^= 1;
        }
    }

    if constexpr (EMAX == 0) {
        auto emit = [&](int mrow, int n, float v0, float v1) {
            if (EPI == 3) {
                C[(size_t)mrow * ldc + n]     += v0 + bias[n];
                C[(size_t)mrow * ldc + n + 1] += v1 + bias[n + 1];
                return;
            }
            if (EPI == 0) {
                if (bias) { v0 += bias[n]; v1 += bias[n + 1]; }
            } else if (EPI == 1) {
                v0 = fmaxf((v0 + bias[n]) * (p1[n] * bnscale) + p2[n], 0.f);
                v1 = fmaxf((v1 + bias[n + 1]) * (p1[n + 1] * bnscale) + p2[n + 1], 0.f);
            } else if (EPI == 2) {
                v0 += bias[n]; v1 += bias[n + 1];
                v0 = fmaxf(v0, 0.f) + log1pf(__expf(-fabsf(v0)));
                v1 = fmaxf(v1, 0.f) + log1pf(__expf(-fabsf(v1)));
            }
            if (ROUNDC) { v0 = rnd_tf32(v0); v1 = rnd_tf32(v1); }
            float2 o; o.x = v0; o.y = v1;
            *(float2*)&C[(size_t)mrow * ldc + n] = o;
        };
#pragma unroll
        for (int mt = 0; mt < MT; mt++) {
            int mrow = m0 + wm * WTM + mt * 16 + grp;
#pragma unroll
            for (int nt = 0; nt < NT; nt++) {
                int n = n0 + wn * WTN + nt * 8 + tig * 2;
                emit(mrow,     n, acc[mt][nt][0], acc[mt][nt][1]);
                emit(mrow + 8, n, acc[mt][nt][2], acc[mt][nt][3]);
            }
        }
    } else {
        constexpr int GPW = WTM / 32;
        float mx[GPW][NT][2];
#pragma unroll
        for (int g = 0; g < GPW; g++)
#pragma unroll
            for (int nt = 0; nt < NT; nt++) {
                mx[g][nt][0] = -FLT_MAX; mx[g][nt][1] = -FLT_MAX;
            }
#pragma unroll
        for (int mt = 0; mt < MT; mt++) {
            int gsel = mt / 2;
            int mrow = m0 + wm * WTM + mt * 16 + grp;
#pragma unroll
            for (int nt = 0; nt < NT; nt++) {
                int n = n0 + wn * WTN + nt * 8 + tig * 2;
                float v0 = acc[mt][nt][0] + bias[n];
                float v1 = acc[mt][nt][1] + bias[n + 1];
                float v2 = acc[mt][nt][2] + bias[n];
                float v3 = acc[mt][nt][3] + bias[n + 1];
                if (ROUNDC) {
                    v0 = rnd_tf32(v0); v1 = rnd_tf32(v1);
                    v2 = rnd_tf32(v2); v3 = rnd_tf32(v3);
                }
                if (EMAX == 1) {
                    float2 o0; o0.x = v0; o0.y = v1;
                    float2 o1; o1.x = v2; o1.y = v3;
                    *(float2*)&C[(size_t)mrow * ldc + n] = o0;
                    *(float2*)&C[(size_t)(mrow + 8) * ldc + n] = o1;
                }
                mx[gsel][nt][0] = fmaxf(mx[gsel][nt][0], fmaxf(v0, v2));
                mx[gsel][nt][1] = fmaxf(mx[gsel][nt][1], fmaxf(v1, v3));
            }
        }
#pragma unroll
        for (int g = 0; g < GPW; g++) {
#pragma unroll
            for (int nt = 0; nt < NT; nt++)
#pragma unroll
                for (int c = 0; c < 2; c++) {
                    float v = mx[g][nt][c];
                    v = fmaxf(v, __shfl_xor_sync(0xffffffffu, v, 4));
                    v = fmaxf(v, __shfl_xor_sync(0xffffffffu, v, 8));
                    v = fmaxf(v, __shfl_xor_sync(0xffffffffu, v, 16));
                    mx[g][nt][c] = v;
                }
            if (lane < 4) {
                int grow = (m0 >> 5) + wm * GPW + g;
#pragma unroll
                for (int nt = 0; nt < NT; nt++) {
                    int n = n0 + wn * WTN + nt * 8 + tig * 2;
                    fgout[(size_t)grow * ldfg + n]     = mx[g][nt][0];
                    fgout[(size_t)grow * ldfg + n + 1] = mx[g][nt][1];
                }
            }
        }
    }
}

// ---------------------------------------------------------------------------
// Pre-round all GEMM weights to tf32 (RNA); pad xp_w/dt_w
// ---------------------------------------------------------------------------
constexpr int PW_N0 = 256 * 128;
constexpr int PW_N1 = 512 * 512;
constexpr int PW_N2 = 384 * 512;
constexpr int PW_N3 = 384 * 128;
constexpr int PW_N4 = cNL * 1536 * 384;
constexpr int PW_N5 = cNL * 384 * 768;
constexpr int PW_N6 = cNL * 64 * cDI;
constexpr int PW_N7 = cNL * cDI * 32;
constexpr int PW_O1 = PW_N0;
constexpr int PW_O2 = PW_O1 + PW_N1;
constexpr int PW_O3 = PW_O2 + PW_N2;
constexpr int PW_O4 = PW_O3 + PW_N3;
constexpr int PW_O5 = PW_O4 + PW_N4;
constexpr int PW_O6 = PW_O5 + PW_N5;
constexpr int PW_O7 = PW_O6 + PW_N6;
constexpr int PW_TOT = PW_O7 + PW_N7;

__global__ void prep_weights(const float* __restrict__ e1w2,
                             const float* __restrict__ e2w1,
                             const float* __restrict__ e2w2,
                             const float* __restrict__ pw2,
                             const float* __restrict__ in_w,
                             const float* __restrict__ out_w,
                             const float* __restrict__ xp_w,
                             const float* __restrict__ dt_w) {
    int idx = blockIdx.x * 256 + threadIdx.x;
    if (idx >= PW_TOT) return;
    float v; float* dst;
    if (idx < PW_O1)      { v = e1w2[idx];          dst = g_we1w2 + idx; }
    else if (idx < PW_O2) { v = e2w1[idx - PW_O1];  dst = g_we2w1 + (idx - PW_O1); }
    else if (idx < PW_O3) { v = e2w2[idx - PW_O2];  dst = g_we2w2 + (idx - PW_O2); }
    else if (idx < PW_O4) { v = pw2[idx - PW_O3];   dst = g_wpw2 + (idx - PW_O3); }
    else if (idx < PW_O5) { v = in_w[idx - PW_O4];  dst = g_winw + (idx - PW_O4); }
    else if (idx < PW_O6) { v = out_w[idx - PW_O5]; dst = g_woutw + (idx - PW_O5); }
    else if (idx < PW_O7) {
        int j = idx - PW_O6;
        int l = j / (64 * cDI);
        int r = (j / cDI) % 64;
        int k = j % cDI;
        v = (r < 56) ? xp_w[((size_t)l * 56 + r) * cDI + k] : 0.f;
        dst = g_xpw + j;
    } else {
        int j = idx - PW_O7;
        int l = j / (cDI * 32);
        int d = (j / 32) % cDI;
        int k = j % 32;
        v = (k < 24) ? dt_w[((size_t)l * cDI + d) * cDTR + k] : 0.f;
        dst = g_dtw + j;
    }
    *dst = __uint_as_float(cvt_tf32(v));
}

// ---------------------------------------------------------------------------
// FPS
// ---------------------------------------------------------------------------
__global__ void fps_kernel(const float* __restrict__ xyz) {
    int b = blockIdx.x;
    __shared__ float px[cN], py[cN], pz[cN], dmin[cN];
    __shared__ float wv[8];
    __shared__ int   wi[8];
    __shared__ int   s_cur;
    int tid = threadIdx.x;
    int wid = tid >> 5, lane = tid & 31;
    for (int i = tid; i < cN; i += 256) {
        px[i] = xyz[(b * cN + i) * 3 + 0];
        py[i] = xyz[(b * cN + i) * 3 + 1];
        pz[i] = xyz[(b * cN + i) * 3 + 2];
        dmin[i] = 1e10f;
    }
    __syncthreads();
    int cur = 0;
    for (int g = 0; g < cG; g++) {
        float cx = px[cur], cy = py[cur], cz = pz[cur];
        if (tid == 0) {
            g_center[(b * cG + g) * 3 + 0] = cx;
            g_center[(b * cG + g) * 3 + 1] = cy;
            g_center[(b * cG + g) * 3 + 2] = cz;
        }
        float bv = -1.f; int bi = 0x7fffffff;
        for (int i = tid; i < cN; i += 256) {
            float dx = __fsub_rn(px[i], cx);
            float dy = __fsub_rn(py[i], cy);
            float dz = __fsub_rn(pz[i], cz);
            float dd = __fadd_rn(__fadd_rn(__fmul_rn(dx, dx), __fmul_rn(dy, dy)),
                                 __fmul_rn(dz, dz));
            float dm = fminf(dmin[i], dd);
            dmin[i] = dm;
            if (dm > bv) { bv = dm; bi = i; }
        }
#pragma unroll
        for (int off = 16; off > 0; off >>= 1) {
            float ov = __shfl_xor_sync(0xffffffffu, bv, off);
            int oi = __shfl_xor_sync(0xffffffffu, bi, off);
            if (ov > bv || (ov == bv && oi < bi)) { bv = ov; bi = oi; }
        }
        if (lane == 0) { wv[wid] = bv; wi[wid] = bi; }
        __syncthreads();
        if (tid < 8) {
            bv = wv[tid]; bi = wi[tid];
#pragma unroll
            for (int off = 4; off > 0; off >>= 1) {
                float ov = __shfl_xor_sync(0xffu, bv, off);
                int oi = __shfl_xor_sync(0xffu, bi, off);
                if (ov > bv || (ov == bv && oi < bi)) { bv = ov; bi = oi; }
            }
            if (tid == 0) s_cur = bi;
        }
        __syncthreads();
        cur = s_cur;
    }
}

// ---------------------------------------------------------------------------
// KNN
// ---------------------------------------------------------------------------
__global__ void knn_kernel(const float* __restrict__ xyz) {
    int bg = blockIdx.x;
    int b = bg >> 7;
    __shared__ float d2s[cN];
    __shared__ float wv[8];
    __shared__ int   wi[8];
    __shared__ int   s_idx;
    int tid = threadIdx.x;
    int wid = tid >> 5, lane = tid & 31;
    float cx = g_center[bg * 3 + 0], cy = g_center[bg * 3 + 1], cz = g_center[bg * 3 + 2];
    const float* P = xyz + (size_t)b * cN * 3;
    for (int i = tid; i < cN; i += 256) {
        float dx = __fsub_rn(cx, P[i * 3 + 0]);
        float dy = __fsub_rn(cy, P[i * 3 + 1]);
        float dz = __fsub_rn(cz, P[i * 3 + 2]);
        d2s[i] = __fadd_rn(__fadd_rn(__fmul_rn(dx, dx), __fmul_rn(dy, dy)),
                           __fmul_rn(dz, dz));
    }
    __syncthreads();
    for (int m = 0; m < cM; m++) {
        float bv = FLT_MAX; int bi = 0x7fffffff;
        for (int i = tid; i < cN; i += 256) {
            float v = d2s[i];
            if (v < bv) { bv = v; bi = i; }
        }
#pragma unroll
        for (int off = 16; off > 0; off >>= 1) {
            float ov = __shfl_xor_sync(0xffffffffu, bv, off);
            int oi = __shfl_xor_sync(0xffffffffu, bi, off);
            if (ov < bv || (ov == bv && oi < bi)) { bv = ov; bi = oi; }
        }
        if (lane == 0) { wv[wid] = bv; wi[wid] = bi; }
        __syncthreads();
        if (tid < 8) {
            bv = wv[tid]; bi = wi[tid];
#pragma unroll
            for (int off = 4; off > 0; off >>= 1) {
                float ov = __shfl_xor_sync(0xffu, bv, off);
                int oi = __shfl_xor_sync(0xffu, bi, off);
                if (ov < bv || (ov == bv && oi < bi)) { bv = ov; bi = oi; }
            }
            if (tid == 0) s_idx = bi;
        }
        __syncthreads();
        int idx = s_idx;
        if (tid < 3) {
            float c = (tid == 0) ? cx : ((tid == 1) ? cy : cz);
            g_nb[((size_t)bg * cM + m) * 3 + tid] = __fsub_rn(P[idx * 3 + tid], c);
        }
        if (tid == 0) d2s[idx] = FLT_MAX;
        __syncthreads();
    }
}

// ---------------------------------------------------------------------------
// Residual accumulate + LayerNorm (xln rounded to tf32; res stays fp32)
// ---------------------------------------------------------------------------
__device__ __forceinline__ float block_sum_128(float v, float* sm) {
    int tid = threadIdx.x;
    sm[tid] = v; __syncthreads();
    for (int s = 64; s > 0; s >>= 1) {
        if (tid < s) sm[tid] += sm[tid + s];
        __syncthreads();
    }
    float r = sm[0]; __syncthreads();
    return r;
}

__global__ void resln_kernel(const float* __restrict__ w, const float* __restrict__ b,
                             int first) {
    __shared__ float sm[128];
    int t = blockIdx.x;
    float v[3];
#pragma unroll
    for (int j = 0; j < 3; j++) {
        int c = threadIdx.x + j * 128;
        float r = g_h[t * 384 + c];
        if (!first) r += g_res[t * 384 + c];
        g_res[t * 384 + c] = r;
        v[j] = r;
    }
    float mean = block_sum_128(v[0] + v[1] + v[2], sm) * (1.0f / 384.0f);
    float sq = 0.f;
#pragma unroll
    for (int j = 0; j < 3; j++) { float d = v[j] - mean; sq += d * d; }
    float var = block_sum_128(sq, sm) * (1.0f / 384.0f);
    float inv = rsqrtf(var + 1e-5f);
#pragma unroll
    for (int j = 0; j < 3; j++) {
        int c = threadIdx.x + j * 128;
        g_xln[t * 384 + c] = rnd_tf32((v[j] - mean) * inv * w[c] + b[c]);
    }
}

__global__ void final_kernel(const float* __restrict__ w, const float* __restrict__ b,
                             float* __restrict__ out) {
    __shared__ float sm[128];
    int t = blockIdx.x;
    float v[3];
#pragma unroll
    for (int j = 0; j < 3; j++) {
        int c = threadIdx.x + j * 128;
        v[j] = g_h[t * 384 + c] + g_res[t * 384 + c];
    }
    float mean = block_sum_128(v[0] + v[1] + v[2], sm) * (1.0f / 384.0f);
    float sq = 0.f;
#pragma unroll
    for (int j = 0; j < 3; j++) { float d = v[j] - mean; sq += d * d; }
    float var = block_sum_128(sq, sm) * (1.0f / 384.0f);
    float inv = rsqrtf(var + 1e-5f);
#pragma unroll
    for (int j = 0; j < 3; j++) {
        int c = threadIdx.x + j * 128;
        out[t * 384 + c] = (v[j] - mean) * inv * w[c] + b[c];
    }
}

// ---------------------------------------------------------------------------
// Depthwise causal conv (DC=4) + bias + silu (output rounded to tf32)
// ---------------------------------------------------------------------------
__global__ void conv_kernel(const float* __restrict__ cw, const float* __restrict__ cb) {
    int idx = blockIdx.x * blockDim.x + threadIdx.x;
    if (idx >= cTOK * cDI) return;
    int t = idx / cDI, d = idx % cDI;
    int l = t & 127;
    int tbase = t - l;
    float acc = cb[d];
#pragma unroll
    for (int k = 0; k < 4; k++) {
        int lk = l - 3 + k;
        if (lk >= 0)
            acc += g_xz[(size_t)(tbase + lk) * 1536 + d] * cw[d * 4 + k];
    }
    float sig = 1.0f / (1.0f + __expf(-acc));
    g_xc[idx] = rnd_tf32(acc * sig);
}

// ---------------------------------------------------------------------------
// Selective scan v4: dt computed inline (dbl[:24] @ dtw row + softplus),
// full dbl64 rows staged in smem; one thread per (b,d); q-power fast path.
// ---------------------------------------------------------------------------
template<bool FAST>
__device__ __forceinline__ void scan_body(
    int b, int d, float a0, const float* a, float Dpd,
    const float* dtr, float dtbd) {
    extern __shared__ float sD[];   // [128][64]
    float h[16];
#pragma unroll
    for (int s = 0; s < 16; s++) h[s] = 0.f;

    const float* pxc = g_xc + (size_t)b * 128 * cDI + d;
    const float* pz  = g_xz + (size_t)b * 128 * 1536 + cDI + d;
    float* pu = g_u + (size_t)b * 128 * cDI + d;

    for (int t = 0; t < 128; t++) {
        const float* Dt = sD + t * 64;
        float acc = dtbd;
#pragma unroll
        for (int r = 0; r < 24; r++) acc += Dt[r] * dtr[r];
        float dt = fmaxf(acc, 0.f) + log1pf(__expf(-fabsf(acc)));
        float xin = pxc[(size_t)t * cDI];
        float u = dt * xin;
        float p[16];
        if (FAST) {
            float q = __expf(dt * a0);
            float q2 = q * q, q4 = q2 * q2, q8 = q4 * q4;
            p[0] = q;        p[1] = q2;       p[2] = q2 * q;   p[3] = q4;
            p[4] = q4 * q;   p[5] = q4 * q2;  p[6] = p[5] * q; p[7] = q8;
            p[8] = q8 * q;   p[9] = q8 * q2;  p[10] = p[9] * q;
            p[11] = q8 * q4; p[12] = p[11] * q; p[13] = p[11] * q2;
            p[14] = p[13] * q; p[15] = q8 * q8;
        } else {
#pragma unroll
            for (int s = 0; s < 16; s++) p[s] = __expf(dt * a[s]);
        }
        float y = 0.f;
#pragma unroll
        for (int s = 0; s < 16; s++) {
            h[s] = p[s] * h[s] + u * Dt[24 + s];
            y += h[s] * Dt[40 + s];
        }
        y += Dpd * xin;
        float z = pz[(size_t)t * 1536];
        float sz = z / (1.0f + __expf(-z));
        pu[(size_t)t * cDI] = rnd_tf32(y * sz);
    }
}

__global__ void __launch_bounds__(256)
scan_kernel(const float* __restrict__ Alog, const float* __restrict__ Dp,
            const float* __restrict__ dtw, const float* __restrict__ dtb) {
    extern __shared__ float sD[];   // 128*64 floats = 32KB
    int tid = threadIdx.x;
    int b = blockIdx.y;
    int d = blockIdx.x * 256 + tid;

    for (int i = tid; i < 128 * 16; i += 256)
        ((float4*)sD)[i] = ((const float4*)g_dbl64)[(size_t)b * 128 * 16 + i];
    __syncthreads();

    float dtr[24];
#pragma unroll
    for (int r = 0; r < 24; r++) dtr[r] = dtw[d * 32 + r];
    float dtbd = dtb[d];

    float a[16];
    bool fast = true;
#pragma unroll
    for (int s = 0; s < 16; s++) a[s] = -expf(Alog[d * 16 + s]);
    float a0 = a[0];
#pragma unroll
    for (int s = 1; s < 16; s++) {
        float ideal = (float)(s + 1) * a0;
        if (fabsf(a[s] - ideal) > 1e-4f * fabsf(ideal)) fast = false;
    }
    float Dpd = Dp[d];

    if (fast) scan_body<true>(b, d, a0, a, Dpd, dtr, dtbd);
    else      scan_body<false>(b, d, a0, a, Dpd, dtr, dtbd);
}

// ---------------------------------------------------------------------------
// Host-side launch sequence
// ---------------------------------------------------------------------------
extern "C" void kernel_launch(void* const* d_in, const int* in_sizes, int n_in,
                              void* d_out, int out_size) {
    const float* xyz   = (const float*)d_in[0];
    const float* e1w1  = (const float*)d_in[1];
    const float* e1b1  = (const float*)d_in[2];
    const float* bn1g  = (const float*)d_in[3];
    const float* bn1b  = (const float*)d_in[4];
    const float* e1w2  = (const float*)d_in[5];
    const float* e1b2  = (const float*)d_in[6];
    const float* e2w1  = (const float*)d_in[7];
    const float* e2b1  = (const float*)d_in[8];
    const float* bn2g  = (const float*)d_in[9];
    const float* bn2b  = (const float*)d_in[10];
    const float* e2w2  = (const float*)d_in[11];
    const float* e2b2  = (const float*)d_in[12];
    const float* pw1   = (const float*)d_in[13];
    const float* pb1   = (const float*)d_in[14];
    const float* pw2   = (const float*)d_in[15];
    const float* pb2   = (const float*)d_in[16];
    const float* in_w  = (const float*)d_in[17];
    const float* convw = (const float*)d_in[18];
    const float* convb = (const float*)d_in[19];
    const float* xp_w  = (const float*)d_in[20];
    const float* dt_w  = (const float*)d_in[21];
    const float* dt_b  = (const float*)d_in[22];
    const float* A_log = (const float*)d_in[23];
    const float* Dp    = (const float*)d_in[24];
    const float* out_w = (const float*)d_in[25];
    const float* lnw   = (const float*)d_in[26];
    const float* lnb   = (const float*)d_in[27];
    const float* fnw   = (const float*)d_in[28];
    const float* fnb   = (const float*)d_in[29];
    float* out = (float*)d_out;

    float *pnb, *pf2, *pfg, *pf3, *pxln, *pxz, *pxc, *pu, *ph, *pcenter,
          *pdbl, *pxpw, *pdtw;
    float *pwe1w2, *pwe2w1, *pwe2w2, *pwpw2, *pwinw, *pwoutw;
    cudaGetSymbolAddress((void**)&pnb,  g_nb);
    cudaGetSymbolAddress((void**)&pf2,  g_f2);
    cudaGetSymbolAddress((void**)&pfg,  g_fg);
    cudaGetSymbolAddress((void**)&pf3,  g_f3);
    cudaGetSymbolAddress((void**)&pxln, g_xln);
    cudaGetSymbolAddress((void**)&pxz,  g_xz);
    cudaGetSymbolAddress((void**)&pxc,  g_xc);
    cudaGetSymbolAddress((void**)&pu,   g_u);
    cudaGetSymbolAddress((void**)&ph,   g_h);
    cudaGetSymbolAddress((void**)&pcenter, g_center);
    cudaGetSymbolAddress((void**)&pdbl, g_dbl64);
    cudaGetSymbolAddress((void**)&pxpw, g_xpw);
    cudaGetSymbolAddress((void**)&pdtw, g_dtw);
    cudaGetSymbolAddress((void**)&pwe1w2, g_we1w2);
    cudaGetSymbolAddress((void**)&pwe2w1, g_we2w1);
    cudaGetSymbolAddress((void**)&pwe2w2, g_we2w2);
    cudaGetSymbolAddress((void**)&pwpw2,  g_wpw2);
    cudaGetSymbolAddress((void**)&pwinw,  g_winw);
    cudaGetSymbolAddress((void**)&pwoutw, g_woutw);

    // ---- weight prep (pre-round to tf32) ----
    prep_weights<<<(PW_TOT + 255) / 256, 256>>>(
        e1w2, e2w1, e2w2, pw2, in_w, out_w, xp_w, dt_w);

    // ---- grouping ----
    fps_kernel<<<cB, 256>>>(xyz);
    knn_kernel<<<cTOK, 256>>>(xyz);

    // ---- encoder (128x128 tiles, 8 warps: WGM=4 x WGN=2) ----
    tc2<128, 128, 4, 2, 0, 2, 1, 1><<<dim3(cPTS / 128, 2), 256>>>(
        pnb, pwe1w2, e1b2, bn1g, bn1b, pf2, 128, 3, 128, 256,
        e1w1, e1b1, pfg, 256);
    tc2<128, 128, 4, 2, 1, 1, 0, 1><<<dim3(cPTS / 128, 4), 256>>>(
        pf2, pwe2w1, e2b1, bn2g, bn2b, pf3, 512, 256, 512, 512,
        pfg, nullptr, nullptr, 0);
    tc2<128, 128, 4, 2, 0, 0, 2, 0><<<dim3(cPTS / 128, 3), 256>>>(
        pf3, pwe2w2, e2b2, nullptr, nullptr, nullptr, 512, 512, 512, 384,
        nullptr, nullptr, ph, 384);

    // ---- positional MLP (pos1 fused into pos2 A-loader) ----
    tc2<64, 128, 2, 2, 3, 4, 0, 0><<<dim3(cTOK / 64, 3), 128>>>(
        pcenter, pwpw2, pb2, nullptr, nullptr, ph, 128, 3, 128, 384,
        pw1, pb1, nullptr, 0);

    // ---- mamba layers ----
    constexpr int SCAN_SMEM = 128 * 64 * sizeof(float);   // 32KB
    for (int i = 0; i < cNL; i++) {
        const float* in_w_i  = pwinw  + (size_t)i * 1536 * 384;
        const float* cw_i    = convw  + (size_t)i * cDI * 4;
        const float* cb_i    = convb  + (size_t)i * cDI;
        const float* dtb_i   = dt_b   + (size_t)i * cDI;
        const float* Al_i    = A_log  + (size_t)i * cDI * cDS;
        const float* Dp_i    = Dp     + (size_t)i * cDI;
        const float* ow_i    = pwoutw + (size_t)i * 384 * 768;
        const float* lnw_i   = lnw    + (size_t)i * cDM;
        const float* lnb_i   = lnb    + (size_t)i * cDM;
        const float* xpw_i   = pxpw   + (size_t)i * 64 * cDI;
        const float* dtw_i   = pdtw   + (size_t)i * cDI * 32;

        resln_kernel<<<cTOK, 128>>>(lnw_i, lnb_i, i == 0 ? 1 : 0);
        // in-proj: (2048,384)@(1536,384)^T
        tc2<64, 128, 2, 2, 0, 0, 0, 1><<<dim3(cTOK / 64, 12), 128>>>(
            pxln, in_w_i, nullptr, nullptr, nullptr, pxz, 384, 384, 384, 1536,
            nullptr, nullptr, nullptr, 0);
        conv_kernel<<<(cTOK * cDI + 255) / 256, 256>>>(cw_i, cb_i);
        // xp: (2048,768)@(64,768)^T -> g_dbl64
        tc2<64, 64, 2, 1, 0, 0, 0, 1><<<dim3(cTOK / 64, 1), 64>>>(
            pxc, xpw_i, nullptr, nullptr, nullptr, pdbl, 768, 768, 768, 64,
            nullptr, nullptr, nullptr, 0);
        // scan with dt fused (dbl[:24] @ dtw + softplus computed inline)
        scan_kernel<<<dim3(cDI / 256, cB), 256, SCAN_SMEM>>>(
            Al_i, Dp_i, dtw_i, dtb_i);
        // out-proj: (2048,768)@(384,768)^T
        tc2<64, 128, 2, 2, 0, 0, 0, 0><<<dim3(cTOK / 64, 3), 128>>>(
            pu, ow_i, nullptr, nullptr, nullptr, ph, 768, 768, 768, 384,
            nullptr, nullptr, nullptr, 0);
    }

    // ---- final LN ----
    final_kernel<<<cTOK, 128>>>(fnw, fnb, out);
}

// round 14
// speedup vs baseline: 2.1375x; 1.1134x over previous
#include <cuda_runtime.h>
#include <math.h>
#include <float.h>

// ---------------------------------------------------------------------------
// Problem constants
// ---------------------------------------------------------------------------
constexpr int cB   = 16;
constexpr int cN   = 2048;
constexpr int cG   = 128;
constexpr int cM   = 32;
constexpr int cDM  = 384;
constexpr int cNL  = 12;
constexpr int cDI  = 768;
constexpr int cDS  = 16;
constexpr int cDTR = 24;
constexpr int cTOK = cB * cG;        // 2048 tokens
constexpr int cPTS = cTOK * cM;      // 65536 points

// ---------------------------------------------------------------------------
// Scratch (device globals; no dynamic allocation allowed)
// ---------------------------------------------------------------------------
__device__ __align__(16) float g_center[cTOK * 3];
__device__ __align__(16) float g_nb[cPTS * 3];
__device__ __align__(16) float g_f2[(size_t)cPTS * 256];
__device__ __align__(16) float g_fg[cTOK * 256];
__device__ __align__(16) float g_f3[(size_t)cPTS * 512];
__device__ __align__(16) float g_h[cTOK * cDM];
__device__ __align__(16) float g_res[cTOK * cDM];
__device__ __align__(16) float g_xln[cTOK * cDM];
__device__ __align__(16) float g_xz[(size_t)cTOK * 2 * cDI];
__device__ __align__(16) float g_xc[(size_t)cTOK * cDI];
__device__ __align__(16) float g_dbl64[cTOK * 64];
__device__ __align__(16) float g_u[(size_t)cTOK * cDI];
// pre-rounded (tf32/RNA) weights
__device__ __align__(16) float g_xpw[cNL * 64 * cDI];
__device__ __align__(16) float g_dtw[cNL * cDI * 32];
__device__ __align__(16) float g_we1w2[256 * 128];
__device__ __align__(16) float g_we2w1[512 * 512];
__device__ __align__(16) float g_we2w2[384 * 512];
__device__ __align__(16) float g_wpw2[384 * 128];
__device__ __align__(16) float g_winw[(size_t)cNL * 1536 * 384];
__device__ __align__(16) float g_woutw[(size_t)cNL * 384 * 768];

using u32 = unsigned int;

__device__ __forceinline__ u32 cvt_tf32(float x) {
    u32 r;
    asm("cvt.rna.tf32.f32 %0, %1;" : "=r"(r) : "f"(x));
    return r;
}
__device__ __forceinline__ float rnd_tf32(float x) {
    return __uint_as_float(cvt_tf32(x));
}

__device__ __forceinline__ u32 smem_u32(const void* p) {
    u32 a;
    asm("{ .reg .u64 t; cvta.to.shared.u64 t, %1; cvt.u32.u64 %0, t; }"
        : "=r"(a) : "l"(p));
    return a;
}

__device__ __forceinline__ void ldsm4(u32& r0, u32& r1, u32& r2, u32& r3, u32 addr) {
    asm volatile("ldmatrix.sync.aligned.m8n8.x4.shared.b16 {%0,%1,%2,%3}, [%4];"
                 : "=r"(r0), "=r"(r1), "=r"(r2), "=r"(r3) : "r"(addr));
}

__device__ __forceinline__ void cpasync16(u32 dst, const void* src) {
    asm volatile("cp.async.cg.shared.global [%0], [%1], 16;"
                 :: "r"(dst), "l"(src) : "memory");
}
#define CP_COMMIT() asm volatile("cp.async.commit_group;" ::: "memory")
#define CP_WAIT0()  asm volatile("cp.async.wait_group 0;" ::: "memory")
#define CP_WAIT1()  asm volatile("cp.async.wait_group 1;" ::: "memory")

__device__ __forceinline__ void mma_tf32(float* c, u32 a0, u32 a1, u32 a2, u32 a3,
                                         u32 b0, u32 b1) {
    asm volatile(
        "mma.sync.aligned.m16n8k8.row.col.f32.tf32.tf32.f32 "
        "{%0,%1,%2,%3}, {%4,%5,%6,%7}, {%8,%9}, {%0,%1,%2,%3};"
        : "+f"(c[0]), "+f"(c[1]), "+f"(c[2]), "+f"(c[3])
        : "r"(a0), "r"(a1), "r"(a2), "r"(a3), "r"(b0), "r"(b1));
}

// ---------------------------------------------------------------------------
// Generic tf32 tensor-core GEMM: C = epi(A' @ W^T).
//   Smem row-major [row][k] (stride 20 floats), ldmatrix.x4.b16 fragments,
//   3-stage cp.async pipeline (wait_group 1 keeps one group in flight).
//   Inputs must be pre-rounded to tf32 (RNA) by producers.
//   EPI 0:+bias(opt). 1: relu(bn(.+bias)). 2: softplus(.+bias). 3: C+=.+bias
//   MODEA 0: A'=A. 1: cols[0,256) from aux1[row>>5][k].
//         2: relu(bn1(nb@w1^T+b1)) on the fly. 4: gelu(center@pw1^T+pb1).
//   EMAX 0: normal. 1: write C AND 32-row group max. 2: ONLY group max.
//   ROUNDC 1: RNA-round outputs (consumer is a GEMM).
// ---------------------------------------------------------------------------
template<int BM, int BN, int WGM, int WGN, int EPI, int MODEA, int EMAX, int ROUNDC>
__global__ void __launch_bounds__(WGM * WGN * 32)
tc2(const float* __restrict__ A, const float* __restrict__ W,
    const float* __restrict__ bias, const float* __restrict__ p1,
    const float* __restrict__ p2, float* __restrict__ C,
    int K, int lda, int ldw, int ldc,
    const float* __restrict__ aux1, const float* __restrict__ aux2,
    float* __restrict__ fgout, int ldfg)
{
    constexpr int THREADS = WGM * WGN * 32;
    constexpr int WTM = BM / WGM, WTN = BN / WGN;
    constexpr int MT = WTM / 16, NT = WTN / 8;
    constexpr int NP = NT / 2;
    constexpr int KS = 20;
    constexpr int A4 = (BM * 16) / (THREADS * 4);
    constexpr int W4 = (BN * 16) / (THREADS * 4);
    static_assert(EMAX == 0 || (WTM % 32) == 0, "EMAX needs WTM%32==0");
    static_assert(NT % 2 == 0, "NT must be even");

    __shared__ __align__(16) float As[3][BM][KS];
    __shared__ __align__(16) float Ws[3][BN][KS];

    const int tid = threadIdx.x;
    const int wid = tid >> 5, lane = tid & 31;
    const int grp = lane >> 2, tig = lane & 3;
    const int wm = wid % WGM, wn = wid / WGM;
    const int m0 = blockIdx.x * BM, n0 = blockIdx.y * BN;
    const float bnscale = rsqrtf(1.0f + 1e-5f);

    const u32 asBase = smem_u32(&As[0][0][0]);
    const u32 wsBase = smem_u32(&Ws[0][0][0]);
    constexpr u32 ABUF = BM * KS * 4;
    constexpr u32 WBUF = BN * KS * 4;

    u32 aOff[MT], bOff[NP];
    {
        int l7 = lane & 7;
        int aRow = ((lane >> 3) & 1) * 8;
        int aCol = (lane >> 4) * 16;
#pragma unroll
        for (int mt = 0; mt < MT; mt++) {
            int row = wm * WTM + mt * 16 + aRow + l7;
            aOff[mt] = (u32)(row * KS * 4 + aCol);
        }
        int bRow = (lane >> 4) * 8;
        int bCol = ((lane >> 3) & 1) * 16;
#pragma unroll
        for (int p = 0; p < NP; p++) {
            int row = wn * WTN + p * 16 + bRow + l7;
            bOff[p] = (u32)(row * KS * 4 + bCol);
        }
    }

    float acc[MT][NT][4];
#pragma unroll
    for (int mt = 0; mt < MT; mt++)
#pragma unroll
        for (int nt = 0; nt < NT; nt++)
#pragma unroll
            for (int r = 0; r < 4; r++) acc[mt][nt][r] = 0.f;

    float nbr[(MODEA >= 2) ? A4 : 1][3];
    if (MODEA >= 2) {
#pragma unroll
        for (int v = 0; v < A4; v++) {
            int row = (tid + v * THREADS) >> 2;
            nbr[v][0] = A[(size_t)(m0 + row) * 3 + 0];
            nbr[v][1] = A[(size_t)(m0 + row) * 3 + 1];
            nbr[v][2] = A[(size_t)(m0 + row) * 3 + 2];
        }
    }

    // issue cp.async for tile kc into buffer bufSel; for computed-A modes the
    // A tile is computed and stored synchronously (buffer not in use).
    auto issueAW = [&](int kc, int bufSel) {
        const u32 aB = asBase + (u32)bufSel * ABUF;
        const u32 wB = wsBase + (u32)bufSel * WBUF;
        if (MODEA <= 1) {
#pragma unroll
            for (int v = 0; v < A4; v++) {
                int s = tid + v * THREADS;
                int row = s >> 2;
                int kq = (s & 3) * 4;
                int k = kc + kq;
                const float* src;
                if (MODEA == 0) {
                    src = A + (size_t)(m0 + row) * lda + k;
                } else {
                    int r = m0 + row;
                    src = (k < 256)
                        ? (aux1 + ((size_t)(r >> 5)) * 256 + k)
                        : (A + (size_t)r * lda + (k - 256));
                }
                cpasync16(aB + (u32)((row * KS + kq) * 4), src);
            }
        } else {
#pragma unroll
            for (int v = 0; v < A4; v++) {
                int s = tid + v * THREADS;
                int row = s >> 2;
                int kq = (s & 3) * 4;
                int k = kc + kq;
                float out[4];
#pragma unroll
                for (int e = 0; e < 4; e++) {
                    int kk = k + e;
                    float val = nbr[v][0] * aux1[kk * 3 + 0]
                              + nbr[v][1] * aux1[kk * 3 + 1]
                              + nbr[v][2] * aux1[kk * 3 + 2] + aux2[kk];
                    if (MODEA == 2) {
                        val = val * (p1[kk] * bnscale) + p2[kk];
                        out[e] = fmaxf(val, 0.f);
                    } else {  // gelu (tanh approx)
                        float v3 = val * val * val;
                        out[e] = 0.5f * val *
                            (1.0f + tanhf(0.7978845608028654f *
                                          (val + 0.044715f * v3)));
                    }
                }
                uint4 o;
                o.x = cvt_tf32(out[0]); o.y = cvt_tf32(out[1]);
                o.z = cvt_tf32(out[2]); o.w = cvt_tf32(out[3]);
                *reinterpret_cast<uint4*>(&As[bufSel][row][kq]) = o;
            }
        }
#pragma unroll
        for (int v = 0; v < W4; v++) {
            int s = tid + v * THREADS;
            int row = s >> 2;
            int kq = (s & 3) * 4;
            cpasync16(wB + (u32)((row * KS + kq) * 4),
                      W + (size_t)(n0 + row) * ldw + kc + kq);
        }
        CP_COMMIT();
    };

    const int nIter = K >> 4;
    issueAW(0, 0);
    if (nIter > 1) {
        issueAW(16, 1);
        CP_WAIT1();
    } else {
        CP_WAIT0();
    }
    __syncthreads();

    for (int it = 0; it < nIter; it++) {
        if (it + 2 < nIter) issueAW((it + 2) << 4, (it + 2) % 3);
        const int buf = it % 3;
        const u32 aB = asBase + (u32)buf * ABUF;
        const u32 wB = wsBase + (u32)buf * WBUF;
#pragma unroll
        for (int ks = 0; ks < 2; ks++) {
            const u32 kb = (u32)(ks * 32);
            u32 af[MT][4];
#pragma unroll
            for (int mt = 0; mt < MT; mt++)
                ldsm4(af[mt][0], af[mt][1], af[mt][2], af[mt][3],
                      aB + aOff[mt] + kb);
            u32 bf[NT][2];
#pragma unroll
            for (int p = 0; p < NP; p++) {
                u32 r0, r1, r2, r3;
                ldsm4(r0, r1, r2, r3, wB + bOff[p] + kb);
                bf[2 * p][0] = r0;     bf[2 * p][1] = r1;
                bf[2 * p + 1][0] = r2; bf[2 * p + 1][1] = r3;
            }
#pragma unroll
            for (int mt = 0; mt < MT; mt++)
#pragma unroll
                for (int nt = 0; nt < NT; nt++)
                    mma_tf32(acc[mt][nt], af[mt][0], af[mt][1], af[mt][2], af[mt][3],
                             bf[nt][0], bf[nt][1]);
        }
        if (it + 1 < nIter) {
            if (it + 2 < nIter) { CP_WAIT1(); } else { CP_WAIT0(); }
            __syncthreads();
        }
    }

    if constexpr (EMAX == 0) {
        auto emit = [&](int mrow, int n, float v0, float v1) {
            if (EPI == 3) {
                C[(size_t)mrow * ldc + n]     += v0 + bias[n];
                C[(size_t)mrow * ldc + n + 1] += v1 + bias[n + 1];
                return;
            }
            if (EPI == 0) {
                if (bias) { v0 += bias[n]; v1 += bias[n + 1]; }
            } else if (EPI == 1) {
                v0 = fmaxf((v0 + bias[n]) * (p1[n] * bnscale) + p2[n], 0.f);
                v1 = fmaxf((v1 + bias[n + 1]) * (p1[n + 1] * bnscale) + p2[n + 1], 0.f);
            } else if (EPI == 2) {
                v0 += bias[n]; v1 += bias[n + 1];
                v0 = fmaxf(v0, 0.f) + log1pf(__expf(-fabsf(v0)));
                v1 = fmaxf(v1, 0.f) + log1pf(__expf(-fabsf(v1)));
            }
            if (ROUNDC) { v0 = rnd_tf32(v0); v1 = rnd_tf32(v1); }
            float2 o; o.x = v0; o.y = v1;
            *(float2*)&C[(size_t)mrow * ldc + n] = o;
        };
#pragma unroll
        for (int mt = 0; mt < MT; mt++) {
            int mrow = m0 + wm * WTM + mt * 16 + grp;
#pragma unroll
            for (int nt = 0; nt < NT; nt++) {
                int n = n0 + wn * WTN + nt * 8 + tig * 2;
                emit(mrow,     n, acc[mt][nt][0], acc[mt][nt][1]);
                emit(mrow + 8, n, acc[mt][nt][2], acc[mt][nt][3]);
            }
        }
    } else {
        constexpr int GPW = WTM / 32;
        float mx[GPW][NT][2];
#pragma unroll
        for (int g = 0; g < GPW; g++)
#pragma unroll
            for (int nt = 0; nt < NT; nt++) {
                mx[g][nt][0] = -FLT_MAX; mx[g][nt][1] = -FLT_MAX;
            }
#pragma unroll
        for (int mt = 0; mt < MT; mt++) {
            int gsel = mt / 2;
            int mrow = m0 + wm * WTM + mt * 16 + grp;
#pragma unroll
            for (int nt = 0; nt < NT; nt++) {
                int n = n0 + wn * WTN + nt * 8 + tig * 2;
                float v0 = acc[mt][nt][0] + bias[n];
                float v1 = acc[mt][nt][1] + bias[n + 1];
                float v2 = acc[mt][nt][2] + bias[n];
                float v3 = acc[mt][nt][3] + bias[n + 1];
                if (ROUNDC) {
                    v0 = rnd_tf32(v0); v1 = rnd_tf32(v1);
                    v2 = rnd_tf32(v2); v3 = rnd_tf32(v3);
                }
                if (EMAX == 1) {
                    float2 o0; o0.x = v0; o0.y = v1;
                    float2 o1; o1.x = v2; o1.y = v3;
                    *(float2*)&C[(size_t)mrow * ldc + n] = o0;
                    *(float2*)&C[(size_t)(mrow + 8) * ldc + n] = o1;
                }
                mx[gsel][nt][0] = fmaxf(mx[gsel][nt][0], fmaxf(v0, v2));
                mx[gsel][nt][1] = fmaxf(mx[gsel][nt][1], fmaxf(v1, v3));
            }
        }
#pragma unroll
        for (int g = 0; g < GPW; g++) {
#pragma unroll
            for (int nt = 0; nt < NT; nt++)
#pragma unroll
                for (int c = 0; c < 2; c++) {
                    float v = mx[g][nt][c];
                    v = fmaxf(v, __shfl_xor_sync(0xffffffffu, v, 4));
                    v = fmaxf(v, __shfl_xor_sync(0xffffffffu, v, 8));
                    v = fmaxf(v, __shfl_xor_sync(0xffffffffu, v, 16));
                    mx[g][nt][c] = v;
                }
            if (lane < 4) {
                int grow = (m0 >> 5) + wm * GPW + g;
#pragma unroll
                for (int nt = 0; nt < NT; nt++) {
                    int n = n0 + wn * WTN + nt * 8 + tig * 2;
                    fgout[(size_t)grow * ldfg + n]     = mx[g][nt][0];
                    fgout[(size_t)grow * ldfg + n + 1] = mx[g][nt][1];
                }
            }
        }
    }
}

// ---------------------------------------------------------------------------
// Pre-round all GEMM weights to tf32 (RNA); pad xp_w/dt_w
// ---------------------------------------------------------------------------
constexpr int PW_N0 = 256 * 128;
constexpr int PW_N1 = 512 * 512;
constexpr int PW_N2 = 384 * 512;
constexpr int PW_N3 = 384 * 128;
constexpr int PW_N4 = cNL * 1536 * 384;
constexpr int PW_N5 = cNL * 384 * 768;
constexpr int PW_N6 = cNL * 64 * cDI;
constexpr int PW_N7 = cNL * cDI * 32;
constexpr int PW_O1 = PW_N0;
constexpr int PW_O2 = PW_O1 + PW_N1;
constexpr int PW_O3 = PW_O2 + PW_N2;
constexpr int PW_O4 = PW_O3 + PW_N3;
constexpr int PW_O5 = PW_O4 + PW_N4;
constexpr int PW_O6 = PW_O5 + PW_N5;
constexpr int PW_O7 = PW_O6 + PW_N6;
constexpr int PW_TOT = PW_O7 + PW_N7;

__global__ void prep_weights(const float* __restrict__ e1w2,
                             const float* __restrict__ e2w1,
                             const float* __restrict__ e2w2,
                             const float* __restrict__ pw2,
                             const float* __restrict__ in_w,
                             const float* __restrict__ out_w,
                             const float* __restrict__ xp_w,
                             const float* __restrict__ dt_w) {
    int idx = blockIdx.x * 256 + threadIdx.x;
    if (idx >= PW_TOT) return;
    float v; float* dst;
    if (idx < PW_O1)      { v = e1w2[idx];          dst = g_we1w2 + idx; }
    else if (idx < PW_O2) { v = e2w1[idx - PW_O1];  dst = g_we2w1 + (idx - PW_O1); }
    else if (idx < PW_O3) { v = e2w2[idx - PW_O2];  dst = g_we2w2 + (idx - PW_O2); }
    else if (idx < PW_O4) { v = pw2[idx - PW_O3];   dst = g_wpw2 + (idx - PW_O3); }
    else if (idx < PW_O5) { v = in_w[idx - PW_O4];  dst = g_winw + (idx - PW_O4); }
    else if (idx < PW_O6) { v = out_w[idx - PW_O5]; dst = g_woutw + (idx - PW_O5); }
    else if (idx < PW_O7) {
        int j = idx - PW_O6;
        int l = j / (64 * cDI);
        int r = (j / cDI) % 64;
        int k = j % cDI;
        v = (r < 56) ? xp_w[((size_t)l * 56 + r) * cDI + k] : 0.f;
        dst = g_xpw + j;
    } else {
        int j = idx - PW_O7;
        int l = j / (cDI * 32);
        int d = (j / 32) % cDI;
        int k = j % 32;
        v = (k < 24) ? dt_w[((size_t)l * cDI + d) * cDTR + k] : 0.f;
        dst = g_dtw + j;
    }
    *dst = __uint_as_float(cvt_tf32(v));
}

// ---------------------------------------------------------------------------
// FPS
// ---------------------------------------------------------------------------
__global__ void fps_kernel(const float* __restrict__ xyz) {
    int b = blockIdx.x;
    __shared__ float px[cN], py[cN], pz[cN], dmin[cN];
    __shared__ float wv[8];
    __shared__ int   wi[8];
    __shared__ int   s_cur;
    int tid = threadIdx.x;
    int wid = tid >> 5, lane = tid & 31;
    for (int i = tid; i < cN; i += 256) {
        px[i] = xyz[(b * cN + i) * 3 + 0];
        py[i] = xyz[(b * cN + i) * 3 + 1];
        pz[i] = xyz[(b * cN + i) * 3 + 2];
        dmin[i] = 1e10f;
    }
    __syncthreads();
    int cur = 0;
    for (int g = 0; g < cG; g++) {
        float cx = px[cur], cy = py[cur], cz = pz[cur];
        if (tid == 0) {
            g_center[(b * cG + g) * 3 + 0] = cx;
            g_center[(b * cG + g) * 3 + 1] = cy;
            g_center[(b * cG + g) * 3 + 2] = cz;
        }
        float bv = -1.f; int bi = 0x7fffffff;
        for (int i = tid; i < cN; i += 256) {
            float dx = __fsub_rn(px[i], cx);
            float dy = __fsub_rn(py[i], cy);
            float dz = __fsub_rn(pz[i], cz);
            float dd = __fadd_rn(__fadd_rn(__fmul_rn(dx, dx), __fmul_rn(dy, dy)),
                                 __fmul_rn(dz, dz));
            float dm = fminf(dmin[i], dd);
            dmin[i] = dm;
            if (dm > bv) { bv = dm; bi = i; }
        }
#pragma unroll
        for (int off = 16; off > 0; off >>= 1) {
            float ov = __shfl_xor_sync(0xffffffffu, bv, off);
            int oi = __shfl_xor_sync(0xffffffffu, bi, off);
            if (ov > bv || (ov == bv && oi < bi)) { bv = ov; bi = oi; }
        }
        if (lane == 0) { wv[wid] = bv; wi[wid] = bi; }
        __syncthreads();
        if (tid < 8) {
            bv = wv[tid]; bi = wi[tid];
#pragma unroll
            for (int off = 4; off > 0; off >>= 1) {
                float ov = __shfl_xor_sync(0xffu, bv, off);
                int oi = __shfl_xor_sync(0xffu, bi, off);
                if (ov > bv || (ov == bv && oi < bi)) { bv = ov; bi = oi; }
            }
            if (tid == 0) s_cur = bi;
        }
        __syncthreads();
        cur = s_cur;
    }
}

// ---------------------------------------------------------------------------
// KNN
// ---------------------------------------------------------------------------
__global__ void knn_kernel(const float* __restrict__ xyz) {
    int bg = blockIdx.x;
    int b = bg >> 7;
    __shared__ float d2s[cN];
    __shared__ float wv[8];
    __shared__ int   wi[8];
    __shared__ int   s_idx;
    int tid = threadIdx.x;
    int wid = tid >> 5, lane = tid & 31;
    float cx = g_center[bg * 3 + 0], cy = g_center[bg * 3 + 1], cz = g_center[bg * 3 + 2];
    const float* P = xyz + (size_t)b * cN * 3;
    for (int i = tid; i < cN; i += 256) {
        float dx = __fsub_rn(cx, P[i * 3 + 0]);
        float dy = __fsub_rn(cy, P[i * 3 + 1]);
        float dz = __fsub_rn(cz, P[i * 3 + 2]);
        d2s[i] = __fadd_rn(__fadd_rn(__fmul_rn(dx, dx), __fmul_rn(dy, dy)),
                           __fmul_rn(dz, dz));
    }
    __syncthreads();
    for (int m = 0; m < cM; m++) {
        float bv = FLT_MAX; int bi = 0x7fffffff;
        for (int i = tid; i < cN; i += 256) {
            float v = d2s[i];
            if (v < bv) { bv = v; bi = i; }
        }
#pragma unroll
        for (int off = 16; off > 0; off >>= 1) {
            float ov = __shfl_xor_sync(0xffffffffu, bv, off);
            int oi = __shfl_xor_sync(0xffffffffu, bi, off);
            if (ov < bv || (ov == bv && oi < bi)) { bv = ov; bi = oi; }
        }
        if (lane == 0) { wv[wid] = bv; wi[wid] = bi; }
        __syncthreads();
        if (tid < 8) {
            bv = wv[tid]; bi = wi[tid];
#pragma unroll
            for (int off = 4; off > 0; off >>= 1) {
                float ov = __shfl_xor_sync(0xffu, bv, off);
                int oi = __shfl_xor_sync(0xffu, bi, off);
                if (ov < bv || (ov == bv && oi < bi)) { bv = ov; bi = oi; }
            }
            if (tid == 0) s_idx = bi;
        }
        __syncthreads();
        int idx = s_idx;
        if (tid < 3) {
            float c = (tid == 0) ? cx : ((tid == 1) ? cy : cz);
            g_nb[((size_t)bg * cM + m) * 3 + tid] = __fsub_rn(P[idx * 3 + tid], c);
        }
        if (tid == 0) d2s[idx] = FLT_MAX;
        __syncthreads();
    }
}

// ---------------------------------------------------------------------------
// Residual accumulate + LayerNorm (xln rounded to tf32; res stays fp32)
// ---------------------------------------------------------------------------
__device__ __forceinline__ float block_sum_128(float v, float* sm) {
    int tid = threadIdx.x;
    sm[tid] = v; __syncthreads();
    for (int s = 64; s > 0; s >>= 1) {
        if (tid < s) sm[tid] += sm[tid + s];
        __syncthreads();
    }
    float r = sm[0]; __syncthreads();
    return r;
}

__global__ void resln_kernel(const float* __restrict__ w, const float* __restrict__ b,
                             int first) {
    __shared__ float sm[128];
    int t = blockIdx.x;
    float v[3];
#pragma unroll
    for (int j = 0; j < 3; j++) {
        int c = threadIdx.x + j * 128;
        float r = g_h[t * 384 + c];
        if (!first) r += g_res[t * 384 + c];
        g_res[t * 384 + c] = r;
        v[j] = r;
    }
    float mean = block_sum_128(v[0] + v[1] + v[2], sm) * (1.0f / 384.0f);
    float sq = 0.f;
#pragma unroll
    for (int j = 0; j < 3; j++) { float d = v[j] - mean; sq += d * d; }
    float var = block_sum_128(sq, sm) * (1.0f / 384.0f);
    float inv = rsqrtf(var + 1e-5f);
#pragma unroll
    for (int j = 0; j < 3; j++) {
        int c = threadIdx.x + j * 128;
        g_xln[t * 384 + c] = rnd_tf32((v[j] - mean) * inv * w[c] + b[c]);
    }
}

__global__ void final_kernel(const float* __restrict__ w, const float* __restrict__ b,
                             float* __restrict__ out) {
    __shared__ float sm[128];
    int t = blockIdx.x;
    float v[3];
#pragma unroll
    for (int j = 0; j < 3; j++) {
        int c = threadIdx.x + j * 128;
        v[j] = g_h[t * 384 + c] + g_res[t * 384 + c];
    }
    float mean = block_sum_128(v[0] + v[1] + v[2], sm) * (1.0f / 384.0f);
    float sq = 0.f;
#pragma unroll
    for (int j = 0; j < 3; j++) { float d = v[j] - mean; sq += d * d; }
    float var = block_sum_128(sq, sm) * (1.0f / 384.0f);
    float inv = rsqrtf(var + 1e-5f);
#pragma unroll
    for (int j = 0; j < 3; j++) {
        int c = threadIdx.x + j * 128;
        out[t * 384 + c] = (v[j] - mean) * inv * w[c] + b[c];
    }
}

// ---------------------------------------------------------------------------
// Depthwise causal conv (DC=4) + bias + silu (output rounded to tf32)
// ---------------------------------------------------------------------------
__global__ void conv_kernel(const float* __restrict__ cw, const float* __restrict__ cb) {
    int idx = blockIdx.x * blockDim.x + threadIdx.x;
    if (idx >= cTOK * cDI) return;
    int t = idx / cDI, d = idx % cDI;
    int l = t & 127;
    int tbase = t - l;
    float acc = cb[d];
#pragma unroll
    for (int k = 0; k < 4; k++) {
        int lk = l - 3 + k;
        if (lk >= 0)
            acc += g_xz[(size_t)(tbase + lk) * 1536 + d] * cw[d * 4 + k];
    }
    float sig = 1.0f / (1.0f + __expf(-acc));
    g_xc[idx] = rnd_tf32(acc * sig);
}

// ---------------------------------------------------------------------------
// Selective scan v4: dt computed inline (dbl[:24] @ dtw row + softplus),
// full dbl64 rows staged in smem; one thread per (b,d); q-power fast path.
// ---------------------------------------------------------------------------
template<bool FAST>
__device__ __forceinline__ void scan_body(
    int b, int d, float a0, const float* a, float Dpd,
    const float* dtr, float dtbd) {
    extern __shared__ float sD[];   // [128][64]
    float h[16];
#pragma unroll
    for (int s = 0; s < 16; s++) h[s] = 0.f;

    const float* pxc = g_xc + (size_t)b * 128 * cDI + d;
    const float* pz  = g_xz + (size_t)b * 128 * 1536 + cDI + d;
    float* pu = g_u + (size_t)b * 128 * cDI + d;

    for (int t = 0; t < 128; t++) {
        const float* Dt = sD + t * 64;
        float acc = dtbd;
#pragma unroll
        for (int r = 0; r < 24; r++) acc += Dt[r] * dtr[r];
        float dt = fmaxf(acc, 0.f) + log1pf(__expf(-fabsf(acc)));
        float xin = pxc[(size_t)t * cDI];
        float u = dt * xin;
        float p[16];
        if (FAST) {
            float q = __expf(dt * a0);
            float q2 = q * q, q4 = q2 * q2, q8 = q4 * q4;
            p[0] = q;        p[1] = q2;       p[2] = q2 * q;   p[3] = q4;
            p[4] = q4 * q;   p[5] = q4 * q2;  p[6] = p[5] * q; p[7] = q8;
            p[8] = q8 * q;   p[9] = q8 * q2;  p[10] = p[9] * q;
            p[11] = q8 * q4; p[12] = p[11] * q; p[13] = p[11] * q2;
            p[14] = p[13] * q; p[15] = q8 * q8;
        } else {
#pragma unroll
            for (int s = 0; s < 16; s++) p[s] = __expf(dt * a[s]);
        }
        float y = 0.f;
#pragma unroll
        for (int s = 0; s < 16; s++) {
            h[s] = p[s] * h[s] + u * Dt[24 + s];
            y += h[s] * Dt[40 + s];
        }
        y += Dpd * xin;
        float z = pz[(size_t)t * 1536];
        float sz = z / (1.0f + __expf(-z));
        pu[(size_t)t * cDI] = rnd_tf32(y * sz);
    }
}

__global__ void __launch_bounds__(256)
scan_kernel(const float* __restrict__ Alog, const float* __restrict__ Dp,
            const float* __restrict__ dtw, const float* __restrict__ dtb) {
    extern __shared__ float sD[];   // 128*64 floats = 32KB
    int tid = threadIdx.x;
    int b = blockIdx.y;
    int d = blockIdx.x * 256 + tid;

    for (int i = tid; i < 128 * 16; i += 256)
        ((float4*)sD)[i] = ((const float4*)g_dbl64)[(size_t)b * 128 * 16 + i];
    __syncthreads();

    float dtr[24];
#pragma unroll
    for (int r = 0; r < 24; r++) dtr[r] = dtw[d * 32 + r];
    float dtbd = dtb[d];

    float a[16];
    bool fast = true;
#pragma unroll
    for (int s = 0; s < 16; s++) a[s] = -expf(Alog[d * 16 + s]);
    float a0 = a[0];
#pragma unroll
    for (int s = 1; s < 16; s++) {
        float ideal = (float)(s + 1) * a0;
        if (fabsf(a[s] - ideal) > 1e-4f * fabsf(ideal)) fast = false;
    }
    float Dpd = Dp[d];

    if (fast) scan_body<true>(b, d, a0, a, Dpd, dtr, dtbd);
    else      scan_body<false>(b, d, a0, a, Dpd, dtr, dtbd);
}

// ---------------------------------------------------------------------------
// Host-side launch sequence
// ---------------------------------------------------------------------------
extern "C" void kernel_launch(void* const* d_in, const int* in_sizes, int n_in,
                              void* d_out, int out_size) {
    const float* xyz   = (const float*)d_in[0];
    const float* e1w1  = (const float*)d_in[1];
    const float* e1b1  = (const float*)d_in[2];
    const float* bn1g  = (const float*)d_in[3];
    const float* bn1b  = (const float*)d_in[4];
    const float* e1w2  = (const float*)d_in[5];
    const float* e1b2  = (const float*)d_in[6];
    const float* e2w1  = (const float*)d_in[7];
    const float* e2b1  = (const float*)d_in[8];
    const float* bn2g  = (const float*)d_in[9];
    const float* bn2b  = (const float*)d_in[10];
    const float* e2w2  = (const float*)d_in[11];
    const float* e2b2  = (const float*)d_in[12];
    const float* pw1   = (const float*)d_in[13];
    const float* pb1   = (const float*)d_in[14];
    const float* pw2   = (const float*)d_in[15];
    const float* pb2   = (const float*)d_in[16];
    const float* in_w  = (const float*)d_in[17];
    const float* convw = (const float*)d_in[18];
    const float* convb = (const float*)d_in[19];
    const float* xp_w  = (const float*)d_in[20];
    const float* dt_w  = (const float*)d_in[21];
    const float* dt_b  = (const float*)d_in[22];
    const float* A_log = (const float*)d_in[23];
    const float* Dp    = (const float*)d_in[24];
    const float* out_w = (const float*)d_in[25];
    const float* lnw   = (const float*)d_in[26];
    const float* lnb   = (const float*)d_in[27];
    const float* fnw   = (const float*)d_in[28];
    const float* fnb   = (const float*)d_in[29];
    float* out = (float*)d_out;

    float *pnb, *pf2, *pfg, *pf3, *pxln, *pxz, *pxc, *pu, *ph, *pcenter,
          *pdbl, *pxpw, *pdtw;
    float *pwe1w2, *pwe2w1, *pwe2w2, *pwpw2, *pwinw, *pwoutw;
    cudaGetSymbolAddress((void**)&pnb,  g_nb);
    cudaGetSymbolAddress((void**)&pf2,  g_f2);
    cudaGetSymbolAddress((void**)&pfg,  g_fg);
    cudaGetSymbolAddress((void**)&pf3,  g_f3);
    cudaGetSymbolAddress((void**)&pxln, g_xln);
    cudaGetSymbolAddress((void**)&pxz,  g_xz);
    cudaGetSymbolAddress((void**)&pxc,  g_xc);
    cudaGetSymbolAddress((void**)&pu,   g_u);
    cudaGetSymbolAddress((void**)&ph,   g_h);
    cudaGetSymbolAddress((void**)&pcenter, g_center);
    cudaGetSymbolAddress((void**)&pdbl, g_dbl64);
    cudaGetSymbolAddress((void**)&pxpw, g_xpw);
    cudaGetSymbolAddress((void**)&pdtw, g_dtw);
    cudaGetSymbolAddress((void**)&pwe1w2, g_we1w2);
    cudaGetSymbolAddress((void**)&pwe2w1, g_we2w1);
    cudaGetSymbolAddress((void**)&pwe2w2, g_we2w2);
    cudaGetSymbolAddress((void**)&pwpw2,  g_wpw2);
    cudaGetSymbolAddress((void**)&pwinw,  g_winw);
    cudaGetSymbolAddress((void**)&pwoutw, g_woutw);

    // ---- weight prep (pre-round to tf32) ----
    prep_weights<<<(PW_TOT + 255) / 256, 256>>>(
        e1w2, e2w1, e2w2, pw2, in_w, out_w, xp_w, dt_w);

    // ---- grouping ----
    fps_kernel<<<cB, 256>>>(xyz);
    knn_kernel<<<cTOK, 256>>>(xyz);

    // ---- encoder (128x128 tiles, 8 warps: WGM=4 x WGN=2) ----
    tc2<128, 128, 4, 2, 0, 2, 1, 1><<<dim3(cPTS / 128, 2), 256>>>(
        pnb, pwe1w2, e1b2, bn1g, bn1b, pf2, 128, 3, 128, 256,
        e1w1, e1b1, pfg, 256);
    tc2<128, 128, 4, 2, 1, 1, 0, 1><<<dim3(cPTS / 128, 4), 256>>>(
        pf2, pwe2w1, e2b1, bn2g, bn2b, pf3, 512, 256, 512, 512,
        pfg, nullptr, nullptr, 0);
    tc2<128, 128, 4, 2, 0, 0, 2, 0><<<dim3(cPTS / 128, 3), 256>>>(
        pf3, pwe2w2, e2b2, nullptr, nullptr, nullptr, 512, 512, 512, 384,
        nullptr, nullptr, ph, 384);

    // ---- positional MLP (pos1 fused into pos2 A-loader) ----
    tc2<64, 128, 2, 2, 3, 4, 0, 0><<<dim3(cTOK / 64, 3), 128>>>(
        pcenter, pwpw2, pb2, nullptr, nullptr, ph, 128, 3, 128, 384,
        pw1, pb1, nullptr, 0);

    // ---- mamba layers ----
    constexpr int SCAN_SMEM = 128 * 64 * sizeof(float);   // 32KB
    for (int i = 0; i < cNL; i++) {
        const float* in_w_i  = pwinw  + (size_t)i * 1536 * 384;
        const float* cw_i    = convw  + (size_t)i * cDI * 4;
        const float* cb_i    = convb  + (size_t)i * cDI;
        const float* dtb_i   = dt_b   + (size_t)i * cDI;
        const float* Al_i    = A_log  + (size_t)i * cDI * cDS;
        const float* Dp_i    = Dp     + (size_t)i * cDI;
        const float* ow_i    = pwoutw + (size_t)i * 384 * 768;
        const float* lnw_i   = lnw    + (size_t)i * cDM;
        const float* lnb_i   = lnb    + (size_t)i * cDM;
        const float* xpw_i   = pxpw   + (size_t)i * 64 * cDI;
        const float* dtw_i   = pdtw   + (size_t)i * cDI * 32;

        resln_kernel<<<cTOK, 128>>>(lnw_i, lnb_i, i == 0 ? 1 : 0);
        // in-proj: (2048,384)@(1536,384)^T
        tc2<64, 128, 2, 2, 0, 0, 0, 1><<<dim3(cTOK / 64, 12), 128>>>(
            pxln, in_w_i, nullptr, nullptr, nullptr, pxz, 384, 384, 384, 1536,
            nullptr, nullptr, nullptr, 0);
        conv_kernel<<<(cTOK * cDI + 255) / 256, 256>>>(cw_i, cb_i);
        // xp: (2048,768)@(64,768)^T -> g_dbl64
        tc2<64, 64, 2, 1, 0, 0, 0, 1><<<dim3(cTOK / 64, 1), 64>>>(
            pxc, xpw_i, nullptr, nullptr, nullptr, pdbl, 768, 768, 768, 64,
            nullptr, nullptr, nullptr, 0);
        // scan with dt fused (dbl[:24] @ dtw + softplus computed inline)
        scan_kernel<<<dim3(cDI / 256, cB), 256, SCAN_SMEM>>>(
            Al_i, Dp_i, dtw_i, dtb_i);
        // out-proj: (2048,768)@(384,768)^T
        tc2<64, 128, 2, 2, 0, 0, 0, 0><<<dim3(cTOK / 64, 3), 128>>>(
            pu, ow_i, nullptr, nullptr, nullptr, ph, 768, 768, 768, 384,
            nullptr, nullptr, nullptr, 0);
    }

    // ---- final LN ----
    final_kernel<<<cTOK, 128>>>(fnw, fnb, out);
}

// round 15
// speedup vs baseline: 2.1756x; 1.0178x over previous
#include <cuda_runtime.h>
#include <math.h>
#include <float.h>

// ---------------------------------------------------------------------------
// Problem constants
// ---------------------------------------------------------------------------
constexpr int cB   = 16;
constexpr int cN   = 2048;
constexpr int cG   = 128;
constexpr int cM   = 32;
constexpr int cDM  = 384;
constexpr int cNL  = 12;
constexpr int cDI  = 768;
constexpr int cDS  = 16;
constexpr int cDTR = 24;
constexpr int cTOK = cB * cG;        // 2048 tokens
constexpr int cPTS = cTOK * cM;      // 65536 points

// ---------------------------------------------------------------------------
// Scratch (device globals; no dynamic allocation allowed)
// ---------------------------------------------------------------------------
__device__ __align__(16) float g_center[cTOK * 3];
__device__ __align__(16) float g_nb[cPTS * 3];
__device__ __align__(16) float g_f2[(size_t)cPTS * 256];
__device__ __align__(16) float g_fg[cTOK * 256];
__device__ __align__(16) float g_f3[(size_t)cPTS * 512];
__device__ __align__(16) float g_h[cTOK * cDM];
__device__ __align__(16) float g_res[cTOK * cDM];
__device__ __align__(16) float g_xln[cTOK * cDM];
__device__ __align__(16) float g_xz[(size_t)cTOK * 2 * cDI];
__device__ __align__(16) float g_xc[(size_t)cTOK * cDI];
__device__ __align__(16) float g_dbl64[cTOK * 64];
__device__ __align__(16) float g_u[(size_t)cTOK * cDI];
// pre-rounded (tf32/RNA) weights
__device__ __align__(16) float g_xpw[cNL * 64 * cDI];
__device__ __align__(16) float g_dtw[cNL * cDI * 32];
__device__ __align__(16) float g_we1w2[256 * 128];
__device__ __align__(16) float g_we2w1[512 * 512];
__device__ __align__(16) float g_we2w2[384 * 512];
__device__ __align__(16) float g_wpw2[384 * 128];
__device__ __align__(16) float g_winw[(size_t)cNL * 1536 * 384];
__device__ __align__(16) float g_woutw[(size_t)cNL * 384 * 768];

using u32 = unsigned int;

__device__ __forceinline__ u32 cvt_tf32(float x) {
    u32 r;
    asm("cvt.rna.tf32.f32 %0, %1;" : "=r"(r) : "f"(x));
    return r;
}
__device__ __forceinline__ float rnd_tf32(float x) {
    return __uint_as_float(cvt_tf32(x));
}

__device__ __forceinline__ u32 smem_u32(const void* p) {
    u32 a;
    asm("{ .reg .u64 t; cvta.to.shared.u64 t, %1; cvt.u32.u64 %0, t; }"
        : "=r"(a) : "l"(p));
    return a;
}

__device__ __forceinline__ void ldsm4(u32& r0, u32& r1, u32& r2, u32& r3, u32 addr) {
    asm volatile("ldmatrix.sync.aligned.m8n8.x4.shared.b16 {%0,%1,%2,%3}, [%4];"
                 : "=r"(r0), "=r"(r1), "=r"(r2), "=r"(r3) : "r"(addr));
}

__device__ __forceinline__ void cpasync16(u32 dst, const void* src) {
    asm volatile("cp.async.cg.shared.global [%0], [%1], 16;"
                 :: "r"(dst), "l"(src) : "memory");
}
#define CP_COMMIT() asm volatile("cp.async.commit_group;" ::: "memory")
#define CP_WAIT0()  asm volatile("cp.async.wait_group 0;" ::: "memory")
#define CP_WAIT1()  asm volatile("cp.async.wait_group 1;" ::: "memory")

__device__ __forceinline__ void mma_tf32(float* c, u32 a0, u32 a1, u32 a2, u32 a3,
                                         u32 b0, u32 b1) {
    asm volatile(
        "mma.sync.aligned.m16n8k8.row.col.f32.tf32.tf32.f32 "
        "{%0,%1,%2,%3}, {%4,%5,%6,%7}, {%8,%9}, {%0,%1,%2,%3};"
        : "+f"(c[0]), "+f"(c[1]), "+f"(c[2]), "+f"(c[3])
        : "r"(a0), "r"(a1), "r"(a2), "r"(a3), "r"(b0), "r"(b1));
}

// ---------------------------------------------------------------------------
// Generic tf32 tensor-core GEMM: C = epi(A' @ W^T).
//   Smem row-major [row][k] (stride 20 floats), ldmatrix.x4.b16 fragments,
//   3-stage cp.async pipeline (wait_group 1 keeps one group in flight).
//   Inputs must be pre-rounded to tf32 (RNA) by producers.
//   EPI 0:+bias(opt). 1: relu(bn(.+bias)). 2: softplus(.+bias). 3: C+=.+bias
//   MODEA 0: A'=A. 1: cols[0,256) from aux1[row>>5][k].
//         2: relu(bn1(nb@w1^T+b1)) on the fly. 4: gelu(center@pw1^T+pb1).
//   EMAX 0: normal. 1: write C AND 32-row group max. 2: ONLY group max.
//   ROUNDC 1: RNA-round outputs (consumer is a GEMM).
// ---------------------------------------------------------------------------
template<int BM, int BN, int WGM, int WGN, int EPI, int MODEA, int EMAX, int ROUNDC>
__global__ void __launch_bounds__(WGM * WGN * 32)
tc2(const float* __restrict__ A, const float* __restrict__ W,
    const float* __restrict__ bias, const float* __restrict__ p1,
    const float* __restrict__ p2, float* __restrict__ C,
    int K, int lda, int ldw, int ldc,
    const float* __restrict__ aux1, const float* __restrict__ aux2,
    float* __restrict__ fgout, int ldfg)
{
    constexpr int THREADS = WGM * WGN * 32;
    constexpr int WTM = BM / WGM, WTN = BN / WGN;
    constexpr int MT = WTM / 16, NT = WTN / 8;
    constexpr int NP = NT / 2;
    constexpr int KS = 20;
    constexpr int A4 = (BM * 16) / (THREADS * 4);
    constexpr int W4 = (BN * 16) / (THREADS * 4);
    static_assert(EMAX == 0 || (WTM % 32) == 0, "EMAX needs WTM%32==0");
    static_assert(NT % 2 == 0, "NT must be even");

    __shared__ __align__(16) float As[3][BM][KS];
    __shared__ __align__(16) float Ws[3][BN][KS];

    const int tid = threadIdx.x;
    const int wid = tid >> 5, lane = tid & 31;
    const int grp = lane >> 2, tig = lane & 3;
    const int wm = wid % WGM, wn = wid / WGM;
    const int m0 = blockIdx.x * BM, n0 = blockIdx.y * BN;
    const float bnscale = rsqrtf(1.0f + 1e-5f);

    const u32 asBase = smem_u32(&As[0][0][0]);
    const u32 wsBase = smem_u32(&Ws[0][0][0]);
    constexpr u32 ABUF = BM * KS * 4;
    constexpr u32 WBUF = BN * KS * 4;

    u32 aOff[MT], bOff[NP];
    {
        int l7 = lane & 7;
        int aRow = ((lane >> 3) & 1) * 8;
        int aCol = (lane >> 4) * 16;
#pragma unroll
        for (int mt = 0; mt < MT; mt++) {
            int row = wm * WTM + mt * 16 + aRow + l7;
            aOff[mt] = (u32)(row * KS * 4 + aCol);
        }
        int bRow = (lane >> 4) * 8;
        int bCol = ((lane >> 3) & 1) * 16;
#pragma unroll
        for (int p = 0; p < NP; p++) {
            int row = wn * WTN + p * 16 + bRow + l7;
            bOff[p] = (u32)(row * KS * 4 + bCol);
        }
    }

    float acc[MT][NT][4];
#pragma unroll
    for (int mt = 0; mt < MT; mt++)
#pragma unroll
        for (int nt = 0; nt < NT; nt++)
#pragma unroll
            for (int r = 0; r < 4; r++) acc[mt][nt][r] = 0.f;

    float nbr[(MODEA >= 2) ? A4 : 1][3];
    if (MODEA >= 2) {
#pragma unroll
        for (int v = 0; v < A4; v++) {
            int row = (tid + v * THREADS) >> 2;
            nbr[v][0] = A[(size_t)(m0 + row) * 3 + 0];
            nbr[v][1] = A[(size_t)(m0 + row) * 3 + 1];
            nbr[v][2] = A[(size_t)(m0 + row) * 3 + 2];
        }
    }

    auto issueAW = [&](int kc, int bufSel) {
        const u32 aB = asBase + (u32)bufSel * ABUF;
        const u32 wB = wsBase + (u32)bufSel * WBUF;
        if (MODEA <= 1) {
#pragma unroll
            for (int v = 0; v < A4; v++) {
                int s = tid + v * THREADS;
                int row = s >> 2;
                int kq = (s & 3) * 4;
                int k = kc + kq;
                const float* src;
                if (MODEA == 0) {
                    src = A + (size_t)(m0 + row) * lda + k;
                } else {
                    int r = m0 + row;
                    src = (k < 256)
                        ? (aux1 + ((size_t)(r >> 5)) * 256 + k)
                        : (A + (size_t)r * lda + (k - 256));
                }
                cpasync16(aB + (u32)((row * KS + kq) * 4), src);
            }
        } else {
#pragma unroll
            for (int v = 0; v < A4; v++) {
                int s = tid + v * THREADS;
                int row = s >> 2;
                int kq = (s & 3) * 4;
                int k = kc + kq;
                float out[4];
#pragma unroll
                for (int e = 0; e < 4; e++) {
                    int kk = k + e;
                    float val = nbr[v][0] * aux1[kk * 3 + 0]
                              + nbr[v][1] * aux1[kk * 3 + 1]
                              + nbr[v][2] * aux1[kk * 3 + 2] + aux2[kk];
                    if (MODEA == 2) {
                        val = val * (p1[kk] * bnscale) + p2[kk];
                        out[e] = fmaxf(val, 0.f);
                    } else {  // gelu (tanh approx)
                        float v3 = val * val * val;
                        out[e] = 0.5f * val *
                            (1.0f + tanhf(0.7978845608028654f *
                                          (val + 0.044715f * v3)));
                    }
                }
                uint4 o;
                o.x = cvt_tf32(out[0]); o.y = cvt_tf32(out[1]);
                o.z = cvt_tf32(out[2]); o.w = cvt_tf32(out[3]);
                *reinterpret_cast<uint4*>(&As[bufSel][row][kq]) = o;
            }
        }
#pragma unroll
        for (int v = 0; v < W4; v++) {
            int s = tid + v * THREADS;
            int row = s >> 2;
            int kq = (s & 3) * 4;
            cpasync16(wB + (u32)((row * KS + kq) * 4),
                      W + (size_t)(n0 + row) * ldw + kc + kq);
        }
        CP_COMMIT();
    };

    const int nIter = K >> 4;
    issueAW(0, 0);
    if (nIter > 1) {
        issueAW(16, 1);
        CP_WAIT1();
    } else {
        CP_WAIT0();
    }
    __syncthreads();

    for (int it = 0; it < nIter; it++) {
        if (it + 2 < nIter) issueAW((it + 2) << 4, (it + 2) % 3);
        const int buf = it % 3;
        const u32 aB = asBase + (u32)buf * ABUF;
        const u32 wB = wsBase + (u32)buf * WBUF;
#pragma unroll
        for (int ks = 0; ks < 2; ks++) {
            const u32 kb = (u32)(ks * 32);
            u32 af[MT][4];
#pragma unroll
            for (int mt = 0; mt < MT; mt++)
                ldsm4(af[mt][0], af[mt][1], af[mt][2], af[mt][3],
                      aB + aOff[mt] + kb);
            u32 bf[NT][2];
#pragma unroll
            for (int p = 0; p < NP; p++) {
                u32 r0, r1, r2, r3;
                ldsm4(r0, r1, r2, r3, wB + bOff[p] + kb);
                bf[2 * p][0] = r0;     bf[2 * p][1] = r1;
                bf[2 * p + 1][0] = r2; bf[2 * p + 1][1] = r3;
            }
#pragma unroll
            for (int mt = 0; mt < MT; mt++)
#pragma unroll
                for (int nt = 0; nt < NT; nt++)
                    mma_tf32(acc[mt][nt], af[mt][0], af[mt][1], af[mt][2], af[mt][3],
                             bf[nt][0], bf[nt][1]);
        }
        if (it + 1 < nIter) {
            if (it + 2 < nIter) { CP_WAIT1(); } else { CP_WAIT0(); }
            __syncthreads();
        }
    }

    if constexpr (EMAX == 0) {
        auto emit = [&](int mrow, int n, float v0, float v1) {
            if (EPI == 3) {
                C[(size_t)mrow * ldc + n]     += v0 + bias[n];
                C[(size_t)mrow * ldc + n + 1] += v1 + bias[n + 1];
                return;
            }
            if (EPI == 0) {
                if (bias) { v0 += bias[n]; v1 += bias[n + 1]; }
            } else if (EPI == 1) {
                v0 = fmaxf((v0 + bias[n]) * (p1[n] * bnscale) + p2[n], 0.f);
                v1 = fmaxf((v1 + bias[n + 1]) * (p1[n + 1] * bnscale) + p2[n + 1], 0.f);
            } else if (EPI == 2) {
                v0 += bias[n]; v1 += bias[n + 1];
                v0 = fmaxf(v0, 0.f) + log1pf(__expf(-fabsf(v0)));
                v1 = fmaxf(v1, 0.f) + log1pf(__expf(-fabsf(v1)));
            }
            if (ROUNDC) { v0 = rnd_tf32(v0); v1 = rnd_tf32(v1); }
            float2 o; o.x = v0; o.y = v1;
            *(float2*)&C[(size_t)mrow * ldc + n] = o;
        };
#pragma unroll
        for (int mt = 0; mt < MT; mt++) {
            int mrow = m0 + wm * WTM + mt * 16 + grp;
#pragma unroll
            for (int nt = 0; nt < NT; nt++) {
                int n = n0 + wn * WTN + nt * 8 + tig * 2;
                emit(mrow,     n, acc[mt][nt][0], acc[mt][nt][1]);
                emit(mrow + 8, n, acc[mt][nt][2], acc[mt][nt][3]);
            }
        }
    } else {
        constexpr int GPW = WTM / 32;
        float mx[GPW][NT][2];
#pragma unroll
        for (int g = 0; g < GPW; g++)
#pragma unroll
            for (int nt = 0; nt < NT; nt++) {
                mx[g][nt][0] = -FLT_MAX; mx[g][nt][1] = -FLT_MAX;
            }
#pragma unroll
        for (int mt = 0; mt < MT; mt++) {
            int gsel = mt / 2;
            int mrow = m0 + wm * WTM + mt * 16 + grp;
#pragma unroll
            for (int nt = 0; nt < NT; nt++) {
                int n = n0 + wn * WTN + nt * 8 + tig * 2;
                float v0 = acc[mt][nt][0] + bias[n];
                float v1 = acc[mt][nt][1] + bias[n + 1];
                float v2 = acc[mt][nt][2] + bias[n];
                float v3 = acc[mt][nt][3] + bias[n + 1];
                if (ROUNDC) {
                    v0 = rnd_tf32(v0); v1 = rnd_tf32(v1);
                    v2 = rnd_tf32(v2); v3 = rnd_tf32(v3);
                }
                if (EMAX == 1) {
                    float2 o0; o0.x = v0; o0.y = v1;
                    float2 o1; o1.x = v2; o1.y = v3;
                    *(float2*)&C[(size_t)mrow * ldc + n] = o0;
                    *(float2*)&C[(size_t)(mrow + 8) * ldc + n] = o1;
                }
                mx[gsel][nt][0] = fmaxf(mx[gsel][nt][0], fmaxf(v0, v2));
                mx[gsel][nt][1] = fmaxf(mx[gsel][nt][1], fmaxf(v1, v3));
            }
        }
#pragma unroll
        for (int g = 0; g < GPW; g++) {
#pragma unroll
            for (int nt = 0; nt < NT; nt++)
#pragma unroll
                for (int c = 0; c < 2; c++) {
                    float v = mx[g][nt][c];
                    v = fmaxf(v, __shfl_xor_sync(0xffffffffu, v, 4));
                    v = fmaxf(v, __shfl_xor_sync(0xffffffffu, v, 8));
                    v = fmaxf(v, __shfl_xor_sync(0xffffffffu, v, 16));
                    mx[g][nt][c] = v;
                }
            if (lane < 4) {
                int grow = (m0 >> 5) + wm * GPW + g;
#pragma unroll
                for (int nt = 0; nt < NT; nt++) {
                    int n = n0 + wn * WTN + nt * 8 + tig * 2;
                    fgout[(size_t)grow * ldfg + n]     = mx[g][nt][0];
                    fgout[(size_t)grow * ldfg + n + 1] = mx[g][nt][1];
                }
            }
        }
    }
}

// ---------------------------------------------------------------------------
// Pre-round all GEMM weights to tf32 (RNA); pad xp_w/dt_w
// ---------------------------------------------------------------------------
constexpr int PW_N0 = 256 * 128;
constexpr int PW_N1 = 512 * 512;
constexpr int PW_N2 = 384 * 512;
constexpr int PW_N3 = 384 * 128;
constexpr int PW_N4 = cNL * 1536 * 384;
constexpr int PW_N5 = cNL * 384 * 768;
constexpr int PW_N6 = cNL * 64 * cDI;
constexpr int PW_N7 = cNL * cDI * 32;
constexpr int PW_O1 = PW_N0;
constexpr int PW_O2 = PW_O1 + PW_N1;
constexpr int PW_O3 = PW_O2 + PW_N2;
constexpr int PW_O4 = PW_O3 + PW_N3;
constexpr int PW_O5 = PW_O4 + PW_N4;
constexpr int PW_O6 = PW_O5 + PW_N5;
constexpr int PW_O7 = PW_O6 + PW_N6;
constexpr int PW_TOT = PW_O7 + PW_N7;

__global__ void prep_weights(const float* __restrict__ e1w2,
                             const float* __restrict__ e2w1,
                             const float* __restrict__ e2w2,
                             const float* __restrict__ pw2,
                             const float* __restrict__ in_w,
                             const float* __restrict__ out_w,
                             const float* __restrict__ xp_w,
                             const float* __restrict__ dt_w) {
    int idx = blockIdx.x * 256 + threadIdx.x;
    if (idx >= PW_TOT) return;
    float v; float* dst;
    if (idx < PW_O1)      { v = e1w2[idx];          dst = g_we1w2 + idx; }
    else if (idx < PW_O2) { v = e2w1[idx - PW_O1];  dst = g_we2w1 + (idx - PW_O1); }
    else if (idx < PW_O3) { v = e2w2[idx - PW_O2];  dst = g_we2w2 + (idx - PW_O2); }
    else if (idx < PW_O4) { v = pw2[idx - PW_O3];   dst = g_wpw2 + (idx - PW_O3); }
    else if (idx < PW_O5) { v = in_w[idx - PW_O4];  dst = g_winw + (idx - PW_O4); }
    else if (idx < PW_O6) { v = out_w[idx - PW_O5]; dst = g_woutw + (idx - PW_O5); }
    else if (idx < PW_O7) {
        int j = idx - PW_O6;
        int l = j / (64 * cDI);
        int r = (j / cDI) % 64;
        int k = j % cDI;
        v = (r < 56) ? xp_w[((size_t)l * 56 + r) * cDI + k] : 0.f;
        dst = g_xpw + j;
    } else {
        int j = idx - PW_O7;
        int l = j / (cDI * 32);
        int d = (j / 32) % cDI;
        int k = j % 32;
        v = (k < 24) ? dt_w[((size_t)l * cDI + d) * cDTR + k] : 0.f;
        dst = g_dtw + j;
    }
    *dst = __uint_as_float(cvt_tf32(v));
}

// ---------------------------------------------------------------------------
// FPS
// ---------------------------------------------------------------------------
__global__ void fps_kernel(const float* __restrict__ xyz) {
    int b = blockIdx.x;
    __shared__ float px[cN], py[cN], pz[cN], dmin[cN];
    __shared__ float wv[8];
    __shared__ int   wi[8];
    __shared__ int   s_cur;
    int tid = threadIdx.x;
    int wid = tid >> 5, lane = tid & 31;
    for (int i = tid; i < cN; i += 256) {
        px[i] = xyz[(b * cN + i) * 3 + 0];
        py[i] = xyz[(b * cN + i) * 3 + 1];
        pz[i] = xyz[(b * cN + i) * 3 + 2];
        dmin[i] = 1e10f;
    }
    __syncthreads();
    int cur = 0;
    for (int g = 0; g < cG; g++) {
        float cx = px[cur], cy = py[cur], cz = pz[cur];
        if (tid == 0) {
            g_center[(b * cG + g) * 3 + 0] = cx;
            g_center[(b * cG + g) * 3 + 1] = cy;
            g_center[(b * cG + g) * 3 + 2] = cz;
        }
        float bv = -1.f; int bi = 0x7fffffff;
        for (int i = tid; i < cN; i += 256) {
            float dx = __fsub_rn(px[i], cx);
            float dy = __fsub_rn(py[i], cy);
            float dz = __fsub_rn(pz[i], cz);
            float dd = __fadd_rn(__fadd_rn(__fmul_rn(dx, dx), __fmul_rn(dy, dy)),
                                 __fmul_rn(dz, dz));
            float dm = fminf(dmin[i], dd);
            dmin[i] = dm;
            if (dm > bv) { bv = dm; bi = i; }
        }
#pragma unroll
        for (int off = 16; off > 0; off >>= 1) {
            float ov = __shfl_xor_sync(0xffffffffu, bv, off);
            int oi = __shfl_xor_sync(0xffffffffu, bi, off);
            if (ov > bv || (ov == bv && oi < bi)) { bv = ov; bi = oi; }
        }
        if (lane == 0) { wv[wid] = bv; wi[wid] = bi; }
        __syncthreads();
        if (tid < 8) {
            bv = wv[tid]; bi = wi[tid];
#pragma unroll
            for (int off = 4; off > 0; off >>= 1) {
                float ov = __shfl_xor_sync(0xffu, bv, off);
                int oi = __shfl_xor_sync(0xffu, bi, off);
                if (ov > bv || (ov == bv && oi < bi)) { bv = ov; bi = oi; }
            }
            if (tid == 0) s_cur = bi;
        }
        __syncthreads();
        cur = s_cur;
    }
}

// ---------------------------------------------------------------------------
// KNN
// ---------------------------------------------------------------------------
__global__ void knn_kernel(const float* __restrict__ xyz) {
    int bg = blockIdx.x;
    int b = bg >> 7;
    __shared__ float d2s[cN];
    __shared__ float wv[8];
    __shared__ int   wi[8];
    __shared__ int   s_idx;
    int tid = threadIdx.x;
    int wid = tid >> 5, lane = tid & 31;
    float cx = g_center[bg * 3 + 0], cy = g_center[bg * 3 + 1], cz = g_center[bg * 3 + 2];
    const float* P = xyz + (size_t)b * cN * 3;
    for (int i = tid; i < cN; i += 256) {
        float dx = __fsub_rn(cx, P[i * 3 + 0]);
        float dy = __fsub_rn(cy, P[i * 3 + 1]);
        float dz = __fsub_rn(cz, P[i * 3 + 2]);
        d2s[i] = __fadd_rn(__fadd_rn(__fmul_rn(dx, dx), __fmul_rn(dy, dy)),
                           __fmul_rn(dz, dz));
    }
    __syncthreads();
    for (int m = 0; m < cM; m++) {
        float bv = FLT_MAX; int bi = 0x7fffffff;
        for (int i = tid; i < cN; i += 256) {
            float v = d2s[i];
            if (v < bv) { bv = v; bi = i; }
        }
#pragma unroll
        for (int off = 16; off > 0; off >>= 1) {
            float ov = __shfl_xor_sync(0xffffffffu, bv, off);
            int oi = __shfl_xor_sync(0xffffffffu, bi, off);
            if (ov < bv || (ov == bv && oi < bi)) { bv = ov; bi = oi; }
        }
        if (lane == 0) { wv[wid] = bv; wi[wid] = bi; }
        __syncthreads();
        if (tid < 8) {
            bv = wv[tid]; bi = wi[tid];
#pragma unroll
            for (int off = 4; off > 0; off >>= 1) {
                float ov = __shfl_xor_sync(0xffu, bv, off);
                int oi = __shfl_xor_sync(0xffu, bi, off);
                if (ov < bv || (ov == bv && oi < bi)) { bv = ov; bi = oi; }
            }
            if (tid == 0) s_idx = bi;
        }
        __syncthreads();
        int idx = s_idx;
        if (tid < 3) {
            float c = (tid == 0) ? cx : ((tid == 1) ? cy : cz);
            g_nb[((size_t)bg * cM + m) * 3 + tid] = __fsub_rn(P[idx * 3 + tid], c);
        }
        if (tid == 0) d2s[idx] = FLT_MAX;
        __syncthreads();
    }
}

// ---------------------------------------------------------------------------
// Residual accumulate + LayerNorm (xln rounded to tf32; res stays fp32)
// ---------------------------------------------------------------------------
__device__ __forceinline__ float block_sum_128(float v, float* sm) {
    int tid = threadIdx.x;
    sm[tid] = v; __syncthreads();
    for (int s = 64; s > 0; s >>= 1) {
        if (tid < s) sm[tid] += sm[tid + s];
        __syncthreads();
    }
    float r = sm[0]; __syncthreads();
    return r;
}

__global__ void resln_kernel(const float* __restrict__ w, const float* __restrict__ b,
                             int first) {
    __shared__ float sm[128];
    int t = blockIdx.x;
    float v[3];
#pragma unroll
    for (int j = 0; j < 3; j++) {
        int c = threadIdx.x + j * 128;
        float r = g_h[t * 384 + c];
        if (!first) r += g_res[t * 384 + c];
        g_res[t * 384 + c] = r;
        v[j] = r;
    }
    float mean = block_sum_128(v[0] + v[1] + v[2], sm) * (1.0f / 384.0f);
    float sq = 0.f;
#pragma unroll
    for (int j = 0; j < 3; j++) { float d = v[j] - mean; sq += d * d; }
    float var = block_sum_128(sq, sm) * (1.0f / 384.0f);
    float inv = rsqrtf(var + 1e-5f);
#pragma unroll
    for (int j = 0; j < 3; j++) {
        int c = threadIdx.x + j * 128;
        g_xln[t * 384 + c] = rnd_tf32((v[j] - mean) * inv * w[c] + b[c]);
    }
}

__global__ void final_kernel(const float* __restrict__ w, const float* __restrict__ b,
                             float* __restrict__ out) {
    __shared__ float sm[128];
    int t = blockIdx.x;
    float v[3];
#pragma unroll
    for (int j = 0; j < 3; j++) {
        int c = threadIdx.x + j * 128;
        v[j] = g_h[t * 384 + c] + g_res[t * 384 + c];
    }
    float mean = block_sum_128(v[0] + v[1] + v[2], sm) * (1.0f / 384.0f);
    float sq = 0.f;
#pragma unroll
    for (int j = 0; j < 3; j++) { float d = v[j] - mean; sq += d * d; }
    float var = block_sum_128(sq, sm) * (1.0f / 384.0f);
    float inv = rsqrtf(var + 1e-5f);
#pragma unroll
    for (int j = 0; j < 3; j++) {
        int c = threadIdx.x + j * 128;
        out[t * 384 + c] = (v[j] - mean) * inv * w[c] + b[c];
    }
}

// ---------------------------------------------------------------------------
// Depthwise causal conv (DC=4) + bias + silu (output rounded to tf32)
// ---------------------------------------------------------------------------
__global__ void conv_kernel(const float* __restrict__ cw, const float* __restrict__ cb) {
    int idx = blockIdx.x * blockDim.x + threadIdx.x;
    if (idx >= cTOK * cDI) return;
    int t = idx / cDI, d = idx % cDI;
    int l = t & 127;
    int tbase = t - l;
    float acc = cb[d];
#pragma unroll
    for (int k = 0; k < 4; k++) {
        int lk = l - 3 + k;
        if (lk >= 0)
            acc += g_xz[(size_t)(tbase + lk) * 1536 + d] * cw[d * 4 + k];
    }
    float sig = 1.0f / (1.0f + __expf(-acc));
    g_xc[idx] = rnd_tf32(acc * sig);
}

// ---------------------------------------------------------------------------
// Selective scan v4: dt computed inline (dbl[:24] @ dtw row + softplus),
// full dbl64 rows staged in smem; one thread per (b,d); q-power fast path.
// 128 threads/block -> 6 d-blocks x 16 batches = 96 blocks.
// ---------------------------------------------------------------------------
template<bool FAST>
__device__ __forceinline__ void scan_body(
    int b, int d, float a0, const float* a, float Dpd,
    const float* dtr, float dtbd) {
    extern __shared__ float sD[];   // [128][64]
    float h[16];
#pragma unroll
    for (int s = 0; s < 16; s++) h[s] = 0.f;

    const float* pxc = g_xc + (size_t)b * 128 * cDI + d;
    const float* pz  = g_xz + (size_t)b * 128 * 1536 + cDI + d;
    float* pu = g_u + (size_t)b * 128 * cDI + d;

    for (int t = 0; t < 128; t++) {
        const float* Dt = sD + t * 64;
        float acc = dtbd;
#pragma unroll
        for (int r = 0; r < 24; r++) acc += Dt[r] * dtr[r];
        float dt = fmaxf(acc, 0.f) + log1pf(__expf(-fabsf(acc)));
        float xin = pxc[(size_t)t * cDI];
        float u = dt * xin;
        float p[16];
        if (FAST) {
            float q = __expf(dt * a0);
            float q2 = q * q, q4 = q2 * q2, q8 = q4 * q4;
            p[0] = q;        p[1] = q2;       p[2] = q2 * q;   p[3] = q4;
            p[4] = q4 * q;   p[5] = q4 * q2;  p[6] = p[5] * q; p[7] = q8;
            p[8] = q8 * q;   p[9] = q8 * q2;  p[10] = p[9] * q;
            p[11] = q8 * q4; p[12] = p[11] * q; p[13] = p[11] * q2;
            p[14] = p[13] * q; p[15] = q8 * q8;
        } else {
#pragma unroll
            for (int s = 0; s < 16; s++) p[s] = __expf(dt * a[s]);
        }
        float y = 0.f;
#pragma unroll
        for (int s = 0; s < 16; s++) {
            h[s] = p[s] * h[s] + u * Dt[24 + s];
            y += h[s] * Dt[40 + s];
        }
        y += Dpd * xin;
        float z = pz[(size_t)t * 1536];
        float sz = z / (1.0f + __expf(-z));
        pu[(size_t)t * cDI] = rnd_tf32(y * sz);
    }
}

__global__ void __launch_bounds__(128)
scan_kernel(const float* __restrict__ Alog, const float* __restrict__ Dp,
            const float* __restrict__ dtw, const float* __restrict__ dtb) {
    extern __shared__ float sD[];   // 128*64 floats = 32KB
    int tid = threadIdx.x;
    int b = blockIdx.y;
    int d = blockIdx.x * 128 + tid;

    for (int i = tid; i < 128 * 16; i += 128)
        ((float4*)sD)[i] = ((const float4*)g_dbl64)[(size_t)b * 128 * 16 + i];
    __syncthreads();

    float dtr[24];
#pragma unroll
    for (int r = 0; r < 24; r++) dtr[r] = dtw[d * 32 + r];
    float dtbd = dtb[d];

    float a[16];
    bool fast = true;
#pragma unroll
    for (int s = 0; s < 16; s++) a[s] = -expf(Alog[d * 16 + s]);
    float a0 = a[0];
#pragma unroll
    for (int s = 1; s < 16; s++) {
        float ideal = (float)(s + 1) * a0;
        if (fabsf(a[s] - ideal) > 1e-4f * fabsf(ideal)) fast = false;
    }
    float Dpd = Dp[d];

    if (fast) scan_body<true>(b, d, a0, a, Dpd, dtr, dtbd);
    else      scan_body<false>(b, d, a0, a, Dpd, dtr, dtbd);
}

// ---------------------------------------------------------------------------
// Host-side launch sequence
// ---------------------------------------------------------------------------
extern "C" void kernel_launch(void* const* d_in, const int* in_sizes, int n_in,
                              void* d_out, int out_size) {
    const float* xyz   = (const float*)d_in[0];
    const float* e1w1  = (const float*)d_in[1];
    const float* e1b1  = (const float*)d_in[2];
    const float* bn1g  = (const float*)d_in[3];
    const float* bn1b  = (const float*)d_in[4];
    const float* e1w2  = (const float*)d_in[5];
    const float* e1b2  = (const float*)d_in[6];
    const float* e2w1  = (const float*)d_in[7];
    const float* e2b1  = (const float*)d_in[8];
    const float* bn2g  = (const float*)d_in[9];
    const float* bn2b  = (const float*)d_in[10];
    const float* e2w2  = (const float*)d_in[11];
    const float* e2b2  = (const float*)d_in[12];
    const float* pw1   = (const float*)d_in[13];
    const float* pb1   = (const float*)d_in[14];
    const float* pw2   = (const float*)d_in[15];
    const float* pb2   = (const float*)d_in[16];
    const float* in_w  = (const float*)d_in[17];
    const float* convw = (const float*)d_in[18];
    const float* convb = (const float*)d_in[19];
    const float* xp_w  = (const float*)d_in[20];
    const float* dt_w  = (const float*)d_in[21];
    const float* dt_b  = (const float*)d_in[22];
    const float* A_log = (const float*)d_in[23];
    const float* Dp    = (const float*)d_in[24];
    const float* out_w = (const float*)d_in[25];
    const float* lnw   = (const float*)d_in[26];
    const float* lnb   = (const float*)d_in[27];
    const float* fnw   = (const float*)d_in[28];
    const float* fnb   = (const float*)d_in[29];
    float* out = (float*)d_out;

    float *pnb, *pf2, *pfg, *pf3, *pxln, *pxz, *pxc, *pu, *ph, *pcenter,
          *pdbl, *pxpw, *pdtw;
    float *pwe1w2, *pwe2w1, *pwe2w2, *pwpw2, *pwinw, *pwoutw;
    cudaGetSymbolAddress((void**)&pnb,  g_nb);
    cudaGetSymbolAddress((void**)&pf2,  g_f2);
    cudaGetSymbolAddress((void**)&pfg,  g_fg);
    cudaGetSymbolAddress((void**)&pf3,  g_f3);
    cudaGetSymbolAddress((void**)&pxln, g_xln);
    cudaGetSymbolAddress((void**)&pxz,  g_xz);
    cudaGetSymbolAddress((void**)&pxc,  g_xc);
    cudaGetSymbolAddress((void**)&pu,   g_u);
    cudaGetSymbolAddress((void**)&ph,   g_h);
    cudaGetSymbolAddress((void**)&pcenter, g_center);
    cudaGetSymbolAddress((void**)&pdbl, g_dbl64);
    cudaGetSymbolAddress((void**)&pxpw, g_xpw);
    cudaGetSymbolAddress((void**)&pdtw, g_dtw);
    cudaGetSymbolAddress((void**)&pwe1w2, g_we1w2);
    cudaGetSymbolAddress((void**)&pwe2w1, g_we2w1);
    cudaGetSymbolAddress((void**)&pwe2w2, g_we2w2);
    cudaGetSymbolAddress((void**)&pwpw2,  g_wpw2);
    cudaGetSymbolAddress((void**)&pwinw,  g_winw);
    cudaGetSymbolAddress((void**)&pwoutw, g_woutw);

    // ---- weight prep (pre-round to tf32) ----
    prep_weights<<<(PW_TOT + 255) / 256, 256>>>(
        e1w2, e2w1, e2w2, pw2, in_w, out_w, xp_w, dt_w);

    // ---- grouping ----
    fps_kernel<<<cB, 256>>>(xyz);
    knn_kernel<<<cTOK, 256>>>(xyz);

    // ---- encoder (128x128 tiles, 8 warps) ----
    tc2<128, 128, 4, 2, 0, 2, 1, 1><<<dim3(cPTS / 128, 2), 256>>>(
        pnb, pwe1w2, e1b2, bn1g, bn1b, pf2, 128, 3, 128, 256,
        e1w1, e1b1, pfg, 256);
    tc2<128, 128, 4, 2, 1, 1, 0, 1><<<dim3(cPTS / 128, 4), 256>>>(
        pf2, pwe2w1, e2b1, bn2g, bn2b, pf3, 512, 256, 512, 512,
        pfg, nullptr, nullptr, 0);
    tc2<128, 128, 4, 2, 0, 0, 2, 0><<<dim3(cPTS / 128, 3), 256>>>(
        pf3, pwe2w2, e2b2, nullptr, nullptr, nullptr, 512, 512, 512, 384,
        nullptr, nullptr, ph, 384);

    // ---- positional MLP (pos1 fused into pos2 A-loader) ----
    tc2<64, 128, 2, 2, 3, 4, 0, 0><<<dim3(cTOK / 64, 3), 128>>>(
        pcenter, pwpw2, pb2, nullptr, nullptr, ph, 128, 3, 128, 384,
        pw1, pb1, nullptr, 0);

    // ---- mamba layers ----
    constexpr int SCAN_SMEM = 128 * 64 * sizeof(float);   // 32KB
    for (int i = 0; i < cNL; i++) {
        const float* in_w_i  = pwinw  + (size_t)i * 1536 * 384;
        const float* cw_i    = convw  + (size_t)i * cDI * 4;
        const float* cb_i    = convb  + (size_t)i * cDI;
        const float* dtb_i   = dt_b   + (size_t)i * cDI;
        const float* Al_i    = A_log  + (size_t)i * cDI * cDS;
        const float* Dp_i    = Dp     + (size_t)i * cDI;
        const float* ow_i    = pwoutw + (size_t)i * 384 * 768;
        const float* lnw_i   = lnw    + (size_t)i * cDM;
        const float* lnb_i   = lnb    + (size_t)i * cDM;
        const float* xpw_i   = pxpw   + (size_t)i * 64 * cDI;
        const float* dtw_i   = pdtw   + (size_t)i * cDI * 32;

        resln_kernel<<<cTOK, 128>>>(lnw_i, lnb_i, i == 0 ? 1 : 0);
        // in-proj: (2048,384)@(1536,384)^T — 128x128, 192 blocks (one wave)
        tc2<128, 128, 4, 2, 0, 0, 0, 1><<<dim3(cTOK / 128, 12), 256>>>(
            pxln, in_w_i, nullptr, nullptr, nullptr, pxz, 384, 384, 384, 1536,
            nullptr, nullptr, nullptr, 0);
        conv_kernel<<<(cTOK * cDI + 255) / 256, 256>>>(cw_i, cb_i);
        // xp: (2048,768)@(64,768)^T — 32x64 tiles, 64 blocks
        tc2<32, 64, 2, 1, 0, 0, 0, 1><<<dim3(cTOK / 32, 1), 64>>>(
            pxc, xpw_i, nullptr, nullptr, nullptr, pdbl, 768, 768, 768, 64,
            nullptr, nullptr, nullptr, 0);
        // scan with dt fused — 128 threads, 96 blocks
        scan_kernel<<<dim3(cDI / 128, cB), 128, SCAN_SMEM>>>(
            Al_i, Dp_i, dtw_i, dtb_i);
        // out-proj: (2048,768)@(384,768)^T — 64x64, 192 blocks
        tc2<64, 64, 2, 2, 0, 0, 0, 0><<<dim3(cTOK / 64, 6), 128>>>(
            pu, ow_i, nullptr, nullptr, nullptr, ph, 768, 768, 768, 384,
            nullptr, nullptr, nullptr, 0);
    }

    // ---- final LN ----
    final_kernel<<<cTOK, 128>>>(fnw, fnb, out);
}

// round 16
// speedup vs baseline: 2.2667x; 1.0418x over previous
#include <cuda_runtime.h>
#include <math.h>
#include <float.h>

// ---------------------------------------------------------------------------
// Problem constants
// ---------------------------------------------------------------------------
constexpr int cB   = 16;
constexpr int cN   = 2048;
constexpr int cG   = 128;
constexpr int cM   = 32;
constexpr int cDM  = 384;
constexpr int cNL  = 12;
constexpr int cDI  = 768;
constexpr int cDS  = 16;
constexpr int cDTR = 24;
constexpr int cTOK = cB * cG;        // 2048 tokens
constexpr int cPTS = cTOK * cM;      // 65536 points

// ---------------------------------------------------------------------------
// Scratch (device globals; no dynamic allocation allowed)
// ---------------------------------------------------------------------------
__device__ __align__(16) float g_center[cTOK * 3];
__device__ __align__(16) float g_nb[cPTS * 3];
__device__ __align__(16) float g_f2[(size_t)cPTS * 256];
__device__ __align__(16) float g_fg[cTOK * 256];
__device__ __align__(16) float g_fgp[cTOK * 512];
__device__ __align__(16) float g_f3[(size_t)cPTS * 512];
__device__ __align__(16) float g_h[cTOK * cDM];
__device__ __align__(16) float g_res[cTOK * cDM];
__device__ __align__(16) float g_xln[cTOK * cDM];
__device__ __align__(16) float g_xz[(size_t)cTOK * 2 * cDI];
__device__ __align__(16) float g_xc[(size_t)cTOK * cDI];
__device__ __align__(16) float g_dbl64[cTOK * 64];
__device__ __align__(16) float g_u[(size_t)cTOK * cDI];
// pre-rounded (tf32/RNA) weights
__device__ __align__(16) float g_xpw[cNL * 64 * cDI];
__device__ __align__(16) float g_dtw[cNL * cDI * 32];
__device__ __align__(16) float g_we1w2[256 * 128];
__device__ __align__(16) float g_we2w1[512 * 512];
__device__ __align__(16) float g_we2w2[384 * 512];
__device__ __align__(16) float g_wpw2[384 * 128];
__device__ __align__(16) float g_winw[(size_t)cNL * 1536 * 384];
__device__ __align__(16) float g_woutw[(size_t)cNL * 384 * 768];

using u32 = unsigned int;

__device__ __forceinline__ u32 cvt_tf32(float x) {
    u32 r;
    asm("cvt.rna.tf32.f32 %0, %1;" : "=r"(r) : "f"(x));
    return r;
}
__device__ __forceinline__ float rnd_tf32(float x) {
    return __uint_as_float(cvt_tf32(x));
}

__device__ __forceinline__ u32 smem_u32(const void* p) {
    u32 a;
    asm("{ .reg .u64 t; cvta.to.shared.u64 t, %1; cvt.u32.u64 %0, t; }"
        : "=r"(a) : "l"(p));
    return a;
}

__device__ __forceinline__ void ldsm4(u32& r0, u32& r1, u32& r2, u32& r3, u32 addr) {
    asm volatile("ldmatrix.sync.aligned.m8n8.x4.shared.b16 {%0,%1,%2,%3}, [%4];"
                 : "=r"(r0), "=r"(r1), "=r"(r2), "=r"(r3) : "r"(addr));
}

__device__ __forceinline__ void cpasync16(u32 dst, const void* src) {
    asm volatile("cp.async.cg.shared.global [%0], [%1], 16;"
                 :: "r"(dst), "l"(src) : "memory");
}
#define CP_COMMIT() asm volatile("cp.async.commit_group;" ::: "memory")
#define CP_WAIT0()  asm volatile("cp.async.wait_group 0;" ::: "memory")
#define CP_WAIT1()  asm volatile("cp.async.wait_group 1;" ::: "memory")

__device__ __forceinline__ void mma_tf32(float* c, u32 a0, u32 a1, u32 a2, u32 a3,
                                         u32 b0, u32 b1) {
    asm volatile(
        "mma.sync.aligned.m16n8k8.row.col.f32.tf32.tf32.f32 "
        "{%0,%1,%2,%3}, {%4,%5,%6,%7}, {%8,%9}, {%0,%1,%2,%3};"
        : "+f"(c[0]), "+f"(c[1]), "+f"(c[2]), "+f"(c[3])
        : "r"(a0), "r"(a1), "r"(a2), "r"(a3), "r"(b0), "r"(b1));
}

// ---------------------------------------------------------------------------
// Generic tf32 tensor-core GEMM: C = epi(A' @ W^T [+ addc]).
//   Smem row-major [row][k] (stride 20 floats), ldmatrix.x4.b16 fragments,
//   3-stage cp.async pipeline. Inputs pre-rounded to tf32 (RNA) by producers.
//   EPI 0:+bias(opt). 1: relu(bn(.+bias)). 2: softplus(.+bias). 3: C+=.+bias
//   MODEA 0: A'=A. 1: cols[0,256) from aux1[row>>5][k].
//         2: relu(bn1(nb@w1^T+b1)) on the fly. 4: gelu(center@pw1^T+pb1).
//   EMAX 0: normal. 1: write C AND 32-row group max. 2: ONLY group max.
//   ROUNDC 1: RNA-round outputs (consumer is a GEMM).
//   ADDC 1: (EMAX==0 only) add fgout[(row>>5)*ldfg + n] before epilogue.
// ---------------------------------------------------------------------------
template<int BM, int BN, int WGM, int WGN, int EPI, int MODEA, int EMAX,
         int ROUNDC, int ADDC = 0>
__global__ void __launch_bounds__(WGM * WGN * 32)
tc2(const float* __restrict__ A, const float* __restrict__ W,
    const float* __restrict__ bias, const float* __restrict__ p1,
    const float* __restrict__ p2, float* __restrict__ C,
    int K, int lda, int ldw, int ldc,
    const float* __restrict__ aux1, const float* __restrict__ aux2,
    float* __restrict__ fgout, int ldfg)
{
    constexpr int THREADS = WGM * WGN * 32;
    constexpr int WTM = BM / WGM, WTN = BN / WGN;
    constexpr int MT = WTM / 16, NT = WTN / 8;
    constexpr int NP = NT / 2;
    constexpr int KS = 20;
    constexpr int A4 = (BM * 16) / (THREADS * 4);
    constexpr int W4 = (BN * 16) / (THREADS * 4);
    static_assert(EMAX == 0 || (WTM % 32) == 0, "EMAX needs WTM%32==0");
    static_assert(NT % 2 == 0, "NT must be even");

    __shared__ __align__(16) float As[3][BM][KS];
    __shared__ __align__(16) float Ws[3][BN][KS];

    const int tid = threadIdx.x;
    const int wid = tid >> 5, lane = tid & 31;
    const int grp = lane >> 2, tig = lane & 3;
    const int wm = wid % WGM, wn = wid / WGM;
    const int m0 = blockIdx.x * BM, n0 = blockIdx.y * BN;
    const float bnscale = rsqrtf(1.0f + 1e-5f);

    const u32 asBase = smem_u32(&As[0][0][0]);
    const u32 wsBase = smem_u32(&Ws[0][0][0]);
    constexpr u32 ABUF = BM * KS * 4;
    constexpr u32 WBUF = BN * KS * 4;

    u32 aOff[MT], bOff[NP];
    {
        int l7 = lane & 7;
        int aRow = ((lane >> 3) & 1) * 8;
        int aCol = (lane >> 4) * 16;
#pragma unroll
        for (int mt = 0; mt < MT; mt++) {
            int row = wm * WTM + mt * 16 + aRow + l7;
            aOff[mt] = (u32)(row * KS * 4 + aCol);
        }
        int bRow = (lane >> 4) * 8;
        int bCol = ((lane >> 3) & 1) * 16;
#pragma unroll
        for (int p = 0; p < NP; p++) {
            int row = wn * WTN + p * 16 + bRow + l7;
            bOff[p] = (u32)(row * KS * 4 + bCol);
        }
    }

    float acc[MT][NT][4];
#pragma unroll
    for (int mt = 0; mt < MT; mt++)
#pragma unroll
        for (int nt = 0; nt < NT; nt++)
#pragma unroll
            for (int r = 0; r < 4; r++) acc[mt][nt][r] = 0.f;

    float nbr[(MODEA >= 2) ? A4 : 1][3];
    if (MODEA >= 2) {
#pragma unroll
        for (int v = 0; v < A4; v++) {
            int row = (tid + v * THREADS) >> 2;
            nbr[v][0] = A[(size_t)(m0 + row) * 3 + 0];
            nbr[v][1] = A[(size_t)(m0 + row) * 3 + 1];
            nbr[v][2] = A[(size_t)(m0 + row) * 3 + 2];
        }
    }

    auto issueAW = [&](int kc, int bufSel) {
        const u32 aB = asBase + (u32)bufSel * ABUF;
        const u32 wB = wsBase + (u32)bufSel * WBUF;
        if (MODEA <= 1) {
#pragma unroll
            for (int v = 0; v < A4; v++) {
                int s = tid + v * THREADS;
                int row = s >> 2;
                int kq = (s & 3) * 4;
                int k = kc + kq;
                const float* src;
                if (MODEA == 0) {
                    src = A + (size_t)(m0 + row) * lda + k;
                } else {
                    int r = m0 + row;
                    src = (k < 256)
                        ? (aux1 + ((size_t)(r >> 5)) * 256 + k)
                        : (A + (size_t)r * lda + (k - 256));
                }
                cpasync16(aB + (u32)((row * KS + kq) * 4), src);
            }
        } else {
#pragma unroll
            for (int v = 0; v < A4; v++) {
                int s = tid + v * THREADS;
                int row = s >> 2;
                int kq = (s & 3) * 4;
                int k = kc + kq;
                float out[4];
#pragma unroll
                for (int e = 0; e < 4; e++) {
                    int kk = k + e;
                    float val = nbr[v][0] * aux1[kk * 3 + 0]
                              + nbr[v][1] * aux1[kk * 3 + 1]
                              + nbr[v][2] * aux1[kk * 3 + 2] + aux2[kk];
                    if (MODEA == 2) {
                        val = val * (p1[kk] * bnscale) + p2[kk];
                        out[e] = fmaxf(val, 0.f);
                    } else {  // gelu (tanh approx)
                        float v3 = val * val * val;
                        out[e] = 0.5f * val *
                            (1.0f + tanhf(0.7978845608028654f *
                                          (val + 0.044715f * v3)));
                    }
                }
                uint4 o;
                o.x = cvt_tf32(out[0]); o.y = cvt_tf32(out[1]);
                o.z = cvt_tf32(out[2]); o.w = cvt_tf32(out[3]);
                *reinterpret_cast<uint4*>(&As[bufSel][row][kq]) = o;
            }
        }
#pragma unroll
        for (int v = 0; v < W4; v++) {
            int s = tid + v * THREADS;
            int row = s >> 2;
            int kq = (s & 3) * 4;
            cpasync16(wB + (u32)((row * KS + kq) * 4),
                      W + (size_t)(n0 + row) * ldw + kc + kq);
        }
        CP_COMMIT();
    };

    const int nIter = K >> 4;
    issueAW(0, 0);
    if (nIter > 1) {
        issueAW(16, 1);
        CP_WAIT1();
    } else {
        CP_WAIT0();
    }
    __syncthreads();

    for (int it = 0; it < nIter; it++) {
        if (it + 2 < nIter) issueAW((it + 2) << 4, (it + 2) % 3);
        const int buf = it % 3;
        const u32 aB = asBase + (u32)buf * ABUF;
        const u32 wB = wsBase + (u32)buf * WBUF;
#pragma unroll
        for (int ks = 0; ks < 2; ks++) {
            const u32 kb = (u32)(ks * 32);
            u32 af[MT][4];
#pragma unroll
            for (int mt = 0; mt < MT; mt++)
                ldsm4(af[mt][0], af[mt][1], af[mt][2], af[mt][3],
                      aB + aOff[mt] + kb);
            u32 bf[NT][2];
#pragma unroll
            for (int p = 0; p < NP; p++) {
                u32 r0, r1, r2, r3;
                ldsm4(r0, r1, r2, r3, wB + bOff[p] + kb);
                bf[2 * p][0] = r0;     bf[2 * p][1] = r1;
                bf[2 * p + 1][0] = r2; bf[2 * p + 1][1] = r3;
            }
#pragma unroll
            for (int mt = 0; mt < MT; mt++)
#pragma unroll
                for (int nt = 0; nt < NT; nt++)
                    mma_tf32(acc[mt][nt], af[mt][0], af[mt][1], af[mt][2], af[mt][3],
                             bf[nt][0], bf[nt][1]);
        }
        if (it + 1 < nIter) {
            if (it + 2 < nIter) { CP_WAIT1(); } else { CP_WAIT0(); }
            __syncthreads();
        }
    }

    if constexpr (EMAX == 0) {
        auto emit = [&](int mrow, int n, float v0, float v1) {
            if (ADDC) {
                const float* ac = fgout + (size_t)(mrow >> 5) * ldfg + n;
                v0 += ac[0]; v1 += ac[1];
            }
            if (EPI == 3) {
                C[(size_t)mrow * ldc + n]     += v0 + bias[n];
                C[(size_t)mrow * ldc + n + 1] += v1 + bias[n + 1];
                return;
            }
            if (EPI == 0) {
                if (bias) { v0 += bias[n]; v1 += bias[n + 1]; }
            } else if (EPI == 1) {
                v0 = fmaxf((v0 + bias[n]) * (p1[n] * bnscale) + p2[n], 0.f);
                v1 = fmaxf((v1 + bias[n + 1]) * (p1[n + 1] * bnscale) + p2[n + 1], 0.f);
            } else if (EPI == 2) {
                v0 += bias[n]; v1 += bias[n + 1];
                v0 = fmaxf(v0, 0.f) + log1pf(__expf(-fabsf(v0)));
                v1 = fmaxf(v1, 0.f) + log1pf(__expf(-fabsf(v1)));
            }
            if (ROUNDC) { v0 = rnd_tf32(v0); v1 = rnd_tf32(v1); }
            float2 o; o.x = v0; o.y = v1;
            *(float2*)&C[(size_t)mrow * ldc + n] = o;
        };
#pragma unroll
        for (int mt = 0; mt < MT; mt++) {
            int mrow = m0 + wm * WTM + mt * 16 + grp;
#pragma unroll
            for (int nt = 0; nt < NT; nt++) {
                int n = n0 + wn * WTN + nt * 8 + tig * 2;
                emit(mrow,     n, acc[mt][nt][0], acc[mt][nt][1]);
                emit(mrow + 8, n, acc[mt][nt][2], acc[mt][nt][3]);
            }
        }
    } else {
        constexpr int GPW = WTM / 32;
        float mx[GPW][NT][2];
#pragma unroll
        for (int g = 0; g < GPW; g++)
#pragma unroll
            for (int nt = 0; nt < NT; nt++) {
                mx[g][nt][0] = -FLT_MAX; mx[g][nt][1] = -FLT_MAX;
            }
#pragma unroll
        for (int mt = 0; mt < MT; mt++) {
            int gsel = mt / 2;
            int mrow = m0 + wm * WTM + mt * 16 + grp;
#pragma unroll
            for (int nt = 0; nt < NT; nt++) {
                int n = n0 + wn * WTN + nt * 8 + tig * 2;
                float v0 = acc[mt][nt][0] + bias[n];
                float v1 = acc[mt][nt][1] + bias[n + 1];
                float v2 = acc[mt][nt][2] + bias[n];
                float v3 = acc[mt][nt][3] + bias[n + 1];
                if (ROUNDC) {
                    v0 = rnd_tf32(v0); v1 = rnd_tf32(v1);
                    v2 = rnd_tf32(v2); v3 = rnd_tf32(v3);
                }
                if (EMAX == 1) {
                    float2 o0; o0.x = v0; o0.y = v1;
                    float2 o1; o1.x = v2; o1.y = v3;
                    *(float2*)&C[(size_t)mrow * ldc + n] = o0;
                    *(float2*)&C[(size_t)(mrow + 8) * ldc + n] = o1;
                }
                mx[gsel][nt][0] = fmaxf(mx[gsel][nt][0], fmaxf(v0, v2));
                mx[gsel][nt][1] = fmaxf(mx[gsel][nt][1], fmaxf(v1, v3));
            }
        }
#pragma unroll
        for (int g = 0; g < GPW; g++) {
#pragma unroll
            for (int nt = 0; nt < NT; nt++)
#pragma unroll
                for (int c = 0; c < 2; c++) {
                    float v = mx[g][nt][c];
                    v = fmaxf(v, __shfl_xor_sync(0xffffffffu, v, 4));
                    v = fmaxf(v, __shfl_xor_sync(0xffffffffu, v, 8));
                    v = fmaxf(v, __shfl_xor_sync(0xffffffffu, v, 16));
                    mx[g][nt][c] = v;
                }
            if (lane < 4) {
                int grow = (m0 >> 5) + wm * GPW + g;
#pragma unroll
                for (int nt = 0; nt < NT; nt++) {
                    int n = n0 + wn * WTN + nt * 8 + tig * 2;
                    fgout[(size_t)grow * ldfg + n]     = mx[g][nt][0];
                    fgout[(size_t)grow * ldfg + n + 1] = mx[g][nt][1];
                }
            }
        }
    }
}

// ---------------------------------------------------------------------------
// Pre-round all GEMM weights to tf32 (RNA); pad xp_w/dt_w
// ---------------------------------------------------------------------------
constexpr int PW_N0 = 256 * 128;
constexpr int PW_N1 = 512 * 512;
constexpr int PW_N2 = 384 * 512;
constexpr int PW_N3 = 384 * 128;
constexpr int PW_N4 = cNL * 1536 * 384;
constexpr int PW_N5 = cNL * 384 * 768;
constexpr int PW_N6 = cNL * 64 * cDI;
constexpr int PW_N7 = cNL * cDI * 32;
constexpr int PW_O1 = PW_N0;
constexpr int PW_O2 = PW_O1 + PW_N1;
constexpr int PW_O3 = PW_O2 + PW_N2;
constexpr int PW_O4 = PW_O3 + PW_N3;
constexpr int PW_O5 = PW_O4 + PW_N4;
constexpr int PW_O6 = PW_O5 + PW_N5;
constexpr int PW_O7 = PW_O6 + PW_N6;
constexpr int PW_TOT = PW_O7 + PW_N7;

__global__ void prep_weights(const float* __restrict__ e1w2,
                             const float* __restrict__ e2w1,
                             const float* __restrict__ e2w2,
                             const float* __restrict__ pw2,
                             const float* __restrict__ in_w,
                             const float* __restrict__ out_w,
                             const float* __restrict__ xp_w,
                             const float* __restrict__ dt_w) {
    int idx = blockIdx.x * 256 + threadIdx.x;
    if (idx >= PW_TOT) return;
    float v; float* dst;
    if (idx < PW_O1)      { v = e1w2[idx];          dst = g_we1w2 + idx; }
    else if (idx < PW_O2) { v = e2w1[idx - PW_O1];  dst = g_we2w1 + (idx - PW_O1); }
    else if (idx < PW_O3) { v = e2w2[idx - PW_O2];  dst = g_we2w2 + (idx - PW_O2); }
    else if (idx < PW_O4) { v = pw2[idx - PW_O3];   dst = g_wpw2 + (idx - PW_O3); }
    else if (idx < PW_O5) { v = in_w[idx - PW_O4];  dst = g_winw + (idx - PW_O4); }
    else if (idx < PW_O6) { v = out_w[idx - PW_O5]; dst = g_woutw + (idx - PW_O5); }
    else if (idx < PW_O7) {
        int j = idx - PW_O6;
        int l = j / (64 * cDI);
        int r = (j / cDI) % 64;
        int k = j % cDI;
        v = (r < 56) ? xp_w[((size_t)l * 56 + r) * cDI + k] : 0.f;
        dst = g_xpw + j;
    } else {
        int j = idx - PW_O7;
        int l = j / (cDI * 32);
        int d = (j / 32) % cDI;
        int k = j % 32;
        v = (k < 24) ? dt_w[((size_t)l * cDI + d) * cDTR + k] : 0.f;
        dst = g_dtw + j;
    }
    *dst = __uint_as_float(cvt_tf32(v));
}

// ---------------------------------------------------------------------------
// FPS
// ---------------------------------------------------------------------------
__global__ void fps_kernel(const float* __restrict__ xyz) {
    int b = blockIdx.x;
    __shared__ float px[cN], py[cN], pz[cN], dmin[cN];
    __shared__ float wv[8];
    __shared__ int   wi[8];
    __shared__ int   s_cur;
    int tid = threadIdx.x;
    int wid = tid >> 5, lane = tid & 31;
    for (int i = tid; i < cN; i += 256) {
        px[i] = xyz[(b * cN + i) * 3 + 0];
        py[i] = xyz[(b * cN + i) * 3 + 1];
        pz[i] = xyz[(b * cN + i) * 3 + 2];
        dmin[i] = 1e10f;
    }
    __syncthreads();
    int cur = 0;
    for (int g = 0; g < cG; g++) {
        float cx = px[cur], cy = py[cur], cz = pz[cur];
        if (tid == 0) {
            g_center[(b * cG + g) * 3 + 0] = cx;
            g_center[(b * cG + g) * 3 + 1] = cy;
            g_center[(b * cG + g) * 3 + 2] = cz;
        }
        float bv = -1.f; int bi = 0x7fffffff;
        for (int i = tid; i < cN; i += 256) {
            float dx = __fsub_rn(px[i], cx);
            float dy = __fsub_rn(py[i], cy);
            float dz = __fsub_rn(pz[i], cz);
            float dd = __fadd_rn(__fadd_rn(__fmul_rn(dx, dx), __fmul_rn(dy, dy)),
                                 __fmul_rn(dz, dz));
            float dm = fminf(dmin[i], dd);
            dmin[i] = dm;
            if (dm > bv) { bv = dm; bi = i; }
        }
#pragma unroll
        for (int off = 16; off > 0; off >>= 1) {
            float ov = __shfl_xor_sync(0xffffffffu, bv, off);
            int oi = __shfl_xor_sync(0xffffffffu, bi, off);
            if (ov > bv || (ov == bv && oi < bi)) { bv = ov; bi = oi; }
        }
        if (lane == 0) { wv[wid] = bv; wi[wid] = bi; }
        __syncthreads();
        if (tid < 8) {
            bv = wv[tid]; bi = wi[tid];
#pragma unroll
            for (int off = 4; off > 0; off >>= 1) {
                float ov = __shfl_xor_sync(0xffu, bv, off);
                int oi = __shfl_xor_sync(0xffu, bi, off);
                if (ov > bv || (ov == bv && oi < bi)) { bv = ov; bi = oi; }
            }
            if (tid == 0) s_cur = bi;
        }
        __syncthreads();
        cur = s_cur;
    }
}

// ---------------------------------------------------------------------------
// KNN
// ---------------------------------------------------------------------------
__global__ void knn_kernel(const float* __restrict__ xyz) {
    int bg = blockIdx.x;
    int b = bg >> 7;
    __shared__ float d2s[cN];
    __shared__ float wv[8];
    __shared__ int   wi[8];
    __shared__ int   s_idx;
    int tid = threadIdx.x;
    int wid = tid >> 5, lane = tid & 31;
    float cx = g_center[bg * 3 + 0], cy = g_center[bg * 3 + 1], cz = g_center[bg * 3 + 2];
    const float* P = xyz + (size_t)b * cN * 3;
    for (int i = tid; i < cN; i += 256) {
        float dx = __fsub_rn(cx, P[i * 3 + 0]);
        float dy = __fsub_rn(cy, P[i * 3 + 1]);
        float dz = __fsub_rn(cz, P[i * 3 + 2]);
        d2s[i] = __fadd_rn(__fadd_rn(__fmul_rn(dx, dx), __fmul_rn(dy, dy)),
                           __fmul_rn(dz, dz));
    }
    __syncthreads();
    for (int m = 0; m < cM; m++) {
        float bv = FLT_MAX; int bi = 0x7fffffff;
        for (int i = tid; i < cN; i += 256) {
            float v = d2s[i];
            if (v < bv) { bv = v; bi = i; }
        }
#pragma unroll
        for (int off = 16; off > 0; off >>= 1) {
            float ov = __shfl_xor_sync(0xffffffffu, bv, off);
            int oi = __shfl_xor_sync(0xffffffffu, bi, off);
            if (ov < bv || (ov == bv && oi < bi)) { bv = ov; bi = oi; }
        }
        if (lane == 0) { wv[wid] = bv; wi[wid] = bi; }
        __syncthreads();
        if (tid < 8) {
            bv = wv[tid]; bi = wi[tid];
#pragma unroll
            for (int off = 4; off > 0; off >>= 1) {
                float ov = __shfl_xor_sync(0xffu, bv, off);
                int oi = __shfl_xor_sync(0xffu, bi, off);
                if (ov < bv || (ov == bv && oi < bi)) { bv = ov; bi = oi; }
            }
            if (tid == 0) s_idx = bi;
        }
        __syncthreads();
        int idx = s_idx;
        if (tid < 3) {
            float c = (tid == 0) ? cx : ((tid == 1) ? cy : cz);
            g_nb[((size_t)bg * cM + m) * 3 + tid] = __fsub_rn(P[idx * 3 + tid], c);
        }
        if (tid == 0) d2s[idx] = FLT_MAX;
        __syncthreads();
    }
}

// ---------------------------------------------------------------------------
// Residual accumulate + LayerNorm (xln rounded to tf32; res stays fp32)
// ---------------------------------------------------------------------------
__device__ __forceinline__ float block_sum_128(float v, float* sm) {
    int tid = threadIdx.x;
    sm[tid] = v; __syncthreads();
    for (int s = 64; s > 0; s >>= 1) {
        if (tid < s) sm[tid] += sm[tid + s];
        __syncthreads();
    }
    float r = sm[0]; __syncthreads();
    return r;
}

__global__ void resln_kernel(const float* __restrict__ w, const float* __restrict__ b,
                             int first) {
    __shared__ float sm[128];
    int t = blockIdx.x;
    float v[3];
#pragma unroll
    for (int j = 0; j < 3; j++) {
        int c = threadIdx.x + j * 128;
        float r = g_h[t * 384 + c];
        if (!first) r += g_res[t * 384 + c];
        g_res[t * 384 + c] = r;
        v[j] = r;
    }
    float mean = block_sum_128(v[0] + v[1] + v[2], sm) * (1.0f / 384.0f);
    float sq = 0.f;
#pragma unroll
    for (int j = 0; j < 3; j++) { float d = v[j] - mean; sq += d * d; }
    float var = block_sum_128(sq, sm) * (1.0f / 384.0f);
    float inv = rsqrtf(var + 1e-5f);
#pragma unroll
    for (int j = 0; j < 3; j++) {
        int c = threadIdx.x + j * 128;
        g_xln[t * 384 + c] = rnd_tf32((v[j] - mean) * inv * w[c] + b[c]);
    }
}

__global__ void final_kernel(const float* __restrict__ w, const float* __restrict__ b,
                             float* __restrict__ out) {
    __shared__ float sm[128];
    int t = blockIdx.x;
    float v[3];
#pragma unroll
    for (int j = 0; j < 3; j++) {
        int c = threadIdx.x + j * 128;
        v[j] = g_h[t * 384 + c] + g_res[t * 384 + c];
    }
    float mean = block_sum_128(v[0] + v[1] + v[2], sm) * (1.0f / 384.0f);
    float sq = 0.f;
#pragma unroll
    for (int j = 0; j < 3; j++) { float d = v[j] - mean; sq += d * d; }
    float var = block_sum_128(sq, sm) * (1.0f / 384.0f);
    float inv = rsqrtf(var + 1e-5f);
#pragma unroll
    for (int j = 0; j < 3; j++) {
        int c = threadIdx.x + j * 128;
        out[t * 384 + c] = (v[j] - mean) * inv * w[c] + b[c];
    }
}

// ---------------------------------------------------------------------------
// Depthwise causal conv (DC=4) + bias + silu (output rounded to tf32)
// ---------------------------------------------------------------------------
__global__ void conv_kernel(const float* __restrict__ cw, const float* __restrict__ cb) {
    int idx = blockIdx.x * blockDim.x + threadIdx.x;
    if (idx >= cTOK * cDI) return;
    int t = idx / cDI, d = idx % cDI;
    int l = t & 127;
    int tbase = t - l;
    float acc = cb[d];
#pragma unroll
    for (int k = 0; k < 4; k++) {
        int lk = l - 3 + k;
        if (lk >= 0)
            acc += g_xz[(size_t)(tbase + lk) * 1536 + d] * cw[d * 4 + k];
    }
    float sig = 1.0f / (1.0f + __expf(-acc));
    g_xc[idx] = rnd_tf32(acc * sig);
}

// ---------------------------------------------------------------------------
// Selective scan v4: dt computed inline (dbl[:24] @ dtw row + softplus),
// full dbl64 rows staged in smem; one thread per (b,d); q-power fast path.
// ---------------------------------------------------------------------------
template<bool FAST>
__device__ __forceinline__ void scan_body(
    int b, int d, float a0, const float* a, float Dpd,
    const float* dtr, float dtbd) {
    extern __shared__ float sD[];   // [128][64]
    float h[16];
#pragma unroll
    for (int s = 0; s < 16; s++) h[s] = 0.f;

    const float* pxc = g_xc + (size_t)b * 128 * cDI + d;
    const float* pz  = g_xz + (size_t)b * 128 * 1536 + cDI + d;
    float* pu = g_u + (size_t)b * 128 * cDI + d;

    for (int t = 0; t < 128; t++) {
        const float* Dt = sD + t * 64;
        float acc = dtbd;
#pragma unroll
        for (int r = 0; r < 24; r++) acc += Dt[r] * dtr[r];
        float dt = fmaxf(acc, 0.f) + log1pf(__expf(-fabsf(acc)));
        float xin = pxc[(size_t)t * cDI];
        float u = dt * xin;
        float p[16];
        if (FAST) {
            float q = __expf(dt * a0);
            float q2 = q * q, q4 = q2 * q2, q8 = q4 * q4;
            p[0] = q;        p[1] = q2;       p[2] = q2 * q;   p[3] = q4;
            p[4] = q4 * q;   p[5] = q4 * q2;  p[6] = p[5] * q; p[7] = q8;
            p[8] = q8 * q;   p[9] = q8 * q2;  p[10] = p[9] * q;
            p[11] = q8 * q4; p[12] = p[11] * q; p[13] = p[11] * q2;
            p[14] = p[13] * q; p[15] = q8 * q8;
        } else {
#pragma unroll
            for (int s = 0; s < 16; s++) p[s] = __expf(dt * a[s]);
        }
        float y = 0.f;
#pragma unroll
        for (int s = 0; s < 16; s++) {
            h[s] = p[s] * h[s] + u * Dt[24 + s];
            y += h[s] * Dt[40 + s];
        }
        y += Dpd * xin;
        float z = pz[(size_t)t * 1536];
        float sz = z / (1.0f + __expf(-z));
        pu[(size_t)t * cDI] = rnd_tf32(y * sz);
    }
}

__global__ void __launch_bounds__(128)
scan_kernel(const float* __restrict__ Alog, const float* __restrict__ Dp,
            const float* __restrict__ dtw, const float* __restrict__ dtb) {
    extern __shared__ float sD[];   // 128*64 floats = 32KB
    int tid = threadIdx.x;
    int b = blockIdx.y;
    int d = blockIdx.x * 128 + tid;

    for (int i = tid; i < 128 * 16; i += 128)
        ((float4*)sD)[i] = ((const float4*)g_dbl64)[(size_t)b * 128 * 16 + i];
    __syncthreads();

    float dtr[24];
#pragma unroll
    for (int r = 0; r < 24; r++) dtr[r] = dtw[d * 32 + r];
    float dtbd = dtb[d];

    float a[16];
    bool fast = true;
#pragma unroll
    for (int s = 0; s < 16; s++) a[s] = -expf(Alog[d * 16 + s]);
    float a0 = a[0];
#pragma unroll
    for (int s = 1; s < 16; s++) {
        float ideal = (float)(s + 1) * a0;
        if (fabsf(a[s] - ideal) > 1e-4f * fabsf(ideal)) fast = false;
    }
    float Dpd = Dp[d];

    if (fast) scan_body<true>(b, d, a0, a, Dpd, dtr, dtbd);
    else      scan_body<false>(b, d, a0, a, Dpd, dtr, dtbd);
}

// ---------------------------------------------------------------------------
// Host-side launch sequence
// ---------------------------------------------------------------------------
extern "C" void kernel_launch(void* const* d_in, const int* in_sizes, int n_in,
                              void* d_out, int out_size) {
    const float* xyz   = (const float*)d_in[0];
    const float* e1w1  = (const float*)d_in[1];
    const float* e1b1  = (const float*)d_in[2];
    const float* bn1g  = (const float*)d_in[3];
    const float* bn1b  = (const float*)d_in[4];
    const float* e1w2  = (const float*)d_in[5];
    const float* e1b2  = (const float*)d_in[6];
    const float* e2w1  = (const float*)d_in[7];
    const float* e2b1  = (const float*)d_in[8];
    const float* bn2g  = (const float*)d_in[9];
    const float* bn2b  = (const float*)d_in[10];
    const float* e2w2  = (const float*)d_in[11];
    const float* e2b2  = (const float*)d_in[12];
    const float* pw1   = (const float*)d_in[13];
    const float* pb1   = (const float*)d_in[14];
    const float* pw2   = (const float*)d_in[15];
    const float* pb2   = (const float*)d_in[16];
    const float* in_w  = (const float*)d_in[17];
    const float* convw = (const float*)d_in[18];
    const float* convb = (const float*)d_in[19];
    const float* xp_w  = (const float*)d_in[20];
    const float* dt_w  = (const float*)d_in[21];
    const float* dt_b  = (const float*)d_in[22];
    const float* A_log = (const float*)d_in[23];
    const float* Dp    = (const float*)d_in[24];
    const float* out_w = (const float*)d_in[25];
    const float* lnw   = (const float*)d_in[26];
    const float* lnb   = (const float*)d_in[27];
    const float* fnw   = (const float*)d_in[28];
    const float* fnb   = (const float*)d_in[29];
    float* out = (float*)d_out;

    float *pnb, *pf2, *pfg, *pfgp, *pf3, *pxln, *pxz, *pxc, *pu, *ph, *pcenter,
          *pdbl, *pxpw, *pdtw;
    float *pwe1w2, *pwe2w1, *pwe2w2, *pwpw2, *pwinw, *pwoutw;
    cudaGetSymbolAddress((void**)&pnb,  g_nb);
    cudaGetSymbolAddress((void**)&pf2,  g_f2);
    cudaGetSymbolAddress((void**)&pfg,  g_fg);
    cudaGetSymbolAddress((void**)&pfgp, g_fgp);
    cudaGetSymbolAddress((void**)&pf3,  g_f3);
    cudaGetSymbolAddress((void**)&pxln, g_xln);
    cudaGetSymbolAddress((void**)&pxz,  g_xz);
    cudaGetSymbolAddress((void**)&pxc,  g_xc);
    cudaGetSymbolAddress((void**)&pu,   g_u);
    cudaGetSymbolAddress((void**)&ph,   g_h);
    cudaGetSymbolAddress((void**)&pcenter, g_center);
    cudaGetSymbolAddress((void**)&pdbl, g_dbl64);
    cudaGetSymbolAddress((void**)&pxpw, g_xpw);
    cudaGetSymbolAddress((void**)&pdtw, g_dtw);
    cudaGetSymbolAddress((void**)&pwe1w2, g_we1w2);
    cudaGetSymbolAddress((void**)&pwe2w1, g_we2w1);
    cudaGetSymbolAddress((void**)&pwe2w2, g_we2w2);
    cudaGetSymbolAddress((void**)&pwpw2,  g_wpw2);
    cudaGetSymbolAddress((void**)&pwinw,  g_winw);
    cudaGetSymbolAddress((void**)&pwoutw, g_woutw);

    // ---- weight prep (pre-round to tf32) ----
    prep_weights<<<(PW_TOT + 255) / 256, 256>>>(
        e1w2, e2w1, e2w2, pw2, in_w, out_w, xp_w, dt_w);

    // ---- grouping ----
    fps_kernel<<<cB, 256>>>(xyz);
    knn_kernel<<<cTOK, 256>>>(xyz);

    // ---- encoder ----
    // f2 = relu(bn1(nb@e1w1^T+e1b1)) @ e1w2^T + e1b2; also emits g_fg (group max)
    tc2<128, 128, 4, 2, 0, 2, 1, 1><<<dim3(cPTS / 128, 2), 256>>>(
        pnb, pwe1w2, e1b2, bn1g, bn1b, pf2, 128, 3, 128, 256,
        e1w1, e1b1, pfg, 256);
    // fgp = fg @ e2w1[:, 0:256]^T  (group-level half of f3; 2048 rows only)
    tc2<128, 128, 4, 2, 0, 0, 0, 0><<<dim3(cTOK / 128, 4), 256>>>(
        pfg, pwe2w1, nullptr, nullptr, nullptr, pfgp, 256, 256, 512, 512,
        nullptr, nullptr, nullptr, 0);
    // f3 = relu(bn2(f2 @ e2w1[:, 256:512]^T + fgp[group] + e2b1))  (K halved)
    tc2<128, 128, 4, 2, 1, 0, 0, 1, 1><<<dim3(cPTS / 128, 4), 256>>>(
        pf2, pwe2w1 + 256, e2b1, bn2g, bn2b, pf3, 256, 256, 512, 512,
        nullptr, nullptr, pfgp, 512);
    // f4: epilogue emits ONLY token max -> g_h
    tc2<128, 128, 4, 2, 0, 0, 2, 0><<<dim3(cPTS / 128, 3), 256>>>(
        pf3, pwe2w2, e2b2, nullptr, nullptr, nullptr, 512, 512, 512, 384,
        nullptr, nullptr, ph, 384);

    // ---- positional MLP (pos1 fused into pos2 A-loader) ----
    tc2<64, 128, 2, 2, 3, 4, 0, 0><<<dim3(cTOK / 64, 3), 128>>>(
        pcenter, pwpw2, pb2, nullptr, nullptr, ph, 128, 3, 128, 384,
        pw1, pb1, nullptr, 0);

    // ---- mamba layers ----
    constexpr int SCAN_SMEM = 128 * 64 * sizeof(float);   // 32KB
    for (int i = 0; i < cNL; i++) {
        const float* in_w_i  = pwinw  + (size_t)i * 1536 * 384;
        const float* cw_i    = convw  + (size_t)i * cDI * 4;
        const float* cb_i    = convb  + (size_t)i * cDI;
        const float* dtb_i   = dt_b   + (size_t)i * cDI;
        const float* Al_i    = A_log  + (size_t)i * cDI * cDS;
        const float* Dp_i    = Dp     + (size_t)i * cDI;
        const float* ow_i    = pwoutw + (size_t)i * 384 * 768;
        const float* lnw_i   = lnw    + (size_t)i * cDM;
        const float* lnb_i   = lnb    + (size_t)i * cDM;
        const float* xpw_i   = pxpw   + (size_t)i * 64 * cDI;
        const float* dtw_i   = pdtw   + (size_t)i * cDI * 32;

        resln_kernel<<<cTOK, 128>>>(lnw_i, lnb_i, i == 0 ? 1 : 0);
        // in-proj: (2048,384)@(1536,384)^T — 128x128, 192 blocks (one wave)
        tc2<128, 128, 4, 2, 0, 0, 0, 1><<<dim3(cTOK / 128, 12), 256>>>(
            pxln, in_w_i, nullptr, nullptr, nullptr, pxz, 384, 384, 384, 1536,
            nullptr, nullptr, nullptr, 0);
        conv_kernel<<<(cTOK * cDI + 255) / 256, 256>>>(cw_i, cb_i);
        // xp: (2048,768)@(64,768)^T — 32x64 tiles, 64 blocks
        tc2<32, 64, 2, 1, 0, 0, 0, 1><<<dim3(cTOK / 32, 1), 64>>>(
            pxc, xpw_i, nullptr, nullptr, nullptr, pdbl, 768, 768, 768, 64,
            nullptr, nullptr, nullptr, 0);
        // scan with dt fused — 128 threads, 96 blocks
        scan_kernel<<<dim3(cDI / 128, cB), 128, SCAN_SMEM>>>(
            Al_i, Dp_i, dtw_i, dtb_i);
        // out-proj: (2048,768)@(384,768)^T — 64x64, 192 blocks
        tc2<64, 64, 2, 2, 0, 0, 0, 0><<<dim3(cTOK / 64, 6), 128>>>(
            pu, ow_i, nullptr, nullptr, nullptr, ph, 768, 768, 768, 384,
            nullptr, nullptr, nullptr, 0);
    }

    // ---- final LN ----
    final_kernel<<<cTOK, 128>>>(fnw, fnb, out);
}

// round 17
// speedup vs baseline: 2.2850x; 1.0081x over previous
#include <cuda_runtime.h>
#include <math.h>
#include <float.h>

// ---------------------------------------------------------------------------
// Problem constants
// ---------------------------------------------------------------------------
constexpr int cB   = 16;
constexpr int cN   = 2048;
constexpr int cG   = 128;
constexpr int cM   = 32;
constexpr int cDM  = 384;
constexpr int cNL  = 12;
constexpr int cDI  = 768;
constexpr int cDS  = 16;
constexpr int cDTR = 24;
constexpr int cTOK = cB * cG;        // 2048 tokens
constexpr int cPTS = cTOK * cM;      // 65536 points

// ---------------------------------------------------------------------------
// Scratch (device globals; no dynamic allocation allowed)
// ---------------------------------------------------------------------------
__device__ __align__(16) float g_center[cTOK * 3];
__device__ __align__(16) float g_nb[cPTS * 3];
__device__ __align__(16) float g_f2[(size_t)cPTS * 256];
__device__ __align__(16) float g_fg[cTOK * 256];
__device__ __align__(16) float g_fgp[cTOK * 512];
__device__ __align__(16) float g_f3[(size_t)cPTS * 512];
__device__ __align__(16) float g_h[cTOK * cDM];
__device__ __align__(16) float g_res[cTOK * cDM];
__device__ __align__(16) float g_xln[cTOK * cDM];
__device__ __align__(16) float g_xz[(size_t)cTOK * 2 * cDI];
__device__ __align__(16) float g_xc[(size_t)cTOK * cDI];
__device__ __align__(16) float g_dbl64[cTOK * 64];
__device__ __align__(16) float g_u[(size_t)cTOK * cDI];
// pre-rounded (tf32/RNA) weights
__device__ __align__(16) float g_xpw[cNL * 64 * cDI];
__device__ __align__(16) float g_dtw[cNL * cDI * 32];
__device__ __align__(16) float g_we1w2[256 * 128];
__device__ __align__(16) float g_we2w1[512 * 512];
__device__ __align__(16) float g_we2w2[384 * 512];
__device__ __align__(16) float g_wpw2[384 * 128];
__device__ __align__(16) float g_winw[(size_t)cNL * 1536 * 384];
__device__ __align__(16) float g_woutw[(size_t)cNL * 384 * 768];

using u32 = unsigned int;

__device__ __forceinline__ u32 cvt_tf32(float x) {
    u32 r;
    asm("cvt.rna.tf32.f32 %0, %1;" : "=r"(r) : "f"(x));
    return r;
}
__device__ __forceinline__ float rnd_tf32(float x) {
    return __uint_as_float(cvt_tf32(x));
}

__device__ __forceinline__ u32 smem_u32(const void* p) {
    u32 a;
    asm("{ .reg .u64 t; cvta.to.shared.u64 t, %1; cvt.u32.u64 %0, t; }"
        : "=r"(a) : "l"(p));
    return a;
}

__device__ __forceinline__ void ldsm4(u32& r0, u32& r1, u32& r2, u32& r3, u32 addr) {
    asm volatile("ldmatrix.sync.aligned.m8n8.x4.shared.b16 {%0,%1,%2,%3}, [%4];"
                 : "=r"(r0), "=r"(r1), "=r"(r2), "=r"(r3) : "r"(addr));
}

__device__ __forceinline__ void cpasync16(u32 dst, const void* src) {
    asm volatile("cp.async.cg.shared.global [%0], [%1], 16;"
                 :: "r"(dst), "l"(src) : "memory");
}
#define CP_COMMIT() asm volatile("cp.async.commit_group;" ::: "memory")
#define CP_WAIT0()  asm volatile("cp.async.wait_group 0;" ::: "memory")
#define CP_WAIT1()  asm volatile("cp.async.wait_group 1;" ::: "memory")

__device__ __forceinline__ void mma_tf32(float* c, u32 a0, u32 a1, u32 a2, u32 a3,
                                         u32 b0, u32 b1) {
    asm volatile(
        "mma.sync.aligned.m16n8k8.row.col.f32.tf32.tf32.f32 "
        "{%0,%1,%2,%3}, {%4,%5,%6,%7}, {%8,%9}, {%0,%1,%2,%3};"
        : "+f"(c[0]), "+f"(c[1]), "+f"(c[2]), "+f"(c[3])
        : "r"(a0), "r"(a1), "r"(a2), "r"(a3), "r"(b0), "r"(b1));
}

// ---------------------------------------------------------------------------
// Generic tf32 tensor-core GEMM: C = epi(A' @ W^T [+ addc]).
//   Smem row-major [row][k] (stride 20 floats), ldmatrix.x4.b16 fragments,
//   3-stage cp.async pipeline. Inputs pre-rounded to tf32 (RNA) by producers.
//   EPI 0:+bias(opt). 1: relu(bn(.+bias)). 2: softplus(.+bias). 3: C+=.+bias
//   MODEA 0: A'=A. 1: cols[0,256) from aux1[row>>5][k].
//         2: relu(bn1(nb@w1^T+b1)) on the fly. 4: gelu(center@pw1^T+pb1).
//   EMAX 0: normal. 1: write C AND 32-row group max. 2: ONLY group max.
//   ROUNDC 1: RNA-round outputs (consumer is a GEMM).
//   ADDC 1: (EMAX==0 only) add fgout[(row>>5)*ldfg + n] before epilogue.
// ---------------------------------------------------------------------------
template<int BM, int BN, int WGM, int WGN, int EPI, int MODEA, int EMAX,
         int ROUNDC, int ADDC = 0>
__global__ void __launch_bounds__(WGM * WGN * 32)
tc2(const float* __restrict__ A, const float* __restrict__ W,
    const float* __restrict__ bias, const float* __restrict__ p1,
    const float* __restrict__ p2, float* __restrict__ C,
    int K, int lda, int ldw, int ldc,
    const float* __restrict__ aux1, const float* __restrict__ aux2,
    float* __restrict__ fgout, int ldfg)
{
    constexpr int THREADS = WGM * WGN * 32;
    constexpr int WTM = BM / WGM, WTN = BN / WGN;
    constexpr int MT = WTM / 16, NT = WTN / 8;
    constexpr int NP = NT / 2;
    constexpr int KS = 20;
    constexpr int A4 = (BM * 16) / (THREADS * 4);
    constexpr int W4 = (BN * 16) / (THREADS * 4);
    static_assert(EMAX == 0 || (WTM % 32) == 0, "EMAX needs WTM%32==0");
    static_assert(NT % 2 == 0, "NT must be even");

    __shared__ __align__(16) float As[3][BM][KS];
    __shared__ __align__(16) float Ws[3][BN][KS];

    const int tid = threadIdx.x;
    const int wid = tid >> 5, lane = tid & 31;
    const int grp = lane >> 2, tig = lane & 3;
    const int wm = wid % WGM, wn = wid / WGM;
    const int m0 = blockIdx.x * BM, n0 = blockIdx.y * BN;
    const float bnscale = rsqrtf(1.0f + 1e-5f);

    const u32 asBase = smem_u32(&As[0][0][0]);
    const u32 wsBase = smem_u32(&Ws[0][0][0]);
    constexpr u32 ABUF = BM * KS * 4;
    constexpr u32 WBUF = BN * KS * 4;

    u32 aOff[MT], bOff[NP];
    {
        int l7 = lane & 7;
        int aRow = ((lane >> 3) & 1) * 8;
        int aCol = (lane >> 4) * 16;
#pragma unroll
        for (int mt = 0; mt < MT; mt++) {
            int row = wm * WTM + mt * 16 + aRow + l7;
            aOff[mt] = (u32)(row * KS * 4 + aCol);
        }
        int bRow = (lane >> 4) * 8;
        int bCol = ((lane >> 3) & 1) * 16;
#pragma unroll
        for (int p = 0; p < NP; p++) {
            int row = wn * WTN + p * 16 + bRow + l7;
            bOff[p] = (u32)(row * KS * 4 + bCol);
        }
    }

    float acc[MT][NT][4];
#pragma unroll
    for (int mt = 0; mt < MT; mt++)
#pragma unroll
        for (int nt = 0; nt < NT; nt++)
#pragma unroll
            for (int r = 0; r < 4; r++) acc[mt][nt][r] = 0.f;

    float nbr[(MODEA >= 2) ? A4 : 1][3];
    if (MODEA >= 2) {
#pragma unroll
        for (int v = 0; v < A4; v++) {
            int row = (tid + v * THREADS) >> 2;
            nbr[v][0] = A[(size_t)(m0 + row) * 3 + 0];
            nbr[v][1] = A[(size_t)(m0 + row) * 3 + 1];
            nbr[v][2] = A[(size_t)(m0 + row) * 3 + 2];
        }
    }

    auto issueAW = [&](int kc, int bufSel) {
        const u32 aB = asBase + (u32)bufSel * ABUF;
        const u32 wB = wsBase + (u32)bufSel * WBUF;
        if (MODEA <= 1) {
#pragma unroll
            for (int v = 0; v < A4; v++) {
                int s = tid + v * THREADS;
                int row = s >> 2;
                int kq = (s & 3) * 4;
                int k = kc + kq;
                const float* src;
                if (MODEA == 0) {
                    src = A + (size_t)(m0 + row) * lda + k;
                } else {
                    int r = m0 + row;
                    src = (k < 256)
                        ? (aux1 + ((size_t)(r >> 5)) * 256 + k)
                        : (A + (size_t)r * lda + (k - 256));
                }
                cpasync16(aB + (u32)((row * KS + kq) * 4), src);
            }
        } else {
#pragma unroll
            for (int v = 0; v < A4; v++) {
                int s = tid + v * THREADS;
                int row = s >> 2;
                int kq = (s & 3) * 4;
                int k = kc + kq;
                float out[4];
#pragma unroll
                for (int e = 0; e < 4; e++) {
                    int kk = k + e;
                    float val = nbr[v][0] * aux1[kk * 3 + 0]
                              + nbr[v][1] * aux1[kk * 3 + 1]
                              + nbr[v][2] * aux1[kk * 3 + 2] + aux2[kk];
                    if (MODEA == 2) {
                        val = val * (p1[kk] * bnscale) + p2[kk];
                        out[e] = fmaxf(val, 0.f);
                    } else {  // gelu (tanh approx)
                        float v3 = val * val * val;
                        out[e] = 0.5f * val *
                            (1.0f + tanhf(0.7978845608028654f *
                                          (val + 0.044715f * v3)));
                    }
                }
                uint4 o;
                o.x = cvt_tf32(out[0]); o.y = cvt_tf32(out[1]);
                o.z = cvt_tf32(out[2]); o.w = cvt_tf32(out[3]);
                *reinterpret_cast<uint4*>(&As[bufSel][row][kq]) = o;
            }
        }
#pragma unroll
        for (int v = 0; v < W4; v++) {
            int s = tid + v * THREADS;
            int row = s >> 2;
            int kq = (s & 3) * 4;
            cpasync16(wB + (u32)((row * KS + kq) * 4),
                      W + (size_t)(n0 + row) * ldw + kc + kq);
        }
        CP_COMMIT();
    };

    const int nIter = K >> 4;
    issueAW(0, 0);
    if (nIter > 1) {
        issueAW(16, 1);
        CP_WAIT1();
    } else {
        CP_WAIT0();
    }
    __syncthreads();

    for (int it = 0; it < nIter; it++) {
        if (it + 2 < nIter) issueAW((it + 2) << 4, (it + 2) % 3);
        const int buf = it % 3;
        const u32 aB = asBase + (u32)buf * ABUF;
        const u32 wB = wsBase + (u32)buf * WBUF;
#pragma unroll
        for (int ks = 0; ks < 2; ks++) {
            const u32 kb = (u32)(ks * 32);
            u32 af[MT][4];
#pragma unroll
            for (int mt = 0; mt < MT; mt++)
                ldsm4(af[mt][0], af[mt][1], af[mt][2], af[mt][3],
                      aB + aOff[mt] + kb);
            u32 bf[NT][2];
#pragma unroll
            for (int p = 0; p < NP; p++) {
                u32 r0, r1, r2, r3;
                ldsm4(r0, r1, r2, r3, wB + bOff[p] + kb);
                bf[2 * p][0] = r0;     bf[2 * p][1] = r1;
                bf[2 * p + 1][0] = r2; bf[2 * p + 1][1] = r3;
            }
#pragma unroll
            for (int mt = 0; mt < MT; mt++)
#pragma unroll
                for (int nt = 0; nt < NT; nt++)
                    mma_tf32(acc[mt][nt], af[mt][0], af[mt][1], af[mt][2], af[mt][3],
                             bf[nt][0], bf[nt][1]);
        }
        if (it + 1 < nIter) {
            if (it + 2 < nIter) { CP_WAIT1(); } else { CP_WAIT0(); }
            __syncthreads();
        }
    }

    if constexpr (EMAX == 0) {
        auto emit = [&](int mrow, int n, float v0, float v1) {
            if (ADDC) {
                const float* ac = fgout + (size_t)(mrow >> 5) * ldfg + n;
                v0 += ac[0]; v1 += ac[1];
            }
            if (EPI == 3) {
                C[(size_t)mrow * ldc + n]     += v0 + bias[n];
                C[(size_t)mrow * ldc + n + 1] += v1 + bias[n + 1];
                return;
            }
            if (EPI == 0) {
                if (bias) { v0 += bias[n]; v1 += bias[n + 1]; }
            } else if (EPI == 1) {
                v0 = fmaxf((v0 + bias[n]) * (p1[n] * bnscale) + p2[n], 0.f);
                v1 = fmaxf((v1 + bias[n + 1]) * (p1[n + 1] * bnscale) + p2[n + 1], 0.f);
            } else if (EPI == 2) {
                v0 += bias[n]; v1 += bias[n + 1];
                v0 = fmaxf(v0, 0.f) + log1pf(__expf(-fabsf(v0)));
                v1 = fmaxf(v1, 0.f) + log1pf(__expf(-fabsf(v1)));
            }
            if (ROUNDC) { v0 = rnd_tf32(v0); v1 = rnd_tf32(v1); }
            float2 o; o.x = v0; o.y = v1;
            *(float2*)&C[(size_t)mrow * ldc + n] = o;
        };
#pragma unroll
        for (int mt = 0; mt < MT; mt++) {
            int mrow = m0 + wm * WTM + mt * 16 + grp;
#pragma unroll
            for (int nt = 0; nt < NT; nt++) {
                int n = n0 + wn * WTN + nt * 8 + tig * 2;
                emit(mrow,     n, acc[mt][nt][0], acc[mt][nt][1]);
                emit(mrow + 8, n, acc[mt][nt][2], acc[mt][nt][3]);
            }
        }
    } else {
        constexpr int GPW = WTM / 32;
        float mx[GPW][NT][2];
#pragma unroll
        for (int g = 0; g < GPW; g++)
#pragma unroll
            for (int nt = 0; nt < NT; nt++) {
                mx[g][nt][0] = -FLT_MAX; mx[g][nt][1] = -FLT_MAX;
            }
#pragma unroll
        for (int mt = 0; mt < MT; mt++) {
            int gsel = mt / 2;
            int mrow = m0 + wm * WTM + mt * 16 + grp;
#pragma unroll
            for (int nt = 0; nt < NT; nt++) {
                int n = n0 + wn * WTN + nt * 8 + tig * 2;
                float v0 = acc[mt][nt][0] + bias[n];
                float v1 = acc[mt][nt][1] + bias[n + 1];
                float v2 = acc[mt][nt][2] + bias[n];
                float v3 = acc[mt][nt][3] + bias[n + 1];
                if (ROUNDC) {
                    v0 = rnd_tf32(v0); v1 = rnd_tf32(v1);
                    v2 = rnd_tf32(v2); v3 = rnd_tf32(v3);
                }
                if (EMAX == 1) {
                    float2 o0; o0.x = v0; o0.y = v1;
                    float2 o1; o1.x = v2; o1.y = v3;
                    *(float2*)&C[(size_t)mrow * ldc + n] = o0;
                    *(float2*)&C[(size_t)(mrow + 8) * ldc + n] = o1;
                }
                mx[gsel][nt][0] = fmaxf(mx[gsel][nt][0], fmaxf(v0, v2));
                mx[gsel][nt][1] = fmaxf(mx[gsel][nt][1], fmaxf(v1, v3));
            }
        }
#pragma unroll
        for (int g = 0; g < GPW; g++) {
#pragma unroll
            for (int nt = 0; nt < NT; nt++)
#pragma unroll
                for (int c = 0; c < 2; c++) {
                    float v = mx[g][nt][c];
                    v = fmaxf(v, __shfl_xor_sync(0xffffffffu, v, 4));
                    v = fmaxf(v, __shfl_xor_sync(0xffffffffu, v, 8));
                    v = fmaxf(v, __shfl_xor_sync(0xffffffffu, v, 16));
                    mx[g][nt][c] = v;
                }
            if (lane < 4) {
                int grow = (m0 >> 5) + wm * GPW + g;
#pragma unroll
                for (int nt = 0; nt < NT; nt++) {
                    int n = n0 + wn * WTN + nt * 8 + tig * 2;
                    fgout[(size_t)grow * ldfg + n]     = mx[g][nt][0];
                    fgout[(size_t)grow * ldfg + n + 1] = mx[g][nt][1];
                }
            }
        }
    }
}

// ---------------------------------------------------------------------------
// Pre-round all GEMM weights to tf32 (RNA); pad xp_w/dt_w
// ---------------------------------------------------------------------------
constexpr int PW_N0 = 256 * 128;
constexpr int PW_N1 = 512 * 512;
constexpr int PW_N2 = 384 * 512;
constexpr int PW_N3 = 384 * 128;
constexpr int PW_N4 = cNL * 1536 * 384;
constexpr int PW_N5 = cNL * 384 * 768;
constexpr int PW_N6 = cNL * 64 * cDI;
constexpr int PW_N7 = cNL * cDI * 32;
constexpr int PW_O1 = PW_N0;
constexpr int PW_O2 = PW_O1 + PW_N1;
constexpr int PW_O3 = PW_O2 + PW_N2;
constexpr int PW_O4 = PW_O3 + PW_N3;
constexpr int PW_O5 = PW_O4 + PW_N4;
constexpr int PW_O6 = PW_O5 + PW_N5;
constexpr int PW_O7 = PW_O6 + PW_N6;
constexpr int PW_TOT = PW_O7 + PW_N7;

__global__ void prep_weights(const float* __restrict__ e1w2,
                             const float* __restrict__ e2w1,
                             const float* __restrict__ e2w2,
                             const float* __restrict__ pw2,
                             const float* __restrict__ in_w,
                             const float* __restrict__ out_w,
                             const float* __restrict__ xp_w,
                             const float* __restrict__ dt_w) {
    int idx = blockIdx.x * 256 + threadIdx.x;
    if (idx >= PW_TOT) return;
    float v; float* dst;
    if (idx < PW_O1)      { v = e1w2[idx];          dst = g_we1w2 + idx; }
    else if (idx < PW_O2) { v = e2w1[idx - PW_O1];  dst = g_we2w1 + (idx - PW_O1); }
    else if (idx < PW_O3) { v = e2w2[idx - PW_O2];  dst = g_we2w2 + (idx - PW_O2); }
    else if (idx < PW_O4) { v = pw2[idx - PW_O3];   dst = g_wpw2 + (idx - PW_O3); }
    else if (idx < PW_O5) { v = in_w[idx - PW_O4];  dst = g_winw + (idx - PW_O4); }
    else if (idx < PW_O6) { v = out_w[idx - PW_O5]; dst = g_woutw + (idx - PW_O5); }
    else if (idx < PW_O7) {
        int j = idx - PW_O6;
        int l = j / (64 * cDI);
        int r = (j / cDI) % 64;
        int k = j % cDI;
        v = (r < 56) ? xp_w[((size_t)l * 56 + r) * cDI + k] : 0.f;
        dst = g_xpw + j;
    } else {
        int j = idx - PW_O7;
        int l = j / (cDI * 32);
        int d = (j / 32) % cDI;
        int k = j % 32;
        v = (k < 24) ? dt_w[((size_t)l * cDI + d) * cDTR + k] : 0.f;
        dst = g_dtw + j;
    }
    *dst = __uint_as_float(cvt_tf32(v));
}

// ---------------------------------------------------------------------------
// FPS
// ---------------------------------------------------------------------------
__global__ void fps_kernel(const float* __restrict__ xyz) {
    int b = blockIdx.x;
    __shared__ float px[cN], py[cN], pz[cN], dmin[cN];
    __shared__ float wv[8];
    __shared__ int   wi[8];
    __shared__ int   s_cur;
    int tid = threadIdx.x;
    int wid = tid >> 5, lane = tid & 31;
    for (int i = tid; i < cN; i += 256) {
        px[i] = xyz[(b * cN + i) * 3 + 0];
        py[i] = xyz[(b * cN + i) * 3 + 1];
        pz[i] = xyz[(b * cN + i) * 3 + 2];
        dmin[i] = 1e10f;
    }
    __syncthreads();
    int cur = 0;
    for (int g = 0; g < cG; g++) {
        float cx = px[cur], cy = py[cur], cz = pz[cur];
        if (tid == 0) {
            g_center[(b * cG + g) * 3 + 0] = cx;
            g_center[(b * cG + g) * 3 + 1] = cy;
            g_center[(b * cG + g) * 3 + 2] = cz;
        }
        float bv = -1.f; int bi = 0x7fffffff;
        for (int i = tid; i < cN; i += 256) {
            float dx = __fsub_rn(px[i], cx);
            float dy = __fsub_rn(py[i], cy);
            float dz = __fsub_rn(pz[i], cz);
            float dd = __fadd_rn(__fadd_rn(__fmul_rn(dx, dx), __fmul_rn(dy, dy)),
                                 __fmul_rn(dz, dz));
            float dm = fminf(dmin[i], dd);
            dmin[i] = dm;
            if (dm > bv) { bv = dm; bi = i; }
        }
#pragma unroll
        for (int off = 16; off > 0; off >>= 1) {
            float ov = __shfl_xor_sync(0xffffffffu, bv, off);
            int oi = __shfl_xor_sync(0xffffffffu, bi, off);
            if (ov > bv || (ov == bv && oi < bi)) { bv = ov; bi = oi; }
        }
        if (lane == 0) { wv[wid] = bv; wi[wid] = bi; }
        __syncthreads();
        if (tid < 8) {
            bv = wv[tid]; bi = wi[tid];
#pragma unroll
            for (int off = 4; off > 0; off >>= 1) {
                float ov = __shfl_xor_sync(0xffu, bv, off);
                int oi = __shfl_xor_sync(0xffu, bi, off);
                if (ov > bv || (ov == bv && oi < bi)) { bv = ov; bi = oi; }
            }
            if (tid == 0) s_cur = bi;
        }
        __syncthreads();
        cur = s_cur;
    }
}

// ---------------------------------------------------------------------------
// KNN
// ---------------------------------------------------------------------------
__global__ void knn_kernel(const float* __restrict__ xyz) {
    int bg = blockIdx.x;
    int b = bg >> 7;
    __shared__ float d2s[cN];
    __shared__ float wv[8];
    __shared__ int   wi[8];
    __shared__ int   s_idx;
    int tid = threadIdx.x;
    int wid = tid >> 5, lane = tid & 31;
    float cx = g_center[bg * 3 + 0], cy = g_center[bg * 3 + 1], cz = g_center[bg * 3 + 2];
    const float* P = xyz + (size_t)b * cN * 3;
    for (int i = tid; i < cN; i += 256) {
        float dx = __fsub_rn(cx, P[i * 3 + 0]);
        float dy = __fsub_rn(cy, P[i * 3 + 1]);
        float dz = __fsub_rn(cz, P[i * 3 + 2]);
        d2s[i] = __fadd_rn(__fadd_rn(__fmul_rn(dx, dx), __fmul_rn(dy, dy)),
                           __fmul_rn(dz, dz));
    }
    __syncthreads();
    for (int m = 0; m < cM; m++) {
        float bv = FLT_MAX; int bi = 0x7fffffff;
        for (int i = tid; i < cN; i += 256) {
            float v = d2s[i];
            if (v < bv) { bv = v; bi = i; }
        }
#pragma unroll
        for (int off = 16; off > 0; off >>= 1) {
            float ov = __shfl_xor_sync(0xffffffffu, bv, off);
            int oi = __shfl_xor_sync(0xffffffffu, bi, off);
            if (ov < bv || (ov == bv && oi < bi)) { bv = ov; bi = oi; }
        }
        if (lane == 0) { wv[wid] = bv; wi[wid] = bi; }
        __syncthreads();
        if (tid < 8) {
            bv = wv[tid]; bi = wi[tid];
#pragma unroll
            for (int off = 4; off > 0; off >>= 1) {
                float ov = __shfl_xor_sync(0xffu, bv, off);
                int oi = __shfl_xor_sync(0xffu, bi, off);
                if (ov < bv || (ov == bv && oi < bi)) { bv = ov; bi = oi; }
            }
            if (tid == 0) s_idx = bi;
        }
        __syncthreads();
        int idx = s_idx;
        if (tid < 3) {
            float c = (tid == 0) ? cx : ((tid == 1) ? cy : cz);
            g_nb[((size_t)bg * cM + m) * 3 + tid] = __fsub_rn(P[idx * 3 + tid], c);
        }
        if (tid == 0) d2s[idx] = FLT_MAX;
        __syncthreads();
    }
}

// ---------------------------------------------------------------------------
// Residual accumulate + LayerNorm (xln rounded to tf32; res stays fp32)
// ---------------------------------------------------------------------------
__device__ __forceinline__ float block_sum_128(float v, float* sm) {
    int tid = threadIdx.x;
    sm[tid] = v; __syncthreads();
    for (int s = 64; s > 0; s >>= 1) {
        if (tid < s) sm[tid] += sm[tid + s];
        __syncthreads();
    }
    float r = sm[0]; __syncthreads();
    return r;
}

__global__ void resln_kernel(const float* __restrict__ w, const float* __restrict__ b,
                             int first) {
    __shared__ float sm[128];
    int t = blockIdx.x;
    float v[3];
#pragma unroll
    for (int j = 0; j < 3; j++) {
        int c = threadIdx.x + j * 128;
        float r = g_h[t * 384 + c];
        if (!first) r += g_res[t * 384 + c];
        g_res[t * 384 + c] = r;
        v[j] = r;
    }
    float mean = block_sum_128(v[0] + v[1] + v[2], sm) * (1.0f / 384.0f);
    float sq = 0.f;
#pragma unroll
    for (int j = 0; j < 3; j++) { float d = v[j] - mean; sq += d * d; }
    float var = block_sum_128(sq, sm) * (1.0f / 384.0f);
    float inv = rsqrtf(var + 1e-5f);
#pragma unroll
    for (int j = 0; j < 3; j++) {
        int c = threadIdx.x + j * 128;
        g_xln[t * 384 + c] = rnd_tf32((v[j] - mean) * inv * w[c] + b[c]);
    }
}

__global__ void final_kernel(const float* __restrict__ w, const float* __restrict__ b,
                             float* __restrict__ out) {
    __shared__ float sm[128];
    int t = blockIdx.x;
    float v[3];
#pragma unroll
    for (int j = 0; j < 3; j++) {
        int c = threadIdx.x + j * 128;
        v[j] = g_h[t * 384 + c] + g_res[t * 384 + c];
    }
    float mean = block_sum_128(v[0] + v[1] + v[2], sm) * (1.0f / 384.0f);
    float sq = 0.f;
#pragma unroll
    for (int j = 0; j < 3; j++) { float d = v[j] - mean; sq += d * d; }
    float var = block_sum_128(sq, sm) * (1.0f / 384.0f);
    float inv = rsqrtf(var + 1e-5f);
#pragma unroll
    for (int j = 0; j < 3; j++) {
        int c = threadIdx.x + j * 128;
        out[t * 384 + c] = (v[j] - mean) * inv * w[c] + b[c];
    }
}

// ---------------------------------------------------------------------------
// Depthwise causal conv (DC=4) + bias + silu (output rounded to tf32)
// ---------------------------------------------------------------------------
__global__ void conv_kernel(const float* __restrict__ cw, const float* __restrict__ cb) {
    int idx = blockIdx.x * blockDim.x + threadIdx.x;
    if (idx >= cTOK * cDI) return;
    int t = idx / cDI, d = idx % cDI;
    int l = t & 127;
    int tbase = t - l;
    float acc = cb[d];
#pragma unroll
    for (int k = 0; k < 4; k++) {
        int lk = l - 3 + k;
        if (lk >= 0)
            acc += g_xz[(size_t)(tbase + lk) * 1536 + d] * cw[d * 4 + k];
    }
    float sig = 1.0f / (1.0f + __expf(-acc));
    g_xc[idx] = rnd_tf32(acc * sig);
}

// ---------------------------------------------------------------------------
// Selective scan v4: dt computed inline (dbl[:24] @ dtw row + softplus),
// full dbl64 rows staged in smem; one thread per (b,d); q-power fast path.
// ---------------------------------------------------------------------------
template<bool FAST>
__device__ __forceinline__ void scan_body(
    int b, int d, float a0, const float* a, float Dpd,
    const float* dtr, float dtbd) {
    extern __shared__ float sD[];   // [128][64]
    float h[16];
#pragma unroll
    for (int s = 0; s < 16; s++) h[s] = 0.f;

    const float* pxc = g_xc + (size_t)b * 128 * cDI + d;
    const float* pz  = g_xz + (size_t)b * 128 * 1536 + cDI + d;
    float* pu = g_u + (size_t)b * 128 * cDI + d;

    for (int t = 0; t < 128; t++) {
        const float* Dt = sD + t * 64;
        float acc = dtbd;
#pragma unroll
        for (int r = 0; r < 24; r++) acc += Dt[r] * dtr[r];
        float dt = fmaxf(acc, 0.f) + log1pf(__expf(-fabsf(acc)));
        float xin = pxc[(size_t)t * cDI];
        float u = dt * xin;
        float p[16];
        if (FAST) {
            float q = __expf(dt * a0);
            float q2 = q * q, q4 = q2 * q2, q8 = q4 * q4;
            p[0] = q;        p[1] = q2;       p[2] = q2 * q;   p[3] = q4;
            p[4] = q4 * q;   p[5] = q4 * q2;  p[6] = p[5] * q; p[7] = q8;
            p[8] = q8 * q;   p[9] = q8 * q2;  p[10] = p[9] * q;
            p[11] = q8 * q4; p[12] = p[11] * q; p[13] = p[11] * q2;
            p[14] = p[13] * q; p[15] = q8 * q8;
        } else {
#pragma unroll
            for (int s = 0; s < 16; s++) p[s] = __expf(dt * a[s]);
        }
        float y = 0.f;
#pragma unroll
        for (int s = 0; s < 16; s++) {
            h[s] = p[s] * h[s] + u * Dt[24 + s];
            y += h[s] * Dt[40 + s];
        }
        y += Dpd * xin;
        float z = pz[(size_t)t * 1536];
        float sz = z / (1.0f + __expf(-z));
        pu[(size_t)t * cDI] = rnd_tf32(y * sz);
    }
}

__global__ void __launch_bounds__(128)
scan_kernel(const float* __restrict__ Alog, const float* __restrict__ Dp,
            const float* __restrict__ dtw, const float* __restrict__ dtb) {
    extern __shared__ float sD[];   // 128*64 floats = 32KB
    int tid = threadIdx.x;
    int b = blockIdx.y;
    int d = blockIdx.x * 128 + tid;

    for (int i = tid; i < 128 * 16; i += 128)
        ((float4*)sD)[i] = ((const float4*)g_dbl64)[(size_t)b * 128 * 16 + i];
    __syncthreads();

    float dtr[24];
#pragma unroll
    for (int r = 0; r < 24; r++) dtr[r] = dtw[d * 32 + r];
    float dtbd = dtb[d];

    float a[16];
    bool fast = true;
#pragma unroll
    for (int s = 0; s < 16; s++) a[s] = -expf(Alog[d * 16 + s]);
    float a0 = a[0];
#pragma unroll
    for (int s = 1; s < 16; s++) {
        float ideal = (float)(s + 1) * a0;
        if (fabsf(a[s] - ideal) > 1e-4f * fabsf(ideal)) fast = false;
    }
    float Dpd = Dp[d];

    if (fast) scan_body<true>(b, d, a0, a, Dpd, dtr, dtbd);
    else      scan_body<false>(b, d, a0, a, Dpd, dtr, dtbd);
}

// ---------------------------------------------------------------------------
// Host-side launch sequence
// ---------------------------------------------------------------------------
extern "C" void kernel_launch(void* const* d_in, const int* in_sizes, int n_in,
                              void* d_out, int out_size) {
    const float* xyz   = (const float*)d_in[0];
    const float* e1w1  = (const float*)d_in[1];
    const float* e1b1  = (const float*)d_in[2];
    const float* bn1g  = (const float*)d_in[3];
    const float* bn1b  = (const float*)d_in[4];
    const float* e1w2  = (const float*)d_in[5];
    const float* e1b2  = (const float*)d_in[6];
    const float* e2w1  = (const float*)d_in[7];
    const float* e2b1  = (const float*)d_in[8];
    const float* bn2g  = (const float*)d_in[9];
    const float* bn2b  = (const float*)d_in[10];
    const float* e2w2  = (const float*)d_in[11];
    const float* e2b2  = (const float*)d_in[12];
    const float* pw1   = (const float*)d_in[13];
    const float* pb1   = (const float*)d_in[14];
    const float* pw2   = (const float*)d_in[15];
    const float* pb2   = (const float*)d_in[16];
    const float* in_w  = (const float*)d_in[17];
    const float* convw = (const float*)d_in[18];
    const float* convb = (const float*)d_in[19];
    const float* xp_w  = (const float*)d_in[20];
    const float* dt_w  = (const float*)d_in[21];
    const float* dt_b  = (const float*)d_in[22];
    const float* A_log = (const float*)d_in[23];
    const float* Dp    = (const float*)d_in[24];
    const float* out_w = (const float*)d_in[25];
    const float* lnw   = (const float*)d_in[26];
    const float* lnb   = (const float*)d_in[27];
    const float* fnw   = (const float*)d_in[28];
    const float* fnb   = (const float*)d_in[29];
    float* out = (float*)d_out;

    float *pnb, *pf2, *pfg, *pfgp, *pf3, *pxln, *pxz, *pxc, *pu, *ph, *pcenter,
          *pdbl, *pxpw, *pdtw;
    float *pwe1w2, *pwe2w1, *pwe2w2, *pwpw2, *pwinw, *pwoutw;
    cudaGetSymbolAddress((void**)&pnb,  g_nb);
    cudaGetSymbolAddress((void**)&pf2,  g_f2);
    cudaGetSymbolAddress((void**)&pfg,  g_fg);
    cudaGetSymbolAddress((void**)&pfgp, g_fgp);
    cudaGetSymbolAddress((void**)&pf3,  g_f3);
    cudaGetSymbolAddress((void**)&pxln, g_xln);
    cudaGetSymbolAddress((void**)&pxz,  g_xz);
    cudaGetSymbolAddress((void**)&pxc,  g_xc);
    cudaGetSymbolAddress((void**)&pu,   g_u);
    cudaGetSymbolAddress((void**)&ph,   g_h);
    cudaGetSymbolAddress((void**)&pcenter, g_center);
    cudaGetSymbolAddress((void**)&pdbl, g_dbl64);
    cudaGetSymbolAddress((void**)&pxpw, g_xpw);
    cudaGetSymbolAddress((void**)&pdtw, g_dtw);
    cudaGetSymbolAddress((void**)&pwe1w2, g_we1w2);
    cudaGetSymbolAddress((void**)&pwe2w1, g_we2w1);
    cudaGetSymbolAddress((void**)&pwe2w2, g_we2w2);
    cudaGetSymbolAddress((void**)&pwpw2,  g_wpw2);
    cudaGetSymbolAddress((void**)&pwinw,  g_winw);
    cudaGetSymbolAddress((void**)&pwoutw, g_woutw);

    // ---- weight prep (pre-round to tf32) ----
    prep_weights<<<(PW_TOT + 255) / 256, 256>>>(
        e1w2, e2w1, e2w2, pw2, in_w, out_w, xp_w, dt_w);

    // ---- grouping ----
    fps_kernel<<<cB, 256>>>(xyz);
    knn_kernel<<<cTOK, 256>>>(xyz);

    // ---- encoder (128x128 CTA, 4 warps, 64x64 warp tiles) ----
    // f2 = relu(bn1(nb@e1w1^T+e1b1)) @ e1w2^T + e1b2; also emits g_fg (group max)
    tc2<128, 128, 2, 2, 0, 2, 1, 1><<<dim3(cPTS / 128, 2), 128>>>(
        pnb, pwe1w2, e1b2, bn1g, bn1b, pf2, 128, 3, 128, 256,
        e1w1, e1b1, pfg, 256);
    // fgp = fg @ e2w1[:, 0:256]^T  (group-level half of f3; 2048 rows only)
    tc2<128, 128, 2, 2, 0, 0, 0, 0><<<dim3(cTOK / 128, 4), 128>>>(
        pfg, pwe2w1, nullptr, nullptr, nullptr, pfgp, 256, 256, 512, 512,
        nullptr, nullptr, nullptr, 0);
    // f3 = relu(bn2(f2 @ e2w1[:, 256:512]^T + fgp[group] + e2b1))  (K halved)
    tc2<128, 128, 2, 2, 1, 0, 0, 1, 1><<<dim3(cPTS / 128, 4), 128>>>(
        pf2, pwe2w1 + 256, e2b1, bn2g, bn2b, pf3, 256, 256, 512, 512,
        nullptr, nullptr, pfgp, 512);
    // f4: epilogue emits ONLY token max -> g_h
    tc2<128, 128, 2, 2, 0, 0, 2, 0><<<dim3(cPTS / 128, 3), 128>>>(
        pf3, pwe2w2, e2b2, nullptr, nullptr, nullptr, 512, 512, 512, 384,
        nullptr, nullptr, ph, 384);

    // ---- positional MLP (pos1 fused into pos2 A-loader) ----
    tc2<64, 128, 2, 2, 3, 4, 0, 0><<<dim3(cTOK / 64, 3), 128>>>(
        pcenter, pwpw2, pb2, nullptr, nullptr, ph, 128, 3, 128, 384,
        pw1, pb1, nullptr, 0);

    // ---- mamba layers ----
    constexpr int SCAN_SMEM = 128 * 64 * sizeof(float);   // 32KB
    for (int i = 0; i < cNL; i++) {
        const float* in_w_i  = pwinw  + (size_t)i * 1536 * 384;
        const float* cw_i    = convw  + (size_t)i * cDI * 4;
        const float* cb_i    = convb  + (size_t)i * cDI;
        const float* dtb_i   = dt_b   + (size_t)i * cDI;
        const float* Al_i    = A_log  + (size_t)i * cDI * cDS;
        const float* Dp_i    = Dp     + (size_t)i * cDI;
        const float* ow_i    = pwoutw + (size_t)i * 384 * 768;
        const float* lnw_i   = lnw    + (size_t)i * cDM;
        const float* lnb_i   = lnb    + (size_t)i * cDM;
        const float* xpw_i   = pxpw   + (size_t)i * 64 * cDI;
        const float* dtw_i   = pdtw   + (size_t)i * cDI * 32;

        resln_kernel<<<cTOK, 128>>>(lnw_i, lnb_i, i == 0 ? 1 : 0);
        // in-proj: (2048,384)@(1536,384)^T — 128x128 CTA, 4 warps
        tc2<128, 128, 2, 2, 0, 0, 0, 1><<<dim3(cTOK / 128, 12), 128>>>(
            pxln, in_w_i, nullptr, nullptr, nullptr, pxz, 384, 384, 384, 1536,
            nullptr, nullptr, nullptr, 0);
        conv_kernel<<<(cTOK * cDI + 255) / 256, 256>>>(cw_i, cb_i);
        // xp: (2048,768)@(64,768)^T — 32x64 tiles, 64 blocks
        tc2<32, 64, 2, 1, 0, 0, 0, 1><<<dim3(cTOK / 32, 1), 64>>>(
            pxc, xpw_i, nullptr, nullptr, nullptr, pdbl, 768, 768, 768, 64,
            nullptr, nullptr, nullptr, 0);
        // scan with dt fused — 128 threads, 96 blocks
        scan_kernel<<<dim3(cDI / 128, cB), 128, SCAN_SMEM>>>(
            Al_i, Dp_i, dtw_i, dtb_i);
        // out-proj: (2048,768)@(384,768)^T — 64x64, 192 blocks
        tc2<64, 64, 2, 2, 0, 0, 0, 0><<<dim3(cTOK / 64, 6), 128>>>(
            pu, ow_i, nullptr, nullptr, nullptr, ph, 768, 768, 768, 384,
            nullptr, nullptr, nullptr, 0);
    }

    // ---- final LN ----
    final_kernel<<<cTOK, 128>>>(fnw, fnb, out);
}